// round 4
// baseline (speedup 1.0000x reference)
#include <cuda_runtime.h>
#include <cuda_bf16.h>
#include <math.h>
#include <stdint.h>

// ---------------- problem constants ----------------
#define Bsz   128
#define NTOK  64
#define Cdim  784
#define NHd   8
#define HD    98
#define HID   3136
#define ROWS  (Bsz*NTOK)  // 8192
#define NREG  49
#define TOPK  4
#define OUT_OFF (Bsz*NTOK*Cdim)

// ---------------- scratch ----------------
__device__ __nv_bfloat16 g_h_hi [ROWS*Cdim];
__device__ __nv_bfloat16 g_h_lo [ROWS*Cdim];
__device__ float         g_qkv  [ROWS*3*Cdim];
__device__ __nv_bfloat16 g_att_hi[ROWS*Cdim];
__device__ __nv_bfloat16 g_att_lo[ROWS*Cdim];
__device__ float         g_o    [ROWS*Cdim];
__device__ float         g_xr   [ROWS*Cdim];
__device__ __nv_bfloat16 g_h2_hi[ROWS*Cdim];
__device__ __nv_bfloat16 g_h2_lo[ROWS*Cdim];
__device__ __nv_bfloat16 g_hid_hi[ROWS*HID];
__device__ __nv_bfloat16 g_hid_lo[ROWS*HID];
// weight splits
__device__ __nv_bfloat16 g_wqkv_hi[Cdim*3*Cdim];
__device__ __nv_bfloat16 g_wqkv_lo[Cdim*3*Cdim];
__device__ __nv_bfloat16 g_wproj_hi[Cdim*Cdim];
__device__ __nv_bfloat16 g_wproj_lo[Cdim*Cdim];
__device__ __nv_bfloat16 g_wfc1_hi[Cdim*HID];
__device__ __nv_bfloat16 g_wfc1_lo[Cdim*HID];
__device__ __nv_bfloat16 g_wfc2_hi[HID*Cdim];
__device__ __nv_bfloat16 g_wfc2_lo[HID*Cdim];
// biformer
__device__ float g_bfqkv[Bsz*192*784];
__device__ float g_attg [Bsz*64*784];
__device__ float g_qr  [Bsz*64*NREG];
__device__ float g_kr  [Bsz*64*NREG];
__device__ int   g_idx [Bsz*NREG*TOPK];

// ---------------- helpers ----------------
__device__ __forceinline__ uint32_t smem_u32(const void* p) {
    return (uint32_t)__cvta_generic_to_shared(p);
}
#define CP_ASYNC16(dst_u32, src, sz) \
    asm volatile("cp.async.cg.shared.global [%0], [%1], 16, %2;\n" :: "r"(dst_u32), "l"(src), "r"(sz))
#define CP_COMMIT() asm volatile("cp.async.commit_group;\n")
#define CP_WAIT1()  asm volatile("cp.async.wait_group 1;\n")
#define CP_WAIT0()  asm volatile("cp.async.wait_group 0;\n")
#define LDSM4(r0,r1,r2,r3,a) \
    asm volatile("ldmatrix.sync.aligned.m8n8.x4.shared.b16 {%0,%1,%2,%3},[%4];" \
        : "=r"(r0),"=r"(r1),"=r"(r2),"=r"(r3) : "r"(a))
#define LDSM4T(r0,r1,r2,r3,a) \
    asm volatile("ldmatrix.sync.aligned.m8n8.x4.trans.shared.b16 {%0,%1,%2,%3},[%4];" \
        : "=r"(r0),"=r"(r1),"=r"(r2),"=r"(r3) : "r"(a))
#define MMA_BF16(d, a, b) \
    asm volatile("mma.sync.aligned.m16n8k16.row.col.f32.bf16.bf16.f32 " \
        "{%0,%1,%2,%3},{%4,%5,%6,%7},{%8,%9},{%0,%1,%2,%3};" \
        : "+f"(d[0]),"+f"(d[1]),"+f"(d[2]),"+f"(d[3]) \
        : "r"(a[0]),"r"(a[1]),"r"(a[2]),"r"(a[3]),"r"(b[0]),"r"(b[1]))

__device__ __forceinline__ void split_write(float v, __nv_bfloat16* hi, __nv_bfloat16* lo, size_t o) {
    __nv_bfloat16 h = __float2bfloat16(v);
    hi[o] = h;
    lo[o] = __float2bfloat16(v - __bfloat162float(h));
}

// ---------------- weight split ----------------
__global__ void split_kernel(const float* __restrict__ in, __nv_bfloat16* __restrict__ hi,
                             __nv_bfloat16* __restrict__ lo, int n) {
    int i = blockIdx.x * blockDim.x + threadIdx.x;
    if (i < n) {
        float v = in[i];
        __nv_bfloat16 h = __float2bfloat16(v);
        hi[i] = h;
        lo[i] = __float2bfloat16(v - __bfloat162float(h));
    }
}

// ---------------- LN1: x -> (h_hi, h_lo) ----------------
__global__ void ln_kernel(const float* __restrict__ x,
                          const float* __restrict__ g, const float* __restrict__ b,
                          __nv_bfloat16* __restrict__ ohi, __nv_bfloat16* __restrict__ olo) {
    int row = blockIdx.x;
    const float* xr = x + (size_t)row * Cdim;
    __shared__ float buf[Cdim];
    __shared__ float rs[2];
    __shared__ float red[64];
    float s = 0.f, ss = 0.f;
    for (int i = threadIdx.x; i < Cdim; i += blockDim.x) {
        float v = xr[i]; buf[i] = v; s += v; ss += v * v;
    }
    for (int o = 16; o > 0; o >>= 1) { s += __shfl_down_sync(~0u, s, o); ss += __shfl_down_sync(~0u, ss, o); }
    int wid = threadIdx.x >> 5, lid = threadIdx.x & 31;
    if (lid == 0) { red[wid] = s; red[wid + 32] = ss; }
    __syncthreads();
    if (threadIdx.x == 0) {
        float t = 0.f, tt = 0.f;
        int nw = blockDim.x >> 5;
        for (int i = 0; i < nw; i++) { t += red[i]; tt += red[i + 32]; }
        float mean = t / Cdim, var = tt / Cdim - mean * mean;
        rs[0] = mean; rs[1] = rsqrtf(var + 1e-5f);
    }
    __syncthreads();
    float mean = rs[0], inv = rs[1];
    for (int i = threadIdx.x; i < Cdim; i += blockDim.x)
        split_write((buf[i] - mean) * inv * g[i] + b[i], ohi, olo, (size_t)row * Cdim + i);
}

// ---------------- LN2: xr = o + x (fp32 out), h2 split ----------------
__global__ void ln2_kernel(const float* __restrict__ ov, const float* __restrict__ x,
                           const float* __restrict__ g, const float* __restrict__ b,
                           float* __restrict__ xr_out,
                           __nv_bfloat16* __restrict__ ohi, __nv_bfloat16* __restrict__ olo) {
    int row = blockIdx.x;
    const float* a = ov + (size_t)row * Cdim;
    const float* c = x  + (size_t)row * Cdim;
    __shared__ float buf[Cdim];
    __shared__ float rs[2];
    __shared__ float red[64];
    float s = 0.f, ss = 0.f;
    for (int i = threadIdx.x; i < Cdim; i += blockDim.x) {
        float v = a[i] + c[i];
        buf[i] = v;
        xr_out[(size_t)row * Cdim + i] = v;
        s += v; ss += v * v;
    }
    for (int o = 16; o > 0; o >>= 1) { s += __shfl_down_sync(~0u, s, o); ss += __shfl_down_sync(~0u, ss, o); }
    int wid = threadIdx.x >> 5, lid = threadIdx.x & 31;
    if (lid == 0) { red[wid] = s; red[wid + 32] = ss; }
    __syncthreads();
    if (threadIdx.x == 0) {
        float t = 0.f, tt = 0.f;
        int nw = blockDim.x >> 5;
        for (int i = 0; i < nw; i++) { t += red[i]; tt += red[i + 32]; }
        float mean = t / Cdim, var = tt / Cdim - mean * mean;
        rs[0] = mean; rs[1] = rsqrtf(var + 1e-5f);
    }
    __syncthreads();
    float mean = rs[0], inv = rs[1];
    for (int i = threadIdx.x; i < Cdim; i += blockDim.x)
        split_write((buf[i] - mean) * inv * g[i] + b[i], ohi, olo, (size_t)row * Cdim + i);
}

// ---------------- bf16x3 tensor-core GEMM ----------------
// C[M,N] = A[M,K] @ B[K,N], A/B given as (hi,lo) bf16 splits, fp32 accumulate.
// EP: 0 plain fp32 out; 1 +bias fp32 out; 2 +bias, GELU, split-bf16 out; 3 +bias +res fp32 out
#define BM 128
#define BN 128
#define BK 16
#define ASTR 24
#define BSTR 136

template<int EP>
__global__ __launch_bounds__(256, 1)
void mma_gemm(const __nv_bfloat16* __restrict__ Ah, const __nv_bfloat16* __restrict__ Al,
              const __nv_bfloat16* __restrict__ Bh, const __nv_bfloat16* __restrict__ Bl,
              const float* __restrict__ bias, const float* __restrict__ res,
              float* __restrict__ Cf, __nv_bfloat16* __restrict__ Chi, __nv_bfloat16* __restrict__ Clo,
              int M, int N, int K) {
    __shared__ __nv_bfloat16 As[2][2][BM][ASTR];
    __shared__ __nv_bfloat16 Bs[2][2][BK][BSTR];
    int tid = threadIdx.x;
    int warp = tid >> 5, lane = tid & 31;
    int wm = warp & 1, wn = warp >> 1;          // 2 x 4 warp grid
    int rowBase = blockIdx.y * BM, colBase = blockIdx.x * BN;

    int a_row = tid >> 1;                        // 0..127
    int a_col = (tid & 1) * 8;                   // 0/8
    int b_row = tid >> 4;                        // 0..15
    int b_col = (tid & 15) * 8;                  // 0..120
    int gcol  = colBase + b_col;
    int bsz   = (gcol < N) ? 16 : 0;

    const int KT = K / BK;
    float acc[4][4][4];
    #pragma unroll
    for (int i = 0; i < 4; i++)
        #pragma unroll
        for (int j = 0; j < 4; j++)
            #pragma unroll
            for (int k = 0; k < 4; k++) acc[i][j][k] = 0.f;

    // precomputed smem write addresses
    uint32_t sAh[2], sAl[2], sBh[2], sBl[2];
    #pragma unroll
    for (int bf = 0; bf < 2; bf++) {
        sAh[bf] = smem_u32(&As[bf][0][a_row][a_col]);
        sAl[bf] = smem_u32(&As[bf][1][a_row][a_col]);
        sBh[bf] = smem_u32(&Bs[bf][0][b_row][b_col]);
        sBl[bf] = smem_u32(&Bs[bf][1][b_row][b_col]);
    }
    // ldmatrix read addresses (per buffer, hi/lo)
    int lrow = lane & 15, lhalf = (lane >> 4) * 8;

    // prologue: stage 0
    {
        size_t a_off = (size_t)(rowBase + a_row) * K + a_col;
        CP_ASYNC16(sAh[0], Ah + a_off, 16);
        CP_ASYNC16(sAl[0], Al + a_off, 16);
        size_t b_off = (size_t)b_row * N + gcol;
        const __nv_bfloat16* ph = (bsz ? Bh + b_off : Bh);
        const __nv_bfloat16* pl = (bsz ? Bl + b_off : Bl);
        CP_ASYNC16(sBh[0], ph, bsz);
        CP_ASYNC16(sBl[0], pl, bsz);
        CP_COMMIT();
    }

    for (int kt = 0; kt < KT; kt++) {
        if (kt + 1 < KT) {
            int bf = (kt + 1) & 1;
            size_t a_off = (size_t)(rowBase + a_row) * K + (kt + 1) * BK + a_col;
            CP_ASYNC16(sAh[bf], Ah + a_off, 16);
            CP_ASYNC16(sAl[bf], Al + a_off, 16);
            size_t b_off = (size_t)((kt + 1) * BK + b_row) * N + gcol;
            const __nv_bfloat16* ph = (bsz ? Bh + b_off : Bh);
            const __nv_bfloat16* pl = (bsz ? Bl + b_off : Bl);
            CP_ASYNC16(sBh[bf], ph, bsz);
            CP_ASYNC16(sBl[bf], pl, bsz);
            CP_COMMIT();
            CP_WAIT1();
        } else {
            CP_WAIT0();
        }
        __syncthreads();
        int bf = kt & 1;

        uint32_t ah[4][4], al[4][4], bh[4][2], bl[4][2];
        #pragma unroll
        for (int mi = 0; mi < 4; mi++) {
            uint32_t a0 = smem_u32(&As[bf][0][wm * 64 + mi * 16 + lrow][lhalf]);
            LDSM4(ah[mi][0], ah[mi][1], ah[mi][2], ah[mi][3], a0);
            uint32_t a1 = smem_u32(&As[bf][1][wm * 64 + mi * 16 + lrow][lhalf]);
            LDSM4(al[mi][0], al[mi][1], al[mi][2], al[mi][3], a1);
        }
        #pragma unroll
        for (int pr = 0; pr < 2; pr++) {
            uint32_t r0, r1, r2, r3;
            uint32_t b0 = smem_u32(&Bs[bf][0][lrow][wn * 32 + pr * 16 + lhalf]);
            LDSM4T(r0, r1, r2, r3, b0);
            bh[pr * 2][0] = r0; bh[pr * 2][1] = r1; bh[pr * 2 + 1][0] = r2; bh[pr * 2 + 1][1] = r3;
            uint32_t b1 = smem_u32(&Bs[bf][1][lrow][wn * 32 + pr * 16 + lhalf]);
            LDSM4T(r0, r1, r2, r3, b1);
            bl[pr * 2][0] = r0; bl[pr * 2][1] = r1; bl[pr * 2 + 1][0] = r2; bl[pr * 2 + 1][1] = r3;
        }
        #pragma unroll
        for (int mi = 0; mi < 4; mi++)
            #pragma unroll
            for (int ni = 0; ni < 4; ni++) {
                MMA_BF16(acc[mi][ni], ah[mi], bh[ni]);
                MMA_BF16(acc[mi][ni], ah[mi], bl[ni]);
                MMA_BF16(acc[mi][ni], al[mi], bh[ni]);
            }
        __syncthreads();
    }

    // epilogue
    #pragma unroll
    for (int mi = 0; mi < 4; mi++) {
        int r0 = rowBase + wm * 64 + mi * 16 + (lane >> 2);
        #pragma unroll
        for (int ni = 0; ni < 4; ni++) {
            int c0 = colBase + wn * 32 + ni * 8 + (lane & 3) * 2;
            #pragma unroll
            for (int q = 0; q < 4; q++) {
                int r = r0 + (q >> 1) * 8;
                int c = c0 + (q & 1);
                if (c < N) {
                    float v = acc[mi][ni][q];
                    if (EP >= 1) v += bias[c];
                    size_t o = (size_t)r * N + c;
                    if (EP == 2) {
                        v = 0.5f * v * (1.0f + erff(v * 0.70710678118654752440f));
                        split_write(v, Chi, Clo, o);
                    } else {
                        if (EP == 3) v += res[o];
                        Cf[o] = v;
                    }
                }
            }
        }
    }
}

// ---------------- MHA: block per (head, batch); writes att split ----------------
__global__ void mha_kernel(const float* __restrict__ qkv,
                           __nv_bfloat16* __restrict__ ahi, __nv_bfloat16* __restrict__ alo) {
    extern __shared__ float sm[];
    float* Q  = sm;
    float* Kx = Q + 64 * HD;
    float* V  = Kx + 64 * HD;
    float* SC = V + 64 * HD;
    int h = blockIdx.x, b = blockIdx.y;
    int tid = threadIdx.x;
    const float* base = qkv + (size_t)(b * NTOK) * (3 * Cdim);
    for (int e = tid; e < 64 * HD; e += blockDim.x) {
        int t = e / HD, d = e % HD;
        Q[e]  = base[(size_t)t * (3 * Cdim) + h * HD + d];
        Kx[e] = base[(size_t)t * (3 * Cdim) + Cdim + h * HD + d];
        V[e]  = base[(size_t)t * (3 * Cdim) + 2 * Cdim + h * HD + d];
    }
    __syncthreads();
    const float scale = rsqrtf((float)HD);
    for (int e = tid; e < 64 * 64; e += blockDim.x) {
        int i = e >> 6, j = e & 63;
        float a = 0.f;
        const float* qi = Q + i * HD;
        const float* kj = Kx + j * HD;
        #pragma unroll 7
        for (int d = 0; d < HD; d++) a += qi[d] * kj[d];
        SC[e] = a * scale;
    }
    __syncthreads();
    if (tid < 64) {
        float* row = SC + tid * 64;
        float mx = -1e30f;
        for (int j = 0; j < 64; j++) mx = fmaxf(mx, row[j]);
        float s = 0.f;
        for (int j = 0; j < 64; j++) { float e = expf(row[j] - mx); row[j] = e; s += e; }
        float inv = 1.f / s;
        for (int j = 0; j < 64; j++) row[j] *= inv;
    }
    __syncthreads();
    for (int e = tid; e < 64 * HD; e += blockDim.x) {
        int i = e / HD, d = e % HD;
        float a = 0.f;
        const float* row = SC + i * 64;
        for (int j = 0; j < 64; j++) a += row[j] * V[j * HD + d];
        split_write(a, ahi, alo, ((size_t)(b * NTOK + i)) * Cdim + h * HD + d);
    }
}

// ---------------- BiFormer (unchanged fp32, small) ----------------
__global__ void bf_qkv_kernel(const float* __restrict__ o,
                              const float* __restrict__ w, const float* __restrict__ bias) {
    int y = blockIdx.x, b = blockIdx.y;
    __shared__ float xin[64][28];
    for (int e = threadIdx.x; e < 64 * 28; e += blockDim.x) {
        int c = e / 28, xx = e % 28;
        xin[c][xx] = o[((size_t)b * 64 + c) * 784 + y * 28 + xx];
    }
    __syncthreads();
    for (int e = threadIdx.x; e < 192 * 28; e += blockDim.x) {
        int oc = e / 28, xx = e % 28;
        float a = bias[oc];
        const float* wr = w + oc * 64;
        #pragma unroll 16
        for (int c = 0; c < 64; c++) a += xin[c][xx] * wr[c];
        g_bfqkv[((size_t)b * 192 + oc) * 784 + y * 28 + xx] = a;
    }
}

__global__ void bf_pool_kernel() {
    int b = blockIdx.x;
    for (int e = threadIdx.x; e < 64 * NREG; e += blockDim.x) {
        int c = e / NREG, r = e % NREG;
        int rh = r / 7, rw = r % 7;
        float sq = 0.f, sk = 0.f;
        const float* qc = g_bfqkv + ((size_t)b * 192 + c) * 784;
        const float* kc = g_bfqkv + ((size_t)b * 192 + 64 + c) * 784;
        for (int pr = 0; pr < 4; pr++)
            for (int pc = 0; pc < 4; pc++) {
                int s = (rh * 4 + pr) * 28 + rw * 4 + pc;
                sq += qc[s]; sk += kc[s];
            }
        g_qr[(b * 64 + c) * NREG + r] = sq * 0.0625f;
        g_kr[(b * 64 + c) * NREG + r] = sk * 0.0625f;
    }
}

__global__ void bf_topk_kernel() {
    int r = blockIdx.x, b = blockIdx.y;
    __shared__ float qv[64];
    __shared__ float sc[NREG];
    int tid = threadIdx.x;
    if (tid < 64) qv[tid] = g_qr[(b * 64 + tid) * NREG + r];
    __syncthreads();
    if (tid < NREG) {
        float a = 0.f;
        for (int c = 0; c < 64; c++) a += qv[c] * g_kr[(b * 64 + c) * NREG + tid];
        sc[tid] = a;
    }
    __syncthreads();
    if (tid == 0) {
        for (int j = 0; j < TOPK; j++) {
            float mx = -1e30f; int mi = 0;
            for (int s = 0; s < NREG; s++) if (sc[s] > mx) { mx = sc[s]; mi = s; }
            sc[mi] = -1e30f;
            g_idx[(b * NREG + r) * TOPK + j] = mi;
        }
    }
}

__global__ void bf_attn_kernel() {
    int r = blockIdx.x, h = blockIdx.y, b = blockIdx.z;
    __shared__ float q[16][8], kg[64][8], vg[64][8], sc[16][64];
    __shared__ int idx4[4];
    int tid = threadIdx.x;
    if (tid < 4) idx4[tid] = g_idx[(b * NREG + r) * TOPK + tid];
    int rh = r / 7, rw = r % 7;
    {
        int p = tid / 8, d = tid % 8;
        int s = (rh * 4 + p / 4) * 28 + rw * 4 + (p % 4);
        q[p][d] = g_bfqkv[((size_t)b * 192 + h * 8 + d) * 784 + s] * 0.125f;
    }
    __syncthreads();
    for (int e = tid; e < 512; e += 128) {
        int t = e / 8, d = e % 8;
        int reg = idx4[t / 16];
        int p2 = t % 16;
        int s = ((reg / 7) * 4 + p2 / 4) * 28 + (reg % 7) * 4 + (p2 % 4);
        kg[t][d] = g_bfqkv[((size_t)b * 192 + 64 + h * 8 + d) * 784 + s];
        vg[t][d] = g_bfqkv[((size_t)b * 192 + 128 + h * 8 + d) * 784 + s];
    }
    __syncthreads();
    for (int e = tid; e < 1024; e += 128) {
        int p = e >> 6, t = e & 63;
        float a = 0.f;
        #pragma unroll
        for (int d = 0; d < 8; d++) a += q[p][d] * kg[t][d];
        sc[p][t] = a;
    }
    __syncthreads();
    if (tid < 16) {
        float mx = -1e30f;
        for (int t = 0; t < 64; t++) mx = fmaxf(mx, sc[tid][t]);
        float s = 0.f;
        for (int t = 0; t < 64; t++) { float e = expf(sc[tid][t] - mx); sc[tid][t] = e; s += e; }
        float inv = 1.f / s;
        for (int t = 0; t < 64; t++) sc[tid][t] *= inv;
    }
    __syncthreads();
    {
        int p = tid / 8, d = tid % 8;
        float a = 0.f;
        for (int t = 0; t < 64; t++) a += sc[p][t] * vg[t][d];
        int s = (rh * 4 + p / 4) * 28 + rw * 4 + (p % 4);
        g_attg[((size_t)b * 64 + h * 8 + d) * 784 + s] = a;
    }
}

__global__ void bf_out_kernel(const float* __restrict__ lepe_w, const float* __restrict__ lepe_b,
                              const float* __restrict__ out_w, const float* __restrict__ out_b,
                              float* __restrict__ outp) {
    int y = blockIdx.x, b = blockIdx.y;
    __shared__ float v3[3][64][28];
    __shared__ float tmp[64][28];
    int tid = threadIdx.x;
    for (int ry = 0; ry < 3; ry++) {
        int yy = y + ry - 1;
        for (int e = tid; e < 64 * 28; e += blockDim.x) {
            int c = e / 28, xx = e % 28;
            v3[ry][c][xx] = (yy >= 0 && yy < 28)
                ? g_bfqkv[((size_t)b * 192 + 128 + c) * 784 + yy * 28 + xx] : 0.f;
        }
    }
    __syncthreads();
    for (int e = tid; e < 64 * 28; e += blockDim.x) {
        int c = e / 28, xx = e % 28;
        float a = g_attg[((size_t)b * 64 + c) * 784 + y * 28 + xx] + lepe_b[c];
        #pragma unroll
        for (int ky = 0; ky < 3; ky++)
            #pragma unroll
            for (int kx = 0; kx < 3; kx++) {
                int xx2 = xx + kx - 1;
                if (xx2 >= 0 && xx2 < 28) a += v3[ky][c][xx2] * lepe_w[c * 9 + ky * 3 + kx];
            }
        tmp[c][xx] = a;
    }
    __syncthreads();
    for (int e = tid; e < 64 * 28; e += blockDim.x) {
        int oc = e / 28, xx = e % 28;
        float a = out_b[oc];
        const float* wr = out_w + oc * 64;
        #pragma unroll 16
        for (int c = 0; c < 64; c++) a += tmp[c][xx] * wr[c];
        outp[((size_t)b * 64 + oc) * 784 + y * 28 + xx] = a;
    }
}

// ---------------- launch ----------------
extern "C" void kernel_launch(void* const* d_in, const int* in_sizes, int n_in,
                              void* d_out, int out_size) {
    (void)in_sizes; (void)n_in; (void)out_size;
    const float* x        = (const float*)d_in[0];
    const float* norm1_g  = (const float*)d_in[1];
    const float* norm1_b  = (const float*)d_in[2];
    const float* qkv_w    = (const float*)d_in[3];
    const float* proj_w   = (const float*)d_in[4];
    const float* proj_b   = (const float*)d_in[5];
    const float* norm2_g  = (const float*)d_in[6];
    const float* norm2_b  = (const float*)d_in[7];
    const float* fc1_w    = (const float*)d_in[8];
    const float* fc1_b    = (const float*)d_in[9];
    const float* fc2_w    = (const float*)d_in[10];
    const float* fc2_b    = (const float*)d_in[11];
    const float* bf_qkv_w = (const float*)d_in[12];
    const float* bf_qkv_b = (const float*)d_in[13];
    const float* bf_lepe_w= (const float*)d_in[14];
    const float* bf_lepe_b= (const float*)d_in[15];
    const float* bf_out_w = (const float*)d_in[16];
    const float* bf_out_b = (const float*)d_in[17];
    float* out = (float*)d_out;

    __nv_bfloat16 *p_h_hi, *p_h_lo, *p_att_hi, *p_att_lo, *p_h2_hi, *p_h2_lo, *p_hid_hi, *p_hid_lo;
    __nv_bfloat16 *p_wqkv_hi, *p_wqkv_lo, *p_wproj_hi, *p_wproj_lo, *p_wfc1_hi, *p_wfc1_lo, *p_wfc2_hi, *p_wfc2_lo;
    float *p_qkv, *p_o, *p_xr;
    cudaGetSymbolAddress((void**)&p_h_hi, g_h_hi);     cudaGetSymbolAddress((void**)&p_h_lo, g_h_lo);
    cudaGetSymbolAddress((void**)&p_att_hi, g_att_hi); cudaGetSymbolAddress((void**)&p_att_lo, g_att_lo);
    cudaGetSymbolAddress((void**)&p_h2_hi, g_h2_hi);   cudaGetSymbolAddress((void**)&p_h2_lo, g_h2_lo);
    cudaGetSymbolAddress((void**)&p_hid_hi, g_hid_hi); cudaGetSymbolAddress((void**)&p_hid_lo, g_hid_lo);
    cudaGetSymbolAddress((void**)&p_wqkv_hi, g_wqkv_hi);   cudaGetSymbolAddress((void**)&p_wqkv_lo, g_wqkv_lo);
    cudaGetSymbolAddress((void**)&p_wproj_hi, g_wproj_hi); cudaGetSymbolAddress((void**)&p_wproj_lo, g_wproj_lo);
    cudaGetSymbolAddress((void**)&p_wfc1_hi, g_wfc1_hi);   cudaGetSymbolAddress((void**)&p_wfc1_lo, g_wfc1_lo);
    cudaGetSymbolAddress((void**)&p_wfc2_hi, g_wfc2_hi);   cudaGetSymbolAddress((void**)&p_wfc2_lo, g_wfc2_lo);
    cudaGetSymbolAddress((void**)&p_qkv, g_qkv);
    cudaGetSymbolAddress((void**)&p_o, g_o);
    cudaGetSymbolAddress((void**)&p_xr, g_xr);

    const int MHA_SMEM = (3 * 64 * HD + 64 * 64) * 4;
    cudaFuncSetAttribute(mha_kernel, cudaFuncAttributeMaxDynamicSharedMemorySize, MHA_SMEM);

    // weight splits
    split_kernel<<<(Cdim * 3 * Cdim + 255) / 256, 256>>>(qkv_w,  p_wqkv_hi,  p_wqkv_lo,  Cdim * 3 * Cdim);
    split_kernel<<<(Cdim * Cdim + 255) / 256, 256>>>(proj_w, p_wproj_hi, p_wproj_lo, Cdim * Cdim);
    split_kernel<<<(Cdim * HID + 255) / 256, 256>>>(fc1_w,  p_wfc1_hi,  p_wfc1_lo,  Cdim * HID);
    split_kernel<<<(HID * Cdim + 255) / 256, 256>>>(fc2_w,  p_wfc2_hi,  p_wfc2_lo,  HID * Cdim);

    // 1) LN1 -> h split
    ln_kernel<<<ROWS, 256>>>(x, norm1_g, norm1_b, p_h_hi, p_h_lo);
    // 2) qkv = h @ qkv_w (fp32)
    mma_gemm<0><<<dim3((3 * Cdim + BN - 1) / BN, ROWS / BM), 256>>>(
        p_h_hi, p_h_lo, p_wqkv_hi, p_wqkv_lo, nullptr, nullptr,
        p_qkv, nullptr, nullptr, ROWS, 3 * Cdim, Cdim);
    // 3) MHA -> att split
    mha_kernel<<<dim3(NHd, Bsz), 256, MHA_SMEM>>>(p_qkv, p_att_hi, p_att_lo);
    // 4) o = att @ proj_w + proj_b (fp32)
    mma_gemm<1><<<dim3((Cdim + BN - 1) / BN, ROWS / BM), 256>>>(
        p_att_hi, p_att_lo, p_wproj_hi, p_wproj_lo, proj_b, nullptr,
        p_o, nullptr, nullptr, ROWS, Cdim, Cdim);
    // 5-9) BiFormer branch
    bf_qkv_kernel<<<dim3(28, Bsz), 256>>>(p_o, bf_qkv_w, bf_qkv_b);
    bf_pool_kernel<<<Bsz, 256>>>();
    bf_topk_kernel<<<dim3(NREG, Bsz), 64>>>();
    bf_attn_kernel<<<dim3(NREG, 8, Bsz), 128>>>();
    bf_out_kernel<<<dim3(28, Bsz), 256>>>(bf_lepe_w, bf_lepe_b, bf_out_w, bf_out_b, out + OUT_OFF);
    // 10) LN2
    ln2_kernel<<<ROWS, 256>>>(p_o, x, norm2_g, norm2_b, p_xr, p_h2_hi, p_h2_lo);
    // 11) hid = gelu(h2 @ fc1_w + b) -> split
    mma_gemm<2><<<dim3((HID + BN - 1) / BN, ROWS / BM), 256>>>(
        p_h2_hi, p_h2_lo, p_wfc1_hi, p_wfc1_lo, fc1_b, nullptr,
        nullptr, p_hid_hi, p_hid_lo, ROWS, HID, Cdim);
    // 12) out = hid @ fc2_w + b + xr
    mma_gemm<3><<<dim3((Cdim + BN - 1) / BN, ROWS / BM), 256>>>(
        p_hid_hi, p_hid_lo, p_wfc2_hi, p_wfc2_lo, fc2_b, p_xr,
        out, nullptr, nullptr, ROWS, Cdim, HID);
}

// round 6
// speedup vs baseline: 1.0262x; 1.0262x over previous
#include <cuda_runtime.h>
#include <cuda_bf16.h>
#include <math.h>
#include <stdint.h>

// ---------------- problem constants ----------------
#define Bsz   128
#define NTOK  64
#define Cdim  784
#define NHd   8
#define HD    98
#define HID   3136
#define ROWS  (Bsz*NTOK)  // 8192
#define NREG  49
#define TOPK  4
#define OUT_OFF (Bsz*NTOK*Cdim)

// ---------------- scratch ----------------
__device__ __nv_bfloat16 g_h_hi [ROWS*Cdim];
__device__ __nv_bfloat16 g_h_lo [ROWS*Cdim];
__device__ float         g_qkv  [ROWS*3*Cdim];
__device__ __nv_bfloat16 g_att_hi[ROWS*Cdim];
__device__ __nv_bfloat16 g_att_lo[ROWS*Cdim];
__device__ float         g_o    [ROWS*Cdim];
__device__ float         g_xr   [ROWS*Cdim];
__device__ __nv_bfloat16 g_h2_hi[ROWS*Cdim];
__device__ __nv_bfloat16 g_h2_lo[ROWS*Cdim];
__device__ __nv_bfloat16 g_hid_hi[ROWS*HID];
__device__ __nv_bfloat16 g_hid_lo[ROWS*HID];
// weight splits [K, N]
__device__ __nv_bfloat16 g_wqkv_hi[Cdim*3*Cdim];
__device__ __nv_bfloat16 g_wqkv_lo[Cdim*3*Cdim];
__device__ __nv_bfloat16 g_wproj_hi[Cdim*Cdim];
__device__ __nv_bfloat16 g_wproj_lo[Cdim*Cdim];
__device__ __nv_bfloat16 g_wfc1_hi[Cdim*HID];
__device__ __nv_bfloat16 g_wfc1_lo[Cdim*HID];
__device__ __nv_bfloat16 g_wfc2_hi[HID*Cdim];
__device__ __nv_bfloat16 g_wfc2_lo[HID*Cdim];
// biformer
__device__ float g_bfqkv[Bsz*192*784];
__device__ float g_attg [Bsz*64*784];
__device__ float g_qr  [Bsz*64*NREG];
__device__ float g_kr  [Bsz*64*NREG];
__device__ int   g_idx [Bsz*NREG*TOPK];

// ---------------- helpers ----------------
__device__ __forceinline__ uint32_t smem_u32(const void* p) {
    return (uint32_t)__cvta_generic_to_shared(p);
}
#define CP_ASYNC16(dst_u32, src, sz) \
    asm volatile("cp.async.cg.shared.global [%0], [%1], 16, %2;\n" :: "r"(dst_u32), "l"(src), "r"(sz))
#define CP_COMMIT() asm volatile("cp.async.commit_group;\n")
#define LDSM4(r0,r1,r2,r3,a) \
    asm volatile("ldmatrix.sync.aligned.m8n8.x4.shared.b16 {%0,%1,%2,%3},[%4];" \
        : "=r"(r0),"=r"(r1),"=r"(r2),"=r"(r3) : "r"(a))
#define LDSM4T(r0,r1,r2,r3,a) \
    asm volatile("ldmatrix.sync.aligned.m8n8.x4.trans.shared.b16 {%0,%1,%2,%3},[%4];" \
        : "=r"(r0),"=r"(r1),"=r"(r2),"=r"(r3) : "r"(a))
#define MMA_BF16(d, a, b) \
    asm volatile("mma.sync.aligned.m16n8k16.row.col.f32.bf16.bf16.f32 " \
        "{%0,%1,%2,%3},{%4,%5,%6,%7},{%8,%9},{%0,%1,%2,%3};" \
        : "+f"(d[0]),"+f"(d[1]),"+f"(d[2]),"+f"(d[3]) \
        : "r"(a[0]),"r"(a[1]),"r"(a[2]),"r"(a[3]),"r"(b[0]),"r"(b[1]))

__device__ __forceinline__ void split_write(float v, __nv_bfloat16* hi, __nv_bfloat16* lo, size_t o) {
    __nv_bfloat16 h = __float2bfloat16(v);
    hi[o] = h;
    lo[o] = __float2bfloat16(v - __bfloat162float(h));
}

// ---------------- weight split ----------------
__global__ void split_kernel(const float* __restrict__ in, __nv_bfloat16* __restrict__ hi,
                             __nv_bfloat16* __restrict__ lo, int n) {
    int i = blockIdx.x * blockDim.x + threadIdx.x;
    if (i < n) {
        float v = in[i];
        __nv_bfloat16 h = __float2bfloat16(v);
        hi[i] = h;
        lo[i] = __float2bfloat16(v - __bfloat162float(h));
    }
}

// ---------------- LN1 ----------------
__global__ void ln_kernel(const float* __restrict__ x,
                          const float* __restrict__ g, const float* __restrict__ b,
                          __nv_bfloat16* __restrict__ ohi, __nv_bfloat16* __restrict__ olo) {
    int row = blockIdx.x;
    const float* xr = x + (size_t)row * Cdim;
    __shared__ float buf[Cdim];
    __shared__ float rs[2];
    __shared__ float red[64];
    float s = 0.f, ss = 0.f;
    for (int i = threadIdx.x; i < Cdim; i += blockDim.x) {
        float v = xr[i]; buf[i] = v; s += v; ss += v * v;
    }
    for (int o = 16; o > 0; o >>= 1) { s += __shfl_down_sync(~0u, s, o); ss += __shfl_down_sync(~0u, ss, o); }
    int wid = threadIdx.x >> 5, lid = threadIdx.x & 31;
    if (lid == 0) { red[wid] = s; red[wid + 32] = ss; }
    __syncthreads();
    if (threadIdx.x == 0) {
        float t = 0.f, tt = 0.f;
        int nw = blockDim.x >> 5;
        for (int i = 0; i < nw; i++) { t += red[i]; tt += red[i + 32]; }
        float mean = t / Cdim, var = tt / Cdim - mean * mean;
        rs[0] = mean; rs[1] = rsqrtf(var + 1e-5f);
    }
    __syncthreads();
    float mean = rs[0], inv = rs[1];
    for (int i = threadIdx.x; i < Cdim; i += blockDim.x)
        split_write((buf[i] - mean) * inv * g[i] + b[i], ohi, olo, (size_t)row * Cdim + i);
}

// ---------------- LN2 ----------------
__global__ void ln2_kernel(const float* __restrict__ ov, const float* __restrict__ x,
                           const float* __restrict__ g, const float* __restrict__ b,
                           float* __restrict__ xr_out,
                           __nv_bfloat16* __restrict__ ohi, __nv_bfloat16* __restrict__ olo) {
    int row = blockIdx.x;
    const float* a = ov + (size_t)row * Cdim;
    const float* c = x  + (size_t)row * Cdim;
    __shared__ float buf[Cdim];
    __shared__ float rs[2];
    __shared__ float red[64];
    float s = 0.f, ss = 0.f;
    for (int i = threadIdx.x; i < Cdim; i += blockDim.x) {
        float v = a[i] + c[i];
        buf[i] = v;
        xr_out[(size_t)row * Cdim + i] = v;
        s += v; ss += v * v;
    }
    for (int o = 16; o > 0; o >>= 1) { s += __shfl_down_sync(~0u, s, o); ss += __shfl_down_sync(~0u, ss, o); }
    int wid = threadIdx.x >> 5, lid = threadIdx.x & 31;
    if (lid == 0) { red[wid] = s; red[wid + 32] = ss; }
    __syncthreads();
    if (threadIdx.x == 0) {
        float t = 0.f, tt = 0.f;
        int nw = blockDim.x >> 5;
        for (int i = 0; i < nw; i++) { t += red[i]; tt += red[i + 32]; }
        float mean = t / Cdim, var = tt / Cdim - mean * mean;
        rs[0] = mean; rs[1] = rsqrtf(var + 1e-5f);
    }
    __syncthreads();
    float mean = rs[0], inv = rs[1];
    for (int i = threadIdx.x; i < Cdim; i += blockDim.x)
        split_write((buf[i] - mean) * inv * g[i] + b[i], ohi, olo, (size_t)row * Cdim + i);
}

// ---------------- bf16x3 tensor-core GEMM, BK=32, 3-stage cp.async ----------------
// C[M,N] = A[M,K] @ B[K,N]; A/B as bf16 hi/lo splits; fp32 accumulate.
// Tile 128x128, 8 warps (2x4), warp tile 64x32.
// EP: 0 fp32; 1 +bias fp32; 2 +bias GELU -> bf16 split; 3 +bias +res fp32.
#define ASTR 40
#define BSTR 136
#define A_ST_ELE (2*128*ASTR)   // 10240 per stage (hi+lo)
#define B_ST_ELE (2*32*BSTR)    // 8704 per stage
#define GEMM_SMEM ((3*A_ST_ELE + 3*B_ST_ELE) * 2)  // 113664 bytes

template<int EP>
__global__ __launch_bounds__(256, 1)
void mma_gemm(const __nv_bfloat16* __restrict__ Ah, const __nv_bfloat16* __restrict__ Al,
              const __nv_bfloat16* __restrict__ Bh, const __nv_bfloat16* __restrict__ Bl,
              const float* __restrict__ bias, const float* __restrict__ res,
              float* __restrict__ Cf, __nv_bfloat16* __restrict__ Chi, __nv_bfloat16* __restrict__ Clo,
              int M, int N, int K) {
    extern __shared__ __nv_bfloat16 sm[];
    __nv_bfloat16* Asm = sm;                 // [3][2][128][ASTR]
    __nv_bfloat16* Bsm = sm + 3 * A_ST_ELE;  // [3][2][32][BSTR]

    int tid = threadIdx.x;
    int warp = tid >> 5, lane = tid & 31;
    int wm = warp & 1, wn = warp >> 1;
    int rowBase = blockIdx.y * 128, colBase = blockIdx.x * 128;

    const int KT = (K + 31) >> 5;
    float acc[4][4][4];
    #pragma unroll
    for (int i = 0; i < 4; i++)
        #pragma unroll
        for (int j = 0; j < 4; j++)
            #pragma unroll
            for (int q = 0; q < 4; q++) acc[i][j][q] = 0.f;

    // load one stage (koff = kt*32)
    auto load_stage = [&](int st, int kt) {
        int koff = kt * 32;
        __nv_bfloat16* Ast = Asm + st * A_ST_ELE;
        __nv_bfloat16* Bst = Bsm + st * B_ST_ELE;
        #pragma unroll
        for (int part = 0; part < 2; part++) {
            const __nv_bfloat16* Aasrc = part ? Al : Ah;
            #pragma unroll
            for (int i = 0; i < 2; i++) {
                int chunk = i * 256 + tid;            // 0..511
                int r = chunk >> 2, cc = (chunk & 3) * 8;
                int k = koff + cc;
                uint32_t dst = smem_u32(Ast + part * (128 * ASTR) + r * ASTR + cc);
                const __nv_bfloat16* src = Aasrc + (size_t)(rowBase + r) * K + (k < K ? k : 0);
                CP_ASYNC16(dst, src, (k < K) ? 16 : 0);
            }
        }
        #pragma unroll
        for (int part = 0; part < 2; part++) {
            const __nv_bfloat16* Bbsrc = part ? Bl : Bh;
            #pragma unroll
            for (int i = 0; i < 2; i++) {
                int chunk = i * 256 + tid;
                int r = chunk >> 4, cc = (chunk & 15) * 8;
                int k = koff + r, n = colBase + cc;
                bool ok = (k < K) && (n < N);
                uint32_t dst = smem_u32(Bst + part * (32 * BSTR) + r * BSTR + cc);
                const __nv_bfloat16* src = Bbsrc + (ok ? ((size_t)k * N + n) : 0);
                CP_ASYNC16(dst, src, ok ? 16 : 0);
            }
        }
    };

    // prologue: stages 0, 1
    load_stage(0, 0); CP_COMMIT();
    if (KT > 1) { load_stage(1, 1); }
    CP_COMMIT();

    int lrow = lane & 15, lhalf = (lane >> 4) * 8;

    for (int kt = 0; kt < KT; kt++) {
        if (kt + 2 < KT) load_stage((kt + 2) % 3, kt + 2);
        CP_COMMIT();
        asm volatile("cp.async.wait_group 2;");
        __syncthreads();

        int st = kt % 3;
        __nv_bfloat16* Ast = Asm + st * A_ST_ELE;
        __nv_bfloat16* Bst = Bsm + st * B_ST_ELE;

        #pragma unroll
        for (int kk = 0; kk < 32; kk += 16) {
            uint32_t ah[4][4], al[4][4], bh[4][2], bl[4][2];
            #pragma unroll
            for (int mi = 0; mi < 4; mi++) {
                uint32_t a0 = smem_u32(Ast + (wm * 64 + mi * 16 + lrow) * ASTR + kk + lhalf);
                LDSM4(ah[mi][0], ah[mi][1], ah[mi][2], ah[mi][3], a0);
                uint32_t a1 = smem_u32(Ast + 128 * ASTR + (wm * 64 + mi * 16 + lrow) * ASTR + kk + lhalf);
                LDSM4(al[mi][0], al[mi][1], al[mi][2], al[mi][3], a1);
            }
            #pragma unroll
            for (int pr = 0; pr < 2; pr++) {
                uint32_t r0, r1, r2, r3;
                uint32_t b0 = smem_u32(Bst + (kk + lrow) * BSTR + wn * 32 + pr * 16 + lhalf);
                LDSM4T(r0, r1, r2, r3, b0);
                bh[pr * 2][0] = r0; bh[pr * 2][1] = r1; bh[pr * 2 + 1][0] = r2; bh[pr * 2 + 1][1] = r3;
                uint32_t b1 = smem_u32(Bst + 32 * BSTR + (kk + lrow) * BSTR + wn * 32 + pr * 16 + lhalf);
                LDSM4T(r0, r1, r2, r3, b1);
                bl[pr * 2][0] = r0; bl[pr * 2][1] = r1; bl[pr * 2 + 1][0] = r2; bl[pr * 2 + 1][1] = r3;
            }
            #pragma unroll
            for (int mi = 0; mi < 4; mi++)
                #pragma unroll
                for (int ni = 0; ni < 4; ni++) {
                    MMA_BF16(acc[mi][ni], ah[mi], bh[ni]);
                    MMA_BF16(acc[mi][ni], ah[mi], bl[ni]);
                    MMA_BF16(acc[mi][ni], al[mi], bh[ni]);
                }
        }
        __syncthreads();
    }

    // epilogue
    #pragma unroll
    for (int mi = 0; mi < 4; mi++) {
        int r0 = rowBase + wm * 64 + mi * 16 + (lane >> 2);
        #pragma unroll
        for (int ni = 0; ni < 4; ni++) {
            int c0 = colBase + wn * 32 + ni * 8 + (lane & 3) * 2;
            #pragma unroll
            for (int q = 0; q < 4; q++) {
                int r = r0 + (q >> 1) * 8;
                int c = c0 + (q & 1);
                if (c < N) {
                    float v = acc[mi][ni][q];
                    if (EP >= 1) v += bias[c];
                    size_t o = (size_t)r * N + c;
                    if (EP == 2) {
                        v = 0.5f * v * (1.0f + erff(v * 0.70710678118654752440f));
                        split_write(v, Chi, Clo, o);
                    } else {
                        if (EP == 3) v += res[o];
                        Cf[o] = v;
                    }
                }
            }
        }
    }
}

// ---------------- MHA ----------------
__global__ void mha_kernel(const float* __restrict__ qkv,
                           __nv_bfloat16* __restrict__ ahi, __nv_bfloat16* __restrict__ alo) {
    extern __shared__ float smf[];
    float* Q  = smf;
    float* Kx = Q + 64 * HD;
    float* V  = Kx + 64 * HD;
    float* SC = V + 64 * HD;
    int h = blockIdx.x, b = blockIdx.y;
    int tid = threadIdx.x;
    const float* base = qkv + (size_t)(b * NTOK) * (3 * Cdim);
    for (int e = tid; e < 64 * HD; e += blockDim.x) {
        int t = e / HD, d = e % HD;
        Q[e]  = base[(size_t)t * (3 * Cdim) + h * HD + d];
        Kx[e] = base[(size_t)t * (3 * Cdim) + Cdim + h * HD + d];
        V[e]  = base[(size_t)t * (3 * Cdim) + 2 * Cdim + h * HD + d];
    }
    __syncthreads();
    const float scale = rsqrtf((float)HD);
    for (int e = tid; e < 64 * 64; e += blockDim.x) {
        int i = e >> 6, j = e & 63;
        float a = 0.f;
        const float* qi = Q + i * HD;
        const float* kj = Kx + j * HD;
        #pragma unroll 7
        for (int d = 0; d < HD; d++) a += qi[d] * kj[d];
        SC[e] = a * scale;
    }
    __syncthreads();
    if (tid < 64) {
        float* row = SC + tid * 64;
        float mx = -1e30f;
        for (int j = 0; j < 64; j++) mx = fmaxf(mx, row[j]);
        float s = 0.f;
        for (int j = 0; j < 64; j++) { float e = expf(row[j] - mx); row[j] = e; s += e; }
        float inv = 1.f / s;
        for (int j = 0; j < 64; j++) row[j] *= inv;
    }
    __syncthreads();
    for (int e = tid; e < 64 * HD; e += blockDim.x) {
        int i = e / HD, d = e % HD;
        float a = 0.f;
        const float* row = SC + i * 64;
        for (int j = 0; j < 64; j++) a += row[j] * V[j * HD + d];
        split_write(a, ahi, alo, ((size_t)(b * NTOK + i)) * Cdim + h * HD + d);
    }
}

// ---------------- BiFormer ----------------
__global__ void bf_qkv_kernel(const float* __restrict__ o,
                              const float* __restrict__ w, const float* __restrict__ bias) {
    int y = blockIdx.x, b = blockIdx.y;
    __shared__ float xin[64][28];
    for (int e = threadIdx.x; e < 64 * 28; e += blockDim.x) {
        int c = e / 28, xx = e % 28;
        xin[c][xx] = o[((size_t)b * 64 + c) * 784 + y * 28 + xx];
    }
    __syncthreads();
    for (int e = threadIdx.x; e < 192 * 28; e += blockDim.x) {
        int oc = e / 28, xx = e % 28;
        float a = bias[oc];
        const float* wr = w + oc * 64;
        #pragma unroll 16
        for (int c = 0; c < 64; c++) a += xin[c][xx] * wr[c];
        g_bfqkv[((size_t)b * 192 + oc) * 784 + y * 28 + xx] = a;
    }
}

__global__ void bf_pool_kernel() {
    int b = blockIdx.x;
    for (int e = threadIdx.x; e < 64 * NREG; e += blockDim.x) {
        int c = e / NREG, r = e % NREG;
        int rh = r / 7, rw = r % 7;
        float sq = 0.f, sk = 0.f;
        const float* qc = g_bfqkv + ((size_t)b * 192 + c) * 784;
        const float* kc = g_bfqkv + ((size_t)b * 192 + 64 + c) * 784;
        for (int pr = 0; pr < 4; pr++)
            for (int pc = 0; pc < 4; pc++) {
                int s = (rh * 4 + pr) * 28 + rw * 4 + pc;
                sq += qc[s]; sk += kc[s];
            }
        g_qr[(b * 64 + c) * NREG + r] = sq * 0.0625f;
        g_kr[(b * 64 + c) * NREG + r] = sk * 0.0625f;
    }
}

__global__ void bf_topk_kernel() {
    int r = blockIdx.x, b = blockIdx.y;
    __shared__ float qv[64];
    __shared__ float sc[NREG];
    int tid = threadIdx.x;
    if (tid < 64) qv[tid] = g_qr[(b * 64 + tid) * NREG + r];
    __syncthreads();
    if (tid < NREG) {
        float a = 0.f;
        for (int c = 0; c < 64; c++) a += qv[c] * g_kr[(b * 64 + c) * NREG + tid];
        sc[tid] = a;
    }
    __syncthreads();
    if (tid == 0) {
        for (int j = 0; j < TOPK; j++) {
            float mx = -1e30f; int mi = 0;
            for (int s = 0; s < NREG; s++) if (sc[s] > mx) { mx = sc[s]; mi = s; }
            sc[mi] = -1e30f;
            g_idx[(b * NREG + r) * TOPK + j] = mi;
        }
    }
}

__global__ void bf_attn_kernel() {
    int r = blockIdx.x, h = blockIdx.y, b = blockIdx.z;
    __shared__ float q[16][8], kg[64][8], vg[64][8], sc[16][64];
    __shared__ int idx4[4];
    int tid = threadIdx.x;
    if (tid < 4) idx4[tid] = g_idx[(b * NREG + r) * TOPK + tid];
    int rh = r / 7, rw = r % 7;
    {
        int p = tid / 8, d = tid % 8;
        int s = (rh * 4 + p / 4) * 28 + rw * 4 + (p % 4);
        q[p][d] = g_bfqkv[((size_t)b * 192 + h * 8 + d) * 784 + s] * 0.125f;
    }
    __syncthreads();
    for (int e = tid; e < 512; e += 128) {
        int t = e / 8, d = e % 8;
        int reg = idx4[t / 16];
        int p2 = t % 16;
        int s = ((reg / 7) * 4 + p2 / 4) * 28 + (reg % 7) * 4 + (p2 % 4);
        kg[t][d] = g_bfqkv[((size_t)b * 192 + 64 + h * 8 + d) * 784 + s];
        vg[t][d] = g_bfqkv[((size_t)b * 192 + 128 + h * 8 + d) * 784 + s];
    }
    __syncthreads();
    for (int e = tid; e < 1024; e += 128) {
        int p = e >> 6, t = e & 63;
        float a = 0.f;
        #pragma unroll
        for (int d = 0; d < 8; d++) a += q[p][d] * kg[t][d];
        sc[p][t] = a;
    }
    __syncthreads();
    if (tid < 16) {
        float mx = -1e30f;
        for (int t = 0; t < 64; t++) mx = fmaxf(mx, sc[tid][t]);
        float s = 0.f;
        for (int t = 0; t < 64; t++) { float e = expf(sc[tid][t] - mx); sc[tid][t] = e; s += e; }
        float inv = 1.f / s;
        for (int t = 0; t < 64; t++) sc[tid][t] *= inv;
    }
    __syncthreads();
    {
        int p = tid / 8, d = tid % 8;
        float a = 0.f;
        for (int t = 0; t < 64; t++) a += sc[p][t] * vg[t][d];
        int s = (rh * 4 + p / 4) * 28 + rw * 4 + (p % 4);
        g_attg[((size_t)b * 64 + h * 8 + d) * 784 + s] = a;
    }
}

__global__ void bf_out_kernel(const float* __restrict__ lepe_w, const float* __restrict__ lepe_b,
                              const float* __restrict__ out_w, const float* __restrict__ out_b,
                              float* __restrict__ outp) {
    int y = blockIdx.x, b = blockIdx.y;
    __shared__ float v3[3][64][28];
    __shared__ float tmp[64][28];
    int tid = threadIdx.x;
    for (int ry = 0; ry < 3; ry++) {
        int yy = y + ry - 1;
        for (int e = tid; e < 64 * 28; e += blockDim.x) {
            int c = e / 28, xx = e % 28;
            v3[ry][c][xx] = (yy >= 0 && yy < 28)
                ? g_bfqkv[((size_t)b * 192 + 128 + c) * 784 + yy * 28 + xx] : 0.f;
        }
    }
    __syncthreads();
    for (int e = tid; e < 64 * 28; e += blockDim.x) {
        int c = e / 28, xx = e % 28;
        float a = g_attg[((size_t)b * 64 + c) * 784 + y * 28 + xx] + lepe_b[c];
        #pragma unroll
        for (int ky = 0; ky < 3; ky++)
            #pragma unroll
            for (int kx = 0; kx < 3; kx++) {
                int xx2 = xx + kx - 1;
                if (xx2 >= 0 && xx2 < 28) a += v3[ky][c][xx2] * lepe_w[c * 9 + ky * 3 + kx];
            }
        tmp[c][xx] = a;
    }
    __syncthreads();
    for (int e = tid; e < 64 * 28; e += blockDim.x) {
        int oc = e / 28, xx = e % 28;
        float a = out_b[oc];
        const float* wr = out_w + oc * 64;
        #pragma unroll 16
        for (int c = 0; c < 64; c++) a += tmp[c][xx] * wr[c];
        outp[((size_t)b * 64 + oc) * 784 + y * 28 + xx] = a;
    }
}

// ---------------- launch ----------------
extern "C" void kernel_launch(void* const* d_in, const int* in_sizes, int n_in,
                              void* d_out, int out_size) {
    (void)in_sizes; (void)n_in; (void)out_size;
    const float* x        = (const float*)d_in[0];
    const float* norm1_g  = (const float*)d_in[1];
    const float* norm1_b  = (const float*)d_in[2];
    const float* qkv_w    = (const float*)d_in[3];
    const float* proj_w   = (const float*)d_in[4];
    const float* proj_b   = (const float*)d_in[5];
    const float* norm2_g  = (const float*)d_in[6];
    const float* norm2_b  = (const float*)d_in[7];
    const float* fc1_w    = (const float*)d_in[8];
    const float* fc1_b    = (const float*)d_in[9];
    const float* fc2_w    = (const float*)d_in[10];
    const float* fc2_b    = (const float*)d_in[11];
    const float* bf_qkv_w = (const float*)d_in[12];
    const float* bf_qkv_b = (const float*)d_in[13];
    const float* bf_lepe_w= (const float*)d_in[14];
    const float* bf_lepe_b= (const float*)d_in[15];
    const float* bf_out_w = (const float*)d_in[16];
    const float* bf_out_b = (const float*)d_in[17];
    float* out = (float*)d_out;

    __nv_bfloat16 *p_h_hi, *p_h_lo, *p_att_hi, *p_att_lo, *p_h2_hi, *p_h2_lo, *p_hid_hi, *p_hid_lo;
    __nv_bfloat16 *p_wqkv_hi, *p_wqkv_lo, *p_wproj_hi, *p_wproj_lo, *p_wfc1_hi, *p_wfc1_lo, *p_wfc2_hi, *p_wfc2_lo;
    float *p_qkv, *p_o, *p_xr;
    cudaGetSymbolAddress((void**)&p_h_hi, g_h_hi);     cudaGetSymbolAddress((void**)&p_h_lo, g_h_lo);
    cudaGetSymbolAddress((void**)&p_att_hi, g_att_hi); cudaGetSymbolAddress((void**)&p_att_lo, g_att_lo);
    cudaGetSymbolAddress((void**)&p_h2_hi, g_h2_hi);   cudaGetSymbolAddress((void**)&p_h2_lo, g_h2_lo);
    cudaGetSymbolAddress((void**)&p_hid_hi, g_hid_hi); cudaGetSymbolAddress((void**)&p_hid_lo, g_hid_lo);
    cudaGetSymbolAddress((void**)&p_wqkv_hi, g_wqkv_hi);   cudaGetSymbolAddress((void**)&p_wqkv_lo, g_wqkv_lo);
    cudaGetSymbolAddress((void**)&p_wproj_hi, g_wproj_hi); cudaGetSymbolAddress((void**)&p_wproj_lo, g_wproj_lo);
    cudaGetSymbolAddress((void**)&p_wfc1_hi, g_wfc1_hi);   cudaGetSymbolAddress((void**)&p_wfc1_lo, g_wfc1_lo);
    cudaGetSymbolAddress((void**)&p_wfc2_hi, g_wfc2_hi);   cudaGetSymbolAddress((void**)&p_wfc2_lo, g_wfc2_lo);
    cudaGetSymbolAddress((void**)&p_qkv, g_qkv);
    cudaGetSymbolAddress((void**)&p_o, g_o);
    cudaGetSymbolAddress((void**)&p_xr, g_xr);

    const int MHA_SMEM = (3 * 64 * HD + 64 * 64) * 4;
    cudaFuncSetAttribute(mha_kernel, cudaFuncAttributeMaxDynamicSharedMemorySize, MHA_SMEM);
    cudaFuncSetAttribute(mma_gemm<0>, cudaFuncAttributeMaxDynamicSharedMemorySize, GEMM_SMEM);
    cudaFuncSetAttribute(mma_gemm<1>, cudaFuncAttributeMaxDynamicSharedMemorySize, GEMM_SMEM);
    cudaFuncSetAttribute(mma_gemm<2>, cudaFuncAttributeMaxDynamicSharedMemorySize, GEMM_SMEM);
    cudaFuncSetAttribute(mma_gemm<3>, cudaFuncAttributeMaxDynamicSharedMemorySize, GEMM_SMEM);

    // weight splits
    split_kernel<<<(Cdim * 3 * Cdim + 255) / 256, 256>>>(qkv_w,  p_wqkv_hi,  p_wqkv_lo,  Cdim * 3 * Cdim);
    split_kernel<<<(Cdim * Cdim + 255) / 256, 256>>>(proj_w, p_wproj_hi, p_wproj_lo, Cdim * Cdim);
    split_kernel<<<(Cdim * HID + 255) / 256, 256>>>(fc1_w,  p_wfc1_hi,  p_wfc1_lo,  Cdim * HID);
    split_kernel<<<(HID * Cdim + 255) / 256, 256>>>(fc2_w,  p_wfc2_hi,  p_wfc2_lo,  HID * Cdim);

    // 1) LN1 -> h split
    ln_kernel<<<ROWS, 256>>>(x, norm1_g, norm1_b, p_h_hi, p_h_lo);
    // 2) qkv = h @ qkv_w
    mma_gemm<0><<<dim3((3 * Cdim + 127) / 128, ROWS / 128), 256, GEMM_SMEM>>>(
        p_h_hi, p_h_lo, p_wqkv_hi, p_wqkv_lo, nullptr, nullptr,
        p_qkv, nullptr, nullptr, ROWS, 3 * Cdim, Cdim);
    // 3) MHA -> att split
    mha_kernel<<<dim3(NHd, Bsz), 256, MHA_SMEM>>>(p_qkv, p_att_hi, p_att_lo);
    // 4) o = att @ proj_w + proj_b
    mma_gemm<1><<<dim3((Cdim + 127) / 128, ROWS / 128), 256, GEMM_SMEM>>>(
        p_att_hi, p_att_lo, p_wproj_hi, p_wproj_lo, proj_b, nullptr,
        p_o, nullptr, nullptr, ROWS, Cdim, Cdim);
    // 5-9) BiFormer branch
    bf_qkv_kernel<<<dim3(28, Bsz), 256>>>(p_o, bf_qkv_w, bf_qkv_b);
    bf_pool_kernel<<<Bsz, 256>>>();
    bf_topk_kernel<<<dim3(NREG, Bsz), 64>>>();
    bf_attn_kernel<<<dim3(NREG, 8, Bsz), 128>>>();
    bf_out_kernel<<<dim3(28, Bsz), 256>>>(bf_lepe_w, bf_lepe_b, bf_out_w, bf_out_b, out + OUT_OFF);
    // 10) LN2
    ln2_kernel<<<ROWS, 256>>>(p_o, x, norm2_g, norm2_b, p_xr, p_h2_hi, p_h2_lo);
    // 11) hid = gelu(h2 @ fc1_w + b) -> split
    mma_gemm<2><<<dim3((HID + 127) / 128, ROWS / 128), 256, GEMM_SMEM>>>(
        p_h2_hi, p_h2_lo, p_wfc1_hi, p_wfc1_lo, fc1_b, nullptr,
        nullptr, p_hid_hi, p_hid_lo, ROWS, HID, Cdim);
    // 12) out = hid @ fc2_w + b + xr
    mma_gemm<3><<<dim3((Cdim + 127) / 128, ROWS / 128), 256, GEMM_SMEM>>>(
        p_hid_hi, p_hid_lo, p_wfc2_hi, p_wfc2_lo, fc2_b, p_xr,
        out, nullptr, nullptr, ROWS, Cdim, HID);
}

// round 8
// speedup vs baseline: 1.1205x; 1.0919x over previous
#include <cuda_runtime.h>
#include <cuda_bf16.h>
#include <cuda_fp16.h>
#include <math.h>
#include <stdint.h>

// ---------------- problem constants ----------------
#define Bsz   128
#define NTOK  64
#define Cdim  784
#define NHd   8
#define HD    98
#define HID   3136
#define ROWS  (Bsz*NTOK)  // 8192
#define NREG  49
#define TOPK  4
#define OUT_OFF (Bsz*NTOK*Cdim)

// ---------------- scratch ----------------
__device__ __nv_bfloat16 g_h_hi [ROWS*Cdim];
__device__ __nv_bfloat16 g_h_lo [ROWS*Cdim];
__device__ float         g_qkv  [ROWS*3*Cdim];
__device__ __nv_bfloat16 g_att_hi[ROWS*Cdim];
__device__ __nv_bfloat16 g_att_lo[ROWS*Cdim];
__device__ float         g_o    [ROWS*Cdim];
__device__ float         g_xr   [ROWS*Cdim];
__device__ __half        g_h2   [ROWS*Cdim];
__device__ __half        g_hid  [ROWS*HID];
// weight splits [K, N]
__device__ __nv_bfloat16 g_wqkv_hi[Cdim*3*Cdim];
__device__ __nv_bfloat16 g_wqkv_lo[Cdim*3*Cdim];
__device__ __nv_bfloat16 g_wproj_hi[Cdim*Cdim];
__device__ __nv_bfloat16 g_wproj_lo[Cdim*Cdim];
__device__ __half        g_wfc1_hi[Cdim*HID];
__device__ __half        g_wfc1_lo[Cdim*HID];
__device__ __half        g_wfc2_hi[HID*Cdim];
__device__ __half        g_wfc2_lo[HID*Cdim];
// biformer
__device__ float g_bfqkv[Bsz*192*784];
__device__ float g_attg [Bsz*64*784];
__device__ float g_qr  [Bsz*64*NREG];
__device__ float g_kr  [Bsz*64*NREG];
__device__ int   g_idx [Bsz*NREG*TOPK];

// ---------------- helpers ----------------
__device__ __forceinline__ uint32_t smem_u32(const void* p) {
    return (uint32_t)__cvta_generic_to_shared(p);
}
#define CP_ASYNC16(dst_u32, src, sz) \
    asm volatile("cp.async.cg.shared.global [%0], [%1], 16, %2;\n" :: "r"(dst_u32), "l"(src), "r"(sz))
#define CP_COMMIT() asm volatile("cp.async.commit_group;\n")
#define LDSM4(r0,r1,r2,r3,a) \
    asm volatile("ldmatrix.sync.aligned.m8n8.x4.shared.b16 {%0,%1,%2,%3},[%4];" \
        : "=r"(r0),"=r"(r1),"=r"(r2),"=r"(r3) : "r"(a))
#define LDSM4T(r0,r1,r2,r3,a) \
    asm volatile("ldmatrix.sync.aligned.m8n8.x4.trans.shared.b16 {%0,%1,%2,%3},[%4];" \
        : "=r"(r0),"=r"(r1),"=r"(r2),"=r"(r3) : "r"(a))
#define MMA_BF16(d, a, b) \
    asm volatile("mma.sync.aligned.m16n8k16.row.col.f32.bf16.bf16.f32 " \
        "{%0,%1,%2,%3},{%4,%5,%6,%7},{%8,%9},{%0,%1,%2,%3};" \
        : "+f"(d[0]),"+f"(d[1]),"+f"(d[2]),"+f"(d[3]) \
        : "r"(a[0]),"r"(a[1]),"r"(a[2]),"r"(a[3]),"r"(b[0]),"r"(b[1]))
#define MMA_FP16(d, a, b) \
    asm volatile("mma.sync.aligned.m16n8k16.row.col.f32.f16.f16.f32 " \
        "{%0,%1,%2,%3},{%4,%5,%6,%7},{%8,%9},{%0,%1,%2,%3};" \
        : "+f"(d[0]),"+f"(d[1]),"+f"(d[2]),"+f"(d[3]) \
        : "r"(a[0]),"r"(a[1]),"r"(a[2]),"r"(a[3]),"r"(b[0]),"r"(b[1]))

__device__ __forceinline__ void split_write_bf(float v, __nv_bfloat16* hi, __nv_bfloat16* lo, size_t o) {
    __nv_bfloat16 h = __float2bfloat16(v);
    hi[o] = h;
    lo[o] = __float2bfloat16(v - __bfloat162float(h));
}

// ---------------- weight splits ----------------
__global__ void split_bf_kernel(const float* __restrict__ in, __nv_bfloat16* __restrict__ hi,
                                __nv_bfloat16* __restrict__ lo, int n) {
    int i = blockIdx.x * blockDim.x + threadIdx.x;
    if (i < n) {
        float v = in[i];
        __nv_bfloat16 h = __float2bfloat16(v);
        hi[i] = h;
        lo[i] = __float2bfloat16(v - __bfloat162float(h));
    }
}
__global__ void split_fp_kernel(const float* __restrict__ in, __half* __restrict__ hi,
                                __half* __restrict__ lo, int n) {
    int i = blockIdx.x * blockDim.x + threadIdx.x;
    if (i < n) {
        float v = in[i];
        __half h = __float2half(v);
        hi[i] = h;
        lo[i] = __float2half(v - __half2float(h));
    }
}

// ---------------- LN1: x -> (h_hi, h_lo) bf16 ----------------
__global__ void ln_kernel(const float* __restrict__ x,
                          const float* __restrict__ g, const float* __restrict__ b,
                          __nv_bfloat16* __restrict__ ohi, __nv_bfloat16* __restrict__ olo) {
    int row = blockIdx.x;
    const float* xr = x + (size_t)row * Cdim;
    __shared__ float buf[Cdim];
    __shared__ float rs[2];
    __shared__ float red[64];
    float s = 0.f, ss = 0.f;
    for (int i = threadIdx.x; i < Cdim; i += blockDim.x) {
        float v = xr[i]; buf[i] = v; s += v; ss += v * v;
    }
    for (int o = 16; o > 0; o >>= 1) { s += __shfl_down_sync(~0u, s, o); ss += __shfl_down_sync(~0u, ss, o); }
    int wid = threadIdx.x >> 5, lid = threadIdx.x & 31;
    if (lid == 0) { red[wid] = s; red[wid + 32] = ss; }
    __syncthreads();
    if (threadIdx.x == 0) {
        float t = 0.f, tt = 0.f;
        int nw = blockDim.x >> 5;
        for (int i = 0; i < nw; i++) { t += red[i]; tt += red[i + 32]; }
        float mean = t / Cdim, var = tt / Cdim - mean * mean;
        rs[0] = mean; rs[1] = rsqrtf(var + 1e-5f);
    }
    __syncthreads();
    float mean = rs[0], inv = rs[1];
    for (int i = threadIdx.x; i < Cdim; i += blockDim.x)
        split_write_bf((buf[i] - mean) * inv * g[i] + b[i], ohi, olo, (size_t)row * Cdim + i);
}

// ---------------- LN2: xr = o + x (fp32), h2 fp16 ----------------
__global__ void ln2_kernel(const float* __restrict__ ov, const float* __restrict__ x,
                           const float* __restrict__ g, const float* __restrict__ b,
                           float* __restrict__ xr_out, __half* __restrict__ oh) {
    int row = blockIdx.x;
    const float* a = ov + (size_t)row * Cdim;
    const float* c = x  + (size_t)row * Cdim;
    __shared__ float buf[Cdim];
    __shared__ float rs[2];
    __shared__ float red[64];
    float s = 0.f, ss = 0.f;
    for (int i = threadIdx.x; i < Cdim; i += blockDim.x) {
        float v = a[i] + c[i];
        buf[i] = v;
        xr_out[(size_t)row * Cdim + i] = v;
        s += v; ss += v * v;
    }
    for (int o = 16; o > 0; o >>= 1) { s += __shfl_down_sync(~0u, s, o); ss += __shfl_down_sync(~0u, ss, o); }
    int wid = threadIdx.x >> 5, lid = threadIdx.x & 31;
    if (lid == 0) { red[wid] = s; red[wid + 32] = ss; }
    __syncthreads();
    if (threadIdx.x == 0) {
        float t = 0.f, tt = 0.f;
        int nw = blockDim.x >> 5;
        for (int i = 0; i < nw; i++) { t += red[i]; tt += red[i + 32]; }
        float mean = t / Cdim, var = tt / Cdim - mean * mean;
        rs[0] = mean; rs[1] = rsqrtf(var + 1e-5f);
    }
    __syncthreads();
    float mean = rs[0], inv = rs[1];
    for (int i = threadIdx.x; i < Cdim; i += blockDim.x)
        oh[(size_t)row * Cdim + i] = __float2half((buf[i] - mean) * inv * g[i] + b[i]);
}

// ================= bf16x3 GEMM (qkv, proj) — BK=32, 3-stage =================
// EP3: 0 plain fp32 out; 1 +bias fp32 out.
#define ASTR3 40
#define BSTR3 136
#define A3_ST (2*128*ASTR3)
#define B3_ST (2*32*BSTR3)
#define GEMM3_SMEM ((3*A3_ST + 3*B3_ST) * 2)  // 113664

template<int EP>
__global__ __launch_bounds__(256, 1)
void mma_gemm3(const __nv_bfloat16* __restrict__ Ah, const __nv_bfloat16* __restrict__ Al,
               const __nv_bfloat16* __restrict__ Bh, const __nv_bfloat16* __restrict__ Bl,
               const float* __restrict__ bias,
               float* __restrict__ Cf, int M, int N, int K) {
    extern __shared__ __nv_bfloat16 sm3[];
    __nv_bfloat16* Asm = sm3;
    __nv_bfloat16* Bsm = sm3 + 3 * A3_ST;

    int tid = threadIdx.x;
    int warp = tid >> 5, lane = tid & 31;
    int wm = warp & 1, wn = warp >> 1;
    int rowBase = blockIdx.y * 128, colBase = blockIdx.x * 128;

    const int KT = (K + 31) >> 5;
    float acc[4][4][4];
    #pragma unroll
    for (int i = 0; i < 4; i++)
        #pragma unroll
        for (int j = 0; j < 4; j++)
            #pragma unroll
            for (int q = 0; q < 4; q++) acc[i][j][q] = 0.f;

    auto load_stage = [&](int st, int kt) {
        int koff = kt * 32;
        __nv_bfloat16* Ast = Asm + st * A3_ST;
        __nv_bfloat16* Bst = Bsm + st * B3_ST;
        #pragma unroll
        for (int part = 0; part < 2; part++) {
            const __nv_bfloat16* Aasrc = part ? Al : Ah;
            #pragma unroll
            for (int i = 0; i < 2; i++) {
                int chunk = i * 256 + tid;
                int r = chunk >> 2, cc = (chunk & 3) * 8;
                int k = koff + cc;
                uint32_t dst = smem_u32(Ast + part * (128 * ASTR3) + r * ASTR3 + cc);
                const __nv_bfloat16* src = Aasrc + (size_t)(rowBase + r) * K + (k < K ? k : 0);
                CP_ASYNC16(dst, src, (k < K) ? 16 : 0);
            }
        }
        #pragma unroll
        for (int part = 0; part < 2; part++) {
            const __nv_bfloat16* Bbsrc = part ? Bl : Bh;
            #pragma unroll
            for (int i = 0; i < 2; i++) {
                int chunk = i * 256 + tid;
                int r = chunk >> 4, cc = (chunk & 15) * 8;
                int k = koff + r, n = colBase + cc;
                bool ok = (k < K) && (n < N);
                uint32_t dst = smem_u32(Bst + part * (32 * BSTR3) + r * BSTR3 + cc);
                const __nv_bfloat16* src = Bbsrc + (ok ? ((size_t)k * N + n) : 0);
                CP_ASYNC16(dst, src, ok ? 16 : 0);
            }
        }
    };

    load_stage(0, 0); CP_COMMIT();
    if (KT > 1) { load_stage(1, 1); }
    CP_COMMIT();

    int lrow = lane & 15, lhalf = (lane >> 4) * 8;

    for (int kt = 0; kt < KT; kt++) {
        if (kt + 2 < KT) load_stage((kt + 2) % 3, kt + 2);
        CP_COMMIT();
        asm volatile("cp.async.wait_group 2;");
        __syncthreads();

        int st = kt % 3;
        __nv_bfloat16* Ast = Asm + st * A3_ST;
        __nv_bfloat16* Bst = Bsm + st * B3_ST;

        #pragma unroll
        for (int kk = 0; kk < 32; kk += 16) {
            uint32_t ah[4][4], al[4][4], bh[4][2], bl[4][2];
            #pragma unroll
            for (int mi = 0; mi < 4; mi++) {
                uint32_t a0 = smem_u32(Ast + (wm * 64 + mi * 16 + lrow) * ASTR3 + kk + lhalf);
                LDSM4(ah[mi][0], ah[mi][1], ah[mi][2], ah[mi][3], a0);
                uint32_t a1 = smem_u32(Ast + 128 * ASTR3 + (wm * 64 + mi * 16 + lrow) * ASTR3 + kk + lhalf);
                LDSM4(al[mi][0], al[mi][1], al[mi][2], al[mi][3], a1);
            }
            #pragma unroll
            for (int pr = 0; pr < 2; pr++) {
                uint32_t r0, r1, r2, r3;
                uint32_t b0 = smem_u32(Bst + (kk + lrow) * BSTR3 + wn * 32 + pr * 16 + lhalf);
                LDSM4T(r0, r1, r2, r3, b0);
                bh[pr * 2][0] = r0; bh[pr * 2][1] = r1; bh[pr * 2 + 1][0] = r2; bh[pr * 2 + 1][1] = r3;
                uint32_t b1 = smem_u32(Bst + 32 * BSTR3 + (kk + lrow) * BSTR3 + wn * 32 + pr * 16 + lhalf);
                LDSM4T(r0, r1, r2, r3, b1);
                bl[pr * 2][0] = r0; bl[pr * 2][1] = r1; bl[pr * 2 + 1][0] = r2; bl[pr * 2 + 1][1] = r3;
            }
            #pragma unroll
            for (int mi = 0; mi < 4; mi++)
                #pragma unroll
                for (int ni = 0; ni < 4; ni++) {
                    MMA_BF16(acc[mi][ni], ah[mi], bh[ni]);
                    MMA_BF16(acc[mi][ni], ah[mi], bl[ni]);
                    MMA_BF16(acc[mi][ni], al[mi], bh[ni]);
                }
        }
        __syncthreads();
    }

    #pragma unroll
    for (int mi = 0; mi < 4; mi++) {
        int r0 = rowBase + wm * 64 + mi * 16 + (lane >> 2);
        #pragma unroll
        for (int ni = 0; ni < 4; ni++) {
            int c0 = colBase + wn * 32 + ni * 8 + (lane & 3) * 2;
            #pragma unroll
            for (int q = 0; q < 4; q++) {
                int r = r0 + (q >> 1) * 8;
                int c = c0 + (q & 1);
                if (c < N) {
                    float v = acc[mi][ni][q];
                    if (EP >= 1) v += bias[c];
                    Cf[(size_t)r * N + c] = v;
                }
            }
        }
    }
}

// ================= fp16x2 GEMM (fc1, fc2) — BK=32, 3-stage =================
// EP: 2 +bias GELU -> fp16; 3 +bias +res fp32.
#define ASTR2 40
#define BSTR2 136
#define A2_ST (128*ASTR2)
#define B2_ST (2*32*BSTR2)
#define GEMM2_SMEM ((3*A2_ST + 3*B2_ST) * 2)  // 82944

template<int EP>
__global__ __launch_bounds__(256, 1)
void mma_gemm2(const __half* __restrict__ A,
               const __half* __restrict__ Bh, const __half* __restrict__ Bl,
               const float* __restrict__ bias, const float* __restrict__ res,
               float* __restrict__ Cf, __half* __restrict__ Ch,
               int M, int N, int K) {
    extern __shared__ __half sm2[];
    __half* Asm = sm2;
    __half* Bsm = sm2 + 3 * A2_ST;

    int tid = threadIdx.x;
    int warp = tid >> 5, lane = tid & 31;
    int wm = warp & 1, wn = warp >> 1;
    int rowBase = blockIdx.y * 128, colBase = blockIdx.x * 128;

    const int KT = (K + 31) >> 5;
    float acc[4][4][4];
    #pragma unroll
    for (int i = 0; i < 4; i++)
        #pragma unroll
        for (int j = 0; j < 4; j++)
            #pragma unroll
            for (int q = 0; q < 4; q++) acc[i][j][q] = 0.f;

    auto load_stage = [&](int st, int kt) {
        int koff = kt * 32;
        __half* Ast = Asm + st * A2_ST;
        __half* Bst = Bsm + st * B2_ST;
        #pragma unroll
        for (int i = 0; i < 2; i++) {
            int chunk = i * 256 + tid;
            int r = chunk >> 2, cc = (chunk & 3) * 8;
            int k = koff + cc;
            uint32_t dst = smem_u32(Ast + r * ASTR2 + cc);
            const __half* src = A + (size_t)(rowBase + r) * K + (k < K ? k : 0);
            CP_ASYNC16(dst, src, (k < K) ? 16 : 0);
        }
        #pragma unroll
        for (int part = 0; part < 2; part++) {
            const __half* Bbsrc = part ? Bl : Bh;
            #pragma unroll
            for (int i = 0; i < 2; i++) {
                int chunk = i * 256 + tid;
                int r = chunk >> 4, cc = (chunk & 15) * 8;
                int k = koff + r, n = colBase + cc;
                bool ok = (k < K) && (n < N);
                uint32_t dst = smem_u32(Bst + part * (32 * BSTR2) + r * BSTR2 + cc);
                const __half* src = Bbsrc + (ok ? ((size_t)k * N + n) : 0);
                CP_ASYNC16(dst, src, ok ? 16 : 0);
            }
        }
    };

    load_stage(0, 0); CP_COMMIT();
    if (KT > 1) { load_stage(1, 1); }
    CP_COMMIT();

    int lrow = lane & 15, lhalf = (lane >> 4) * 8;

    for (int kt = 0; kt < KT; kt++) {
        if (kt + 2 < KT) load_stage((kt + 2) % 3, kt + 2);
        CP_COMMIT();
        asm volatile("cp.async.wait_group 2;");
        __syncthreads();

        int st = kt % 3;
        __half* Ast = Asm + st * A2_ST;
        __half* Bst = Bsm + st * B2_ST;

        #pragma unroll
        for (int kk = 0; kk < 32; kk += 16) {
            uint32_t a[4][4], bh[4][2], bl[4][2];
            #pragma unroll
            for (int mi = 0; mi < 4; mi++) {
                uint32_t a0 = smem_u32(Ast + (wm * 64 + mi * 16 + lrow) * ASTR2 + kk + lhalf);
                LDSM4(a[mi][0], a[mi][1], a[mi][2], a[mi][3], a0);
            }
            #pragma unroll
            for (int pr = 0; pr < 2; pr++) {
                uint32_t r0, r1, r2, r3;
                uint32_t b0 = smem_u32(Bst + (kk + lrow) * BSTR2 + wn * 32 + pr * 16 + lhalf);
                LDSM4T(r0, r1, r2, r3, b0);
                bh[pr * 2][0] = r0; bh[pr * 2][1] = r1; bh[pr * 2 + 1][0] = r2; bh[pr * 2 + 1][1] = r3;
                uint32_t b1 = smem_u32(Bst + 32 * BSTR2 + (kk + lrow) * BSTR2 + wn * 32 + pr * 16 + lhalf);
                LDSM4T(r0, r1, r2, r3, b1);
                bl[pr * 2][0] = r0; bl[pr * 2][1] = r1; bl[pr * 2 + 1][0] = r2; bl[pr * 2 + 1][1] = r3;
            }
            #pragma unroll
            for (int mi = 0; mi < 4; mi++)
                #pragma unroll
                for (int ni = 0; ni < 4; ni++) {
                    MMA_FP16(acc[mi][ni], a[mi], bh[ni]);
                    MMA_FP16(acc[mi][ni], a[mi], bl[ni]);
                }
        }
        __syncthreads();
    }

    #pragma unroll
    for (int mi = 0; mi < 4; mi++) {
        int r0 = rowBase + wm * 64 + mi * 16 + (lane >> 2);
        #pragma unroll
        for (int ni = 0; ni < 4; ni++) {
            int c0 = colBase + wn * 32 + ni * 8 + (lane & 3) * 2;
            #pragma unroll
            for (int q = 0; q < 4; q++) {
                int r = r0 + (q >> 1) * 8;
                int c = c0 + (q & 1);
                if (c < N) {
                    float v = acc[mi][ni][q] + bias[c];
                    size_t o = (size_t)r * N + c;
                    if (EP == 2) {
                        v = 0.5f * v * (1.0f + erff(v * 0.70710678118654752440f));
                        Ch[o] = __float2half(v);
                    } else {
                        v += res[o];
                        Cf[o] = v;
                    }
                }
            }
        }
    }
}

// ---------------- MHA -> att bf16 split ----------------
__global__ void mha_kernel(const float* __restrict__ qkv,
                           __nv_bfloat16* __restrict__ ahi, __nv_bfloat16* __restrict__ alo) {
    extern __shared__ float smf[];
    float* Q  = smf;
    float* Kx = Q + 64 * HD;
    float* V  = Kx + 64 * HD;
    float* SC = V + 64 * HD;
    int h = blockIdx.x, b = blockIdx.y;
    int tid = threadIdx.x;
    const float* base = qkv + (size_t)(b * NTOK) * (3 * Cdim);
    for (int e = tid; e < 64 * HD; e += blockDim.x) {
        int t = e / HD, d = e % HD;
        Q[e]  = base[(size_t)t * (3 * Cdim) + h * HD + d];
        Kx[e] = base[(size_t)t * (3 * Cdim) + Cdim + h * HD + d];
        V[e]  = base[(size_t)t * (3 * Cdim) + 2 * Cdim + h * HD + d];
    }
    __syncthreads();
    const float scale = rsqrtf((float)HD);
    for (int e = tid; e < 64 * 64; e += blockDim.x) {
        int i = e >> 6, j = e & 63;
        float a = 0.f;
        const float* qi = Q + i * HD;
        const float* kj = Kx + j * HD;
        #pragma unroll 7
        for (int d = 0; d < HD; d++) a += qi[d] * kj[d];
        SC[e] = a * scale;
    }
    __syncthreads();
    if (tid < 64) {
        float* row = SC + tid * 64;
        float mx = -1e30f;
        for (int j = 0; j < 64; j++) mx = fmaxf(mx, row[j]);
        float s = 0.f;
        for (int j = 0; j < 64; j++) { float e = expf(row[j] - mx); row[j] = e; s += e; }
        float inv = 1.f / s;
        for (int j = 0; j < 64; j++) row[j] *= inv;
    }
    __syncthreads();
    for (int e = tid; e < 64 * HD; e += blockDim.x) {
        int i = e / HD, d = e % HD;
        float a = 0.f;
        const float* row = SC + i * 64;
        for (int j = 0; j < 64; j++) a += row[j] * V[j * HD + d];
        split_write_bf(a, ahi, alo, ((size_t)(b * NTOK + i)) * Cdim + h * HD + d);
    }
}

// ---------------- BiFormer ----------------
__global__ void bf_qkv_kernel(const float* __restrict__ o,
                              const float* __restrict__ w, const float* __restrict__ bias) {
    int y = blockIdx.x, b = blockIdx.y;
    __shared__ float xin[64][28];
    for (int e = threadIdx.x; e < 64 * 28; e += blockDim.x) {
        int c = e / 28, xx = e % 28;
        xin[c][xx] = o[((size_t)b * 64 + c) * 784 + y * 28 + xx];
    }
    __syncthreads();
    for (int e = threadIdx.x; e < 192 * 28; e += blockDim.x) {
        int oc = e / 28, xx = e % 28;
        float a = bias[oc];
        const float* wr = w + oc * 64;
        #pragma unroll 16
        for (int c = 0; c < 64; c++) a += xin[c][xx] * wr[c];
        g_bfqkv[((size_t)b * 192 + oc) * 784 + y * 28 + xx] = a;
    }
}

__global__ void bf_pool_kernel() {
    int b = blockIdx.x;
    for (int e = threadIdx.x; e < 64 * NREG; e += blockDim.x) {
        int c = e / NREG, r = e % NREG;
        int rh = r / 7, rw = r % 7;
        float sq = 0.f, sk = 0.f;
        const float* qc = g_bfqkv + ((size_t)b * 192 + c) * 784;
        const float* kc = g_bfqkv + ((size_t)b * 192 + 64 + c) * 784;
        for (int pr = 0; pr < 4; pr++)
            for (int pc = 0; pc < 4; pc++) {
                int s = (rh * 4 + pr) * 28 + rw * 4 + pc;
                sq += qc[s]; sk += kc[s];
            }
        g_qr[(b * 64 + c) * NREG + r] = sq * 0.0625f;
        g_kr[(b * 64 + c) * NREG + r] = sk * 0.0625f;
    }
}

__global__ void bf_topk_kernel() {
    int r = blockIdx.x, b = blockIdx.y;
    __shared__ float qv[64];
    __shared__ float sc[NREG];
    int tid = threadIdx.x;
    if (tid < 64) qv[tid] = g_qr[(b * 64 + tid) * NREG + r];
    __syncthreads();
    if (tid < NREG) {
        float a = 0.f;
        for (int c = 0; c < 64; c++) a += qv[c] * g_kr[(b * 64 + c) * NREG + tid];
        sc[tid] = a;
    }
    __syncthreads();
    if (tid == 0) {
        for (int j = 0; j < TOPK; j++) {
            float mx = -1e30f; int mi = 0;
            for (int s = 0; s < NREG; s++) if (sc[s] > mx) { mx = sc[s]; mi = s; }
            sc[mi] = -1e30f;
            g_idx[(b * NREG + r) * TOPK + j] = mi;
        }
    }
}

__global__ void bf_attn_kernel() {
    int r = blockIdx.x, h = blockIdx.y, b = blockIdx.z;
    __shared__ float q[16][8], kg[64][8], vg[64][8], sc[16][64];
    __shared__ int idx4[4];
    int tid = threadIdx.x;
    if (tid < 4) idx4[tid] = g_idx[(b * NREG + r) * TOPK + tid];
    int rh = r / 7, rw = r % 7;
    {
        int p = tid / 8, d = tid % 8;
        int s = (rh * 4 + p / 4) * 28 + rw * 4 + (p % 4);
        q[p][d] = g_bfqkv[((size_t)b * 192 + h * 8 + d) * 784 + s] * 0.125f;
    }
    __syncthreads();
    for (int e = tid; e < 512; e += 128) {
        int t = e / 8, d = e % 8;
        int reg = idx4[t / 16];
        int p2 = t % 16;
        int s = ((reg / 7) * 4 + p2 / 4) * 28 + (reg % 7) * 4 + (p2 % 4);
        kg[t][d] = g_bfqkv[((size_t)b * 192 + 64 + h * 8 + d) * 784 + s];
        vg[t][d] = g_bfqkv[((size_t)b * 192 + 128 + h * 8 + d) * 784 + s];
    }
    __syncthreads();
    for (int e = tid; e < 1024; e += 128) {
        int p = e >> 6, t = e & 63;
        float a = 0.f;
        #pragma unroll
        for (int d = 0; d < 8; d++) a += q[p][d] * kg[t][d];
        sc[p][t] = a;
    }
    __syncthreads();
    if (tid < 16) {
        float mx = -1e30f;
        for (int t = 0; t < 64; t++) mx = fmaxf(mx, sc[tid][t]);
        float s = 0.f;
        for (int t = 0; t < 64; t++) { float e = expf(sc[tid][t] - mx); sc[tid][t] = e; s += e; }
        float inv = 1.f / s;
        for (int t = 0; t < 64; t++) sc[tid][t] *= inv;
    }
    __syncthreads();
    {
        int p = tid / 8, d = tid % 8;
        float a = 0.f;
        for (int t = 0; t < 64; t++) a += sc[p][t] * vg[t][d];
        int s = (rh * 4 + p / 4) * 28 + rw * 4 + (p % 4);
        g_attg[((size_t)b * 64 + h * 8 + d) * 784 + s] = a;
    }
}

__global__ void bf_out_kernel(const float* __restrict__ lepe_w, const float* __restrict__ lepe_b,
                              const float* __restrict__ out_w, const float* __restrict__ out_b,
                              float* __restrict__ outp) {
    int y = blockIdx.x, b = blockIdx.y;
    __shared__ float v3[3][64][28];
    __shared__ float tmp[64][28];
    int tid = threadIdx.x;
    for (int ry = 0; ry < 3; ry++) {
        int yy = y + ry - 1;
        for (int e = tid; e < 64 * 28; e += blockDim.x) {
            int c = e / 28, xx = e % 28;
            v3[ry][c][xx] = (yy >= 0 && yy < 28)
                ? g_bfqkv[((size_t)b * 192 + 128 + c) * 784 + yy * 28 + xx] : 0.f;
        }
    }
    __syncthreads();
    for (int e = tid; e < 64 * 28; e += blockDim.x) {
        int c = e / 28, xx = e % 28;
        float a = g_attg[((size_t)b * 64 + c) * 784 + y * 28 + xx] + lepe_b[c];
        #pragma unroll
        for (int ky = 0; ky < 3; ky++)
            #pragma unroll
            for (int kx = 0; kx < 3; kx++) {
                int xx2 = xx + kx - 1;
                if (xx2 >= 0 && xx2 < 28) a += v3[ky][c][xx2] * lepe_w[c * 9 + ky * 3 + kx];
            }
        tmp[c][xx] = a;
    }
    __syncthreads();
    for (int e = tid; e < 64 * 28; e += blockDim.x) {
        int oc = e / 28, xx = e % 28;
        float a = out_b[oc];
        const float* wr = out_w + oc * 64;
        #pragma unroll 16
        for (int c = 0; c < 64; c++) a += tmp[c][xx] * wr[c];
        outp[((size_t)b * 64 + oc) * 784 + y * 28 + xx] = a;
    }
}

// ---------------- launch ----------------
extern "C" void kernel_launch(void* const* d_in, const int* in_sizes, int n_in,
                              void* d_out, int out_size) {
    (void)in_sizes; (void)n_in; (void)out_size;
    const float* x        = (const float*)d_in[0];
    const float* norm1_g  = (const float*)d_in[1];
    const float* norm1_b  = (const float*)d_in[2];
    const float* qkv_w    = (const float*)d_in[3];
    const float* proj_w   = (const float*)d_in[4];
    const float* proj_b   = (const float*)d_in[5];
    const float* norm2_g  = (const float*)d_in[6];
    const float* norm2_b  = (const float*)d_in[7];
    const float* fc1_w    = (const float*)d_in[8];
    const float* fc1_b    = (const float*)d_in[9];
    const float* fc2_w    = (const float*)d_in[10];
    const float* fc2_b    = (const float*)d_in[11];
    const float* bf_qkv_w = (const float*)d_in[12];
    const float* bf_qkv_b = (const float*)d_in[13];
    const float* bf_lepe_w= (const float*)d_in[14];
    const float* bf_lepe_b= (const float*)d_in[15];
    const float* bf_out_w = (const float*)d_in[16];
    const float* bf_out_b = (const float*)d_in[17];
    float* out = (float*)d_out;

    __nv_bfloat16 *p_h_hi, *p_h_lo, *p_att_hi, *p_att_lo;
    __nv_bfloat16 *p_wqkv_hi, *p_wqkv_lo, *p_wproj_hi, *p_wproj_lo;
    __half *p_h2, *p_hid, *p_wfc1_hi, *p_wfc1_lo, *p_wfc2_hi, *p_wfc2_lo;
    float *p_qkv, *p_o, *p_xr;
    cudaGetSymbolAddress((void**)&p_h_hi, g_h_hi);     cudaGetSymbolAddress((void**)&p_h_lo, g_h_lo);
    cudaGetSymbolAddress((void**)&p_att_hi, g_att_hi); cudaGetSymbolAddress((void**)&p_att_lo, g_att_lo);
    cudaGetSymbolAddress((void**)&p_h2, g_h2);
    cudaGetSymbolAddress((void**)&p_hid, g_hid);
    cudaGetSymbolAddress((void**)&p_wqkv_hi, g_wqkv_hi);   cudaGetSymbolAddress((void**)&p_wqkv_lo, g_wqkv_lo);
    cudaGetSymbolAddress((void**)&p_wproj_hi, g_wproj_hi); cudaGetSymbolAddress((void**)&p_wproj_lo, g_wproj_lo);
    cudaGetSymbolAddress((void**)&p_wfc1_hi, g_wfc1_hi);   cudaGetSymbolAddress((void**)&p_wfc1_lo, g_wfc1_lo);
    cudaGetSymbolAddress((void**)&p_wfc2_hi, g_wfc2_hi);   cudaGetSymbolAddress((void**)&p_wfc2_lo, g_wfc2_lo);
    cudaGetSymbolAddress((void**)&p_qkv, g_qkv);
    cudaGetSymbolAddress((void**)&p_o, g_o);
    cudaGetSymbolAddress((void**)&p_xr, g_xr);

    const int MHA_SMEM = (3 * 64 * HD + 64 * 64) * 4;
    cudaFuncSetAttribute(mha_kernel, cudaFuncAttributeMaxDynamicSharedMemorySize, MHA_SMEM);
    cudaFuncSetAttribute(mma_gemm3<0>, cudaFuncAttributeMaxDynamicSharedMemorySize, GEMM3_SMEM);
    cudaFuncSetAttribute(mma_gemm3<1>, cudaFuncAttributeMaxDynamicSharedMemorySize, GEMM3_SMEM);
    cudaFuncSetAttribute(mma_gemm2<2>, cudaFuncAttributeMaxDynamicSharedMemorySize, GEMM2_SMEM);
    cudaFuncSetAttribute(mma_gemm2<3>, cudaFuncAttributeMaxDynamicSharedMemorySize, GEMM2_SMEM);

    // weight splits
    split_bf_kernel<<<(Cdim * 3 * Cdim + 255) / 256, 256>>>(qkv_w,  p_wqkv_hi,  p_wqkv_lo,  Cdim * 3 * Cdim);
    split_bf_kernel<<<(Cdim * Cdim + 255) / 256, 256>>>(proj_w, p_wproj_hi, p_wproj_lo, Cdim * Cdim);
    split_fp_kernel<<<(Cdim * HID + 255) / 256, 256>>>(fc1_w,  p_wfc1_hi,  p_wfc1_lo,  Cdim * HID);
    split_fp_kernel<<<(HID * Cdim + 255) / 256, 256>>>(fc2_w,  p_wfc2_hi,  p_wfc2_lo,  HID * Cdim);

    // 1) LN1 -> h split (bf16)
    ln_kernel<<<ROWS, 256>>>(x, norm1_g, norm1_b, p_h_hi, p_h_lo);
    // 2) qkv = h @ qkv_w  (bf16x3)
    mma_gemm3<0><<<dim3((3 * Cdim + 127) / 128, ROWS / 128), 256, GEMM3_SMEM>>>(
        p_h_hi, p_h_lo, p_wqkv_hi, p_wqkv_lo, nullptr,
        p_qkv, ROWS, 3 * Cdim, Cdim);
    // 3) MHA -> att split (bf16)
    mha_kernel<<<dim3(NHd, Bsz), 256, MHA_SMEM>>>(p_qkv, p_att_hi, p_att_lo);
    // 4) o = att @ proj_w + proj_b  (bf16x3)
    mma_gemm3<1><<<dim3((Cdim + 127) / 128, ROWS / 128), 256, GEMM3_SMEM>>>(
        p_att_hi, p_att_lo, p_wproj_hi, p_wproj_lo, proj_b,
        p_o, ROWS, Cdim, Cdim);
    // 5-9) BiFormer branch
    bf_qkv_kernel<<<dim3(28, Bsz), 256>>>(p_o, bf_qkv_w, bf_qkv_b);
    bf_pool_kernel<<<Bsz, 256>>>();
    bf_topk_kernel<<<dim3(NREG, Bsz), 64>>>();
    bf_attn_kernel<<<dim3(NREG, 8, Bsz), 128>>>();
    bf_out_kernel<<<dim3(28, Bsz), 256>>>(bf_lepe_w, bf_lepe_b, bf_out_w, bf_out_b, out + OUT_OFF);
    // 10) LN2 -> xr fp32, h2 fp16
    ln2_kernel<<<ROWS, 256>>>(p_o, x, norm2_g, norm2_b, p_xr, p_h2);
    // 11) hid = gelu(h2 @ fc1_w + b) -> fp16  (fp16x2)
    mma_gemm2<2><<<dim3((HID + 127) / 128, ROWS / 128), 256, GEMM2_SMEM>>>(
        p_h2, p_wfc1_hi, p_wfc1_lo, fc1_b, nullptr,
        nullptr, p_hid, ROWS, HID, Cdim);
    // 12) out = hid @ fc2_w + b + xr  (fp16x2)
    mma_gemm2<3><<<dim3((Cdim + 127) / 128, ROWS / 128), 256, GEMM2_SMEM>>>(
        p_hid, p_wfc2_hi, p_wfc2_lo, fc2_b, p_xr,
        out, nullptr, ROWS, Cdim, HID);
}

// round 9
// speedup vs baseline: 1.1399x; 1.0173x over previous
#include <cuda_runtime.h>
#include <cuda_bf16.h>
#include <cuda_fp16.h>
#include <math.h>
#include <stdint.h>

// ---------------- problem constants ----------------
#define Bsz   128
#define NTOK  64
#define Cdim  784
#define NHd   8
#define HD    98
#define HID   3136
#define ROWS  (Bsz*NTOK)  // 8192
#define NREG  49
#define TOPK  4
#define OUT_OFF (Bsz*NTOK*Cdim)

// ---------------- scratch ----------------
__device__ __nv_bfloat16 g_h_hi [ROWS*Cdim];
__device__ __nv_bfloat16 g_h_lo [ROWS*Cdim];
__device__ float         g_qkv  [ROWS*3*Cdim];
__device__ __nv_bfloat16 g_att_hi[ROWS*Cdim];
__device__ __nv_bfloat16 g_att_lo[ROWS*Cdim];
__device__ float         g_o    [ROWS*Cdim];
__device__ float         g_xr   [ROWS*Cdim];
__device__ __half        g_h2   [ROWS*Cdim];
__device__ __half        g_hid  [ROWS*HID];
// weight splits [K, N]
__device__ __nv_bfloat16 g_wqkv_hi[Cdim*3*Cdim];
__device__ __nv_bfloat16 g_wqkv_lo[Cdim*3*Cdim];
__device__ __nv_bfloat16 g_wproj_hi[Cdim*Cdim];
__device__ __nv_bfloat16 g_wproj_lo[Cdim*Cdim];
__device__ __half        g_wfc1_hi[Cdim*HID];
__device__ __half        g_wfc1_lo[Cdim*HID];
__device__ __half        g_wfc2_hi[HID*Cdim];
__device__ __half        g_wfc2_lo[HID*Cdim];
// biformer
__device__ float g_bfqkv[Bsz*192*784];
__device__ float g_attg [Bsz*64*784];
__device__ int   g_idx [Bsz*NREG*TOPK];

// ---------------- helpers ----------------
__device__ __forceinline__ uint32_t smem_u32(const void* p) {
    return (uint32_t)__cvta_generic_to_shared(p);
}
#define CP_ASYNC16(dst_u32, src, sz) \
    asm volatile("cp.async.cg.shared.global [%0], [%1], 16, %2;\n" :: "r"(dst_u32), "l"(src), "r"(sz))
#define CP_COMMIT() asm volatile("cp.async.commit_group;\n")
#define LDSM4(r0,r1,r2,r3,a) \
    asm volatile("ldmatrix.sync.aligned.m8n8.x4.shared.b16 {%0,%1,%2,%3},[%4];" \
        : "=r"(r0),"=r"(r1),"=r"(r2),"=r"(r3) : "r"(a))
#define LDSM4T(r0,r1,r2,r3,a) \
    asm volatile("ldmatrix.sync.aligned.m8n8.x4.trans.shared.b16 {%0,%1,%2,%3},[%4];" \
        : "=r"(r0),"=r"(r1),"=r"(r2),"=r"(r3) : "r"(a))
#define MMA_BF16(d, a, b) \
    asm volatile("mma.sync.aligned.m16n8k16.row.col.f32.bf16.bf16.f32 " \
        "{%0,%1,%2,%3},{%4,%5,%6,%7},{%8,%9},{%0,%1,%2,%3};" \
        : "+f"(d[0]),"+f"(d[1]),"+f"(d[2]),"+f"(d[3]) \
        : "r"(a[0]),"r"(a[1]),"r"(a[2]),"r"(a[3]),"r"(b[0]),"r"(b[1]))
#define MMA_FP16(d, a, b) \
    asm volatile("mma.sync.aligned.m16n8k16.row.col.f32.f16.f16.f32 " \
        "{%0,%1,%2,%3},{%4,%5,%6,%7},{%8,%9},{%0,%1,%2,%3};" \
        : "+f"(d[0]),"+f"(d[1]),"+f"(d[2]),"+f"(d[3]) \
        : "r"(a[0]),"r"(a[1]),"r"(a[2]),"r"(a[3]),"r"(b[0]),"r"(b[1]))

__device__ __forceinline__ void split_write_bf(float v, __nv_bfloat16* hi, __nv_bfloat16* lo, size_t o) {
    __nv_bfloat16 h = __float2bfloat16(v);
    hi[o] = h;
    lo[o] = __float2bfloat16(v - __bfloat162float(h));
}

// ---------------- weight splits ----------------
__global__ void split_bf_kernel(const float* __restrict__ in, __nv_bfloat16* __restrict__ hi,
                                __nv_bfloat16* __restrict__ lo, int n) {
    int i = blockIdx.x * blockDim.x + threadIdx.x;
    if (i < n) {
        float v = in[i];
        __nv_bfloat16 h = __float2bfloat16(v);
        hi[i] = h;
        lo[i] = __float2bfloat16(v - __bfloat162float(h));
    }
}
__global__ void split_fp_kernel(const float* __restrict__ in, __half* __restrict__ hi,
                                __half* __restrict__ lo, int n) {
    int i = blockIdx.x * blockDim.x + threadIdx.x;
    if (i < n) {
        float v = in[i];
        __half h = __float2half(v);
        hi[i] = h;
        lo[i] = __float2half(v - __half2float(h));
    }
}

// ---------------- LN1: x -> (h_hi, h_lo) bf16 ----------------
__global__ void ln_kernel(const float* __restrict__ x,
                          const float* __restrict__ g, const float* __restrict__ b,
                          __nv_bfloat16* __restrict__ ohi, __nv_bfloat16* __restrict__ olo) {
    int row = blockIdx.x;
    const float* xr = x + (size_t)row * Cdim;
    __shared__ float buf[Cdim];
    __shared__ float rs[2];
    __shared__ float red[64];
    float s = 0.f, ss = 0.f;
    for (int i = threadIdx.x; i < Cdim; i += blockDim.x) {
        float v = xr[i]; buf[i] = v; s += v; ss += v * v;
    }
    for (int o = 16; o > 0; o >>= 1) { s += __shfl_down_sync(~0u, s, o); ss += __shfl_down_sync(~0u, ss, o); }
    int wid = threadIdx.x >> 5, lid = threadIdx.x & 31;
    if (lid == 0) { red[wid] = s; red[wid + 32] = ss; }
    __syncthreads();
    if (threadIdx.x == 0) {
        float t = 0.f, tt = 0.f;
        int nw = blockDim.x >> 5;
        for (int i = 0; i < nw; i++) { t += red[i]; tt += red[i + 32]; }
        float mean = t / Cdim, var = tt / Cdim - mean * mean;
        rs[0] = mean; rs[1] = rsqrtf(var + 1e-5f);
    }
    __syncthreads();
    float mean = rs[0], inv = rs[1];
    for (int i = threadIdx.x; i < Cdim; i += blockDim.x)
        split_write_bf((buf[i] - mean) * inv * g[i] + b[i], ohi, olo, (size_t)row * Cdim + i);
}

// ---------------- LN2: xr = o + x (fp32), h2 fp16 ----------------
__global__ void ln2_kernel(const float* __restrict__ ov, const float* __restrict__ x,
                           const float* __restrict__ g, const float* __restrict__ b,
                           float* __restrict__ xr_out, __half* __restrict__ oh) {
    int row = blockIdx.x;
    const float* a = ov + (size_t)row * Cdim;
    const float* c = x  + (size_t)row * Cdim;
    __shared__ float buf[Cdim];
    __shared__ float rs[2];
    __shared__ float red[64];
    float s = 0.f, ss = 0.f;
    for (int i = threadIdx.x; i < Cdim; i += blockDim.x) {
        float v = a[i] + c[i];
        buf[i] = v;
        xr_out[(size_t)row * Cdim + i] = v;
        s += v; ss += v * v;
    }
    for (int o = 16; o > 0; o >>= 1) { s += __shfl_down_sync(~0u, s, o); ss += __shfl_down_sync(~0u, ss, o); }
    int wid = threadIdx.x >> 5, lid = threadIdx.x & 31;
    if (lid == 0) { red[wid] = s; red[wid + 32] = ss; }
    __syncthreads();
    if (threadIdx.x == 0) {
        float t = 0.f, tt = 0.f;
        int nw = blockDim.x >> 5;
        for (int i = 0; i < nw; i++) { t += red[i]; tt += red[i + 32]; }
        float mean = t / Cdim, var = tt / Cdim - mean * mean;
        rs[0] = mean; rs[1] = rsqrtf(var + 1e-5f);
    }
    __syncthreads();
    float mean = rs[0], inv = rs[1];
    for (int i = threadIdx.x; i < Cdim; i += blockDim.x)
        oh[(size_t)row * Cdim + i] = __float2half((buf[i] - mean) * inv * g[i] + b[i]);
}

// ================= bf16x3 GEMM (qkv, proj) — BK=32, 3-stage =================
#define ASTR3 40
#define BSTR3 136
#define A3_ST (2*128*ASTR3)
#define B3_ST (2*32*BSTR3)
#define GEMM3_SMEM ((3*A3_ST + 3*B3_ST) * 2)  // 113664

template<int EP>
__global__ __launch_bounds__(256, 1)
void mma_gemm3(const __nv_bfloat16* __restrict__ Ah, const __nv_bfloat16* __restrict__ Al,
               const __nv_bfloat16* __restrict__ Bh, const __nv_bfloat16* __restrict__ Bl,
               const float* __restrict__ bias,
               float* __restrict__ Cf, int M, int N, int K) {
    extern __shared__ __nv_bfloat16 sm3[];
    __nv_bfloat16* Asm = sm3;
    __nv_bfloat16* Bsm = sm3 + 3 * A3_ST;

    int tid = threadIdx.x;
    int warp = tid >> 5, lane = tid & 31;
    int wm = warp & 1, wn = warp >> 1;
    int rowBase = blockIdx.y * 128, colBase = blockIdx.x * 128;

    const int KT = (K + 31) >> 5;
    float acc[4][4][4];
    #pragma unroll
    for (int i = 0; i < 4; i++)
        #pragma unroll
        for (int j = 0; j < 4; j++)
            #pragma unroll
            for (int q = 0; q < 4; q++) acc[i][j][q] = 0.f;

    auto load_stage = [&](int st, int kt) {
        int koff = kt * 32;
        __nv_bfloat16* Ast = Asm + st * A3_ST;
        __nv_bfloat16* Bst = Bsm + st * B3_ST;
        #pragma unroll
        for (int part = 0; part < 2; part++) {
            const __nv_bfloat16* Aasrc = part ? Al : Ah;
            #pragma unroll
            for (int i = 0; i < 2; i++) {
                int chunk = i * 256 + tid;
                int r = chunk >> 2, cc = (chunk & 3) * 8;
                int k = koff + cc;
                uint32_t dst = smem_u32(Ast + part * (128 * ASTR3) + r * ASTR3 + cc);
                const __nv_bfloat16* src = Aasrc + (size_t)(rowBase + r) * K + (k < K ? k : 0);
                CP_ASYNC16(dst, src, (k < K) ? 16 : 0);
            }
        }
        #pragma unroll
        for (int part = 0; part < 2; part++) {
            const __nv_bfloat16* Bbsrc = part ? Bl : Bh;
            #pragma unroll
            for (int i = 0; i < 2; i++) {
                int chunk = i * 256 + tid;
                int r = chunk >> 4, cc = (chunk & 15) * 8;
                int k = koff + r, n = colBase + cc;
                bool ok = (k < K) && (n < N);
                uint32_t dst = smem_u32(Bst + part * (32 * BSTR3) + r * BSTR3 + cc);
                const __nv_bfloat16* src = Bbsrc + (ok ? ((size_t)k * N + n) : 0);
                CP_ASYNC16(dst, src, ok ? 16 : 0);
            }
        }
    };

    load_stage(0, 0); CP_COMMIT();
    if (KT > 1) { load_stage(1, 1); }
    CP_COMMIT();

    int lrow = lane & 15, lhalf = (lane >> 4) * 8;

    for (int kt = 0; kt < KT; kt++) {
        if (kt + 2 < KT) load_stage((kt + 2) % 3, kt + 2);
        CP_COMMIT();
        asm volatile("cp.async.wait_group 2;");
        __syncthreads();

        int st = kt % 3;
        __nv_bfloat16* Ast = Asm + st * A3_ST;
        __nv_bfloat16* Bst = Bsm + st * B3_ST;

        #pragma unroll
        for (int kk = 0; kk < 32; kk += 16) {
            uint32_t ah[4][4], al[4][4], bh[4][2], bl[4][2];
            #pragma unroll
            for (int mi = 0; mi < 4; mi++) {
                uint32_t a0 = smem_u32(Ast + (wm * 64 + mi * 16 + lrow) * ASTR3 + kk + lhalf);
                LDSM4(ah[mi][0], ah[mi][1], ah[mi][2], ah[mi][3], a0);
                uint32_t a1 = smem_u32(Ast + 128 * ASTR3 + (wm * 64 + mi * 16 + lrow) * ASTR3 + kk + lhalf);
                LDSM4(al[mi][0], al[mi][1], al[mi][2], al[mi][3], a1);
            }
            #pragma unroll
            for (int pr = 0; pr < 2; pr++) {
                uint32_t r0, r1, r2, r3;
                uint32_t b0 = smem_u32(Bst + (kk + lrow) * BSTR3 + wn * 32 + pr * 16 + lhalf);
                LDSM4T(r0, r1, r2, r3, b0);
                bh[pr * 2][0] = r0; bh[pr * 2][1] = r1; bh[pr * 2 + 1][0] = r2; bh[pr * 2 + 1][1] = r3;
                uint32_t b1 = smem_u32(Bst + 32 * BSTR3 + (kk + lrow) * BSTR3 + wn * 32 + pr * 16 + lhalf);
                LDSM4T(r0, r1, r2, r3, b1);
                bl[pr * 2][0] = r0; bl[pr * 2][1] = r1; bl[pr * 2 + 1][0] = r2; bl[pr * 2 + 1][1] = r3;
            }
            #pragma unroll
            for (int mi = 0; mi < 4; mi++)
                #pragma unroll
                for (int ni = 0; ni < 4; ni++) {
                    MMA_BF16(acc[mi][ni], ah[mi], bh[ni]);
                    MMA_BF16(acc[mi][ni], ah[mi], bl[ni]);
                    MMA_BF16(acc[mi][ni], al[mi], bh[ni]);
                }
        }
        __syncthreads();
    }

    #pragma unroll
    for (int mi = 0; mi < 4; mi++) {
        int r0 = rowBase + wm * 64 + mi * 16 + (lane >> 2);
        #pragma unroll
        for (int ni = 0; ni < 4; ni++) {
            int c0 = colBase + wn * 32 + ni * 8 + (lane & 3) * 2;
            #pragma unroll
            for (int q = 0; q < 4; q++) {
                int r = r0 + (q >> 1) * 8;
                int c = c0 + (q & 1);
                if (c < N) {
                    float v = acc[mi][ni][q];
                    if (EP >= 1) v += bias[c];
                    Cf[(size_t)r * N + c] = v;
                }
            }
        }
    }
}

// ================= fp16x2 GEMM (fc1, fc2) — BK=32, 3-stage =================
#define ASTR2 40
#define BSTR2 136
#define A2_ST (128*ASTR2)
#define B2_ST (2*32*BSTR2)
#define GEMM2_SMEM ((3*A2_ST + 3*B2_ST) * 2)  // 82944

template<int EP>
__global__ __launch_bounds__(256, 1)
void mma_gemm2(const __half* __restrict__ A,
               const __half* __restrict__ Bh, const __half* __restrict__ Bl,
               const float* __restrict__ bias, const float* __restrict__ res,
               float* __restrict__ Cf, __half* __restrict__ Ch,
               int M, int N, int K) {
    extern __shared__ __half sm2[];
    __half* Asm = sm2;
    __half* Bsm = sm2 + 3 * A2_ST;

    int tid = threadIdx.x;
    int warp = tid >> 5, lane = tid & 31;
    int wm = warp & 1, wn = warp >> 1;
    int rowBase = blockIdx.y * 128, colBase = blockIdx.x * 128;

    const int KT = (K + 31) >> 5;
    float acc[4][4][4];
    #pragma unroll
    for (int i = 0; i < 4; i++)
        #pragma unroll
        for (int j = 0; j < 4; j++)
            #pragma unroll
            for (int q = 0; q < 4; q++) acc[i][j][q] = 0.f;

    auto load_stage = [&](int st, int kt) {
        int koff = kt * 32;
        __half* Ast = Asm + st * A2_ST;
        __half* Bst = Bsm + st * B2_ST;
        #pragma unroll
        for (int i = 0; i < 2; i++) {
            int chunk = i * 256 + tid;
            int r = chunk >> 2, cc = (chunk & 3) * 8;
            int k = koff + cc;
            uint32_t dst = smem_u32(Ast + r * ASTR2 + cc);
            const __half* src = A + (size_t)(rowBase + r) * K + (k < K ? k : 0);
            CP_ASYNC16(dst, src, (k < K) ? 16 : 0);
        }
        #pragma unroll
        for (int part = 0; part < 2; part++) {
            const __half* Bbsrc = part ? Bl : Bh;
            #pragma unroll
            for (int i = 0; i < 2; i++) {
                int chunk = i * 256 + tid;
                int r = chunk >> 4, cc = (chunk & 15) * 8;
                int k = koff + r, n = colBase + cc;
                bool ok = (k < K) && (n < N);
                uint32_t dst = smem_u32(Bst + part * (32 * BSTR2) + r * BSTR2 + cc);
                const __half* src = Bbsrc + (ok ? ((size_t)k * N + n) : 0);
                CP_ASYNC16(dst, src, ok ? 16 : 0);
            }
        }
    };

    load_stage(0, 0); CP_COMMIT();
    if (KT > 1) { load_stage(1, 1); }
    CP_COMMIT();

    int lrow = lane & 15, lhalf = (lane >> 4) * 8;

    for (int kt = 0; kt < KT; kt++) {
        if (kt + 2 < KT) load_stage((kt + 2) % 3, kt + 2);
        CP_COMMIT();
        asm volatile("cp.async.wait_group 2;");
        __syncthreads();

        int st = kt % 3;
        __half* Ast = Asm + st * A2_ST;
        __half* Bst = Bsm + st * B2_ST;

        #pragma unroll
        for (int kk = 0; kk < 32; kk += 16) {
            uint32_t a[4][4], bh[4][2], bl[4][2];
            #pragma unroll
            for (int mi = 0; mi < 4; mi++) {
                uint32_t a0 = smem_u32(Ast + (wm * 64 + mi * 16 + lrow) * ASTR2 + kk + lhalf);
                LDSM4(a[mi][0], a[mi][1], a[mi][2], a[mi][3], a0);
            }
            #pragma unroll
            for (int pr = 0; pr < 2; pr++) {
                uint32_t r0, r1, r2, r3;
                uint32_t b0 = smem_u32(Bst + (kk + lrow) * BSTR2 + wn * 32 + pr * 16 + lhalf);
                LDSM4T(r0, r1, r2, r3, b0);
                bh[pr * 2][0] = r0; bh[pr * 2][1] = r1; bh[pr * 2 + 1][0] = r2; bh[pr * 2 + 1][1] = r3;
                uint32_t b1 = smem_u32(Bst + 32 * BSTR2 + (kk + lrow) * BSTR2 + wn * 32 + pr * 16 + lhalf);
                LDSM4T(r0, r1, r2, r3, b1);
                bl[pr * 2][0] = r0; bl[pr * 2][1] = r1; bl[pr * 2 + 1][0] = r2; bl[pr * 2 + 1][1] = r3;
            }
            #pragma unroll
            for (int mi = 0; mi < 4; mi++)
                #pragma unroll
                for (int ni = 0; ni < 4; ni++) {
                    MMA_FP16(acc[mi][ni], a[mi], bh[ni]);
                    MMA_FP16(acc[mi][ni], a[mi], bl[ni]);
                }
        }
        __syncthreads();
    }

    #pragma unroll
    for (int mi = 0; mi < 4; mi++) {
        int r0 = rowBase + wm * 64 + mi * 16 + (lane >> 2);
        #pragma unroll
        for (int ni = 0; ni < 4; ni++) {
            int c0 = colBase + wn * 32 + ni * 8 + (lane & 3) * 2;
            #pragma unroll
            for (int q = 0; q < 4; q++) {
                int r = r0 + (q >> 1) * 8;
                int c = c0 + (q & 1);
                if (c < N) {
                    float v = acc[mi][ni][q] + bias[c];
                    size_t o = (size_t)r * N + c;
                    if (EP == 2) {
                        v = 0.5f * v * (1.0f + erff(v * 0.70710678118654752440f));
                        Ch[o] = __float2half(v);
                    } else {
                        v += res[o];
                        Cf[o] = v;
                    }
                }
            }
        }
    }
}

// ---------------- MHA -> att bf16 split ----------------
__global__ void mha_kernel(const float* __restrict__ qkv,
                           __nv_bfloat16* __restrict__ ahi, __nv_bfloat16* __restrict__ alo) {
    extern __shared__ float smf[];
    float* Q  = smf;
    float* Kx = Q + 64 * HD;
    float* V  = Kx + 64 * HD;
    float* SC = V + 64 * HD;
    int h = blockIdx.x, b = blockIdx.y;
    int tid = threadIdx.x;
    const float* base = qkv + (size_t)(b * NTOK) * (3 * Cdim);
    for (int e = tid; e < 64 * HD; e += blockDim.x) {
        int t = e / HD, d = e % HD;
        Q[e]  = base[(size_t)t * (3 * Cdim) + h * HD + d];
        Kx[e] = base[(size_t)t * (3 * Cdim) + Cdim + h * HD + d];
        V[e]  = base[(size_t)t * (3 * Cdim) + 2 * Cdim + h * HD + d];
    }
    __syncthreads();
    const float scale = rsqrtf((float)HD);
    for (int e = tid; e < 64 * 64; e += blockDim.x) {
        int i = e >> 6, j = e & 63;
        float a = 0.f;
        const float* qi = Q + i * HD;
        const float* kj = Kx + j * HD;
        #pragma unroll 7
        for (int d = 0; d < HD; d++) a += qi[d] * kj[d];
        SC[e] = a * scale;
    }
    __syncthreads();
    if (tid < 64) {
        float* row = SC + tid * 64;
        float mx = -1e30f;
        for (int j = 0; j < 64; j++) mx = fmaxf(mx, row[j]);
        float s = 0.f;
        for (int j = 0; j < 64; j++) { float e = expf(row[j] - mx); row[j] = e; s += e; }
        float inv = 1.f / s;
        for (int j = 0; j < 64; j++) row[j] *= inv;
    }
    __syncthreads();
    for (int e = tid; e < 64 * HD; e += blockDim.x) {
        int i = e / HD, d = e % HD;
        float a = 0.f;
        const float* row = SC + i * 64;
        for (int j = 0; j < 64; j++) a += row[j] * V[j * HD + d];
        split_write_bf(a, ahi, alo, ((size_t)(b * NTOK + i)) * Cdim + h * HD + d);
    }
}

// ---------------- BiFormer ----------------
__global__ void bf_qkv_kernel(const float* __restrict__ o,
                              const float* __restrict__ w, const float* __restrict__ bias) {
    int y = blockIdx.x, b = blockIdx.y;
    __shared__ float xin[64][28];
    for (int e = threadIdx.x; e < 64 * 28; e += blockDim.x) {
        int c = e / 28, xx = e % 28;
        xin[c][xx] = o[((size_t)b * 64 + c) * 784 + y * 28 + xx];
    }
    __syncthreads();
    for (int e = threadIdx.x; e < 192 * 28; e += blockDim.x) {
        int oc = e / 28, xx = e % 28;
        float a = bias[oc];
        const float* wr = w + oc * 64;
        #pragma unroll 16
        for (int c = 0; c < 64; c++) a += xin[c][xx] * wr[c];
        g_bfqkv[((size_t)b * 192 + oc) * 784 + y * 28 + xx] = a;
    }
}

// fused region pooling + routing top-4 (one block per batch)
__global__ void bf_routing_kernel() {
    int b = blockIdx.x;
    int tid = threadIdx.x;  // 256
    __shared__ float qr[64][NREG];
    __shared__ float kr[64][NREG];
    __shared__ float ar[NREG][NREG];
    for (int e = tid; e < 64 * NREG; e += 256) {
        int c = e / NREG, r = e % NREG;
        int rh = r / 7, rw = r % 7;
        float sq = 0.f, sk = 0.f;
        const float* qc = g_bfqkv + ((size_t)b * 192 + c) * 784;
        const float* kc = g_bfqkv + ((size_t)b * 192 + 64 + c) * 784;
        #pragma unroll
        for (int pr = 0; pr < 4; pr++)
            #pragma unroll
            for (int pc = 0; pc < 4; pc++) {
                int s = (rh * 4 + pr) * 28 + rw * 4 + pc;
                sq += qc[s]; sk += kc[s];
            }
        qr[c][r] = sq * 0.0625f;
        kr[c][r] = sk * 0.0625f;
    }
    __syncthreads();
    for (int e = tid; e < NREG * NREG; e += 256) {
        int i = e / NREG, j = e % NREG;
        float a = 0.f;
        #pragma unroll 16
        for (int c = 0; c < 64; c++) a += qr[c][i] * kr[c][j];
        ar[i][j] = a;
    }
    __syncthreads();
    if (tid < NREG) {
        float* row = ar[tid];
        #pragma unroll
        for (int j = 0; j < TOPK; j++) {
            float mx = -1e30f; int mi = 0;
            for (int s = 0; s < NREG; s++) if (row[s] > mx) { mx = row[s]; mi = s; }
            row[mi] = -1e30f;
            g_idx[(b * NREG + tid) * TOPK + j] = mi;
        }
    }
}

__global__ void bf_attn_kernel() {
    int r = blockIdx.x, h = blockIdx.y, b = blockIdx.z;
    __shared__ float q[16][8], kg[64][8], vg[64][8], sc[16][64];
    __shared__ int idx4[4];
    int tid = threadIdx.x;
    if (tid < 4) idx4[tid] = g_idx[(b * NREG + r) * TOPK + tid];
    int rh = r / 7, rw = r % 7;
    {
        int p = tid / 8, d = tid % 8;
        int s = (rh * 4 + p / 4) * 28 + rw * 4 + (p % 4);
        q[p][d] = g_bfqkv[((size_t)b * 192 + h * 8 + d) * 784 + s] * 0.125f;
    }
    __syncthreads();
    for (int e = tid; e < 512; e += 128) {
        int t = e / 8, d = e % 8;
        int reg = idx4[t / 16];
        int p2 = t % 16;
        int s = ((reg / 7) * 4 + p2 / 4) * 28 + (reg % 7) * 4 + (p2 % 4);
        kg[t][d] = g_bfqkv[((size_t)b * 192 + 64 + h * 8 + d) * 784 + s];
        vg[t][d] = g_bfqkv[((size_t)b * 192 + 128 + h * 8 + d) * 784 + s];
    }
    __syncthreads();
    for (int e = tid; e < 1024; e += 128) {
        int p = e >> 6, t = e & 63;
        float a = 0.f;
        #pragma unroll
        for (int d = 0; d < 8; d++) a += q[p][d] * kg[t][d];
        sc[p][t] = a;
    }
    __syncthreads();
    if (tid < 16) {
        float mx = -1e30f;
        for (int t = 0; t < 64; t++) mx = fmaxf(mx, sc[tid][t]);
        float s = 0.f;
        for (int t = 0; t < 64; t++) { float e = expf(sc[tid][t] - mx); sc[tid][t] = e; s += e; }
        float inv = 1.f / s;
        for (int t = 0; t < 64; t++) sc[tid][t] *= inv;
    }
    __syncthreads();
    {
        int p = tid / 8, d = tid % 8;
        float a = 0.f;
        for (int t = 0; t < 64; t++) a += sc[p][t] * vg[t][d];
        int s = (rh * 4 + p / 4) * 28 + rw * 4 + (p % 4);
        g_attg[((size_t)b * 64 + h * 8 + d) * 784 + s] = a;
    }
}

__global__ void bf_out_kernel(const float* __restrict__ lepe_w, const float* __restrict__ lepe_b,
                              const float* __restrict__ out_w, const float* __restrict__ out_b,
                              float* __restrict__ outp) {
    int y = blockIdx.x, b = blockIdx.y;
    __shared__ float v3[3][64][28];
    __shared__ float tmp[64][28];
    int tid = threadIdx.x;
    for (int ry = 0; ry < 3; ry++) {
        int yy = y + ry - 1;
        for (int e = tid; e < 64 * 28; e += blockDim.x) {
            int c = e / 28, xx = e % 28;
            v3[ry][c][xx] = (yy >= 0 && yy < 28)
                ? g_bfqkv[((size_t)b * 192 + 128 + c) * 784 + yy * 28 + xx] : 0.f;
        }
    }
    __syncthreads();
    for (int e = tid; e < 64 * 28; e += blockDim.x) {
        int c = e / 28, xx = e % 28;
        float a = g_attg[((size_t)b * 64 + c) * 784 + y * 28 + xx] + lepe_b[c];
        #pragma unroll
        for (int ky = 0; ky < 3; ky++)
            #pragma unroll
            for (int kx = 0; kx < 3; kx++) {
                int xx2 = xx + kx - 1;
                if (xx2 >= 0 && xx2 < 28) a += v3[ky][c][xx2] * lepe_w[c * 9 + ky * 3 + kx];
            }
        tmp[c][xx] = a;
    }
    __syncthreads();
    for (int e = tid; e < 64 * 28; e += blockDim.x) {
        int oc = e / 28, xx = e % 28;
        float a = out_b[oc];
        const float* wr = out_w + oc * 64;
        #pragma unroll 16
        for (int c = 0; c < 64; c++) a += tmp[c][xx] * wr[c];
        outp[((size_t)b * 64 + oc) * 784 + y * 28 + xx] = a;
    }
}

// ---------------- launch ----------------
extern "C" void kernel_launch(void* const* d_in, const int* in_sizes, int n_in,
                              void* d_out, int out_size) {
    (void)in_sizes; (void)n_in; (void)out_size;
    const float* x        = (const float*)d_in[0];
    const float* norm1_g  = (const float*)d_in[1];
    const float* norm1_b  = (const float*)d_in[2];
    const float* qkv_w    = (const float*)d_in[3];
    const float* proj_w   = (const float*)d_in[4];
    const float* proj_b   = (const float*)d_in[5];
    const float* norm2_g  = (const float*)d_in[6];
    const float* norm2_b  = (const float*)d_in[7];
    const float* fc1_w    = (const float*)d_in[8];
    const float* fc1_b    = (const float*)d_in[9];
    const float* fc2_w    = (const float*)d_in[10];
    const float* fc2_b    = (const float*)d_in[11];
    const float* bf_qkv_w = (const float*)d_in[12];
    const float* bf_qkv_b = (const float*)d_in[13];
    const float* bf_lepe_w= (const float*)d_in[14];
    const float* bf_lepe_b= (const float*)d_in[15];
    const float* bf_out_w = (const float*)d_in[16];
    const float* bf_out_b = (const float*)d_in[17];
    float* out = (float*)d_out;

    __nv_bfloat16 *p_h_hi, *p_h_lo, *p_att_hi, *p_att_lo;
    __nv_bfloat16 *p_wqkv_hi, *p_wqkv_lo, *p_wproj_hi, *p_wproj_lo;
    __half *p_h2, *p_hid, *p_wfc1_hi, *p_wfc1_lo, *p_wfc2_hi, *p_wfc2_lo;
    float *p_qkv, *p_o, *p_xr;
    cudaGetSymbolAddress((void**)&p_h_hi, g_h_hi);     cudaGetSymbolAddress((void**)&p_h_lo, g_h_lo);
    cudaGetSymbolAddress((void**)&p_att_hi, g_att_hi); cudaGetSymbolAddress((void**)&p_att_lo, g_att_lo);
    cudaGetSymbolAddress((void**)&p_h2, g_h2);
    cudaGetSymbolAddress((void**)&p_hid, g_hid);
    cudaGetSymbolAddress((void**)&p_wqkv_hi, g_wqkv_hi);   cudaGetSymbolAddress((void**)&p_wqkv_lo, g_wqkv_lo);
    cudaGetSymbolAddress((void**)&p_wproj_hi, g_wproj_hi); cudaGetSymbolAddress((void**)&p_wproj_lo, g_wproj_lo);
    cudaGetSymbolAddress((void**)&p_wfc1_hi, g_wfc1_hi);   cudaGetSymbolAddress((void**)&p_wfc1_lo, g_wfc1_lo);
    cudaGetSymbolAddress((void**)&p_wfc2_hi, g_wfc2_hi);   cudaGetSymbolAddress((void**)&p_wfc2_lo, g_wfc2_lo);
    cudaGetSymbolAddress((void**)&p_qkv, g_qkv);
    cudaGetSymbolAddress((void**)&p_o, g_o);
    cudaGetSymbolAddress((void**)&p_xr, g_xr);

    const int MHA_SMEM = (3 * 64 * HD + 64 * 64) * 4;
    cudaFuncSetAttribute(mha_kernel, cudaFuncAttributeMaxDynamicSharedMemorySize, MHA_SMEM);
    cudaFuncSetAttribute(mma_gemm3<0>, cudaFuncAttributeMaxDynamicSharedMemorySize, GEMM3_SMEM);
    cudaFuncSetAttribute(mma_gemm3<1>, cudaFuncAttributeMaxDynamicSharedMemorySize, GEMM3_SMEM);
    cudaFuncSetAttribute(mma_gemm2<2>, cudaFuncAttributeMaxDynamicSharedMemorySize, GEMM2_SMEM);
    cudaFuncSetAttribute(mma_gemm2<3>, cudaFuncAttributeMaxDynamicSharedMemorySize, GEMM2_SMEM);

    // one-time stream/event creation (host resources only; no device allocations)
    static cudaStream_t s1 = nullptr;
    static cudaEvent_t eFork = nullptr, eW = nullptr, eO = nullptr, eBF = nullptr;
    if (!s1) {
        cudaStreamCreateWithFlags(&s1, cudaStreamNonBlocking);
        cudaEventCreateWithFlags(&eFork, cudaEventDisableTiming);
        cudaEventCreateWithFlags(&eW,    cudaEventDisableTiming);
        cudaEventCreateWithFlags(&eO,    cudaEventDisableTiming);
        cudaEventCreateWithFlags(&eBF,   cudaEventDisableTiming);
    }

    // fork: s1 joins the (possibly capturing) default stream
    cudaEventRecord(eFork, 0);
    cudaStreamWaitEvent(s1, eFork, 0);

    // s1: proj/fc weight splits (overlap with LN1 + qkv GEMM on s0)
    split_bf_kernel<<<(Cdim * Cdim + 255) / 256, 256, 0, s1>>>(proj_w, p_wproj_hi, p_wproj_lo, Cdim * Cdim);
    split_fp_kernel<<<(Cdim * HID + 255) / 256, 256, 0, s1>>>(fc1_w,  p_wfc1_hi,  p_wfc1_lo,  Cdim * HID);
    split_fp_kernel<<<(HID * Cdim + 255) / 256, 256, 0, s1>>>(fc2_w,  p_wfc2_hi,  p_wfc2_lo,  HID * Cdim);
    cudaEventRecord(eW, s1);

    // s0: qkv weight split + LN1 + qkv GEMM + MHA
    split_bf_kernel<<<(Cdim * 3 * Cdim + 255) / 256, 256>>>(qkv_w, p_wqkv_hi, p_wqkv_lo, Cdim * 3 * Cdim);
    ln_kernel<<<ROWS, 256>>>(x, norm1_g, norm1_b, p_h_hi, p_h_lo);
    mma_gemm3<0><<<dim3((3 * Cdim + 127) / 128, ROWS / 128), 256, GEMM3_SMEM>>>(
        p_h_hi, p_h_lo, p_wqkv_hi, p_wqkv_lo, nullptr,
        p_qkv, ROWS, 3 * Cdim, Cdim);
    mha_kernel<<<dim3(NHd, Bsz), 256, MHA_SMEM>>>(p_qkv, p_att_hi, p_att_lo);
    // proj needs wproj (from s1)
    cudaStreamWaitEvent(0, eW, 0);
    mma_gemm3<1><<<dim3((Cdim + 127) / 128, ROWS / 128), 256, GEMM3_SMEM>>>(
        p_att_hi, p_att_lo, p_wproj_hi, p_wproj_lo, proj_b,
        p_o, ROWS, Cdim, Cdim);
    cudaEventRecord(eO, 0);

    // s1: BiFormer branch (depends on o) — overlaps LN2/fc1/fc2 on s0
    cudaStreamWaitEvent(s1, eO, 0);
    bf_qkv_kernel<<<dim3(28, Bsz), 256, 0, s1>>>(p_o, bf_qkv_w, bf_qkv_b);
    bf_routing_kernel<<<Bsz, 256, 0, s1>>>();
    bf_attn_kernel<<<dim3(NREG, 8, Bsz), 128, 0, s1>>>();
    bf_out_kernel<<<dim3(28, Bsz), 256, 0, s1>>>(bf_lepe_w, bf_lepe_b, bf_out_w, bf_out_b, out + OUT_OFF);
    cudaEventRecord(eBF, s1);

    // s0: MLP branch
    ln2_kernel<<<ROWS, 256>>>(p_o, x, norm2_g, norm2_b, p_xr, p_h2);
    mma_gemm2<2><<<dim3((HID + 127) / 128, ROWS / 128), 256, GEMM2_SMEM>>>(
        p_h2, p_wfc1_hi, p_wfc1_lo, fc1_b, nullptr,
        nullptr, p_hid, ROWS, HID, Cdim);
    mma_gemm2<3><<<dim3((Cdim + 127) / 128, ROWS / 128), 256, GEMM2_SMEM>>>(
        p_hid, p_wfc2_hi, p_wfc2_lo, fc2_b, p_xr,
        out, nullptr, ROWS, Cdim, HID);

    // join
    cudaStreamWaitEvent(0, eBF, 0);
}

// round 10
// speedup vs baseline: 1.2320x; 1.0809x over previous
#include <cuda_runtime.h>
#include <cuda_bf16.h>
#include <cuda_fp16.h>
#include <math.h>
#include <stdint.h>

// ---------------- problem constants ----------------
#define Bsz   128
#define NTOK  64
#define Cdim  784
#define NHd   8
#define HD    98
#define HID   3136
#define ROWS  (Bsz*NTOK)  // 8192
#define NREG  49
#define TOPK  4
#define OUT_OFF (Bsz*NTOK*Cdim)

// ---------------- scratch ----------------
__device__ __nv_bfloat16 g_h_hi [ROWS*Cdim];
__device__ __nv_bfloat16 g_h_lo [ROWS*Cdim];
__device__ float         g_qkv  [ROWS*3*Cdim];
__device__ __nv_bfloat16 g_att_hi[ROWS*Cdim];
__device__ __nv_bfloat16 g_att_lo[ROWS*Cdim];
__device__ float         g_o    [ROWS*Cdim];
__device__ float         g_xr   [ROWS*Cdim];
__device__ __half        g_h2   [ROWS*Cdim];
__device__ __half        g_hid  [ROWS*HID];
// weight splits [K, N]
__device__ __nv_bfloat16 g_wqkv_hi[Cdim*3*Cdim];
__device__ __nv_bfloat16 g_wqkv_lo[Cdim*3*Cdim];
__device__ __nv_bfloat16 g_wproj_hi[Cdim*Cdim];
__device__ __nv_bfloat16 g_wproj_lo[Cdim*Cdim];
__device__ __half        g_wfc1 [Cdim*HID];
__device__ __half        g_wfc2 [HID*Cdim];
// biformer
__device__ float g_bfqkv[Bsz*192*784];
__device__ float g_attg [Bsz*64*784];
__device__ int   g_idx [Bsz*NREG*TOPK];

// ---------------- helpers ----------------
__device__ __forceinline__ uint32_t smem_u32(const void* p) {
    return (uint32_t)__cvta_generic_to_shared(p);
}
#define CP_ASYNC16(dst_u32, src, sz) \
    asm volatile("cp.async.cg.shared.global [%0], [%1], 16, %2;\n" :: "r"(dst_u32), "l"(src), "r"(sz))
#define CP_COMMIT() asm volatile("cp.async.commit_group;\n")
#define LDSM4(r0,r1,r2,r3,a) \
    asm volatile("ldmatrix.sync.aligned.m8n8.x4.shared.b16 {%0,%1,%2,%3},[%4];" \
        : "=r"(r0),"=r"(r1),"=r"(r2),"=r"(r3) : "r"(a))
#define LDSM4T(r0,r1,r2,r3,a) \
    asm volatile("ldmatrix.sync.aligned.m8n8.x4.trans.shared.b16 {%0,%1,%2,%3},[%4];" \
        : "=r"(r0),"=r"(r1),"=r"(r2),"=r"(r3) : "r"(a))
#define MMA_BF16(d, a, b) \
    asm volatile("mma.sync.aligned.m16n8k16.row.col.f32.bf16.bf16.f32 " \
        "{%0,%1,%2,%3},{%4,%5,%6,%7},{%8,%9},{%0,%1,%2,%3};" \
        : "+f"(d[0]),"+f"(d[1]),"+f"(d[2]),"+f"(d[3]) \
        : "r"(a[0]),"r"(a[1]),"r"(a[2]),"r"(a[3]),"r"(b[0]),"r"(b[1]))
#define MMA_FP16(d, a, b) \
    asm volatile("mma.sync.aligned.m16n8k16.row.col.f32.f16.f16.f32 " \
        "{%0,%1,%2,%3},{%4,%5,%6,%7},{%8,%9},{%0,%1,%2,%3};" \
        : "+f"(d[0]),"+f"(d[1]),"+f"(d[2]),"+f"(d[3]) \
        : "r"(a[0]),"r"(a[1]),"r"(a[2]),"r"(a[3]),"r"(b[0]),"r"(b[1]))

__device__ __forceinline__ void split_write_bf(float v, __nv_bfloat16* hi, __nv_bfloat16* lo, size_t o) {
    __nv_bfloat16 h = __float2bfloat16(v);
    hi[o] = h;
    lo[o] = __float2bfloat16(v - __bfloat162float(h));
}

// ---------------- weight prep ----------------
__global__ void split_bf_kernel(const float* __restrict__ in, __nv_bfloat16* __restrict__ hi,
                                __nv_bfloat16* __restrict__ lo, int n) {
    int i = blockIdx.x * blockDim.x + threadIdx.x;
    if (i < n) {
        float v = in[i];
        __nv_bfloat16 h = __float2bfloat16(v);
        hi[i] = h;
        lo[i] = __float2bfloat16(v - __bfloat162float(h));
    }
}
__global__ void conv_fp_kernel(const float* __restrict__ in, __half* __restrict__ o, int n) {
    int i = blockIdx.x * blockDim.x + threadIdx.x;
    if (i < n) o[i] = __float2half(in[i]);
}

// ---------------- LN1: x -> (h_hi, h_lo) bf16 ----------------
__global__ void ln_kernel(const float* __restrict__ x,
                          const float* __restrict__ g, const float* __restrict__ b,
                          __nv_bfloat16* __restrict__ ohi, __nv_bfloat16* __restrict__ olo) {
    int row = blockIdx.x;
    const float* xr = x + (size_t)row * Cdim;
    __shared__ float buf[Cdim];
    __shared__ float rs[2];
    __shared__ float red[64];
    float s = 0.f, ss = 0.f;
    for (int i = threadIdx.x; i < Cdim; i += blockDim.x) {
        float v = xr[i]; buf[i] = v; s += v; ss += v * v;
    }
    for (int o = 16; o > 0; o >>= 1) { s += __shfl_down_sync(~0u, s, o); ss += __shfl_down_sync(~0u, ss, o); }
    int wid = threadIdx.x >> 5, lid = threadIdx.x & 31;
    if (lid == 0) { red[wid] = s; red[wid + 32] = ss; }
    __syncthreads();
    if (threadIdx.x == 0) {
        float t = 0.f, tt = 0.f;
        int nw = blockDim.x >> 5;
        for (int i = 0; i < nw; i++) { t += red[i]; tt += red[i + 32]; }
        float mean = t / Cdim, var = tt / Cdim - mean * mean;
        rs[0] = mean; rs[1] = rsqrtf(var + 1e-5f);
    }
    __syncthreads();
    float mean = rs[0], inv = rs[1];
    for (int i = threadIdx.x; i < Cdim; i += blockDim.x)
        split_write_bf((buf[i] - mean) * inv * g[i] + b[i], ohi, olo, (size_t)row * Cdim + i);
}

// ---------------- LN2: xr = o + x (fp32), h2 fp16 ----------------
__global__ void ln2_kernel(const float* __restrict__ ov, const float* __restrict__ x,
                           const float* __restrict__ g, const float* __restrict__ b,
                           float* __restrict__ xr_out, __half* __restrict__ oh) {
    int row = blockIdx.x;
    const float* a = ov + (size_t)row * Cdim;
    const float* c = x  + (size_t)row * Cdim;
    __shared__ float buf[Cdim];
    __shared__ float rs[2];
    __shared__ float red[64];
    float s = 0.f, ss = 0.f;
    for (int i = threadIdx.x; i < Cdim; i += blockDim.x) {
        float v = a[i] + c[i];
        buf[i] = v;
        xr_out[(size_t)row * Cdim + i] = v;
        s += v; ss += v * v;
    }
    for (int o = 16; o > 0; o >>= 1) { s += __shfl_down_sync(~0u, s, o); ss += __shfl_down_sync(~0u, ss, o); }
    int wid = threadIdx.x >> 5, lid = threadIdx.x & 31;
    if (lid == 0) { red[wid] = s; red[wid + 32] = ss; }
    __syncthreads();
    if (threadIdx.x == 0) {
        float t = 0.f, tt = 0.f;
        int nw = blockDim.x >> 5;
        for (int i = 0; i < nw; i++) { t += red[i]; tt += red[i + 32]; }
        float mean = t / Cdim, var = tt / Cdim - mean * mean;
        rs[0] = mean; rs[1] = rsqrtf(var + 1e-5f);
    }
    __syncthreads();
    float mean = rs[0], inv = rs[1];
    for (int i = threadIdx.x; i < Cdim; i += blockDim.x)
        oh[(size_t)row * Cdim + i] = __float2half((buf[i] - mean) * inv * g[i] + b[i]);
}

// ================= bf16x3 GEMM (qkv, proj) — BK=32, 3-stage =================
#define ASTR3 40
#define BSTR3 136
#define A3_ST (2*128*ASTR3)
#define B3_ST (2*32*BSTR3)
#define GEMM3_SMEM ((3*A3_ST + 3*B3_ST) * 2)  // 113664

template<int EP>
__global__ __launch_bounds__(256, 1)
void mma_gemm3(const __nv_bfloat16* __restrict__ Ah, const __nv_bfloat16* __restrict__ Al,
               const __nv_bfloat16* __restrict__ Bh, const __nv_bfloat16* __restrict__ Bl,
               const float* __restrict__ bias,
               float* __restrict__ Cf, int M, int N, int K) {
    extern __shared__ __nv_bfloat16 sm3[];
    __nv_bfloat16* Asm = sm3;
    __nv_bfloat16* Bsm = sm3 + 3 * A3_ST;

    int tid = threadIdx.x;
    int warp = tid >> 5, lane = tid & 31;
    int wm = warp & 1, wn = warp >> 1;
    int rowBase = blockIdx.y * 128, colBase = blockIdx.x * 128;

    const int KT = (K + 31) >> 5;
    float acc[4][4][4];
    #pragma unroll
    for (int i = 0; i < 4; i++)
        #pragma unroll
        for (int j = 0; j < 4; j++)
            #pragma unroll
            for (int q = 0; q < 4; q++) acc[i][j][q] = 0.f;

    auto load_stage = [&](int st, int kt) {
        int koff = kt * 32;
        __nv_bfloat16* Ast = Asm + st * A3_ST;
        __nv_bfloat16* Bst = Bsm + st * B3_ST;
        #pragma unroll
        for (int part = 0; part < 2; part++) {
            const __nv_bfloat16* Aasrc = part ? Al : Ah;
            #pragma unroll
            for (int i = 0; i < 2; i++) {
                int chunk = i * 256 + tid;
                int r = chunk >> 2, cc = (chunk & 3) * 8;
                int k = koff + cc;
                uint32_t dst = smem_u32(Ast + part * (128 * ASTR3) + r * ASTR3 + cc);
                const __nv_bfloat16* src = Aasrc + (size_t)(rowBase + r) * K + (k < K ? k : 0);
                CP_ASYNC16(dst, src, (k < K) ? 16 : 0);
            }
        }
        #pragma unroll
        for (int part = 0; part < 2; part++) {
            const __nv_bfloat16* Bbsrc = part ? Bl : Bh;
            #pragma unroll
            for (int i = 0; i < 2; i++) {
                int chunk = i * 256 + tid;
                int r = chunk >> 4, cc = (chunk & 15) * 8;
                int k = koff + r, n = colBase + cc;
                bool ok = (k < K) && (n < N);
                uint32_t dst = smem_u32(Bst + part * (32 * BSTR3) + r * BSTR3 + cc);
                const __nv_bfloat16* src = Bbsrc + (ok ? ((size_t)k * N + n) : 0);
                CP_ASYNC16(dst, src, ok ? 16 : 0);
            }
        }
    };

    load_stage(0, 0); CP_COMMIT();
    if (KT > 1) { load_stage(1, 1); }
    CP_COMMIT();

    int lrow = lane & 15, lhalf = (lane >> 4) * 8;

    for (int kt = 0; kt < KT; kt++) {
        if (kt + 2 < KT) load_stage((kt + 2) % 3, kt + 2);
        CP_COMMIT();
        asm volatile("cp.async.wait_group 2;");
        __syncthreads();

        int st = kt % 3;
        __nv_bfloat16* Ast = Asm + st * A3_ST;
        __nv_bfloat16* Bst = Bsm + st * B3_ST;

        #pragma unroll
        for (int kk = 0; kk < 32; kk += 16) {
            uint32_t ah[4][4], al[4][4], bh[4][2], bl[4][2];
            #pragma unroll
            for (int mi = 0; mi < 4; mi++) {
                uint32_t a0 = smem_u32(Ast + (wm * 64 + mi * 16 + lrow) * ASTR3 + kk + lhalf);
                LDSM4(ah[mi][0], ah[mi][1], ah[mi][2], ah[mi][3], a0);
                uint32_t a1 = smem_u32(Ast + 128 * ASTR3 + (wm * 64 + mi * 16 + lrow) * ASTR3 + kk + lhalf);
                LDSM4(al[mi][0], al[mi][1], al[mi][2], al[mi][3], a1);
            }
            #pragma unroll
            for (int pr = 0; pr < 2; pr++) {
                uint32_t r0, r1, r2, r3;
                uint32_t b0 = smem_u32(Bst + (kk + lrow) * BSTR3 + wn * 32 + pr * 16 + lhalf);
                LDSM4T(r0, r1, r2, r3, b0);
                bh[pr * 2][0] = r0; bh[pr * 2][1] = r1; bh[pr * 2 + 1][0] = r2; bh[pr * 2 + 1][1] = r3;
                uint32_t b1 = smem_u32(Bst + 32 * BSTR3 + (kk + lrow) * BSTR3 + wn * 32 + pr * 16 + lhalf);
                LDSM4T(r0, r1, r2, r3, b1);
                bl[pr * 2][0] = r0; bl[pr * 2][1] = r1; bl[pr * 2 + 1][0] = r2; bl[pr * 2 + 1][1] = r3;
            }
            #pragma unroll
            for (int mi = 0; mi < 4; mi++)
                #pragma unroll
                for (int ni = 0; ni < 4; ni++) {
                    MMA_BF16(acc[mi][ni], ah[mi], bh[ni]);
                    MMA_BF16(acc[mi][ni], ah[mi], bl[ni]);
                    MMA_BF16(acc[mi][ni], al[mi], bh[ni]);
                }
        }
        __syncthreads();
    }

    #pragma unroll
    for (int mi = 0; mi < 4; mi++) {
        int r0 = rowBase + wm * 64 + mi * 16 + (lane >> 2);
        #pragma unroll
        for (int ni = 0; ni < 4; ni++) {
            int c0 = colBase + wn * 32 + ni * 8 + (lane & 3) * 2;
            #pragma unroll
            for (int q = 0; q < 4; q++) {
                int r = r0 + (q >> 1) * 8;
                int c = c0 + (q & 1);
                if (c < N) {
                    float v = acc[mi][ni][q];
                    if (EP >= 1) v += bias[c];
                    Cf[(size_t)r * N + c] = v;
                }
            }
        }
    }
}

// ================= fp16 single-term GEMM (fc1, fc2) — BK=32, 3-stage =================
#define ASTR2 40
#define BSTR2 136
#define A2_ST (128*ASTR2)
#define B2_ST (32*BSTR2)
#define GEMM2_SMEM ((3*A2_ST + 3*B2_ST) * 2)  // 56832

template<int EP>
__global__ __launch_bounds__(256, 1)
void mma_gemm2(const __half* __restrict__ A, const __half* __restrict__ B,
               const float* __restrict__ bias, const float* __restrict__ res,
               float* __restrict__ Cf, __half* __restrict__ Ch,
               int M, int N, int K) {
    extern __shared__ __half sm2[];
    __half* Asm = sm2;
    __half* Bsm = sm2 + 3 * A2_ST;

    int tid = threadIdx.x;
    int warp = tid >> 5, lane = tid & 31;
    int wm = warp & 1, wn = warp >> 1;
    int rowBase = blockIdx.y * 128, colBase = blockIdx.x * 128;

    const int KT = (K + 31) >> 5;
    float acc[4][4][4];
    #pragma unroll
    for (int i = 0; i < 4; i++)
        #pragma unroll
        for (int j = 0; j < 4; j++)
            #pragma unroll
            for (int q = 0; q < 4; q++) acc[i][j][q] = 0.f;

    auto load_stage = [&](int st, int kt) {
        int koff = kt * 32;
        __half* Ast = Asm + st * A2_ST;
        __half* Bst = Bsm + st * B2_ST;
        #pragma unroll
        for (int i = 0; i < 2; i++) {
            int chunk = i * 256 + tid;
            int r = chunk >> 2, cc = (chunk & 3) * 8;
            int k = koff + cc;
            uint32_t dst = smem_u32(Ast + r * ASTR2 + cc);
            const __half* src = A + (size_t)(rowBase + r) * K + (k < K ? k : 0);
            CP_ASYNC16(dst, src, (k < K) ? 16 : 0);
        }
        #pragma unroll
        for (int i = 0; i < 2; i++) {
            int chunk = i * 256 + tid;
            int r = chunk >> 4, cc = (chunk & 15) * 8;
            int k = koff + r, n = colBase + cc;
            bool ok = (k < K) && (n < N);
            uint32_t dst = smem_u32(Bst + r * BSTR2 + cc);
            const __half* src = B + (ok ? ((size_t)k * N + n) : 0);
            CP_ASYNC16(dst, src, ok ? 16 : 0);
        }
    };

    load_stage(0, 0); CP_COMMIT();
    if (KT > 1) { load_stage(1, 1); }
    CP_COMMIT();

    int lrow = lane & 15, lhalf = (lane >> 4) * 8;

    for (int kt = 0; kt < KT; kt++) {
        if (kt + 2 < KT) load_stage((kt + 2) % 3, kt + 2);
        CP_COMMIT();
        asm volatile("cp.async.wait_group 2;");
        __syncthreads();

        int st = kt % 3;
        __half* Ast = Asm + st * A2_ST;
        __half* Bst = Bsm + st * B2_ST;

        #pragma unroll
        for (int kk = 0; kk < 32; kk += 16) {
            uint32_t a[4][4], bb[4][2];
            #pragma unroll
            for (int mi = 0; mi < 4; mi++) {
                uint32_t a0 = smem_u32(Ast + (wm * 64 + mi * 16 + lrow) * ASTR2 + kk + lhalf);
                LDSM4(a[mi][0], a[mi][1], a[mi][2], a[mi][3], a0);
            }
            #pragma unroll
            for (int pr = 0; pr < 2; pr++) {
                uint32_t r0, r1, r2, r3;
                uint32_t b0 = smem_u32(Bst + (kk + lrow) * BSTR2 + wn * 32 + pr * 16 + lhalf);
                LDSM4T(r0, r1, r2, r3, b0);
                bb[pr * 2][0] = r0; bb[pr * 2][1] = r1; bb[pr * 2 + 1][0] = r2; bb[pr * 2 + 1][1] = r3;
            }
            #pragma unroll
            for (int mi = 0; mi < 4; mi++)
                #pragma unroll
                for (int ni = 0; ni < 4; ni++)
                    MMA_FP16(acc[mi][ni], a[mi], bb[ni]);
        }
        __syncthreads();
    }

    #pragma unroll
    for (int mi = 0; mi < 4; mi++) {
        int r0 = rowBase + wm * 64 + mi * 16 + (lane >> 2);
        #pragma unroll
        for (int ni = 0; ni < 4; ni++) {
            int c0 = colBase + wn * 32 + ni * 8 + (lane & 3) * 2;
            #pragma unroll
            for (int q = 0; q < 4; q++) {
                int r = r0 + (q >> 1) * 8;
                int c = c0 + (q & 1);
                if (c < N) {
                    float v = acc[mi][ni][q] + bias[c];
                    size_t o = (size_t)r * N + c;
                    if (EP == 2) {
                        v = 0.5f * v * (1.0f + erff(v * 0.70710678118654752440f));
                        Ch[o] = __float2half(v);
                    } else {
                        v += res[o];
                        Cf[o] = v;
                    }
                }
            }
        }
    }
}

// ---------------- MHA -> att bf16 split ----------------
__global__ void mha_kernel(const float* __restrict__ qkv,
                           __nv_bfloat16* __restrict__ ahi, __nv_bfloat16* __restrict__ alo) {
    extern __shared__ float smf[];
    float* Q  = smf;
    float* Kx = Q + 64 * HD;
    float* V  = Kx + 64 * HD;
    float* SC = V + 64 * HD;
    int h = blockIdx.x, b = blockIdx.y;
    int tid = threadIdx.x;
    const float* base = qkv + (size_t)(b * NTOK) * (3 * Cdim);
    for (int e = tid; e < 64 * HD; e += blockDim.x) {
        int t = e / HD, d = e % HD;
        Q[e]  = base[(size_t)t * (3 * Cdim) + h * HD + d];
        Kx[e] = base[(size_t)t * (3 * Cdim) + Cdim + h * HD + d];
        V[e]  = base[(size_t)t * (3 * Cdim) + 2 * Cdim + h * HD + d];
    }
    __syncthreads();
    const float scale = rsqrtf((float)HD);
    for (int e = tid; e < 64 * 64; e += blockDim.x) {
        int i = e >> 6, j = e & 63;
        float a = 0.f;
        const float* qi = Q + i * HD;
        const float* kj = Kx + j * HD;
        #pragma unroll 7
        for (int d = 0; d < HD; d++) a += qi[d] * kj[d];
        SC[e] = a * scale;
    }
    __syncthreads();
    if (tid < 64) {
        float* row = SC + tid * 64;
        float mx = -1e30f;
        for (int j = 0; j < 64; j++) mx = fmaxf(mx, row[j]);
        float s = 0.f;
        for (int j = 0; j < 64; j++) { float e = expf(row[j] - mx); row[j] = e; s += e; }
        float inv = 1.f / s;
        for (int j = 0; j < 64; j++) row[j] *= inv;
    }
    __syncthreads();
    for (int e = tid; e < 64 * HD; e += blockDim.x) {
        int i = e / HD, d = e % HD;
        float a = 0.f;
        const float* row = SC + i * 64;
        for (int j = 0; j < 64; j++) a += row[j] * V[j * HD + d];
        split_write_bf(a, ahi, alo, ((size_t)(b * NTOK + i)) * Cdim + h * HD + d);
    }
}

// ---------------- BiFormer ----------------
__global__ void bf_qkv_kernel(const float* __restrict__ o,
                              const float* __restrict__ w, const float* __restrict__ bias) {
    int y = blockIdx.x, b = blockIdx.y;
    __shared__ float xin[64][28];
    for (int e = threadIdx.x; e < 64 * 28; e += blockDim.x) {
        int c = e / 28, xx = e % 28;
        xin[c][xx] = o[((size_t)b * 64 + c) * 784 + y * 28 + xx];
    }
    __syncthreads();
    for (int e = threadIdx.x; e < 192 * 28; e += blockDim.x) {
        int oc = e / 28, xx = e % 28;
        float a = bias[oc];
        const float* wr = w + oc * 64;
        #pragma unroll 16
        for (int c = 0; c < 64; c++) a += xin[c][xx] * wr[c];
        g_bfqkv[((size_t)b * 192 + oc) * 784 + y * 28 + xx] = a;
    }
}

// fused region pooling + routing top-4 (one block per batch)
__global__ void bf_routing_kernel() {
    int b = blockIdx.x;
    int tid = threadIdx.x;  // 256
    __shared__ float qr[64][NREG];
    __shared__ float kr[64][NREG];
    __shared__ float ar[NREG][NREG];
    for (int e = tid; e < 64 * NREG; e += 256) {
        int c = e / NREG, r = e % NREG;
        int rh = r / 7, rw = r % 7;
        float sq = 0.f, sk = 0.f;
        const float* qc = g_bfqkv + ((size_t)b * 192 + c) * 784;
        const float* kc = g_bfqkv + ((size_t)b * 192 + 64 + c) * 784;
        #pragma unroll
        for (int pr = 0; pr < 4; pr++)
            #pragma unroll
            for (int pc = 0; pc < 4; pc++) {
                int s = (rh * 4 + pr) * 28 + rw * 4 + pc;
                sq += qc[s]; sk += kc[s];
            }
        qr[c][r] = sq * 0.0625f;
        kr[c][r] = sk * 0.0625f;
    }
    __syncthreads();
    for (int e = tid; e < NREG * NREG; e += 256) {
        int i = e / NREG, j = e % NREG;
        float a = 0.f;
        #pragma unroll 16
        for (int c = 0; c < 64; c++) a += qr[c][i] * kr[c][j];
        ar[i][j] = a;
    }
    __syncthreads();
    if (tid < NREG) {
        float* row = ar[tid];
        #pragma unroll
        for (int j = 0; j < TOPK; j++) {
            float mx = -1e30f; int mi = 0;
            for (int s = 0; s < NREG; s++) if (row[s] > mx) { mx = row[s]; mi = s; }
            row[mi] = -1e30f;
            g_idx[(b * NREG + tid) * TOPK + j] = mi;
        }
    }
}

__global__ void bf_attn_kernel() {
    int r = blockIdx.x, h = blockIdx.y, b = blockIdx.z;
    __shared__ float q[16][8], kg[64][8], vg[64][8], sc[16][64];
    __shared__ int idx4[4];
    int tid = threadIdx.x;
    if (tid < 4) idx4[tid] = g_idx[(b * NREG + r) * TOPK + tid];
    int rh = r / 7, rw = r % 7;
    {
        int p = tid / 8, d = tid % 8;
        int s = (rh * 4 + p / 4) * 28 + rw * 4 + (p % 4);
        q[p][d] = g_bfqkv[((size_t)b * 192 + h * 8 + d) * 784 + s] * 0.125f;
    }
    __syncthreads();
    for (int e = tid; e < 512; e += 128) {
        int t = e / 8, d = e % 8;
        int reg = idx4[t / 16];
        int p2 = t % 16;
        int s = ((reg / 7) * 4 + p2 / 4) * 28 + (reg % 7) * 4 + (p2 % 4);
        kg[t][d] = g_bfqkv[((size_t)b * 192 + 64 + h * 8 + d) * 784 + s];
        vg[t][d] = g_bfqkv[((size_t)b * 192 + 128 + h * 8 + d) * 784 + s];
    }
    __syncthreads();
    for (int e = tid; e < 1024; e += 128) {
        int p = e >> 6, t = e & 63;
        float a = 0.f;
        #pragma unroll
        for (int d = 0; d < 8; d++) a += q[p][d] * kg[t][d];
        sc[p][t] = a;
    }
    __syncthreads();
    if (tid < 16) {
        float mx = -1e30f;
        for (int t = 0; t < 64; t++) mx = fmaxf(mx, sc[tid][t]);
        float s = 0.f;
        for (int t = 0; t < 64; t++) { float e = expf(sc[tid][t] - mx); sc[tid][t] = e; s += e; }
        float inv = 1.f / s;
        for (int t = 0; t < 64; t++) sc[tid][t] *= inv;
    }
    __syncthreads();
    {
        int p = tid / 8, d = tid % 8;
        float a = 0.f;
        for (int t = 0; t < 64; t++) a += sc[p][t] * vg[t][d];
        int s = (rh * 4 + p / 4) * 28 + rw * 4 + (p % 4);
        g_attg[((size_t)b * 64 + h * 8 + d) * 784 + s] = a;
    }
}

__global__ void bf_out_kernel(const float* __restrict__ lepe_w, const float* __restrict__ lepe_b,
                              const float* __restrict__ out_w, const float* __restrict__ out_b,
                              float* __restrict__ outp) {
    int y = blockIdx.x, b = blockIdx.y;
    __shared__ float v3[3][64][28];
    __shared__ float tmp[64][28];
    int tid = threadIdx.x;
    for (int ry = 0; ry < 3; ry++) {
        int yy = y + ry - 1;
        for (int e = tid; e < 64 * 28; e += blockDim.x) {
            int c = e / 28, xx = e % 28;
            v3[ry][c][xx] = (yy >= 0 && yy < 28)
                ? g_bfqkv[((size_t)b * 192 + 128 + c) * 784 + yy * 28 + xx] : 0.f;
        }
    }
    __syncthreads();
    for (int e = tid; e < 64 * 28; e += blockDim.x) {
        int c = e / 28, xx = e % 28;
        float a = g_attg[((size_t)b * 64 + c) * 784 + y * 28 + xx] + lepe_b[c];
        #pragma unroll
        for (int ky = 0; ky < 3; ky++)
            #pragma unroll
            for (int kx = 0; kx < 3; kx++) {
                int xx2 = xx + kx - 1;
                if (xx2 >= 0 && xx2 < 28) a += v3[ky][c][xx2] * lepe_w[c * 9 + ky * 3 + kx];
            }
        tmp[c][xx] = a;
    }
    __syncthreads();
    for (int e = tid; e < 64 * 28; e += blockDim.x) {
        int oc = e / 28, xx = e % 28;
        float a = out_b[oc];
        const float* wr = out_w + oc * 64;
        #pragma unroll 16
        for (int c = 0; c < 64; c++) a += tmp[c][xx] * wr[c];
        outp[((size_t)b * 64 + oc) * 784 + y * 28 + xx] = a;
    }
}

// ---------------- launch ----------------
extern "C" void kernel_launch(void* const* d_in, const int* in_sizes, int n_in,
                              void* d_out, int out_size) {
    (void)in_sizes; (void)n_in; (void)out_size;
    const float* x        = (const float*)d_in[0];
    const float* norm1_g  = (const float*)d_in[1];
    const float* norm1_b  = (const float*)d_in[2];
    const float* qkv_w    = (const float*)d_in[3];
    const float* proj_w   = (const float*)d_in[4];
    const float* proj_b   = (const float*)d_in[5];
    const float* norm2_g  = (const float*)d_in[6];
    const float* norm2_b  = (const float*)d_in[7];
    const float* fc1_w    = (const float*)d_in[8];
    const float* fc1_b    = (const float*)d_in[9];
    const float* fc2_w    = (const float*)d_in[10];
    const float* fc2_b    = (const float*)d_in[11];
    const float* bf_qkv_w = (const float*)d_in[12];
    const float* bf_qkv_b = (const float*)d_in[13];
    const float* bf_lepe_w= (const float*)d_in[14];
    const float* bf_lepe_b= (const float*)d_in[15];
    const float* bf_out_w = (const float*)d_in[16];
    const float* bf_out_b = (const float*)d_in[17];
    float* out = (float*)d_out;

    __nv_bfloat16 *p_h_hi, *p_h_lo, *p_att_hi, *p_att_lo;
    __nv_bfloat16 *p_wqkv_hi, *p_wqkv_lo, *p_wproj_hi, *p_wproj_lo;
    __half *p_h2, *p_hid, *p_wfc1, *p_wfc2;
    float *p_qkv, *p_o, *p_xr;
    cudaGetSymbolAddress((void**)&p_h_hi, g_h_hi);     cudaGetSymbolAddress((void**)&p_h_lo, g_h_lo);
    cudaGetSymbolAddress((void**)&p_att_hi, g_att_hi); cudaGetSymbolAddress((void**)&p_att_lo, g_att_lo);
    cudaGetSymbolAddress((void**)&p_h2, g_h2);
    cudaGetSymbolAddress((void**)&p_hid, g_hid);
    cudaGetSymbolAddress((void**)&p_wqkv_hi, g_wqkv_hi);   cudaGetSymbolAddress((void**)&p_wqkv_lo, g_wqkv_lo);
    cudaGetSymbolAddress((void**)&p_wproj_hi, g_wproj_hi); cudaGetSymbolAddress((void**)&p_wproj_lo, g_wproj_lo);
    cudaGetSymbolAddress((void**)&p_wfc1, g_wfc1);
    cudaGetSymbolAddress((void**)&p_wfc2, g_wfc2);
    cudaGetSymbolAddress((void**)&p_qkv, g_qkv);
    cudaGetSymbolAddress((void**)&p_o, g_o);
    cudaGetSymbolAddress((void**)&p_xr, g_xr);

    const int MHA_SMEM = (3 * 64 * HD + 64 * 64) * 4;
    cudaFuncSetAttribute(mha_kernel, cudaFuncAttributeMaxDynamicSharedMemorySize, MHA_SMEM);
    cudaFuncSetAttribute(mma_gemm3<0>, cudaFuncAttributeMaxDynamicSharedMemorySize, GEMM3_SMEM);
    cudaFuncSetAttribute(mma_gemm3<1>, cudaFuncAttributeMaxDynamicSharedMemorySize, GEMM3_SMEM);
    cudaFuncSetAttribute(mma_gemm2<2>, cudaFuncAttributeMaxDynamicSharedMemorySize, GEMM2_SMEM);
    cudaFuncSetAttribute(mma_gemm2<3>, cudaFuncAttributeMaxDynamicSharedMemorySize, GEMM2_SMEM);

    // one-time stream/event creation (host resources only; no device allocations)
    static cudaStream_t s1 = nullptr;
    static cudaEvent_t eFork = nullptr, eW = nullptr, eO = nullptr, eBF = nullptr;
    if (!s1) {
        cudaStreamCreateWithFlags(&s1, cudaStreamNonBlocking);
        cudaEventCreateWithFlags(&eFork, cudaEventDisableTiming);
        cudaEventCreateWithFlags(&eW,    cudaEventDisableTiming);
        cudaEventCreateWithFlags(&eO,    cudaEventDisableTiming);
        cudaEventCreateWithFlags(&eBF,   cudaEventDisableTiming);
    }

    // fork: s1 joins the (possibly capturing) default stream
    cudaEventRecord(eFork, 0);
    cudaStreamWaitEvent(s1, eFork, 0);

    // s1: proj/fc weight prep (overlap with LN1 + qkv GEMM on s0)
    split_bf_kernel<<<(Cdim * Cdim + 255) / 256, 256, 0, s1>>>(proj_w, p_wproj_hi, p_wproj_lo, Cdim * Cdim);
    conv_fp_kernel<<<(Cdim * HID + 255) / 256, 256, 0, s1>>>(fc1_w, p_wfc1, Cdim * HID);
    conv_fp_kernel<<<(HID * Cdim + 255) / 256, 256, 0, s1>>>(fc2_w, p_wfc2, HID * Cdim);
    cudaEventRecord(eW, s1);

    // s0: qkv weight split + LN1 + qkv GEMM + MHA
    split_bf_kernel<<<(Cdim * 3 * Cdim + 255) / 256, 256>>>(qkv_w, p_wqkv_hi, p_wqkv_lo, Cdim * 3 * Cdim);
    ln_kernel<<<ROWS, 256>>>(x, norm1_g, norm1_b, p_h_hi, p_h_lo);
    mma_gemm3<0><<<dim3((3 * Cdim + 127) / 128, ROWS / 128), 256, GEMM3_SMEM>>>(
        p_h_hi, p_h_lo, p_wqkv_hi, p_wqkv_lo, nullptr,
        p_qkv, ROWS, 3 * Cdim, Cdim);
    mha_kernel<<<dim3(NHd, Bsz), 256, MHA_SMEM>>>(p_qkv, p_att_hi, p_att_lo);
    // proj needs wproj (from s1)
    cudaStreamWaitEvent(0, eW, 0);
    mma_gemm3<1><<<dim3((Cdim + 127) / 128, ROWS / 128), 256, GEMM3_SMEM>>>(
        p_att_hi, p_att_lo, p_wproj_hi, p_wproj_lo, proj_b,
        p_o, ROWS, Cdim, Cdim);
    cudaEventRecord(eO, 0);

    // s1: BiFormer branch (depends on o) — overlaps LN2/fc1/fc2 on s0
    cudaStreamWaitEvent(s1, eO, 0);
    bf_qkv_kernel<<<dim3(28, Bsz), 256, 0, s1>>>(p_o, bf_qkv_w, bf_qkv_b);
    bf_routing_kernel<<<Bsz, 256, 0, s1>>>();
    bf_attn_kernel<<<dim3(NREG, 8, Bsz), 128, 0, s1>>>();
    bf_out_kernel<<<dim3(28, Bsz), 256, 0, s1>>>(bf_lepe_w, bf_lepe_b, bf_out_w, bf_out_b, out + OUT_OFF);
    cudaEventRecord(eBF, s1);

    // s0: MLP branch
    ln2_kernel<<<ROWS, 256>>>(p_o, x, norm2_g, norm2_b, p_xr, p_h2);
    mma_gemm2<2><<<dim3((HID + 127) / 128, ROWS / 128), 256, GEMM2_SMEM>>>(
        p_h2, p_wfc1, fc1_b, nullptr,
        nullptr, p_hid, ROWS, HID, Cdim);
    mma_gemm2<3><<<dim3((Cdim + 127) / 128, ROWS / 128), 256, GEMM2_SMEM>>>(
        p_hid, p_wfc2, fc2_b, p_xr,
        out, nullptr, ROWS, Cdim, HID);

    // join
    cudaStreamWaitEvent(0, eBF, 0);
}

// round 11
// speedup vs baseline: 1.9767x; 1.6044x over previous
#include <cuda_runtime.h>
#include <cuda_bf16.h>
#include <cuda_fp16.h>
#include <math.h>
#include <stdint.h>

// ---------------- problem constants ----------------
#define Bsz   128
#define NTOK  64
#define Cdim  784
#define NHd   8
#define HD    98
#define HDP   99
#define HID   3136
#define ROWS  (Bsz*NTOK)  // 8192
#define NREG  49
#define TOPK  4
#define OUT_OFF (Bsz*NTOK*Cdim)

// ---------------- scratch ----------------
__device__ __nv_bfloat16 g_h_hi [ROWS*Cdim];
__device__ __nv_bfloat16 g_h_lo [ROWS*Cdim];
__device__ float         g_qkv  [ROWS*3*Cdim];
__device__ __nv_bfloat16 g_att_hi[ROWS*Cdim];
__device__ __nv_bfloat16 g_att_lo[ROWS*Cdim];
__device__ float         g_o    [ROWS*Cdim];
__device__ float         g_xr   [ROWS*Cdim];
__device__ __half        g_h2   [ROWS*Cdim];
__device__ __half        g_hid  [ROWS*HID];
// weight splits [K, N]
__device__ __nv_bfloat16 g_wqkv_hi[Cdim*3*Cdim];
__device__ __nv_bfloat16 g_wqkv_lo[Cdim*3*Cdim];
__device__ __nv_bfloat16 g_wproj_hi[Cdim*Cdim];
__device__ __nv_bfloat16 g_wproj_lo[Cdim*Cdim];
__device__ __half        g_wfc1 [Cdim*HID];
__device__ __half        g_wfc2 [HID*Cdim];
// biformer
__device__ float g_bfqkv[Bsz*192*784];
__device__ float g_attg [Bsz*64*784];
__device__ int   g_idx [Bsz*NREG*TOPK];

// ---------------- helpers ----------------
__device__ __forceinline__ uint32_t smem_u32(const void* p) {
    return (uint32_t)__cvta_generic_to_shared(p);
}
#define CP_ASYNC16(dst_u32, src, sz) \
    asm volatile("cp.async.cg.shared.global [%0], [%1], 16, %2;\n" :: "r"(dst_u32), "l"(src), "r"(sz))
#define CP_COMMIT() asm volatile("cp.async.commit_group;\n")
#define LDSM4(r0,r1,r2,r3,a) \
    asm volatile("ldmatrix.sync.aligned.m8n8.x4.shared.b16 {%0,%1,%2,%3},[%4];" \
        : "=r"(r0),"=r"(r1),"=r"(r2),"=r"(r3) : "r"(a))
#define LDSM4T(r0,r1,r2,r3,a) \
    asm volatile("ldmatrix.sync.aligned.m8n8.x4.trans.shared.b16 {%0,%1,%2,%3},[%4];" \
        : "=r"(r0),"=r"(r1),"=r"(r2),"=r"(r3) : "r"(a))
#define MMA_BF16(d, a, b) \
    asm volatile("mma.sync.aligned.m16n8k16.row.col.f32.bf16.bf16.f32 " \
        "{%0,%1,%2,%3},{%4,%5,%6,%7},{%8,%9},{%0,%1,%2,%3};" \
        : "+f"(d[0]),"+f"(d[1]),"+f"(d[2]),"+f"(d[3]) \
        : "r"(a[0]),"r"(a[1]),"r"(a[2]),"r"(a[3]),"r"(b[0]),"r"(b[1]))
#define MMA_FP16(d, a, b) \
    asm volatile("mma.sync.aligned.m16n8k16.row.col.f32.f16.f16.f32 " \
        "{%0,%1,%2,%3},{%4,%5,%6,%7},{%8,%9},{%0,%1,%2,%3};" \
        : "+f"(d[0]),"+f"(d[1]),"+f"(d[2]),"+f"(d[3]) \
        : "r"(a[0]),"r"(a[1]),"r"(a[2]),"r"(a[3]),"r"(b[0]),"r"(b[1]))

__device__ __forceinline__ void split_write_bf(float v, __nv_bfloat16* hi, __nv_bfloat16* lo, size_t o) {
    __nv_bfloat16 h = __float2bfloat16(v);
    hi[o] = h;
    lo[o] = __float2bfloat16(v - __bfloat162float(h));
}

// ---------------- weight prep ----------------
__global__ void split_bf_kernel(const float* __restrict__ in, __nv_bfloat16* __restrict__ hi,
                                __nv_bfloat16* __restrict__ lo, int n) {
    int i = blockIdx.x * blockDim.x + threadIdx.x;
    if (i < n) {
        float v = in[i];
        __nv_bfloat16 h = __float2bfloat16(v);
        hi[i] = h;
        lo[i] = __float2bfloat16(v - __bfloat162float(h));
    }
}
__global__ void conv_fp_kernel(const float* __restrict__ in, __half* __restrict__ o, int n) {
    int i = blockIdx.x * blockDim.x + threadIdx.x;
    if (i < n) o[i] = __float2half(in[i]);
}

// ---------------- LN1: x -> (h_hi, h_lo) bf16 ----------------
__global__ void ln_kernel(const float* __restrict__ x,
                          const float* __restrict__ g, const float* __restrict__ b,
                          __nv_bfloat16* __restrict__ ohi, __nv_bfloat16* __restrict__ olo) {
    int row = blockIdx.x;
    const float* xr = x + (size_t)row * Cdim;
    __shared__ float buf[Cdim];
    __shared__ float rs[2];
    __shared__ float red[64];
    float s = 0.f, ss = 0.f;
    for (int i = threadIdx.x; i < Cdim; i += blockDim.x) {
        float v = xr[i]; buf[i] = v; s += v; ss += v * v;
    }
    for (int o = 16; o > 0; o >>= 1) { s += __shfl_down_sync(~0u, s, o); ss += __shfl_down_sync(~0u, ss, o); }
    int wid = threadIdx.x >> 5, lid = threadIdx.x & 31;
    if (lid == 0) { red[wid] = s; red[wid + 32] = ss; }
    __syncthreads();
    if (threadIdx.x == 0) {
        float t = 0.f, tt = 0.f;
        int nw = blockDim.x >> 5;
        for (int i = 0; i < nw; i++) { t += red[i]; tt += red[i + 32]; }
        float mean = t / Cdim, var = tt / Cdim - mean * mean;
        rs[0] = mean; rs[1] = rsqrtf(var + 1e-5f);
    }
    __syncthreads();
    float mean = rs[0], inv = rs[1];
    for (int i = threadIdx.x; i < Cdim; i += blockDim.x)
        split_write_bf((buf[i] - mean) * inv * g[i] + b[i], ohi, olo, (size_t)row * Cdim + i);
}

// ---------------- LN2: xr = o + x (fp32), h2 fp16 ----------------
__global__ void ln2_kernel(const float* __restrict__ ov, const float* __restrict__ x,
                           const float* __restrict__ g, const float* __restrict__ b,
                           float* __restrict__ xr_out, __half* __restrict__ oh) {
    int row = blockIdx.x;
    const float* a = ov + (size_t)row * Cdim;
    const float* c = x  + (size_t)row * Cdim;
    __shared__ float buf[Cdim];
    __shared__ float rs[2];
    __shared__ float red[64];
    float s = 0.f, ss = 0.f;
    for (int i = threadIdx.x; i < Cdim; i += blockDim.x) {
        float v = a[i] + c[i];
        buf[i] = v;
        xr_out[(size_t)row * Cdim + i] = v;
        s += v; ss += v * v;
    }
    for (int o = 16; o > 0; o >>= 1) { s += __shfl_down_sync(~0u, s, o); ss += __shfl_down_sync(~0u, ss, o); }
    int wid = threadIdx.x >> 5, lid = threadIdx.x & 31;
    if (lid == 0) { red[wid] = s; red[wid + 32] = ss; }
    __syncthreads();
    if (threadIdx.x == 0) {
        float t = 0.f, tt = 0.f;
        int nw = blockDim.x >> 5;
        for (int i = 0; i < nw; i++) { t += red[i]; tt += red[i + 32]; }
        float mean = t / Cdim, var = tt / Cdim - mean * mean;
        rs[0] = mean; rs[1] = rsqrtf(var + 1e-5f);
    }
    __syncthreads();
    float mean = rs[0], inv = rs[1];
    for (int i = threadIdx.x; i < Cdim; i += blockDim.x)
        oh[(size_t)row * Cdim + i] = __float2half((buf[i] - mean) * inv * g[i] + b[i]);
}

// ================= bf16x3 GEMM (qkv, proj) — BK=32, 3-stage =================
#define ASTR3 40
#define BSTR3 136
#define A3_ST (2*128*ASTR3)
#define B3_ST (2*32*BSTR3)
#define GEMM3_SMEM ((3*A3_ST + 3*B3_ST) * 2)  // 113664

template<int EP>
__global__ __launch_bounds__(256, 1)
void mma_gemm3(const __nv_bfloat16* __restrict__ Ah, const __nv_bfloat16* __restrict__ Al,
               const __nv_bfloat16* __restrict__ Bh, const __nv_bfloat16* __restrict__ Bl,
               const float* __restrict__ bias,
               float* __restrict__ Cf, int M, int N, int K) {
    extern __shared__ __nv_bfloat16 sm3[];
    __nv_bfloat16* Asm = sm3;
    __nv_bfloat16* Bsm = sm3 + 3 * A3_ST;

    int tid = threadIdx.x;
    int warp = tid >> 5, lane = tid & 31;
    int wm = warp & 1, wn = warp >> 1;
    int rowBase = blockIdx.y * 128, colBase = blockIdx.x * 128;

    const int KT = (K + 31) >> 5;
    float acc[4][4][4];
    #pragma unroll
    for (int i = 0; i < 4; i++)
        #pragma unroll
        for (int j = 0; j < 4; j++)
            #pragma unroll
            for (int q = 0; q < 4; q++) acc[i][j][q] = 0.f;

    auto load_stage = [&](int st, int kt) {
        int koff = kt * 32;
        __nv_bfloat16* Ast = Asm + st * A3_ST;
        __nv_bfloat16* Bst = Bsm + st * B3_ST;
        #pragma unroll
        for (int part = 0; part < 2; part++) {
            const __nv_bfloat16* Aasrc = part ? Al : Ah;
            #pragma unroll
            for (int i = 0; i < 2; i++) {
                int chunk = i * 256 + tid;
                int r = chunk >> 2, cc = (chunk & 3) * 8;
                int k = koff + cc;
                uint32_t dst = smem_u32(Ast + part * (128 * ASTR3) + r * ASTR3 + cc);
                const __nv_bfloat16* src = Aasrc + (size_t)(rowBase + r) * K + (k < K ? k : 0);
                CP_ASYNC16(dst, src, (k < K) ? 16 : 0);
            }
        }
        #pragma unroll
        for (int part = 0; part < 2; part++) {
            const __nv_bfloat16* Bbsrc = part ? Bl : Bh;
            #pragma unroll
            for (int i = 0; i < 2; i++) {
                int chunk = i * 256 + tid;
                int r = chunk >> 4, cc = (chunk & 15) * 8;
                int k = koff + r, n = colBase + cc;
                bool ok = (k < K) && (n < N);
                uint32_t dst = smem_u32(Bst + part * (32 * BSTR3) + r * BSTR3 + cc);
                const __nv_bfloat16* src = Bbsrc + (ok ? ((size_t)k * N + n) : 0);
                CP_ASYNC16(dst, src, ok ? 16 : 0);
            }
        }
    };

    load_stage(0, 0); CP_COMMIT();
    if (KT > 1) { load_stage(1, 1); }
    CP_COMMIT();

    int lrow = lane & 15, lhalf = (lane >> 4) * 8;

    for (int kt = 0; kt < KT; kt++) {
        if (kt + 2 < KT) load_stage((kt + 2) % 3, kt + 2);
        CP_COMMIT();
        asm volatile("cp.async.wait_group 2;");
        __syncthreads();

        int st = kt % 3;
        __nv_bfloat16* Ast = Asm + st * A3_ST;
        __nv_bfloat16* Bst = Bsm + st * B3_ST;

        #pragma unroll
        for (int kk = 0; kk < 32; kk += 16) {
            uint32_t ah[4][4], al[4][4], bh[4][2], bl[4][2];
            #pragma unroll
            for (int mi = 0; mi < 4; mi++) {
                uint32_t a0 = smem_u32(Ast + (wm * 64 + mi * 16 + lrow) * ASTR3 + kk + lhalf);
                LDSM4(ah[mi][0], ah[mi][1], ah[mi][2], ah[mi][3], a0);
                uint32_t a1 = smem_u32(Ast + 128 * ASTR3 + (wm * 64 + mi * 16 + lrow) * ASTR3 + kk + lhalf);
                LDSM4(al[mi][0], al[mi][1], al[mi][2], al[mi][3], a1);
            }
            #pragma unroll
            for (int pr = 0; pr < 2; pr++) {
                uint32_t r0, r1, r2, r3;
                uint32_t b0 = smem_u32(Bst + (kk + lrow) * BSTR3 + wn * 32 + pr * 16 + lhalf);
                LDSM4T(r0, r1, r2, r3, b0);
                bh[pr * 2][0] = r0; bh[pr * 2][1] = r1; bh[pr * 2 + 1][0] = r2; bh[pr * 2 + 1][1] = r3;
                uint32_t b1 = smem_u32(Bst + 32 * BSTR3 + (kk + lrow) * BSTR3 + wn * 32 + pr * 16 + lhalf);
                LDSM4T(r0, r1, r2, r3, b1);
                bl[pr * 2][0] = r0; bl[pr * 2][1] = r1; bl[pr * 2 + 1][0] = r2; bl[pr * 2 + 1][1] = r3;
            }
            #pragma unroll
            for (int mi = 0; mi < 4; mi++)
                #pragma unroll
                for (int ni = 0; ni < 4; ni++) {
                    MMA_BF16(acc[mi][ni], ah[mi], bh[ni]);
                    MMA_BF16(acc[mi][ni], ah[mi], bl[ni]);
                    MMA_BF16(acc[mi][ni], al[mi], bh[ni]);
                }
        }
        __syncthreads();
    }

    #pragma unroll
    for (int mi = 0; mi < 4; mi++) {
        int r0 = rowBase + wm * 64 + mi * 16 + (lane >> 2);
        #pragma unroll
        for (int ni = 0; ni < 4; ni++) {
            int c0 = colBase + wn * 32 + ni * 8 + (lane & 3) * 2;
            #pragma unroll
            for (int q = 0; q < 4; q++) {
                int r = r0 + (q >> 1) * 8;
                int c = c0 + (q & 1);
                if (c < N) {
                    float v = acc[mi][ni][q];
                    if (EP >= 1) v += bias[c];
                    Cf[(size_t)r * N + c] = v;
                }
            }
        }
    }
}

// ===== fp16 single-term GEMM (fc1, fc2) — BK=32, 2-stage, 2 CTAs/SM =====
#define ASTR2 40
#define BSTR2 136
#define A2_ST (128*ASTR2)
#define B2_ST (32*BSTR2)
#define GEMM2_SMEM ((2*A2_ST + 2*B2_ST) * 2)  // 37888

template<int EP>
__global__ __launch_bounds__(256, 2)
void mma_gemm2(const __half* __restrict__ A, const __half* __restrict__ B,
               const float* __restrict__ bias, const float* __restrict__ res,
               float* __restrict__ Cf, __half* __restrict__ Ch,
               int M, int N, int K) {
    extern __shared__ __half sm2[];
    __half* Asm = sm2;
    __half* Bsm = sm2 + 2 * A2_ST;

    int tid = threadIdx.x;
    int warp = tid >> 5, lane = tid & 31;
    int wm = warp & 1, wn = warp >> 1;
    int rowBase = blockIdx.y * 128, colBase = blockIdx.x * 128;

    const int KT = (K + 31) >> 5;
    float acc[4][4][4];
    #pragma unroll
    for (int i = 0; i < 4; i++)
        #pragma unroll
        for (int j = 0; j < 4; j++)
            #pragma unroll
            for (int q = 0; q < 4; q++) acc[i][j][q] = 0.f;

    auto load_stage = [&](int st, int kt) {
        int koff = kt * 32;
        __half* Ast = Asm + st * A2_ST;
        __half* Bst = Bsm + st * B2_ST;
        #pragma unroll
        for (int i = 0; i < 2; i++) {
            int chunk = i * 256 + tid;
            int r = chunk >> 2, cc = (chunk & 3) * 8;
            int k = koff + cc;
            uint32_t dst = smem_u32(Ast + r * ASTR2 + cc);
            const __half* src = A + (size_t)(rowBase + r) * K + (k < K ? k : 0);
            CP_ASYNC16(dst, src, (k < K) ? 16 : 0);
        }
        #pragma unroll
        for (int i = 0; i < 2; i++) {
            int chunk = i * 256 + tid;
            int r = chunk >> 4, cc = (chunk & 15) * 8;
            int k = koff + r, n = colBase + cc;
            bool ok = (k < K) && (n < N);
            uint32_t dst = smem_u32(Bst + r * BSTR2 + cc);
            const __half* src = B + (ok ? ((size_t)k * N + n) : 0);
            CP_ASYNC16(dst, src, ok ? 16 : 0);
        }
    };

    load_stage(0, 0); CP_COMMIT();
    if (KT > 1) { load_stage(1, 1); }
    CP_COMMIT();

    int lrow = lane & 15, lhalf = (lane >> 4) * 8;

    for (int kt = 0; kt < KT; kt++) {
        if (kt + 1 < KT) { asm volatile("cp.async.wait_group 1;"); }
        else             { asm volatile("cp.async.wait_group 0;"); }
        __syncthreads();

        int st = kt & 1;
        __half* Ast = Asm + st * A2_ST;
        __half* Bst = Bsm + st * B2_ST;

        #pragma unroll
        for (int kk = 0; kk < 32; kk += 16) {
            uint32_t a[4][4], bb[4][2];
            #pragma unroll
            for (int mi = 0; mi < 4; mi++) {
                uint32_t a0 = smem_u32(Ast + (wm * 64 + mi * 16 + lrow) * ASTR2 + kk + lhalf);
                LDSM4(a[mi][0], a[mi][1], a[mi][2], a[mi][3], a0);
            }
            #pragma unroll
            for (int pr = 0; pr < 2; pr++) {
                uint32_t r0, r1, r2, r3;
                uint32_t b0 = smem_u32(Bst + (kk + lrow) * BSTR2 + wn * 32 + pr * 16 + lhalf);
                LDSM4T(r0, r1, r2, r3, b0);
                bb[pr * 2][0] = r0; bb[pr * 2][1] = r1; bb[pr * 2 + 1][0] = r2; bb[pr * 2 + 1][1] = r3;
            }
            #pragma unroll
            for (int mi = 0; mi < 4; mi++)
                #pragma unroll
                for (int ni = 0; ni < 4; ni++)
                    MMA_FP16(acc[mi][ni], a[mi], bb[ni]);
        }
        __syncthreads();
        if (kt + 2 < KT) { load_stage(st, kt + 2); CP_COMMIT(); }
    }

    #pragma unroll
    for (int mi = 0; mi < 4; mi++) {
        int r0 = rowBase + wm * 64 + mi * 16 + (lane >> 2);
        #pragma unroll
        for (int ni = 0; ni < 4; ni++) {
            int c0 = colBase + wn * 32 + ni * 8 + (lane & 3) * 2;
            #pragma unroll
            for (int q = 0; q < 4; q++) {
                int r = r0 + (q >> 1) * 8;
                int c = c0 + (q & 1);
                if (c < N) {
                    float v = acc[mi][ni][q] + bias[c];
                    size_t o = (size_t)r * N + c;
                    if (EP == 2) {
                        v = 0.5f * v * (1.0f + erff(v * 0.70710678118654752440f));
                        Ch[o] = __float2half(v);
                    } else {
                        v += res[o];
                        Cf[o] = v;
                    }
                }
            }
        }
    }
}

// ---------------- MHA (register-tiled) -> att bf16 split ----------------
#define MHA_SMEM ((3*64*HDP + 64*64)*4)
__global__ void mha_kernel(const float* __restrict__ qkv,
                           __nv_bfloat16* __restrict__ ahi, __nv_bfloat16* __restrict__ alo) {
    extern __shared__ float smf[];
    float* Q  = smf;
    float* Kx = Q + 64 * HDP;
    float* V  = Kx + 64 * HDP;
    float* SC = V + 64 * HDP;
    int h = blockIdx.x, b = blockIdx.y;
    int tid = threadIdx.x;
    const float* base = qkv + (size_t)(b * NTOK) * (3 * Cdim);
    for (int e = tid; e < 64 * HD; e += 256) {
        int t = e / HD, d = e % HD;
        Q[t * HDP + d]  = base[(size_t)t * (3 * Cdim) + h * HD + d];
        Kx[t * HDP + d] = base[(size_t)t * (3 * Cdim) + Cdim + h * HD + d];
        V[t * HDP + d]  = base[(size_t)t * (3 * Cdim) + 2 * Cdim + h * HD + d];
    }
    __syncthreads();
    const float scale = rsqrtf((float)HD);
    {
        int ti = tid >> 4, tj = tid & 15;
        float acc[4][4] = {};
        #pragma unroll 2
        for (int d = 0; d < HD; d++) {
            float qv[4], kv[4];
            #pragma unroll
            for (int r2 = 0; r2 < 4; r2++) qv[r2] = Q[(ti * 4 + r2) * HDP + d];
            #pragma unroll
            for (int c2 = 0; c2 < 4; c2++) kv[c2] = Kx[(tj * 4 + c2) * HDP + d];
            #pragma unroll
            for (int r2 = 0; r2 < 4; r2++)
                #pragma unroll
                for (int c2 = 0; c2 < 4; c2++) acc[r2][c2] += qv[r2] * kv[c2];
        }
        #pragma unroll
        for (int r2 = 0; r2 < 4; r2++)
            #pragma unroll
            for (int c2 = 0; c2 < 4; c2++)
                SC[(ti * 4 + r2) * 64 + tj * 4 + c2] = acc[r2][c2] * scale;
    }
    __syncthreads();
    if (tid < 64) {
        float* row = SC + tid * 64;
        float mx = -1e30f;
        for (int j = 0; j < 64; j++) mx = fmaxf(mx, row[j]);
        float s = 0.f;
        for (int j = 0; j < 64; j++) { float e = expf(row[j] - mx); row[j] = e; s += e; }
        float inv = 1.f / s;
        for (int j = 0; j < 64; j++) row[j] *= inv;
    }
    __syncthreads();
    {
        int ti = tid >> 4, td = tid & 15;
        if (td < 14) {
            float oacc[4][7] = {};
            for (int j = 0; j < 64; j++) {
                float pr[4], vv[7];
                #pragma unroll
                for (int r2 = 0; r2 < 4; r2++) pr[r2] = SC[(ti * 4 + r2) * 64 + j];
                #pragma unroll
                for (int c2 = 0; c2 < 7; c2++) vv[c2] = V[j * HDP + td * 7 + c2];
                #pragma unroll
                for (int r2 = 0; r2 < 4; r2++)
                    #pragma unroll
                    for (int c2 = 0; c2 < 7; c2++) oacc[r2][c2] += pr[r2] * vv[c2];
            }
            #pragma unroll
            for (int r2 = 0; r2 < 4; r2++)
                #pragma unroll
                for (int c2 = 0; c2 < 7; c2++)
                    split_write_bf(oacc[r2][c2], ahi, alo,
                        ((size_t)(b * NTOK + ti * 4 + r2)) * Cdim + h * HD + td * 7 + c2);
        }
    }
}

// ---------------- BiFormer ----------------
#define BFQ_SMEM ((64*28 + 192*64)*4)  // 56320
__global__ void bf_qkv_kernel(const float* __restrict__ o,
                              const float* __restrict__ w, const float* __restrict__ bias) {
    extern __shared__ float bq[];
    float* xin = bq;             // [64][28]
    float* ws  = bq + 64 * 28;   // [192][64]
    int y = blockIdx.x, b = blockIdx.y;
    int tid = threadIdx.x;
    for (int e = tid; e < 192 * 64; e += 256) ws[e] = w[e];
    for (int e = tid; e < 64 * 28; e += 256) {
        int c = e / 28, xx = e % 28;
        xin[e] = o[((size_t)b * 64 + c) * 784 + y * 28 + xx];
    }
    __syncthreads();
    for (int e = tid; e < 192 * 28; e += 256) {
        int oc = e / 28, xx = e % 28;
        float a = bias[oc];
        const float* wr = ws + oc * 64;
        #pragma unroll 16
        for (int c = 0; c < 64; c++) a += xin[c * 28 + xx] * wr[c];
        g_bfqkv[((size_t)b * 192 + oc) * 784 + y * 28 + xx] = a;
    }
}

// fused region pooling + routing top-4 (one block per batch)
__global__ void bf_routing_kernel() {
    int b = blockIdx.x;
    int tid = threadIdx.x;  // 256
    __shared__ float qr[64][NREG];
    __shared__ float kr[64][NREG];
    __shared__ float ar[NREG][NREG];
    for (int e = tid; e < 64 * NREG; e += 256) {
        int c = e / NREG, r = e % NREG;
        int rh = r / 7, rw = r % 7;
        float sq = 0.f, sk = 0.f;
        const float* qc = g_bfqkv + ((size_t)b * 192 + c) * 784;
        const float* kc = g_bfqkv + ((size_t)b * 192 + 64 + c) * 784;
        #pragma unroll
        for (int pr = 0; pr < 4; pr++)
            #pragma unroll
            for (int pc = 0; pc < 4; pc++) {
                int s = (rh * 4 + pr) * 28 + rw * 4 + pc;
                sq += qc[s]; sk += kc[s];
            }
        qr[c][r] = sq * 0.0625f;
        kr[c][r] = sk * 0.0625f;
    }
    __syncthreads();
    for (int e = tid; e < NREG * NREG; e += 256) {
        int i = e / NREG, j = e % NREG;
        float a = 0.f;
        #pragma unroll 16
        for (int c = 0; c < 64; c++) a += qr[c][i] * kr[c][j];
        ar[i][j] = a;
    }
    __syncthreads();
    if (tid < NREG) {
        float* row = ar[tid];
        #pragma unroll
        for (int j = 0; j < TOPK; j++) {
            float mx = -1e30f; int mi = 0;
            for (int s = 0; s < NREG; s++) if (row[s] > mx) { mx = row[s]; mi = s; }
            row[mi] = -1e30f;
            g_idx[(b * NREG + tid) * TOPK + j] = mi;
        }
    }
}

__global__ void bf_attn_kernel() {
    int r = blockIdx.x, h = blockIdx.y, b = blockIdx.z;
    __shared__ float q[16][8], kg[64][9], vg[64][9];
    __shared__ float sc[16][65];
    __shared__ int idx4[4];
    int tid = threadIdx.x;  // 128
    if (tid < 4) idx4[tid] = g_idx[(b * NREG + r) * TOPK + tid];
    int rh = r / 7, rw = r % 7;
    {
        int p = tid / 8, d = tid % 8;
        int s = (rh * 4 + p / 4) * 28 + rw * 4 + (p % 4);
        q[p][d] = g_bfqkv[((size_t)b * 192 + h * 8 + d) * 784 + s] * 0.125f;
    }
    __syncthreads();
    for (int e = tid; e < 512; e += 128) {
        int t = e / 8, d = e % 8;
        int reg = idx4[t / 16];
        int p2 = t % 16;
        int s = ((reg / 7) * 4 + p2 / 4) * 28 + (reg % 7) * 4 + (p2 % 4);
        kg[t][d] = g_bfqkv[((size_t)b * 192 + 64 + h * 8 + d) * 784 + s];
        vg[t][d] = g_bfqkv[((size_t)b * 192 + 128 + h * 8 + d) * 784 + s];
    }
    __syncthreads();
    {
        int p = tid >> 3, tg = tid & 7;
        float qreg[8];
        #pragma unroll
        for (int d = 0; d < 8; d++) qreg[d] = q[p][d];
        #pragma unroll
        for (int tt = 0; tt < 8; tt++) {
            int t = tt * 8 + tg;
            float a = 0.f;
            #pragma unroll
            for (int d = 0; d < 8; d++) a += qreg[d] * kg[t][d];
            sc[p][t] = a;
        }
    }
    __syncthreads();
    if (tid < 16) {
        float mx = -1e30f;
        for (int t = 0; t < 64; t++) mx = fmaxf(mx, sc[tid][t]);
        float s = 0.f;
        for (int t = 0; t < 64; t++) { float e = expf(sc[tid][t] - mx); sc[tid][t] = e; s += e; }
        float inv = 1.f / s;
        for (int t = 0; t < 64; t++) sc[tid][t] *= inv;
    }
    __syncthreads();
    {
        int p = tid / 8, d = tid % 8;
        float a = 0.f;
        #pragma unroll 8
        for (int t = 0; t < 64; t++) a += sc[p][t] * vg[t][d];
        int s = (rh * 4 + p / 4) * 28 + rw * 4 + (p % 4);
        g_attg[((size_t)b * 64 + h * 8 + d) * 784 + s] = a;
    }
}

__global__ void bf_out_kernel(const float* __restrict__ lepe_w, const float* __restrict__ lepe_b,
                              const float* __restrict__ out_w, const float* __restrict__ out_b,
                              float* __restrict__ outp) {
    int y = blockIdx.x, b = blockIdx.y;
    __shared__ float v3[3][64][28];
    __shared__ float tmp[64][28];
    __shared__ float ws[64][64];
    __shared__ float lw[64][9];
    int tid = threadIdx.x;
    for (int e = tid; e < 64 * 64; e += blockDim.x) ws[e >> 6][e & 63] = out_w[e];
    for (int e = tid; e < 64 * 9; e += blockDim.x) lw[e / 9][e % 9] = lepe_w[e];
    for (int ry = 0; ry < 3; ry++) {
        int yy = y + ry - 1;
        for (int e = tid; e < 64 * 28; e += blockDim.x) {
            int c = e / 28, xx = e % 28;
            v3[ry][c][xx] = (yy >= 0 && yy < 28)
                ? g_bfqkv[((size_t)b * 192 + 128 + c) * 784 + yy * 28 + xx] : 0.f;
        }
    }
    __syncthreads();
    for (int e = tid; e < 64 * 28; e += blockDim.x) {
        int c = e / 28, xx = e % 28;
        float a = g_attg[((size_t)b * 64 + c) * 784 + y * 28 + xx] + lepe_b[c];
        #pragma unroll
        for (int ky = 0; ky < 3; ky++)
            #pragma unroll
            for (int kx = 0; kx < 3; kx++) {
                int xx2 = xx + kx - 1;
                if (xx2 >= 0 && xx2 < 28) a += v3[ky][c][xx2] * lw[c][ky * 3 + kx];
            }
        tmp[c][xx] = a;
    }
    __syncthreads();
    for (int e = tid; e < 64 * 28; e += blockDim.x) {
        int oc = e / 28, xx = e % 28;
        float a = out_b[oc];
        const float* wr = ws[oc];
        #pragma unroll 16
        for (int c = 0; c < 64; c++) a += tmp[c][xx] * wr[c];
        outp[((size_t)b * 64 + oc) * 784 + y * 28 + xx] = a;
    }
}

// ---------------- launch ----------------
extern "C" void kernel_launch(void* const* d_in, const int* in_sizes, int n_in,
                              void* d_out, int out_size) {
    (void)in_sizes; (void)n_in; (void)out_size;
    const float* x        = (const float*)d_in[0];
    const float* norm1_g  = (const float*)d_in[1];
    const float* norm1_b  = (const float*)d_in[2];
    const float* qkv_w    = (const float*)d_in[3];
    const float* proj_w   = (const float*)d_in[4];
    const float* proj_b   = (const float*)d_in[5];
    const float* norm2_g  = (const float*)d_in[6];
    const float* norm2_b  = (const float*)d_in[7];
    const float* fc1_w    = (const float*)d_in[8];
    const float* fc1_b    = (const float*)d_in[9];
    const float* fc2_w    = (const float*)d_in[10];
    const float* fc2_b    = (const float*)d_in[11];
    const float* bf_qkv_w = (const float*)d_in[12];
    const float* bf_qkv_b = (const float*)d_in[13];
    const float* bf_lepe_w= (const float*)d_in[14];
    const float* bf_lepe_b= (const float*)d_in[15];
    const float* bf_out_w = (const float*)d_in[16];
    const float* bf_out_b = (const float*)d_in[17];
    float* out = (float*)d_out;

    __nv_bfloat16 *p_h_hi, *p_h_lo, *p_att_hi, *p_att_lo;
    __nv_bfloat16 *p_wqkv_hi, *p_wqkv_lo, *p_wproj_hi, *p_wproj_lo;
    __half *p_h2, *p_hid, *p_wfc1, *p_wfc2;
    float *p_qkv, *p_o, *p_xr;
    cudaGetSymbolAddress((void**)&p_h_hi, g_h_hi);     cudaGetSymbolAddress((void**)&p_h_lo, g_h_lo);
    cudaGetSymbolAddress((void**)&p_att_hi, g_att_hi); cudaGetSymbolAddress((void**)&p_att_lo, g_att_lo);
    cudaGetSymbolAddress((void**)&p_h2, g_h2);
    cudaGetSymbolAddress((void**)&p_hid, g_hid);
    cudaGetSymbolAddress((void**)&p_wqkv_hi, g_wqkv_hi);   cudaGetSymbolAddress((void**)&p_wqkv_lo, g_wqkv_lo);
    cudaGetSymbolAddress((void**)&p_wproj_hi, g_wproj_hi); cudaGetSymbolAddress((void**)&p_wproj_lo, g_wproj_lo);
    cudaGetSymbolAddress((void**)&p_wfc1, g_wfc1);
    cudaGetSymbolAddress((void**)&p_wfc2, g_wfc2);
    cudaGetSymbolAddress((void**)&p_qkv, g_qkv);
    cudaGetSymbolAddress((void**)&p_o, g_o);
    cudaGetSymbolAddress((void**)&p_xr, g_xr);

    cudaFuncSetAttribute(mha_kernel, cudaFuncAttributeMaxDynamicSharedMemorySize, MHA_SMEM);
    cudaFuncSetAttribute(bf_qkv_kernel, cudaFuncAttributeMaxDynamicSharedMemorySize, BFQ_SMEM);
    cudaFuncSetAttribute(mma_gemm3<0>, cudaFuncAttributeMaxDynamicSharedMemorySize, GEMM3_SMEM);
    cudaFuncSetAttribute(mma_gemm3<1>, cudaFuncAttributeMaxDynamicSharedMemorySize, GEMM3_SMEM);
    cudaFuncSetAttribute(mma_gemm2<2>, cudaFuncAttributeMaxDynamicSharedMemorySize, GEMM2_SMEM);
    cudaFuncSetAttribute(mma_gemm2<3>, cudaFuncAttributeMaxDynamicSharedMemorySize, GEMM2_SMEM);

    // one-time stream/event creation (host resources only; no device allocations)
    static cudaStream_t s1 = nullptr;
    static cudaEvent_t eFork = nullptr, eW = nullptr, eO = nullptr, eBF = nullptr;
    if (!s1) {
        cudaStreamCreateWithFlags(&s1, cudaStreamNonBlocking);
        cudaEventCreateWithFlags(&eFork, cudaEventDisableTiming);
        cudaEventCreateWithFlags(&eW,    cudaEventDisableTiming);
        cudaEventCreateWithFlags(&eO,    cudaEventDisableTiming);
        cudaEventCreateWithFlags(&eBF,   cudaEventDisableTiming);
    }

    // fork
    cudaEventRecord(eFork, 0);
    cudaStreamWaitEvent(s1, eFork, 0);

    // s1: proj/fc weight prep (overlap with LN1 + qkv GEMM on s0)
    split_bf_kernel<<<(Cdim * Cdim + 255) / 256, 256, 0, s1>>>(proj_w, p_wproj_hi, p_wproj_lo, Cdim * Cdim);
    conv_fp_kernel<<<(Cdim * HID + 255) / 256, 256, 0, s1>>>(fc1_w, p_wfc1, Cdim * HID);
    conv_fp_kernel<<<(HID * Cdim + 255) / 256, 256, 0, s1>>>(fc2_w, p_wfc2, HID * Cdim);
    cudaEventRecord(eW, s1);

    // s0: qkv weight split + LN1 + qkv GEMM + MHA
    split_bf_kernel<<<(Cdim * 3 * Cdim + 255) / 256, 256>>>(qkv_w, p_wqkv_hi, p_wqkv_lo, Cdim * 3 * Cdim);
    ln_kernel<<<ROWS, 256>>>(x, norm1_g, norm1_b, p_h_hi, p_h_lo);
    mma_gemm3<0><<<dim3((3 * Cdim + 127) / 128, ROWS / 128), 256, GEMM3_SMEM>>>(
        p_h_hi, p_h_lo, p_wqkv_hi, p_wqkv_lo, nullptr,
        p_qkv, ROWS, 3 * Cdim, Cdim);
    mha_kernel<<<dim3(NHd, Bsz), 256, MHA_SMEM>>>(p_qkv, p_att_hi, p_att_lo);
    cudaStreamWaitEvent(0, eW, 0);
    mma_gemm3<1><<<dim3((Cdim + 127) / 128, ROWS / 128), 256, GEMM3_SMEM>>>(
        p_att_hi, p_att_lo, p_wproj_hi, p_wproj_lo, proj_b,
        p_o, ROWS, Cdim, Cdim);
    cudaEventRecord(eO, 0);

    // s1: BiFormer branch
    cudaStreamWaitEvent(s1, eO, 0);
    bf_qkv_kernel<<<dim3(28, Bsz), 256, BFQ_SMEM, s1>>>(p_o, bf_qkv_w, bf_qkv_b);
    bf_routing_kernel<<<Bsz, 256, 0, s1>>>();
    bf_attn_kernel<<<dim3(NREG, 8, Bsz), 128, 0, s1>>>();
    bf_out_kernel<<<dim3(28, Bsz), 256, 0, s1>>>(bf_lepe_w, bf_lepe_b, bf_out_w, bf_out_b, out + OUT_OFF);
    cudaEventRecord(eBF, s1);

    // s0: MLP branch
    ln2_kernel<<<ROWS, 256>>>(p_o, x, norm2_g, norm2_b, p_xr, p_h2);
    mma_gemm2<2><<<dim3((HID + 127) / 128, ROWS / 128), 256, GEMM2_SMEM>>>(
        p_h2, p_wfc1, fc1_b, nullptr,
        nullptr, p_hid, ROWS, HID, Cdim);
    mma_gemm2<3><<<dim3((Cdim + 127) / 128, ROWS / 128), 256, GEMM2_SMEM>>>(
        p_hid, p_wfc2, fc2_b, p_xr,
        out, nullptr, ROWS, Cdim, HID);

    // join
    cudaStreamWaitEvent(0, eBF, 0);
}

// round 12
// speedup vs baseline: 2.0926x; 1.0586x over previous
#include <cuda_runtime.h>
#include <cuda_bf16.h>
#include <cuda_fp16.h>
#include <math.h>
#include <stdint.h>

// ---------------- problem constants ----------------
#define Bsz   128
#define NTOK  64
#define Cdim  784
#define NHd   8
#define HD    98
#define HDP   99
#define HID   3136
#define ROWS  (Bsz*NTOK)  // 8192
#define NREG  49
#define TOPK  4
#define OUT_OFF (Bsz*NTOK*Cdim)

// ---------------- scratch ----------------
__device__ __nv_bfloat16 g_h_hi [ROWS*Cdim];
__device__ __nv_bfloat16 g_h_lo [ROWS*Cdim];
__device__ float         g_qkv  [ROWS*3*Cdim];
__device__ __nv_bfloat16 g_att_hi[ROWS*Cdim];
__device__ __nv_bfloat16 g_att_lo[ROWS*Cdim];
__device__ float         g_o    [ROWS*Cdim];
__device__ float         g_xr   [ROWS*Cdim];
__device__ __half        g_h2   [ROWS*Cdim];
__device__ __half        g_hid  [ROWS*HID];
// weight splits [K, N]
__device__ __nv_bfloat16 g_wqkv_hi[Cdim*3*Cdim];
__device__ __nv_bfloat16 g_wqkv_lo[Cdim*3*Cdim];
__device__ __nv_bfloat16 g_wproj_hi[Cdim*Cdim];
__device__ __nv_bfloat16 g_wproj_lo[Cdim*Cdim];
__device__ __half        g_wfc1 [Cdim*HID];
__device__ __half        g_wfc2 [HID*Cdim];
// biformer
__device__ float g_bfqkv[Bsz*192*784];
__device__ float g_attg [Bsz*64*784];
__device__ int   g_idx [Bsz*NREG*TOPK];

// ---------------- helpers ----------------
__device__ __forceinline__ uint32_t smem_u32(const void* p) {
    return (uint32_t)__cvta_generic_to_shared(p);
}
#define CP_ASYNC16(dst_u32, src, sz) \
    asm volatile("cp.async.cg.shared.global [%0], [%1], 16, %2;\n" :: "r"(dst_u32), "l"(src), "r"(sz))
#define CP_COMMIT() asm volatile("cp.async.commit_group;\n")
#define LDSM4(r0,r1,r2,r3,a) \
    asm volatile("ldmatrix.sync.aligned.m8n8.x4.shared.b16 {%0,%1,%2,%3},[%4];" \
        : "=r"(r0),"=r"(r1),"=r"(r2),"=r"(r3) : "r"(a))
#define LDSM4T(r0,r1,r2,r3,a) \
    asm volatile("ldmatrix.sync.aligned.m8n8.x4.trans.shared.b16 {%0,%1,%2,%3},[%4];" \
        : "=r"(r0),"=r"(r1),"=r"(r2),"=r"(r3) : "r"(a))
#define MMA_BF16(d, a, b) \
    asm volatile("mma.sync.aligned.m16n8k16.row.col.f32.bf16.bf16.f32 " \
        "{%0,%1,%2,%3},{%4,%5,%6,%7},{%8,%9},{%0,%1,%2,%3};" \
        : "+f"(d[0]),"+f"(d[1]),"+f"(d[2]),"+f"(d[3]) \
        : "r"(a[0]),"r"(a[1]),"r"(a[2]),"r"(a[3]),"r"(b[0]),"r"(b[1]))
#define MMA_FP16(d, a, b) \
    asm volatile("mma.sync.aligned.m16n8k16.row.col.f32.f16.f16.f32 " \
        "{%0,%1,%2,%3},{%4,%5,%6,%7},{%8,%9},{%0,%1,%2,%3};" \
        : "+f"(d[0]),"+f"(d[1]),"+f"(d[2]),"+f"(d[3]) \
        : "r"(a[0]),"r"(a[1]),"r"(a[2]),"r"(a[3]),"r"(b[0]),"r"(b[1]))

__device__ __forceinline__ void split_write_bf(float v, __nv_bfloat16* hi, __nv_bfloat16* lo, size_t o) {
    __nv_bfloat16 h = __float2bfloat16(v);
    hi[o] = h;
    lo[o] = __float2bfloat16(v - __bfloat162float(h));
}

// ---------------- weight prep ----------------
__global__ void split_bf_kernel(const float* __restrict__ in, __nv_bfloat16* __restrict__ hi,
                                __nv_bfloat16* __restrict__ lo, int n) {
    int i = blockIdx.x * blockDim.x + threadIdx.x;
    if (i < n) {
        float v = in[i];
        __nv_bfloat16 h = __float2bfloat16(v);
        hi[i] = h;
        lo[i] = __float2bfloat16(v - __bfloat162float(h));
    }
}
__global__ void conv_fp_kernel(const float* __restrict__ in, __half* __restrict__ o, int n) {
    int i = blockIdx.x * blockDim.x + threadIdx.x;
    if (i < n) o[i] = __float2half(in[i]);
}

// ---------------- LN1: x -> (h_hi, h_lo) bf16 ----------------
__global__ void ln_kernel(const float* __restrict__ x,
                          const float* __restrict__ g, const float* __restrict__ b,
                          __nv_bfloat16* __restrict__ ohi, __nv_bfloat16* __restrict__ olo) {
    int row = blockIdx.x;
    const float* xr = x + (size_t)row * Cdim;
    __shared__ float buf[Cdim];
    __shared__ float rs[2];
    __shared__ float red[64];
    float s = 0.f, ss = 0.f;
    for (int i = threadIdx.x; i < Cdim; i += blockDim.x) {
        float v = xr[i]; buf[i] = v; s += v; ss += v * v;
    }
    for (int o = 16; o > 0; o >>= 1) { s += __shfl_down_sync(~0u, s, o); ss += __shfl_down_sync(~0u, ss, o); }
    int wid = threadIdx.x >> 5, lid = threadIdx.x & 31;
    if (lid == 0) { red[wid] = s; red[wid + 32] = ss; }
    __syncthreads();
    if (threadIdx.x == 0) {
        float t = 0.f, tt = 0.f;
        int nw = blockDim.x >> 5;
        for (int i = 0; i < nw; i++) { t += red[i]; tt += red[i + 32]; }
        float mean = t / Cdim, var = tt / Cdim - mean * mean;
        rs[0] = mean; rs[1] = rsqrtf(var + 1e-5f);
    }
    __syncthreads();
    float mean = rs[0], inv = rs[1];
    for (int i = threadIdx.x; i < Cdim; i += blockDim.x)
        split_write_bf((buf[i] - mean) * inv * g[i] + b[i], ohi, olo, (size_t)row * Cdim + i);
}

// ---------------- LN2: xr = o + x (fp32), h2 fp16 ----------------
__global__ void ln2_kernel(const float* __restrict__ ov, const float* __restrict__ x,
                           const float* __restrict__ g, const float* __restrict__ b,
                           float* __restrict__ xr_out, __half* __restrict__ oh) {
    int row = blockIdx.x;
    const float* a = ov + (size_t)row * Cdim;
    const float* c = x  + (size_t)row * Cdim;
    __shared__ float buf[Cdim];
    __shared__ float rs[2];
    __shared__ float red[64];
    float s = 0.f, ss = 0.f;
    for (int i = threadIdx.x; i < Cdim; i += blockDim.x) {
        float v = a[i] + c[i];
        buf[i] = v;
        xr_out[(size_t)row * Cdim + i] = v;
        s += v; ss += v * v;
    }
    for (int o = 16; o > 0; o >>= 1) { s += __shfl_down_sync(~0u, s, o); ss += __shfl_down_sync(~0u, ss, o); }
    int wid = threadIdx.x >> 5, lid = threadIdx.x & 31;
    if (lid == 0) { red[wid] = s; red[wid + 32] = ss; }
    __syncthreads();
    if (threadIdx.x == 0) {
        float t = 0.f, tt = 0.f;
        int nw = blockDim.x >> 5;
        for (int i = 0; i < nw; i++) { t += red[i]; tt += red[i + 32]; }
        float mean = t / Cdim, var = tt / Cdim - mean * mean;
        rs[0] = mean; rs[1] = rsqrtf(var + 1e-5f);
    }
    __syncthreads();
    float mean = rs[0], inv = rs[1];
    for (int i = threadIdx.x; i < Cdim; i += blockDim.x)
        oh[(size_t)row * Cdim + i] = __float2half((buf[i] - mean) * inv * g[i] + b[i]);
}

// ===== bf16x3 GEMM (qkv, proj) — BK=32, 2-stage, 2 CTAs/SM =====
#define ASTR3 40
#define BSTR3 136
#define A3_ST (2*128*ASTR3)
#define B3_ST (2*32*BSTR3)
#define GEMM3_SMEM ((2*A3_ST + 2*B3_ST) * 2)  // 75776

template<int EP>
__global__ __launch_bounds__(256, 2)
void mma_gemm3(const __nv_bfloat16* __restrict__ Ah, const __nv_bfloat16* __restrict__ Al,
               const __nv_bfloat16* __restrict__ Bh, const __nv_bfloat16* __restrict__ Bl,
               const float* __restrict__ bias,
               float* __restrict__ Cf, int M, int N, int K) {
    extern __shared__ __nv_bfloat16 sm3[];
    __nv_bfloat16* Asm = sm3;
    __nv_bfloat16* Bsm = sm3 + 2 * A3_ST;

    int tid = threadIdx.x;
    int warp = tid >> 5, lane = tid & 31;
    int wm = warp & 1, wn = warp >> 1;
    int rowBase = blockIdx.y * 128, colBase = blockIdx.x * 128;

    const int KT = (K + 31) >> 5;
    float acc[4][4][4];
    #pragma unroll
    for (int i = 0; i < 4; i++)
        #pragma unroll
        for (int j = 0; j < 4; j++)
            #pragma unroll
            for (int q = 0; q < 4; q++) acc[i][j][q] = 0.f;

    auto load_stage = [&](int st, int kt) {
        int koff = kt * 32;
        __nv_bfloat16* Ast = Asm + st * A3_ST;
        __nv_bfloat16* Bst = Bsm + st * B3_ST;
        #pragma unroll
        for (int part = 0; part < 2; part++) {
            const __nv_bfloat16* Aasrc = part ? Al : Ah;
            #pragma unroll
            for (int i = 0; i < 2; i++) {
                int chunk = i * 256 + tid;
                int r = chunk >> 2, cc = (chunk & 3) * 8;
                int k = koff + cc;
                uint32_t dst = smem_u32(Ast + part * (128 * ASTR3) + r * ASTR3 + cc);
                const __nv_bfloat16* src = Aasrc + (size_t)(rowBase + r) * K + (k < K ? k : 0);
                CP_ASYNC16(dst, src, (k < K) ? 16 : 0);
            }
        }
        #pragma unroll
        for (int part = 0; part < 2; part++) {
            const __nv_bfloat16* Bbsrc = part ? Bl : Bh;
            #pragma unroll
            for (int i = 0; i < 2; i++) {
                int chunk = i * 256 + tid;
                int r = chunk >> 4, cc = (chunk & 15) * 8;
                int k = koff + r, n = colBase + cc;
                bool ok = (k < K) && (n < N);
                uint32_t dst = smem_u32(Bst + part * (32 * BSTR3) + r * BSTR3 + cc);
                const __nv_bfloat16* src = Bbsrc + (ok ? ((size_t)k * N + n) : 0);
                CP_ASYNC16(dst, src, ok ? 16 : 0);
            }
        }
    };

    load_stage(0, 0); CP_COMMIT();
    if (KT > 1) { load_stage(1, 1); }
    CP_COMMIT();

    int lrow = lane & 15, lhalf = (lane >> 4) * 8;

    for (int kt = 0; kt < KT; kt++) {
        if (kt + 1 < KT) { asm volatile("cp.async.wait_group 1;"); }
        else             { asm volatile("cp.async.wait_group 0;"); }
        __syncthreads();

        int st = kt & 1;
        __nv_bfloat16* Ast = Asm + st * A3_ST;
        __nv_bfloat16* Bst = Bsm + st * B3_ST;

        #pragma unroll
        for (int kk = 0; kk < 32; kk += 16) {
            uint32_t ah[4][4], bh[4][2], bl[4][2];
            #pragma unroll
            for (int mi = 0; mi < 4; mi++) {
                uint32_t a0 = smem_u32(Ast + (wm * 64 + mi * 16 + lrow) * ASTR3 + kk + lhalf);
                LDSM4(ah[mi][0], ah[mi][1], ah[mi][2], ah[mi][3], a0);
            }
            #pragma unroll
            for (int pr = 0; pr < 2; pr++) {
                uint32_t r0, r1, r2, r3;
                uint32_t b0 = smem_u32(Bst + (kk + lrow) * BSTR3 + wn * 32 + pr * 16 + lhalf);
                LDSM4T(r0, r1, r2, r3, b0);
                bh[pr * 2][0] = r0; bh[pr * 2][1] = r1; bh[pr * 2 + 1][0] = r2; bh[pr * 2 + 1][1] = r3;
                uint32_t b1 = smem_u32(Bst + 32 * BSTR3 + (kk + lrow) * BSTR3 + wn * 32 + pr * 16 + lhalf);
                LDSM4T(r0, r1, r2, r3, b1);
                bl[pr * 2][0] = r0; bl[pr * 2][1] = r1; bl[pr * 2 + 1][0] = r2; bl[pr * 2 + 1][1] = r3;
            }
            // terms with ah first (ah·bh, ah·bl), then reload A-lo and do al·bh
            #pragma unroll
            for (int mi = 0; mi < 4; mi++)
                #pragma unroll
                for (int ni = 0; ni < 4; ni++) {
                    MMA_BF16(acc[mi][ni], ah[mi], bh[ni]);
                    MMA_BF16(acc[mi][ni], ah[mi], bl[ni]);
                }
            uint32_t al[4][4];
            #pragma unroll
            for (int mi = 0; mi < 4; mi++) {
                uint32_t a1 = smem_u32(Ast + 128 * ASTR3 + (wm * 64 + mi * 16 + lrow) * ASTR3 + kk + lhalf);
                LDSM4(al[mi][0], al[mi][1], al[mi][2], al[mi][3], a1);
            }
            #pragma unroll
            for (int mi = 0; mi < 4; mi++)
                #pragma unroll
                for (int ni = 0; ni < 4; ni++)
                    MMA_BF16(acc[mi][ni], al[mi], bh[ni]);
        }
        __syncthreads();
        if (kt + 2 < KT) { load_stage(st, kt + 2); CP_COMMIT(); }
    }

    #pragma unroll
    for (int mi = 0; mi < 4; mi++) {
        int r0 = rowBase + wm * 64 + mi * 16 + (lane >> 2);
        #pragma unroll
        for (int ni = 0; ni < 4; ni++) {
            int c0 = colBase + wn * 32 + ni * 8 + (lane & 3) * 2;
            #pragma unroll
            for (int q = 0; q < 4; q++) {
                int r = r0 + (q >> 1) * 8;
                int c = c0 + (q & 1);
                if (c < N) {
                    float v = acc[mi][ni][q];
                    if (EP >= 1) v += bias[c];
                    Cf[(size_t)r * N + c] = v;
                }
            }
        }
    }
}

// ===== fp16 single-term GEMM (fc1, fc2) — BK=32, 2-stage, 2 CTAs/SM =====
#define ASTR2 40
#define BSTR2 136
#define A2_ST (128*ASTR2)
#define B2_ST (32*BSTR2)
#define GEMM2_SMEM ((2*A2_ST + 2*B2_ST) * 2)  // 37888

template<int EP>
__global__ __launch_bounds__(256, 2)
void mma_gemm2(const __half* __restrict__ A, const __half* __restrict__ B,
               const float* __restrict__ bias, const float* __restrict__ res,
               float* __restrict__ Cf, __half* __restrict__ Ch,
               int M, int N, int K) {
    extern __shared__ __half sm2[];
    __half* Asm = sm2;
    __half* Bsm = sm2 + 2 * A2_ST;

    int tid = threadIdx.x;
    int warp = tid >> 5, lane = tid & 31;
    int wm = warp & 1, wn = warp >> 1;
    int rowBase = blockIdx.y * 128, colBase = blockIdx.x * 128;

    const int KT = (K + 31) >> 5;
    float acc[4][4][4];
    #pragma unroll
    for (int i = 0; i < 4; i++)
        #pragma unroll
        for (int j = 0; j < 4; j++)
            #pragma unroll
            for (int q = 0; q < 4; q++) acc[i][j][q] = 0.f;

    auto load_stage = [&](int st, int kt) {
        int koff = kt * 32;
        __half* Ast = Asm + st * A2_ST;
        __half* Bst = Bsm + st * B2_ST;
        #pragma unroll
        for (int i = 0; i < 2; i++) {
            int chunk = i * 256 + tid;
            int r = chunk >> 2, cc = (chunk & 3) * 8;
            int k = koff + cc;
            uint32_t dst = smem_u32(Ast + r * ASTR2 + cc);
            const __half* src = A + (size_t)(rowBase + r) * K + (k < K ? k : 0);
            CP_ASYNC16(dst, src, (k < K) ? 16 : 0);
        }
        #pragma unroll
        for (int i = 0; i < 2; i++) {
            int chunk = i * 256 + tid;
            int r = chunk >> 4, cc = (chunk & 15) * 8;
            int k = koff + r, n = colBase + cc;
            bool ok = (k < K) && (n < N);
            uint32_t dst = smem_u32(Bst + r * BSTR2 + cc);
            const __half* src = B + (ok ? ((size_t)k * N + n) : 0);
            CP_ASYNC16(dst, src, ok ? 16 : 0);
        }
    };

    load_stage(0, 0); CP_COMMIT();
    if (KT > 1) { load_stage(1, 1); }
    CP_COMMIT();

    int lrow = lane & 15, lhalf = (lane >> 4) * 8;

    for (int kt = 0; kt < KT; kt++) {
        if (kt + 1 < KT) { asm volatile("cp.async.wait_group 1;"); }
        else             { asm volatile("cp.async.wait_group 0;"); }
        __syncthreads();

        int st = kt & 1;
        __half* Ast = Asm + st * A2_ST;
        __half* Bst = Bsm + st * B2_ST;

        #pragma unroll
        for (int kk = 0; kk < 32; kk += 16) {
            uint32_t a[4][4], bb[4][2];
            #pragma unroll
            for (int mi = 0; mi < 4; mi++) {
                uint32_t a0 = smem_u32(Ast + (wm * 64 + mi * 16 + lrow) * ASTR2 + kk + lhalf);
                LDSM4(a[mi][0], a[mi][1], a[mi][2], a[mi][3], a0);
            }
            #pragma unroll
            for (int pr = 0; pr < 2; pr++) {
                uint32_t r0, r1, r2, r3;
                uint32_t b0 = smem_u32(Bst + (kk + lrow) * BSTR2 + wn * 32 + pr * 16 + lhalf);
                LDSM4T(r0, r1, r2, r3, b0);
                bb[pr * 2][0] = r0; bb[pr * 2][1] = r1; bb[pr * 2 + 1][0] = r2; bb[pr * 2 + 1][1] = r3;
            }
            #pragma unroll
            for (int mi = 0; mi < 4; mi++)
                #pragma unroll
                for (int ni = 0; ni < 4; ni++)
                    MMA_FP16(acc[mi][ni], a[mi], bb[ni]);
        }
        __syncthreads();
        if (kt + 2 < KT) { load_stage(st, kt + 2); CP_COMMIT(); }
    }

    #pragma unroll
    for (int mi = 0; mi < 4; mi++) {
        int r0 = rowBase + wm * 64 + mi * 16 + (lane >> 2);
        #pragma unroll
        for (int ni = 0; ni < 4; ni++) {
            int c0 = colBase + wn * 32 + ni * 8 + (lane & 3) * 2;
            #pragma unroll
            for (int q = 0; q < 4; q++) {
                int r = r0 + (q >> 1) * 8;
                int c = c0 + (q & 1);
                if (c < N) {
                    float v = acc[mi][ni][q] + bias[c];
                    size_t o = (size_t)r * N + c;
                    if (EP == 2) {
                        v = 0.5f * v * (1.0f + erff(v * 0.70710678118654752440f));
                        Ch[o] = __float2half(v);
                    } else {
                        v += res[o];
                        Cf[o] = v;
                    }
                }
            }
        }
    }
}

// ---------------- MHA (register-tiled) -> att bf16 split ----------------
#define MHA_SMEM ((3*64*HDP + 64*64)*4)
__global__ void mha_kernel(const float* __restrict__ qkv,
                           __nv_bfloat16* __restrict__ ahi, __nv_bfloat16* __restrict__ alo) {
    extern __shared__ float smf[];
    float* Q  = smf;
    float* Kx = Q + 64 * HDP;
    float* V  = Kx + 64 * HDP;
    float* SC = V + 64 * HDP;
    int h = blockIdx.x, b = blockIdx.y;
    int tid = threadIdx.x;
    const float* base = qkv + (size_t)(b * NTOK) * (3 * Cdim);
    for (int e = tid; e < 64 * HD; e += 256) {
        int t = e / HD, d = e % HD;
        Q[t * HDP + d]  = base[(size_t)t * (3 * Cdim) + h * HD + d];
        Kx[t * HDP + d] = base[(size_t)t * (3 * Cdim) + Cdim + h * HD + d];
        V[t * HDP + d]  = base[(size_t)t * (3 * Cdim) + 2 * Cdim + h * HD + d];
    }
    __syncthreads();
    const float scale = rsqrtf((float)HD);
    {
        int ti = tid >> 4, tj = tid & 15;
        float acc[4][4] = {};
        #pragma unroll 2
        for (int d = 0; d < HD; d++) {
            float qv[4], kv[4];
            #pragma unroll
            for (int r2 = 0; r2 < 4; r2++) qv[r2] = Q[(ti * 4 + r2) * HDP + d];
            #pragma unroll
            for (int c2 = 0; c2 < 4; c2++) kv[c2] = Kx[(tj * 4 + c2) * HDP + d];
            #pragma unroll
            for (int r2 = 0; r2 < 4; r2++)
                #pragma unroll
                for (int c2 = 0; c2 < 4; c2++) acc[r2][c2] += qv[r2] * kv[c2];
        }
        #pragma unroll
        for (int r2 = 0; r2 < 4; r2++)
            #pragma unroll
            for (int c2 = 0; c2 < 4; c2++)
                SC[(ti * 4 + r2) * 64 + tj * 4 + c2] = acc[r2][c2] * scale;
    }
    __syncthreads();
    if (tid < 64) {
        float* row = SC + tid * 64;
        float mx = -1e30f;
        for (int j = 0; j < 64; j++) mx = fmaxf(mx, row[j]);
        float s = 0.f;
        for (int j = 0; j < 64; j++) { float e = expf(row[j] - mx); row[j] = e; s += e; }
        float inv = 1.f / s;
        for (int j = 0; j < 64; j++) row[j] *= inv;
    }
    __syncthreads();
    {
        int ti = tid >> 4, td = tid & 15;
        if (td < 14) {
            float oacc[4][7] = {};
            for (int j = 0; j < 64; j++) {
                float pr[4], vv[7];
                #pragma unroll
                for (int r2 = 0; r2 < 4; r2++) pr[r2] = SC[(ti * 4 + r2) * 64 + j];
                #pragma unroll
                for (int c2 = 0; c2 < 7; c2++) vv[c2] = V[j * HDP + td * 7 + c2];
                #pragma unroll
                for (int r2 = 0; r2 < 4; r2++)
                    #pragma unroll
                    for (int c2 = 0; c2 < 7; c2++) oacc[r2][c2] += pr[r2] * vv[c2];
            }
            #pragma unroll
            for (int r2 = 0; r2 < 4; r2++)
                #pragma unroll
                for (int c2 = 0; c2 < 7; c2++)
                    split_write_bf(oacc[r2][c2], ahi, alo,
                        ((size_t)(b * NTOK + ti * 4 + r2)) * Cdim + h * HD + td * 7 + c2);
        }
    }
}

// ---------------- BiFormer ----------------
#define BFQ_SMEM ((64*28 + 192*64)*4)  // 56320
__global__ void bf_qkv_kernel(const float* __restrict__ o,
                              const float* __restrict__ w, const float* __restrict__ bias) {
    extern __shared__ float bq[];
    float* xin = bq;             // [64][28]
    float* ws  = bq + 64 * 28;   // [192][64]
    int y = blockIdx.x, b = blockIdx.y;
    int tid = threadIdx.x;
    for (int e = tid; e < 192 * 64; e += 256) ws[e] = w[e];
    for (int e = tid; e < 64 * 28; e += 256) {
        int c = e / 28, xx = e % 28;
        xin[e] = o[((size_t)b * 64 + c) * 784 + y * 28 + xx];
    }
    __syncthreads();
    for (int e = tid; e < 192 * 28; e += 256) {
        int oc = e / 28, xx = e % 28;
        float a = bias[oc];
        const float* wr = ws + oc * 64;
        #pragma unroll 16
        for (int c = 0; c < 64; c++) a += xin[c * 28 + xx] * wr[c];
        g_bfqkv[((size_t)b * 192 + oc) * 784 + y * 28 + xx] = a;
    }
}

// fused region pooling + routing top-4 (one block per batch)
__global__ void bf_routing_kernel() {
    int b = blockIdx.x;
    int tid = threadIdx.x;  // 256
    __shared__ float qr[64][NREG];
    __shared__ float kr[64][NREG];
    __shared__ float ar[NREG][NREG];
    for (int e = tid; e < 64 * NREG; e += 256) {
        int c = e / NREG, r = e % NREG;
        int rh = r / 7, rw = r % 7;
        float sq = 0.f, sk = 0.f;
        const float* qc = g_bfqkv + ((size_t)b * 192 + c) * 784;
        const float* kc = g_bfqkv + ((size_t)b * 192 + 64 + c) * 784;
        #pragma unroll
        for (int pr = 0; pr < 4; pr++)
            #pragma unroll
            for (int pc = 0; pc < 4; pc++) {
                int s = (rh * 4 + pr) * 28 + rw * 4 + pc;
                sq += qc[s]; sk += kc[s];
            }
        qr[c][r] = sq * 0.0625f;
        kr[c][r] = sk * 0.0625f;
    }
    __syncthreads();
    for (int e = tid; e < NREG * NREG; e += 256) {
        int i = e / NREG, j = e % NREG;
        float a = 0.f;
        #pragma unroll 16
        for (int c = 0; c < 64; c++) a += qr[c][i] * kr[c][j];
        ar[i][j] = a;
    }
    __syncthreads();
    if (tid < NREG) {
        float* row = ar[tid];
        #pragma unroll
        for (int j = 0; j < TOPK; j++) {
            float mx = -1e30f; int mi = 0;
            for (int s = 0; s < NREG; s++) if (row[s] > mx) { mx = row[s]; mi = s; }
            row[mi] = -1e30f;
            g_idx[(b * NREG + tid) * TOPK + j] = mi;
        }
    }
}

__global__ void bf_attn_kernel() {
    int r = blockIdx.x, h = blockIdx.y, b = blockIdx.z;
    __shared__ float q[16][8], kg[64][9], vg[64][9];
    __shared__ float sc[16][65];
    __shared__ int idx4[4];
    int tid = threadIdx.x;  // 128
    if (tid < 4) idx4[tid] = g_idx[(b * NREG + r) * TOPK + tid];
    int rh = r / 7, rw = r % 7;
    {
        int p = tid / 8, d = tid % 8;
        int s = (rh * 4 + p / 4) * 28 + rw * 4 + (p % 4);
        q[p][d] = g_bfqkv[((size_t)b * 192 + h * 8 + d) * 784 + s] * 0.125f;
    }
    __syncthreads();
    for (int e = tid; e < 512; e += 128) {
        int t = e / 8, d = e % 8;
        int reg = idx4[t / 16];
        int p2 = t % 16;
        int s = ((reg / 7) * 4 + p2 / 4) * 28 + (reg % 7) * 4 + (p2 % 4);
        kg[t][d] = g_bfqkv[((size_t)b * 192 + 64 + h * 8 + d) * 784 + s];
        vg[t][d] = g_bfqkv[((size_t)b * 192 + 128 + h * 8 + d) * 784 + s];
    }
    __syncthreads();
    {
        int p = tid >> 3, tg = tid & 7;
        float qreg[8];
        #pragma unroll
        for (int d = 0; d < 8; d++) qreg[d] = q[p][d];
        #pragma unroll
        for (int tt = 0; tt < 8; tt++) {
            int t = tt * 8 + tg;
            float a = 0.f;
            #pragma unroll
            for (int d = 0; d < 8; d++) a += qreg[d] * kg[t][d];
            sc[p][t] = a;
        }
    }
    __syncthreads();
    if (tid < 16) {
        float mx = -1e30f;
        for (int t = 0; t < 64; t++) mx = fmaxf(mx, sc[tid][t]);
        float s = 0.f;
        for (int t = 0; t < 64; t++) { float e = expf(sc[tid][t] - mx); sc[tid][t] = e; s += e; }
        float inv = 1.f / s;
        for (int t = 0; t < 64; t++) sc[tid][t] *= inv;
    }
    __syncthreads();
    {
        int p = tid / 8, d = tid % 8;
        float a = 0.f;
        #pragma unroll 8
        for (int t = 0; t < 64; t++) a += sc[p][t] * vg[t][d];
        int s = (rh * 4 + p / 4) * 28 + rw * 4 + (p % 4);
        g_attg[((size_t)b * 64 + h * 8 + d) * 784 + s] = a;
    }
}

__global__ void bf_out_kernel(const float* __restrict__ lepe_w, const float* __restrict__ lepe_b,
                              const float* __restrict__ out_w, const float* __restrict__ out_b,
                              float* __restrict__ outp) {
    int y = blockIdx.x, b = blockIdx.y;
    __shared__ float v3[3][64][28];
    __shared__ float tmp[64][28];
    __shared__ float ws[64][64];
    __shared__ float lw[64][9];
    int tid = threadIdx.x;
    for (int e = tid; e < 64 * 64; e += blockDim.x) ws[e >> 6][e & 63] = out_w[e];
    for (int e = tid; e < 64 * 9; e += blockDim.x) lw[e / 9][e % 9] = lepe_w[e];
    for (int ry = 0; ry < 3; ry++) {
        int yy = y + ry - 1;
        for (int e = tid; e < 64 * 28; e += blockDim.x) {
            int c = e / 28, xx = e % 28;
            v3[ry][c][xx] = (yy >= 0 && yy < 28)
                ? g_bfqkv[((size_t)b * 192 + 128 + c) * 784 + yy * 28 + xx] : 0.f;
        }
    }
    __syncthreads();
    for (int e = tid; e < 64 * 28; e += blockDim.x) {
        int c = e / 28, xx = e % 28;
        float a = g_attg[((size_t)b * 64 + c) * 784 + y * 28 + xx] + lepe_b[c];
        #pragma unroll
        for (int ky = 0; ky < 3; ky++)
            #pragma unroll
            for (int kx = 0; kx < 3; kx++) {
                int xx2 = xx + kx - 1;
                if (xx2 >= 0 && xx2 < 28) a += v3[ky][c][xx2] * lw[c][ky * 3 + kx];
            }
        tmp[c][xx] = a;
    }
    __syncthreads();
    for (int e = tid; e < 64 * 28; e += blockDim.x) {
        int oc = e / 28, xx = e % 28;
        float a = out_b[oc];
        const float* wr = ws[oc];
        #pragma unroll 16
        for (int c = 0; c < 64; c++) a += tmp[c][xx] * wr[c];
        outp[((size_t)b * 64 + oc) * 784 + y * 28 + xx] = a;
    }
}

// ---------------- launch ----------------
extern "C" void kernel_launch(void* const* d_in, const int* in_sizes, int n_in,
                              void* d_out, int out_size) {
    (void)in_sizes; (void)n_in; (void)out_size;
    const float* x        = (const float*)d_in[0];
    const float* norm1_g  = (const float*)d_in[1];
    const float* norm1_b  = (const float*)d_in[2];
    const float* qkv_w    = (const float*)d_in[3];
    const float* proj_w   = (const float*)d_in[4];
    const float* proj_b   = (const float*)d_in[5];
    const float* norm2_g  = (const float*)d_in[6];
    const float* norm2_b  = (const float*)d_in[7];
    const float* fc1_w    = (const float*)d_in[8];
    const float* fc1_b    = (const float*)d_in[9];
    const float* fc2_w    = (const float*)d_in[10];
    const float* fc2_b    = (const float*)d_in[11];
    const float* bf_qkv_w = (const float*)d_in[12];
    const float* bf_qkv_b = (const float*)d_in[13];
    const float* bf_lepe_w= (const float*)d_in[14];
    const float* bf_lepe_b= (const float*)d_in[15];
    const float* bf_out_w = (const float*)d_in[16];
    const float* bf_out_b = (const float*)d_in[17];
    float* out = (float*)d_out;

    __nv_bfloat16 *p_h_hi, *p_h_lo, *p_att_hi, *p_att_lo;
    __nv_bfloat16 *p_wqkv_hi, *p_wqkv_lo, *p_wproj_hi, *p_wproj_lo;
    __half *p_h2, *p_hid, *p_wfc1, *p_wfc2;
    float *p_qkv, *p_o, *p_xr;
    cudaGetSymbolAddress((void**)&p_h_hi, g_h_hi);     cudaGetSymbolAddress((void**)&p_h_lo, g_h_lo);
    cudaGetSymbolAddress((void**)&p_att_hi, g_att_hi); cudaGetSymbolAddress((void**)&p_att_lo, g_att_lo);
    cudaGetSymbolAddress((void**)&p_h2, g_h2);
    cudaGetSymbolAddress((void**)&p_hid, g_hid);
    cudaGetSymbolAddress((void**)&p_wqkv_hi, g_wqkv_hi);   cudaGetSymbolAddress((void**)&p_wqkv_lo, g_wqkv_lo);
    cudaGetSymbolAddress((void**)&p_wproj_hi, g_wproj_hi); cudaGetSymbolAddress((void**)&p_wproj_lo, g_wproj_lo);
    cudaGetSymbolAddress((void**)&p_wfc1, g_wfc1);
    cudaGetSymbolAddress((void**)&p_wfc2, g_wfc2);
    cudaGetSymbolAddress((void**)&p_qkv, g_qkv);
    cudaGetSymbolAddress((void**)&p_o, g_o);
    cudaGetSymbolAddress((void**)&p_xr, g_xr);

    cudaFuncSetAttribute(mha_kernel, cudaFuncAttributeMaxDynamicSharedMemorySize, MHA_SMEM);
    cudaFuncSetAttribute(bf_qkv_kernel, cudaFuncAttributeMaxDynamicSharedMemorySize, BFQ_SMEM);
    cudaFuncSetAttribute(mma_gemm3<0>, cudaFuncAttributeMaxDynamicSharedMemorySize, GEMM3_SMEM);
    cudaFuncSetAttribute(mma_gemm3<1>, cudaFuncAttributeMaxDynamicSharedMemorySize, GEMM3_SMEM);
    cudaFuncSetAttribute(mma_gemm2<2>, cudaFuncAttributeMaxDynamicSharedMemorySize, GEMM2_SMEM);
    cudaFuncSetAttribute(mma_gemm2<3>, cudaFuncAttributeMaxDynamicSharedMemorySize, GEMM2_SMEM);

    // one-time stream/event creation (host resources only; no device allocations)
    static cudaStream_t s1 = nullptr;
    static cudaEvent_t eFork = nullptr, eW = nullptr, eO = nullptr, eBF = nullptr;
    if (!s1) {
        cudaStreamCreateWithFlags(&s1, cudaStreamNonBlocking);
        cudaEventCreateWithFlags(&eFork, cudaEventDisableTiming);
        cudaEventCreateWithFlags(&eW,    cudaEventDisableTiming);
        cudaEventCreateWithFlags(&eO,    cudaEventDisableTiming);
        cudaEventCreateWithFlags(&eBF,   cudaEventDisableTiming);
    }

    // fork
    cudaEventRecord(eFork, 0);
    cudaStreamWaitEvent(s1, eFork, 0);

    // s1: proj/fc weight prep (overlap with LN1 + qkv GEMM on s0)
    split_bf_kernel<<<(Cdim * Cdim + 255) / 256, 256, 0, s1>>>(proj_w, p_wproj_hi, p_wproj_lo, Cdim * Cdim);
    conv_fp_kernel<<<(Cdim * HID + 255) / 256, 256, 0, s1>>>(fc1_w, p_wfc1, Cdim * HID);
    conv_fp_kernel<<<(HID * Cdim + 255) / 256, 256, 0, s1>>>(fc2_w, p_wfc2, HID * Cdim);
    cudaEventRecord(eW, s1);

    // s0: qkv weight split + LN1 + qkv GEMM + MHA
    split_bf_kernel<<<(Cdim * 3 * Cdim + 255) / 256, 256>>>(qkv_w, p_wqkv_hi, p_wqkv_lo, Cdim * 3 * Cdim);
    ln_kernel<<<ROWS, 256>>>(x, norm1_g, norm1_b, p_h_hi, p_h_lo);
    mma_gemm3<0><<<dim3((3 * Cdim + 127) / 128, ROWS / 128), 256, GEMM3_SMEM>>>(
        p_h_hi, p_h_lo, p_wqkv_hi, p_wqkv_lo, nullptr,
        p_qkv, ROWS, 3 * Cdim, Cdim);
    mha_kernel<<<dim3(NHd, Bsz), 256, MHA_SMEM>>>(p_qkv, p_att_hi, p_att_lo);
    cudaStreamWaitEvent(0, eW, 0);
    mma_gemm3<1><<<dim3((Cdim + 127) / 128, ROWS / 128), 256, GEMM3_SMEM>>>(
        p_att_hi, p_att_lo, p_wproj_hi, p_wproj_lo, proj_b,
        p_o, ROWS, Cdim, Cdim);
    cudaEventRecord(eO, 0);

    // s1: BiFormer branch
    cudaStreamWaitEvent(s1, eO, 0);
    bf_qkv_kernel<<<dim3(28, Bsz), 256, BFQ_SMEM, s1>>>(p_o, bf_qkv_w, bf_qkv_b);
    bf_routing_kernel<<<Bsz, 256, 0, s1>>>();
    bf_attn_kernel<<<dim3(NREG, 8, Bsz), 128, 0, s1>>>();
    bf_out_kernel<<<dim3(28, Bsz), 256, 0, s1>>>(bf_lepe_w, bf_lepe_b, bf_out_w, bf_out_b, out + OUT_OFF);
    cudaEventRecord(eBF, s1);

    // s0: MLP branch
    ln2_kernel<<<ROWS, 256>>>(p_o, x, norm2_g, norm2_b, p_xr, p_h2);
    mma_gemm2<2><<<dim3((HID + 127) / 128, ROWS / 128), 256, GEMM2_SMEM>>>(
        p_h2, p_wfc1, fc1_b, nullptr,
        nullptr, p_hid, ROWS, HID, Cdim);
    mma_gemm2<3><<<dim3((Cdim + 127) / 128, ROWS / 128), 256, GEMM2_SMEM>>>(
        p_hid, p_wfc2, fc2_b, p_xr,
        out, nullptr, ROWS, Cdim, HID);

    // join
    cudaStreamWaitEvent(0, eBF, 0);
}

// round 13
// speedup vs baseline: 2.1177x; 1.0120x over previous
#include <cuda_runtime.h>
#include <cuda_bf16.h>
#include <cuda_fp16.h>
#include <math.h>
#include <stdint.h>

// ---------------- problem constants ----------------
#define Bsz   128
#define NTOK  64
#define Cdim  784
#define NHd   8
#define HD    98
#define HDP   99
#define HID   3136
#define ROWS  (Bsz*NTOK)  // 8192
#define NREG  49
#define TOPK  4
#define OUT_OFF (Bsz*NTOK*Cdim)

// ---------------- scratch ----------------
__device__ __nv_bfloat16 g_h_hi [ROWS*Cdim];
__device__ __nv_bfloat16 g_h_lo [ROWS*Cdim];
__device__ float         g_qkv  [ROWS*3*Cdim];
__device__ __nv_bfloat16 g_att_hi[ROWS*Cdim];
__device__ __nv_bfloat16 g_att_lo[ROWS*Cdim];
__device__ float         g_o    [ROWS*Cdim];
__device__ float         g_xr   [ROWS*Cdim];
__device__ __half        g_h2   [ROWS*Cdim];
__device__ __half        g_hid  [ROWS*HID];
// weight splits [K, N]
__device__ __nv_bfloat16 g_wqkv_hi[Cdim*3*Cdim];
__device__ __nv_bfloat16 g_wqkv_lo[Cdim*3*Cdim];
__device__ __nv_bfloat16 g_wproj_hi[Cdim*Cdim];
__device__ __nv_bfloat16 g_wproj_lo[Cdim*Cdim];
__device__ __half        g_wfc1 [Cdim*HID];
__device__ __half        g_wfc2 [HID*Cdim];
// biformer
__device__ float g_bfqkv[Bsz*192*784];
__device__ float g_attg [Bsz*64*784];
__device__ int   g_idx [Bsz*NREG*TOPK];

// ---------------- helpers ----------------
__device__ __forceinline__ uint32_t smem_u32(const void* p) {
    return (uint32_t)__cvta_generic_to_shared(p);
}
#define CP_ASYNC16(dst_u32, src, sz) \
    asm volatile("cp.async.cg.shared.global [%0], [%1], 16, %2;\n" :: "r"(dst_u32), "l"(src), "r"(sz))
#define CP_COMMIT() asm volatile("cp.async.commit_group;\n")
#define LDSM4(r0,r1,r2,r3,a) \
    asm volatile("ldmatrix.sync.aligned.m8n8.x4.shared.b16 {%0,%1,%2,%3},[%4];" \
        : "=r"(r0),"=r"(r1),"=r"(r2),"=r"(r3) : "r"(a))
#define LDSM4T(r0,r1,r2,r3,a) \
    asm volatile("ldmatrix.sync.aligned.m8n8.x4.trans.shared.b16 {%0,%1,%2,%3},[%4];" \
        : "=r"(r0),"=r"(r1),"=r"(r2),"=r"(r3) : "r"(a))
#define MMA_BF16(d, a, b) \
    asm volatile("mma.sync.aligned.m16n8k16.row.col.f32.bf16.bf16.f32 " \
        "{%0,%1,%2,%3},{%4,%5,%6,%7},{%8,%9},{%0,%1,%2,%3};" \
        : "+f"(d[0]),"+f"(d[1]),"+f"(d[2]),"+f"(d[3]) \
        : "r"(a[0]),"r"(a[1]),"r"(a[2]),"r"(a[3]),"r"(b[0]),"r"(b[1]))
#define MMA_FP16(d, a, b) \
    asm volatile("mma.sync.aligned.m16n8k16.row.col.f32.f16.f16.f32 " \
        "{%0,%1,%2,%3},{%4,%5,%6,%7},{%8,%9},{%0,%1,%2,%3};" \
        : "+f"(d[0]),"+f"(d[1]),"+f"(d[2]),"+f"(d[3]) \
        : "r"(a[0]),"r"(a[1]),"r"(a[2]),"r"(a[3]),"r"(b[0]),"r"(b[1]))

__device__ __forceinline__ void split_write_bf(float v, __nv_bfloat16* hi, __nv_bfloat16* lo, size_t o) {
    __nv_bfloat16 h = __float2bfloat16(v);
    hi[o] = h;
    lo[o] = __float2bfloat16(v - __bfloat162float(h));
}

// ---------------- weight prep ----------------
__global__ void split_bf_kernel(const float* __restrict__ in, __nv_bfloat16* __restrict__ hi,
                                __nv_bfloat16* __restrict__ lo, int n) {
    int i = blockIdx.x * blockDim.x + threadIdx.x;
    if (i < n) {
        float v = in[i];
        __nv_bfloat16 h = __float2bfloat16(v);
        hi[i] = h;
        lo[i] = __float2bfloat16(v - __bfloat162float(h));
    }
}
__global__ void conv_fp_kernel(const float* __restrict__ in, __half* __restrict__ o, int n) {
    int i = blockIdx.x * blockDim.x + threadIdx.x;
    if (i < n) o[i] = __float2half(in[i]);
}

// ---------------- LN1: x -> (h_hi, h_lo) bf16 ----------------
__global__ void ln_kernel(const float* __restrict__ x,
                          const float* __restrict__ g, const float* __restrict__ b,
                          __nv_bfloat16* __restrict__ ohi, __nv_bfloat16* __restrict__ olo) {
    int row = blockIdx.x;
    const float* xr = x + (size_t)row * Cdim;
    __shared__ float buf[Cdim];
    __shared__ float rs[2];
    __shared__ float red[64];
    float s = 0.f, ss = 0.f;
    for (int i = threadIdx.x; i < Cdim; i += blockDim.x) {
        float v = xr[i]; buf[i] = v; s += v; ss += v * v;
    }
    for (int o = 16; o > 0; o >>= 1) { s += __shfl_down_sync(~0u, s, o); ss += __shfl_down_sync(~0u, ss, o); }
    int wid = threadIdx.x >> 5, lid = threadIdx.x & 31;
    if (lid == 0) { red[wid] = s; red[wid + 32] = ss; }
    __syncthreads();
    if (threadIdx.x == 0) {
        float t = 0.f, tt = 0.f;
        int nw = blockDim.x >> 5;
        for (int i = 0; i < nw; i++) { t += red[i]; tt += red[i + 32]; }
        float mean = t / Cdim, var = tt / Cdim - mean * mean;
        rs[0] = mean; rs[1] = rsqrtf(var + 1e-5f);
    }
    __syncthreads();
    float mean = rs[0], inv = rs[1];
    for (int i = threadIdx.x; i < Cdim; i += blockDim.x)
        split_write_bf((buf[i] - mean) * inv * g[i] + b[i], ohi, olo, (size_t)row * Cdim + i);
}

// ---------------- LN2: xr = o + x (fp32), h2 fp16 ----------------
__global__ void ln2_kernel(const float* __restrict__ ov, const float* __restrict__ x,
                           const float* __restrict__ g, const float* __restrict__ b,
                           float* __restrict__ xr_out, __half* __restrict__ oh) {
    int row = blockIdx.x;
    const float* a = ov + (size_t)row * Cdim;
    const float* c = x  + (size_t)row * Cdim;
    __shared__ float buf[Cdim];
    __shared__ float rs[2];
    __shared__ float red[64];
    float s = 0.f, ss = 0.f;
    for (int i = threadIdx.x; i < Cdim; i += blockDim.x) {
        float v = a[i] + c[i];
        buf[i] = v;
        xr_out[(size_t)row * Cdim + i] = v;
        s += v; ss += v * v;
    }
    for (int o = 16; o > 0; o >>= 1) { s += __shfl_down_sync(~0u, s, o); ss += __shfl_down_sync(~0u, ss, o); }
    int wid = threadIdx.x >> 5, lid = threadIdx.x & 31;
    if (lid == 0) { red[wid] = s; red[wid + 32] = ss; }
    __syncthreads();
    if (threadIdx.x == 0) {
        float t = 0.f, tt = 0.f;
        int nw = blockDim.x >> 5;
        for (int i = 0; i < nw; i++) { t += red[i]; tt += red[i + 32]; }
        float mean = t / Cdim, var = tt / Cdim - mean * mean;
        rs[0] = mean; rs[1] = rsqrtf(var + 1e-5f);
    }
    __syncthreads();
    float mean = rs[0], inv = rs[1];
    for (int i = threadIdx.x; i < Cdim; i += blockDim.x)
        oh[(size_t)row * Cdim + i] = __float2half((buf[i] - mean) * inv * g[i] + b[i]);
}

// ===== bf16x3 GEMM (qkv, proj) — BK=32, 3-stage, single barrier, 2 CTAs/SM =====
#define ASTR3 40
#define BSTR3 136
#define A3_ST (2*128*ASTR3)
#define B3_ST (2*32*BSTR3)
#define GEMM3_SMEM (3*(A3_ST + B3_ST) * 2)  // 113664

template<int EP>
__global__ __launch_bounds__(256, 2)
void mma_gemm3(const __nv_bfloat16* __restrict__ Ah, const __nv_bfloat16* __restrict__ Al,
               const __nv_bfloat16* __restrict__ Bh, const __nv_bfloat16* __restrict__ Bl,
               const float* __restrict__ bias,
               float* __restrict__ Cf, int M, int N, int K) {
    extern __shared__ __nv_bfloat16 sm3[];
    __nv_bfloat16* Asm = sm3;
    __nv_bfloat16* Bsm = sm3 + 3 * A3_ST;

    int tid = threadIdx.x;
    int warp = tid >> 5, lane = tid & 31;
    int wm = warp & 1, wn = warp >> 1;
    int rowBase = blockIdx.y * 128, colBase = blockIdx.x * 128;

    const int KT = (K + 31) >> 5;
    float acc[4][4][4];
    #pragma unroll
    for (int i = 0; i < 4; i++)
        #pragma unroll
        for (int j = 0; j < 4; j++)
            #pragma unroll
            for (int q = 0; q < 4; q++) acc[i][j][q] = 0.f;

    auto load_stage = [&](int st, int kt) {
        int koff = kt * 32;
        __nv_bfloat16* Ast = Asm + st * A3_ST;
        __nv_bfloat16* Bst = Bsm + st * B3_ST;
        #pragma unroll
        for (int part = 0; part < 2; part++) {
            const __nv_bfloat16* Aasrc = part ? Al : Ah;
            #pragma unroll
            for (int i = 0; i < 2; i++) {
                int chunk = i * 256 + tid;
                int r = chunk >> 2, cc = (chunk & 3) * 8;
                int k = koff + cc;
                uint32_t dst = smem_u32(Ast + part * (128 * ASTR3) + r * ASTR3 + cc);
                const __nv_bfloat16* src = Aasrc + (size_t)(rowBase + r) * K + (k < K ? k : 0);
                CP_ASYNC16(dst, src, (k < K) ? 16 : 0);
            }
        }
        #pragma unroll
        for (int part = 0; part < 2; part++) {
            const __nv_bfloat16* Bbsrc = part ? Bl : Bh;
            #pragma unroll
            for (int i = 0; i < 2; i++) {
                int chunk = i * 256 + tid;
                int r = chunk >> 4, cc = (chunk & 15) * 8;
                int k = koff + r, n = colBase + cc;
                bool ok = (k < K) && (n < N);
                uint32_t dst = smem_u32(Bst + part * (32 * BSTR3) + r * BSTR3 + cc);
                const __nv_bfloat16* src = Bbsrc + (ok ? ((size_t)k * N + n) : 0);
                CP_ASYNC16(dst, src, ok ? 16 : 0);
            }
        }
    };

    load_stage(0, 0); CP_COMMIT();
    if (KT > 1) { load_stage(1, 1); }
    CP_COMMIT();

    int lrow = lane & 15, lhalf = (lane >> 4) * 8;

    for (int kt = 0; kt < KT; kt++) {
        if (kt + 1 < KT) { asm volatile("cp.async.wait_group 1;"); }
        else             { asm volatile("cp.async.wait_group 0;"); }
        __syncthreads();
        // issue next load into buffer (kt+2)%3 == (kt-1)%3 — safe: all warps passed iter kt-1
        if (kt + 2 < KT) { load_stage((kt + 2) % 3, kt + 2); CP_COMMIT(); }

        int st = kt % 3;
        __nv_bfloat16* Ast = Asm + st * A3_ST;
        __nv_bfloat16* Bst = Bsm + st * B3_ST;

        #pragma unroll
        for (int kk = 0; kk < 32; kk += 16) {
            uint32_t ah[4][4], bh[4][2], bl[4][2];
            #pragma unroll
            for (int mi = 0; mi < 4; mi++) {
                uint32_t a0 = smem_u32(Ast + (wm * 64 + mi * 16 + lrow) * ASTR3 + kk + lhalf);
                LDSM4(ah[mi][0], ah[mi][1], ah[mi][2], ah[mi][3], a0);
            }
            #pragma unroll
            for (int pr = 0; pr < 2; pr++) {
                uint32_t r0, r1, r2, r3;
                uint32_t b0 = smem_u32(Bst + (kk + lrow) * BSTR3 + wn * 32 + pr * 16 + lhalf);
                LDSM4T(r0, r1, r2, r3, b0);
                bh[pr * 2][0] = r0; bh[pr * 2][1] = r1; bh[pr * 2 + 1][0] = r2; bh[pr * 2 + 1][1] = r3;
                uint32_t b1 = smem_u32(Bst + 32 * BSTR3 + (kk + lrow) * BSTR3 + wn * 32 + pr * 16 + lhalf);
                LDSM4T(r0, r1, r2, r3, b1);
                bl[pr * 2][0] = r0; bl[pr * 2][1] = r1; bl[pr * 2 + 1][0] = r2; bl[pr * 2 + 1][1] = r3;
            }
            #pragma unroll
            for (int mi = 0; mi < 4; mi++)
                #pragma unroll
                for (int ni = 0; ni < 4; ni++) {
                    MMA_BF16(acc[mi][ni], ah[mi], bh[ni]);
                    MMA_BF16(acc[mi][ni], ah[mi], bl[ni]);
                }
            uint32_t al[4][4];
            #pragma unroll
            for (int mi = 0; mi < 4; mi++) {
                uint32_t a1 = smem_u32(Ast + 128 * ASTR3 + (wm * 64 + mi * 16 + lrow) * ASTR3 + kk + lhalf);
                LDSM4(al[mi][0], al[mi][1], al[mi][2], al[mi][3], a1);
            }
            #pragma unroll
            for (int mi = 0; mi < 4; mi++)
                #pragma unroll
                for (int ni = 0; ni < 4; ni++)
                    MMA_BF16(acc[mi][ni], al[mi], bh[ni]);
        }
    }

    #pragma unroll
    for (int mi = 0; mi < 4; mi++) {
        int r0 = rowBase + wm * 64 + mi * 16 + (lane >> 2);
        #pragma unroll
        for (int ni = 0; ni < 4; ni++) {
            int c0 = colBase + wn * 32 + ni * 8 + (lane & 3) * 2;
            #pragma unroll
            for (int q = 0; q < 4; q++) {
                int r = r0 + (q >> 1) * 8;
                int c = c0 + (q & 1);
                if (c < N) {
                    float v = acc[mi][ni][q];
                    if (EP >= 1) v += bias[c];
                    Cf[(size_t)r * N + c] = v;
                }
            }
        }
    }
}

// ===== fp16 single-term GEMM (fc1, fc2) — BK=32, 3-stage, single barrier, 2 CTAs/SM =====
#define ASTR2 40
#define BSTR2 136
#define A2_ST (128*ASTR2)
#define B2_ST (32*BSTR2)
#define GEMM2_SMEM (3*(A2_ST + B2_ST) * 2)  // 56832

template<int EP>
__global__ __launch_bounds__(256, 2)
void mma_gemm2(const __half* __restrict__ A, const __half* __restrict__ B,
               const float* __restrict__ bias, const float* __restrict__ res,
               float* __restrict__ Cf, __half* __restrict__ Ch,
               int M, int N, int K) {
    extern __shared__ __half sm2[];
    __half* Asm = sm2;
    __half* Bsm = sm2 + 3 * A2_ST;

    int tid = threadIdx.x;
    int warp = tid >> 5, lane = tid & 31;
    int wm = warp & 1, wn = warp >> 1;
    int rowBase = blockIdx.y * 128, colBase = blockIdx.x * 128;

    const int KT = (K + 31) >> 5;
    float acc[4][4][4];
    #pragma unroll
    for (int i = 0; i < 4; i++)
        #pragma unroll
        for (int j = 0; j < 4; j++)
            #pragma unroll
            for (int q = 0; q < 4; q++) acc[i][j][q] = 0.f;

    auto load_stage = [&](int st, int kt) {
        int koff = kt * 32;
        __half* Ast = Asm + st * A2_ST;
        __half* Bst = Bsm + st * B2_ST;
        #pragma unroll
        for (int i = 0; i < 2; i++) {
            int chunk = i * 256 + tid;
            int r = chunk >> 2, cc = (chunk & 3) * 8;
            int k = koff + cc;
            uint32_t dst = smem_u32(Ast + r * ASTR2 + cc);
            const __half* src = A + (size_t)(rowBase + r) * K + (k < K ? k : 0);
            CP_ASYNC16(dst, src, (k < K) ? 16 : 0);
        }
        #pragma unroll
        for (int i = 0; i < 2; i++) {
            int chunk = i * 256 + tid;
            int r = chunk >> 4, cc = (chunk & 15) * 8;
            int k = koff + r, n = colBase + cc;
            bool ok = (k < K) && (n < N);
            uint32_t dst = smem_u32(Bst + r * BSTR2 + cc);
            const __half* src = B + (ok ? ((size_t)k * N + n) : 0);
            CP_ASYNC16(dst, src, ok ? 16 : 0);
        }
    };

    load_stage(0, 0); CP_COMMIT();
    if (KT > 1) { load_stage(1, 1); }
    CP_COMMIT();

    int lrow = lane & 15, lhalf = (lane >> 4) * 8;

    for (int kt = 0; kt < KT; kt++) {
        if (kt + 1 < KT) { asm volatile("cp.async.wait_group 1;"); }
        else             { asm volatile("cp.async.wait_group 0;"); }
        __syncthreads();
        if (kt + 2 < KT) { load_stage((kt + 2) % 3, kt + 2); CP_COMMIT(); }

        int st = kt % 3;
        __half* Ast = Asm + st * A2_ST;
        __half* Bst = Bsm + st * B2_ST;

        #pragma unroll
        for (int kk = 0; kk < 32; kk += 16) {
            uint32_t a[4][4], bb[4][2];
            #pragma unroll
            for (int mi = 0; mi < 4; mi++) {
                uint32_t a0 = smem_u32(Ast + (wm * 64 + mi * 16 + lrow) * ASTR2 + kk + lhalf);
                LDSM4(a[mi][0], a[mi][1], a[mi][2], a[mi][3], a0);
            }
            #pragma unroll
            for (int pr = 0; pr < 2; pr++) {
                uint32_t r0, r1, r2, r3;
                uint32_t b0 = smem_u32(Bst + (kk + lrow) * BSTR2 + wn * 32 + pr * 16 + lhalf);
                LDSM4T(r0, r1, r2, r3, b0);
                bb[pr * 2][0] = r0; bb[pr * 2][1] = r1; bb[pr * 2 + 1][0] = r2; bb[pr * 2 + 1][1] = r3;
            }
            #pragma unroll
            for (int mi = 0; mi < 4; mi++)
                #pragma unroll
                for (int ni = 0; ni < 4; ni++)
                    MMA_FP16(acc[mi][ni], a[mi], bb[ni]);
        }
    }

    #pragma unroll
    for (int mi = 0; mi < 4; mi++) {
        int r0 = rowBase + wm * 64 + mi * 16 + (lane >> 2);
        #pragma unroll
        for (int ni = 0; ni < 4; ni++) {
            int c0 = colBase + wn * 32 + ni * 8 + (lane & 3) * 2;
            #pragma unroll
            for (int q = 0; q < 4; q++) {
                int r = r0 + (q >> 1) * 8;
                int c = c0 + (q & 1);
                if (c < N) {
                    float v = acc[mi][ni][q] + bias[c];
                    size_t o = (size_t)r * N + c;
                    if (EP == 2) {
                        v = 0.5f * v * (1.0f + erff(v * 0.70710678118654752440f));
                        Ch[o] = __float2half(v);
                    } else {
                        v += res[o];
                        Cf[o] = v;
                    }
                }
            }
        }
    }
}

// ---------------- MHA (register-tiled) -> att bf16 split ----------------
#define MHA_SMEM ((3*64*HDP + 64*64)*4)
__global__ void mha_kernel(const float* __restrict__ qkv,
                           __nv_bfloat16* __restrict__ ahi, __nv_bfloat16* __restrict__ alo) {
    extern __shared__ float smf[];
    float* Q  = smf;
    float* Kx = Q + 64 * HDP;
    float* V  = Kx + 64 * HDP;
    float* SC = V + 64 * HDP;
    int h = blockIdx.x, b = blockIdx.y;
    int tid = threadIdx.x;
    const float* base = qkv + (size_t)(b * NTOK) * (3 * Cdim);
    for (int e = tid; e < 64 * HD; e += 256) {
        int t = e / HD, d = e % HD;
        Q[t * HDP + d]  = base[(size_t)t * (3 * Cdim) + h * HD + d];
        Kx[t * HDP + d] = base[(size_t)t * (3 * Cdim) + Cdim + h * HD + d];
        V[t * HDP + d]  = base[(size_t)t * (3 * Cdim) + 2 * Cdim + h * HD + d];
    }
    __syncthreads();
    const float scale = rsqrtf((float)HD);
    {
        int ti = tid >> 4, tj = tid & 15;
        float acc[4][4] = {};
        #pragma unroll 2
        for (int d = 0; d < HD; d++) {
            float qv[4], kv[4];
            #pragma unroll
            for (int r2 = 0; r2 < 4; r2++) qv[r2] = Q[(ti * 4 + r2) * HDP + d];
            #pragma unroll
            for (int c2 = 0; c2 < 4; c2++) kv[c2] = Kx[(tj * 4 + c2) * HDP + d];
            #pragma unroll
            for (int r2 = 0; r2 < 4; r2++)
                #pragma unroll
                for (int c2 = 0; c2 < 4; c2++) acc[r2][c2] += qv[r2] * kv[c2];
        }
        #pragma unroll
        for (int r2 = 0; r2 < 4; r2++)
            #pragma unroll
            for (int c2 = 0; c2 < 4; c2++)
                SC[(ti * 4 + r2) * 64 + tj * 4 + c2] = acc[r2][c2] * scale;
    }
    __syncthreads();
    if (tid < 64) {
        float* row = SC + tid * 64;
        float mx = -1e30f;
        for (int j = 0; j < 64; j++) mx = fmaxf(mx, row[j]);
        float s = 0.f;
        for (int j = 0; j < 64; j++) { float e = expf(row[j] - mx); row[j] = e; s += e; }
        float inv = 1.f / s;
        for (int j = 0; j < 64; j++) row[j] *= inv;
    }
    __syncthreads();
    {
        int ti = tid >> 4, td = tid & 15;
        if (td < 14) {
            float oacc[4][7] = {};
            for (int j = 0; j < 64; j++) {
                float pr[4], vv[7];
                #pragma unroll
                for (int r2 = 0; r2 < 4; r2++) pr[r2] = SC[(ti * 4 + r2) * 64 + j];
                #pragma unroll
                for (int c2 = 0; c2 < 7; c2++) vv[c2] = V[j * HDP + td * 7 + c2];
                #pragma unroll
                for (int r2 = 0; r2 < 4; r2++)
                    #pragma unroll
                    for (int c2 = 0; c2 < 7; c2++) oacc[r2][c2] += pr[r2] * vv[c2];
            }
            #pragma unroll
            for (int r2 = 0; r2 < 4; r2++)
                #pragma unroll
                for (int c2 = 0; c2 < 7; c2++)
                    split_write_bf(oacc[r2][c2], ahi, alo,
                        ((size_t)(b * NTOK + ti * 4 + r2)) * Cdim + h * HD + td * 7 + c2);
        }
    }
}

// ---------------- BiFormer ----------------
#define BFQ_SMEM ((64*28 + 192*64)*4)  // 56320
__global__ void bf_qkv_kernel(const float* __restrict__ o,
                              const float* __restrict__ w, const float* __restrict__ bias) {
    extern __shared__ float bq[];
    float* xin = bq;             // [64][28]
    float* ws  = bq + 64 * 28;   // [192][64]
    int y = blockIdx.x, b = blockIdx.y;
    int tid = threadIdx.x;
    for (int e = tid; e < 192 * 64; e += 256) ws[e] = w[e];
    for (int e = tid; e < 64 * 28; e += 256) {
        int c = e / 28, xx = e % 28;
        xin[e] = o[((size_t)b * 64 + c) * 784 + y * 28 + xx];
    }
    __syncthreads();
    for (int e = tid; e < 192 * 28; e += 256) {
        int oc = e / 28, xx = e % 28;
        float a = bias[oc];
        const float* wr = ws + oc * 64;
        #pragma unroll 16
        for (int c = 0; c < 64; c++) a += xin[c * 28 + xx] * wr[c];
        g_bfqkv[((size_t)b * 192 + oc) * 784 + y * 28 + xx] = a;
    }
}

// fused region pooling + routing top-4 (one block per batch)
__global__ void bf_routing_kernel() {
    int b = blockIdx.x;
    int tid = threadIdx.x;  // 256
    __shared__ float qr[64][NREG];
    __shared__ float kr[64][NREG];
    __shared__ float ar[NREG][NREG];
    for (int e = tid; e < 64 * NREG; e += 256) {
        int c = e / NREG, r = e % NREG;
        int rh = r / 7, rw = r % 7;
        float sq = 0.f, sk = 0.f;
        const float* qc = g_bfqkv + ((size_t)b * 192 + c) * 784;
        const float* kc = g_bfqkv + ((size_t)b * 192 + 64 + c) * 784;
        #pragma unroll
        for (int pr = 0; pr < 4; pr++)
            #pragma unroll
            for (int pc = 0; pc < 4; pc++) {
                int s = (rh * 4 + pr) * 28 + rw * 4 + pc;
                sq += qc[s]; sk += kc[s];
            }
        qr[c][r] = sq * 0.0625f;
        kr[c][r] = sk * 0.0625f;
    }
    __syncthreads();
    for (int e = tid; e < NREG * NREG; e += 256) {
        int i = e / NREG, j = e % NREG;
        float a = 0.f;
        #pragma unroll 16
        for (int c = 0; c < 64; c++) a += qr[c][i] * kr[c][j];
        ar[i][j] = a;
    }
    __syncthreads();
    if (tid < NREG) {
        float* row = ar[tid];
        #pragma unroll
        for (int j = 0; j < TOPK; j++) {
            float mx = -1e30f; int mi = 0;
            for (int s = 0; s < NREG; s++) if (row[s] > mx) { mx = row[s]; mi = s; }
            row[mi] = -1e30f;
            g_idx[(b * NREG + tid) * TOPK + j] = mi;
        }
    }
}

__global__ void bf_attn_kernel() {
    int r = blockIdx.x, h = blockIdx.y, b = blockIdx.z;
    __shared__ float q[16][8], kg[64][9], vg[64][9];
    __shared__ float sc[16][65];
    __shared__ int idx4[4];
    int tid = threadIdx.x;  // 128
    if (tid < 4) idx4[tid] = g_idx[(b * NREG + r) * TOPK + tid];
    int rh = r / 7, rw = r % 7;
    {
        int p = tid / 8, d = tid % 8;
        int s = (rh * 4 + p / 4) * 28 + rw * 4 + (p % 4);
        q[p][d] = g_bfqkv[((size_t)b * 192 + h * 8 + d) * 784 + s] * 0.125f;
    }
    __syncthreads();
    for (int e = tid; e < 512; e += 128) {
        int t = e / 8, d = e % 8;
        int reg = idx4[t / 16];
        int p2 = t % 16;
        int s = ((reg / 7) * 4 + p2 / 4) * 28 + (reg % 7) * 4 + (p2 % 4);
        kg[t][d] = g_bfqkv[((size_t)b * 192 + 64 + h * 8 + d) * 784 + s];
        vg[t][d] = g_bfqkv[((size_t)b * 192 + 128 + h * 8 + d) * 784 + s];
    }
    __syncthreads();
    {
        int p = tid >> 3, tg = tid & 7;
        float qreg[8];
        #pragma unroll
        for (int d = 0; d < 8; d++) qreg[d] = q[p][d];
        #pragma unroll
        for (int tt = 0; tt < 8; tt++) {
            int t = tt * 8 + tg;
            float a = 0.f;
            #pragma unroll
            for (int d = 0; d < 8; d++) a += qreg[d] * kg[t][d];
            sc[p][t] = a;
        }
    }
    __syncthreads();
    if (tid < 16) {
        float mx = -1e30f;
        for (int t = 0; t < 64; t++) mx = fmaxf(mx, sc[tid][t]);
        float s = 0.f;
        for (int t = 0; t < 64; t++) { float e = expf(sc[tid][t] - mx); sc[tid][t] = e; s += e; }
        float inv = 1.f / s;
        for (int t = 0; t < 64; t++) sc[tid][t] *= inv;
    }
    __syncthreads();
    {
        int p = tid / 8, d = tid % 8;
        float a = 0.f;
        #pragma unroll 8
        for (int t = 0; t < 64; t++) a += sc[p][t] * vg[t][d];
        int s = (rh * 4 + p / 4) * 28 + rw * 4 + (p % 4);
        g_attg[((size_t)b * 64 + h * 8 + d) * 784 + s] = a;
    }
}

__global__ void bf_out_kernel(const float* __restrict__ lepe_w, const float* __restrict__ lepe_b,
                              const float* __restrict__ out_w, const float* __restrict__ out_b,
                              float* __restrict__ outp) {
    int y = blockIdx.x, b = blockIdx.y;
    __shared__ float v3[3][64][28];
    __shared__ float tmp[64][28];
    __shared__ float ws[64][64];
    __shared__ float lw[64][9];
    int tid = threadIdx.x;
    for (int e = tid; e < 64 * 64; e += blockDim.x) ws[e >> 6][e & 63] = out_w[e];
    for (int e = tid; e < 64 * 9; e += blockDim.x) lw[e / 9][e % 9] = lepe_w[e];
    for (int ry = 0; ry < 3; ry++) {
        int yy = y + ry - 1;
        for (int e = tid; e < 64 * 28; e += blockDim.x) {
            int c = e / 28, xx = e % 28;
            v3[ry][c][xx] = (yy >= 0 && yy < 28)
                ? g_bfqkv[((size_t)b * 192 + 128 + c) * 784 + yy * 28 + xx] : 0.f;
        }
    }
    __syncthreads();
    for (int e = tid; e < 64 * 28; e += blockDim.x) {
        int c = e / 28, xx = e % 28;
        float a = g_attg[((size_t)b * 64 + c) * 784 + y * 28 + xx] + lepe_b[c];
        #pragma unroll
        for (int ky = 0; ky < 3; ky++)
            #pragma unroll
            for (int kx = 0; kx < 3; kx++) {
                int xx2 = xx + kx - 1;
                if (xx2 >= 0 && xx2 < 28) a += v3[ky][c][xx2] * lw[c][ky * 3 + kx];
            }
        tmp[c][xx] = a;
    }
    __syncthreads();
    for (int e = tid; e < 64 * 28; e += blockDim.x) {
        int oc = e / 28, xx = e % 28;
        float a = out_b[oc];
        const float* wr = ws[oc];
        #pragma unroll 16
        for (int c = 0; c < 64; c++) a += tmp[c][xx] * wr[c];
        outp[((size_t)b * 64 + oc) * 784 + y * 28 + xx] = a;
    }
}

// ---------------- launch ----------------
extern "C" void kernel_launch(void* const* d_in, const int* in_sizes, int n_in,
                              void* d_out, int out_size) {
    (void)in_sizes; (void)n_in; (void)out_size;
    const float* x        = (const float*)d_in[0];
    const float* norm1_g  = (const float*)d_in[1];
    const float* norm1_b  = (const float*)d_in[2];
    const float* qkv_w    = (const float*)d_in[3];
    const float* proj_w   = (const float*)d_in[4];
    const float* proj_b   = (const float*)d_in[5];
    const float* norm2_g  = (const float*)d_in[6];
    const float* norm2_b  = (const float*)d_in[7];
    const float* fc1_w    = (const float*)d_in[8];
    const float* fc1_b    = (const float*)d_in[9];
    const float* fc2_w    = (const float*)d_in[10];
    const float* fc2_b    = (const float*)d_in[11];
    const float* bf_qkv_w = (const float*)d_in[12];
    const float* bf_qkv_b = (const float*)d_in[13];
    const float* bf_lepe_w= (const float*)d_in[14];
    const float* bf_lepe_b= (const float*)d_in[15];
    const float* bf_out_w = (const float*)d_in[16];
    const float* bf_out_b = (const float*)d_in[17];
    float* out = (float*)d_out;

    __nv_bfloat16 *p_h_hi, *p_h_lo, *p_att_hi, *p_att_lo;
    __nv_bfloat16 *p_wqkv_hi, *p_wqkv_lo, *p_wproj_hi, *p_wproj_lo;
    __half *p_h2, *p_hid, *p_wfc1, *p_wfc2;
    float *p_qkv, *p_o, *p_xr;
    cudaGetSymbolAddress((void**)&p_h_hi, g_h_hi);     cudaGetSymbolAddress((void**)&p_h_lo, g_h_lo);
    cudaGetSymbolAddress((void**)&p_att_hi, g_att_hi); cudaGetSymbolAddress((void**)&p_att_lo, g_att_lo);
    cudaGetSymbolAddress((void**)&p_h2, g_h2);
    cudaGetSymbolAddress((void**)&p_hid, g_hid);
    cudaGetSymbolAddress((void**)&p_wqkv_hi, g_wqkv_hi);   cudaGetSymbolAddress((void**)&p_wqkv_lo, g_wqkv_lo);
    cudaGetSymbolAddress((void**)&p_wproj_hi, g_wproj_hi); cudaGetSymbolAddress((void**)&p_wproj_lo, g_wproj_lo);
    cudaGetSymbolAddress((void**)&p_wfc1, g_wfc1);
    cudaGetSymbolAddress((void**)&p_wfc2, g_wfc2);
    cudaGetSymbolAddress((void**)&p_qkv, g_qkv);
    cudaGetSymbolAddress((void**)&p_o, g_o);
    cudaGetSymbolAddress((void**)&p_xr, g_xr);

    cudaFuncSetAttribute(mha_kernel, cudaFuncAttributeMaxDynamicSharedMemorySize, MHA_SMEM);
    cudaFuncSetAttribute(bf_qkv_kernel, cudaFuncAttributeMaxDynamicSharedMemorySize, BFQ_SMEM);
    cudaFuncSetAttribute(mma_gemm3<0>, cudaFuncAttributeMaxDynamicSharedMemorySize, GEMM3_SMEM);
    cudaFuncSetAttribute(mma_gemm3<1>, cudaFuncAttributeMaxDynamicSharedMemorySize, GEMM3_SMEM);
    cudaFuncSetAttribute(mma_gemm2<2>, cudaFuncAttributeMaxDynamicSharedMemorySize, GEMM2_SMEM);
    cudaFuncSetAttribute(mma_gemm2<3>, cudaFuncAttributeMaxDynamicSharedMemorySize, GEMM2_SMEM);

    // one-time stream/event creation (host resources only; no device allocations)
    static cudaStream_t s1 = nullptr;
    static cudaEvent_t eFork = nullptr, eW = nullptr, eO = nullptr, eBF = nullptr;
    if (!s1) {
        cudaStreamCreateWithFlags(&s1, cudaStreamNonBlocking);
        cudaEventCreateWithFlags(&eFork, cudaEventDisableTiming);
        cudaEventCreateWithFlags(&eW,    cudaEventDisableTiming);
        cudaEventCreateWithFlags(&eO,    cudaEventDisableTiming);
        cudaEventCreateWithFlags(&eBF,   cudaEventDisableTiming);
    }

    // fork
    cudaEventRecord(eFork, 0);
    cudaStreamWaitEvent(s1, eFork, 0);

    // s1: proj/fc weight prep (overlap with LN1 + qkv GEMM on s0)
    split_bf_kernel<<<(Cdim * Cdim + 255) / 256, 256, 0, s1>>>(proj_w, p_wproj_hi, p_wproj_lo, Cdim * Cdim);
    conv_fp_kernel<<<(Cdim * HID + 255) / 256, 256, 0, s1>>>(fc1_w, p_wfc1, Cdim * HID);
    conv_fp_kernel<<<(HID * Cdim + 255) / 256, 256, 0, s1>>>(fc2_w, p_wfc2, HID * Cdim);
    cudaEventRecord(eW, s1);

    // s0: qkv weight split + LN1 + qkv GEMM + MHA
    split_bf_kernel<<<(Cdim * 3 * Cdim + 255) / 256, 256>>>(qkv_w, p_wqkv_hi, p_wqkv_lo, Cdim * 3 * Cdim);
    ln_kernel<<<ROWS, 256>>>(x, norm1_g, norm1_b, p_h_hi, p_h_lo);
    mma_gemm3<0><<<dim3((3 * Cdim + 127) / 128, ROWS / 128), 256, GEMM3_SMEM>>>(
        p_h_hi, p_h_lo, p_wqkv_hi, p_wqkv_lo, nullptr,
        p_qkv, ROWS, 3 * Cdim, Cdim);
    mha_kernel<<<dim3(NHd, Bsz), 256, MHA_SMEM>>>(p_qkv, p_att_hi, p_att_lo);
    cudaStreamWaitEvent(0, eW, 0);
    mma_gemm3<1><<<dim3((Cdim + 127) / 128, ROWS / 128), 256, GEMM3_SMEM>>>(
        p_att_hi, p_att_lo, p_wproj_hi, p_wproj_lo, proj_b,
        p_o, ROWS, Cdim, Cdim);
    cudaEventRecord(eO, 0);

    // s1: BiFormer branch
    cudaStreamWaitEvent(s1, eO, 0);
    bf_qkv_kernel<<<dim3(28, Bsz), 256, BFQ_SMEM, s1>>>(p_o, bf_qkv_w, bf_qkv_b);
    bf_routing_kernel<<<Bsz, 256, 0, s1>>>();
    bf_attn_kernel<<<dim3(NREG, 8, Bsz), 128, 0, s1>>>();
    bf_out_kernel<<<dim3(28, Bsz), 256, 0, s1>>>(bf_lepe_w, bf_lepe_b, bf_out_w, bf_out_b, out + OUT_OFF);
    cudaEventRecord(eBF, s1);

    // s0: MLP branch
    ln2_kernel<<<ROWS, 256>>>(p_o, x, norm2_g, norm2_b, p_xr, p_h2);
    mma_gemm2<2><<<dim3((HID + 127) / 128, ROWS / 128), 256, GEMM2_SMEM>>>(
        p_h2, p_wfc1, fc1_b, nullptr,
        nullptr, p_hid, ROWS, HID, Cdim);
    mma_gemm2<3><<<dim3((Cdim + 127) / 128, ROWS / 128), 256, GEMM2_SMEM>>>(
        p_hid, p_wfc2, fc2_b, p_xr,
        out, nullptr, ROWS, Cdim, HID);

    // join
    cudaStreamWaitEvent(0, eBF, 0);
}

// round 14
// speedup vs baseline: 2.1912x; 1.0347x over previous
#include <cuda_runtime.h>
#include <cuda_bf16.h>
#include <cuda_fp16.h>
#include <math.h>
#include <stdint.h>

// ---------------- problem constants ----------------
#define Bsz   128
#define NTOK  64
#define Cdim  784
#define NHd   8
#define HD    98
#define HDP   99
#define HID   3136
#define ROWS  (Bsz*NTOK)  // 8192
#define NREG  49
#define TOPK  4
#define OUT_OFF (Bsz*NTOK*Cdim)

// ---------------- scratch ----------------
__device__ __nv_bfloat16 g_h_hi [ROWS*Cdim];
__device__ __nv_bfloat16 g_h_lo [ROWS*Cdim];
__device__ float         g_qkv  [ROWS*3*Cdim];
__device__ __nv_bfloat16 g_att_hi[ROWS*Cdim];
__device__ __nv_bfloat16 g_att_lo[ROWS*Cdim];
__device__ float         g_o    [ROWS*Cdim];
__device__ float         g_xr   [ROWS*Cdim];
__device__ __half        g_h2   [ROWS*Cdim];
__device__ __half        g_hid  [ROWS*HID];
// weight splits [K, N]
__device__ __nv_bfloat16 g_wqkv_hi[Cdim*3*Cdim];
__device__ __nv_bfloat16 g_wqkv_lo[Cdim*3*Cdim];
__device__ __nv_bfloat16 g_wproj_hi[Cdim*Cdim];
__device__ __nv_bfloat16 g_wproj_lo[Cdim*Cdim];
__device__ __half        g_wfc1 [Cdim*HID];
__device__ __half        g_wfc2 [HID*Cdim];
// biformer
__device__ float g_bfqkv[Bsz*192*784];
__device__ float g_attg [Bsz*64*784];
__device__ int   g_idx [Bsz*NREG*TOPK];

// ---------------- helpers ----------------
__device__ __forceinline__ uint32_t smem_u32(const void* p) {
    return (uint32_t)__cvta_generic_to_shared(p);
}
#define CP_ASYNC16(dst_u32, src, sz) \
    asm volatile("cp.async.cg.shared.global [%0], [%1], 16, %2;\n" :: "r"(dst_u32), "l"(src), "r"(sz))
#define CP_COMMIT() asm volatile("cp.async.commit_group;\n")
#define LDSM4(r0,r1,r2,r3,a) \
    asm volatile("ldmatrix.sync.aligned.m8n8.x4.shared.b16 {%0,%1,%2,%3},[%4];" \
        : "=r"(r0),"=r"(r1),"=r"(r2),"=r"(r3) : "r"(a))
#define LDSM4T(r0,r1,r2,r3,a) \
    asm volatile("ldmatrix.sync.aligned.m8n8.x4.trans.shared.b16 {%0,%1,%2,%3},[%4];" \
        : "=r"(r0),"=r"(r1),"=r"(r2),"=r"(r3) : "r"(a))
#define MMA_BF16(d, a, b) \
    asm volatile("mma.sync.aligned.m16n8k16.row.col.f32.bf16.bf16.f32 " \
        "{%0,%1,%2,%3},{%4,%5,%6,%7},{%8,%9},{%0,%1,%2,%3};" \
        : "+f"(d[0]),"+f"(d[1]),"+f"(d[2]),"+f"(d[3]) \
        : "r"(a[0]),"r"(a[1]),"r"(a[2]),"r"(a[3]),"r"(b[0]),"r"(b[1]))
#define MMA_FP16(d, a, b) \
    asm volatile("mma.sync.aligned.m16n8k16.row.col.f32.f16.f16.f32 " \
        "{%0,%1,%2,%3},{%4,%5,%6,%7},{%8,%9},{%0,%1,%2,%3};" \
        : "+f"(d[0]),"+f"(d[1]),"+f"(d[2]),"+f"(d[3]) \
        : "r"(a[0]),"r"(a[1]),"r"(a[2]),"r"(a[3]),"r"(b[0]),"r"(b[1]))

__device__ __forceinline__ void split_write_bf(float v, __nv_bfloat16* hi, __nv_bfloat16* lo, size_t o) {
    __nv_bfloat16 h = __float2bfloat16(v);
    hi[o] = h;
    lo[o] = __float2bfloat16(v - __bfloat162float(h));
}

// ---------------- weight prep (float4 vectorized) ----------------
__global__ void split_bf_kernel(const float* __restrict__ in, __nv_bfloat16* __restrict__ hi,
                                __nv_bfloat16* __restrict__ lo, int n4) {
    int i = blockIdx.x * blockDim.x + threadIdx.x;
    if (i < n4) {
        float4 v = ((const float4*)in)[i];
        __nv_bfloat16 h0 = __float2bfloat16(v.x), h1 = __float2bfloat16(v.y);
        __nv_bfloat16 h2 = __float2bfloat16(v.z), h3 = __float2bfloat16(v.w);
        ((__nv_bfloat162*)hi)[i * 2]     = __nv_bfloat162(h0, h1);
        ((__nv_bfloat162*)hi)[i * 2 + 1] = __nv_bfloat162(h2, h3);
        ((__nv_bfloat162*)lo)[i * 2]     = __nv_bfloat162(
            __float2bfloat16(v.x - __bfloat162float(h0)), __float2bfloat16(v.y - __bfloat162float(h1)));
        ((__nv_bfloat162*)lo)[i * 2 + 1] = __nv_bfloat162(
            __float2bfloat16(v.z - __bfloat162float(h2)), __float2bfloat16(v.w - __bfloat162float(h3)));
    }
}
__global__ void conv_fp_kernel(const float* __restrict__ in, __half* __restrict__ o, int n4) {
    int i = blockIdx.x * blockDim.x + threadIdx.x;
    if (i < n4) {
        float4 v = ((const float4*)in)[i];
        ((__half2*)o)[i * 2]     = __floats2half2_rn(v.x, v.y);
        ((__half2*)o)[i * 2 + 1] = __floats2half2_rn(v.z, v.w);
    }
}

// ---------------- LN1: x -> (h_hi, h_lo) bf16 (float4) ----------------
__global__ void ln_kernel(const float* __restrict__ x,
                          const float* __restrict__ g, const float* __restrict__ b,
                          __nv_bfloat16* __restrict__ ohi, __nv_bfloat16* __restrict__ olo) {
    int row = blockIdx.x;
    const float4* xr4 = (const float4*)(x + (size_t)row * Cdim);
    __shared__ float4 buf[Cdim / 4];
    __shared__ float rs[2];
    __shared__ float red[64];
    int tid = threadIdx.x;
    float s = 0.f, ss = 0.f;
    float4 v;
    if (tid < Cdim / 4) {
        v = xr4[tid];
        buf[tid] = v;
        s = v.x + v.y + v.z + v.w;
        ss = v.x * v.x + v.y * v.y + v.z * v.z + v.w * v.w;
    }
    for (int o = 16; o > 0; o >>= 1) { s += __shfl_down_sync(~0u, s, o); ss += __shfl_down_sync(~0u, ss, o); }
    int wid = tid >> 5, lid = tid & 31;
    if (lid == 0) { red[wid] = s; red[wid + 32] = ss; }
    __syncthreads();
    if (tid == 0) {
        float t = 0.f, tt = 0.f;
        int nw = blockDim.x >> 5;
        for (int i = 0; i < nw; i++) { t += red[i]; tt += red[i + 32]; }
        float mean = t / Cdim, var = tt / Cdim - mean * mean;
        rs[0] = mean; rs[1] = rsqrtf(var + 1e-5f);
    }
    __syncthreads();
    float mean = rs[0], inv = rs[1];
    if (tid < Cdim / 4) {
        v = buf[tid];
        float4 gv = ((const float4*)g)[tid];
        float4 bv = ((const float4*)b)[tid];
        float o0 = (v.x - mean) * inv * gv.x + bv.x;
        float o1 = (v.y - mean) * inv * gv.y + bv.y;
        float o2 = (v.z - mean) * inv * gv.z + bv.z;
        float o3 = (v.w - mean) * inv * gv.w + bv.w;
        size_t base2 = ((size_t)row * Cdim) / 2 + tid * 2;
        __nv_bfloat16 h0 = __float2bfloat16(o0), h1 = __float2bfloat16(o1);
        __nv_bfloat16 h2 = __float2bfloat16(o2), h3 = __float2bfloat16(o3);
        ((__nv_bfloat162*)ohi)[base2]     = __nv_bfloat162(h0, h1);
        ((__nv_bfloat162*)ohi)[base2 + 1] = __nv_bfloat162(h2, h3);
        ((__nv_bfloat162*)olo)[base2]     = __nv_bfloat162(
            __float2bfloat16(o0 - __bfloat162float(h0)), __float2bfloat16(o1 - __bfloat162float(h1)));
        ((__nv_bfloat162*)olo)[base2 + 1] = __nv_bfloat162(
            __float2bfloat16(o2 - __bfloat162float(h2)), __float2bfloat16(o3 - __bfloat162float(h3)));
    }
}

// ---------------- LN2: xr = o + x (fp32), h2 fp16 (float4) ----------------
__global__ void ln2_kernel(const float* __restrict__ ov, const float* __restrict__ x,
                           const float* __restrict__ g, const float* __restrict__ b,
                           float* __restrict__ xr_out, __half* __restrict__ oh) {
    int row = blockIdx.x;
    const float4* a4 = (const float4*)(ov + (size_t)row * Cdim);
    const float4* c4 = (const float4*)(x + (size_t)row * Cdim);
    __shared__ float4 buf[Cdim / 4];
    __shared__ float rs[2];
    __shared__ float red[64];
    int tid = threadIdx.x;
    float s = 0.f, ss = 0.f;
    if (tid < Cdim / 4) {
        float4 av = a4[tid], cv = c4[tid];
        float4 v = make_float4(av.x + cv.x, av.y + cv.y, av.z + cv.z, av.w + cv.w);
        buf[tid] = v;
        ((float4*)(xr_out + (size_t)row * Cdim))[tid] = v;
        s = v.x + v.y + v.z + v.w;
        ss = v.x * v.x + v.y * v.y + v.z * v.z + v.w * v.w;
    }
    for (int o = 16; o > 0; o >>= 1) { s += __shfl_down_sync(~0u, s, o); ss += __shfl_down_sync(~0u, ss, o); }
    int wid = tid >> 5, lid = tid & 31;
    if (lid == 0) { red[wid] = s; red[wid + 32] = ss; }
    __syncthreads();
    if (tid == 0) {
        float t = 0.f, tt = 0.f;
        int nw = blockDim.x >> 5;
        for (int i = 0; i < nw; i++) { t += red[i]; tt += red[i + 32]; }
        float mean = t / Cdim, var = tt / Cdim - mean * mean;
        rs[0] = mean; rs[1] = rsqrtf(var + 1e-5f);
    }
    __syncthreads();
    float mean = rs[0], inv = rs[1];
    if (tid < Cdim / 4) {
        float4 v = buf[tid];
        float4 gv = ((const float4*)g)[tid];
        float4 bv = ((const float4*)b)[tid];
        size_t base2 = ((size_t)row * Cdim) / 2 + tid * 2;
        ((__half2*)oh)[base2] = __floats2half2_rn(
            (v.x - mean) * inv * gv.x + bv.x, (v.y - mean) * inv * gv.y + bv.y);
        ((__half2*)oh)[base2 + 1] = __floats2half2_rn(
            (v.z - mean) * inv * gv.z + bv.z, (v.w - mean) * inv * gv.w + bv.w);
    }
}

// ===== bf16x3 GEMM (qkv, proj) — BK=32, 3-stage, single barrier, 2 CTAs/SM =====
#define ASTR3 40
#define BSTR3 136
#define A3_ST (2*128*ASTR3)
#define B3_ST (2*32*BSTR3)
#define GEMM3_SMEM (3*(A3_ST + B3_ST) * 2)  // 113664

template<int EP>
__global__ __launch_bounds__(256, 2)
void mma_gemm3(const __nv_bfloat16* __restrict__ Ah, const __nv_bfloat16* __restrict__ Al,
               const __nv_bfloat16* __restrict__ Bh, const __nv_bfloat16* __restrict__ Bl,
               const float* __restrict__ bias,
               float* __restrict__ Cf, int M, int N, int K) {
    extern __shared__ __nv_bfloat16 sm3[];
    __nv_bfloat16* Asm = sm3;
    __nv_bfloat16* Bsm = sm3 + 3 * A3_ST;

    int tid = threadIdx.x;
    int warp = tid >> 5, lane = tid & 31;
    int wm = warp & 1, wn = warp >> 1;
    int rowBase = blockIdx.y * 128, colBase = blockIdx.x * 128;

    const int KT = (K + 31) >> 5;
    float acc[4][4][4];
    #pragma unroll
    for (int i = 0; i < 4; i++)
        #pragma unroll
        for (int j = 0; j < 4; j++)
            #pragma unroll
            for (int q = 0; q < 4; q++) acc[i][j][q] = 0.f;

    auto load_stage = [&](int st, int kt) {
        int koff = kt * 32;
        __nv_bfloat16* Ast = Asm + st * A3_ST;
        __nv_bfloat16* Bst = Bsm + st * B3_ST;
        #pragma unroll
        for (int part = 0; part < 2; part++) {
            const __nv_bfloat16* Aasrc = part ? Al : Ah;
            #pragma unroll
            for (int i = 0; i < 2; i++) {
                int chunk = i * 256 + tid;
                int r = chunk >> 2, cc = (chunk & 3) * 8;
                int k = koff + cc;
                uint32_t dst = smem_u32(Ast + part * (128 * ASTR3) + r * ASTR3 + cc);
                const __nv_bfloat16* src = Aasrc + (size_t)(rowBase + r) * K + (k < K ? k : 0);
                CP_ASYNC16(dst, src, (k < K) ? 16 : 0);
            }
        }
        #pragma unroll
        for (int part = 0; part < 2; part++) {
            const __nv_bfloat16* Bbsrc = part ? Bl : Bh;
            #pragma unroll
            for (int i = 0; i < 2; i++) {
                int chunk = i * 256 + tid;
                int r = chunk >> 4, cc = (chunk & 15) * 8;
                int k = koff + r, n = colBase + cc;
                bool ok = (k < K) && (n < N);
                uint32_t dst = smem_u32(Bst + part * (32 * BSTR3) + r * BSTR3 + cc);
                const __nv_bfloat16* src = Bbsrc + (ok ? ((size_t)k * N + n) : 0);
                CP_ASYNC16(dst, src, ok ? 16 : 0);
            }
        }
    };

    load_stage(0, 0); CP_COMMIT();
    if (KT > 1) { load_stage(1, 1); }
    CP_COMMIT();

    int lrow = lane & 15, lhalf = (lane >> 4) * 8;

    for (int kt = 0; kt < KT; kt++) {
        if (kt + 1 < KT) { asm volatile("cp.async.wait_group 1;"); }
        else             { asm volatile("cp.async.wait_group 0;"); }
        __syncthreads();
        if (kt + 2 < KT) { load_stage((kt + 2) % 3, kt + 2); CP_COMMIT(); }

        int st = kt % 3;
        __nv_bfloat16* Ast = Asm + st * A3_ST;
        __nv_bfloat16* Bst = Bsm + st * B3_ST;

        #pragma unroll
        for (int kk = 0; kk < 32; kk += 16) {
            uint32_t ah[4][4], bh[4][2], bl[4][2];
            #pragma unroll
            for (int mi = 0; mi < 4; mi++) {
                uint32_t a0 = smem_u32(Ast + (wm * 64 + mi * 16 + lrow) * ASTR3 + kk + lhalf);
                LDSM4(ah[mi][0], ah[mi][1], ah[mi][2], ah[mi][3], a0);
            }
            #pragma unroll
            for (int pr = 0; pr < 2; pr++) {
                uint32_t r0, r1, r2, r3;
                uint32_t b0 = smem_u32(Bst + (kk + lrow) * BSTR3 + wn * 32 + pr * 16 + lhalf);
                LDSM4T(r0, r1, r2, r3, b0);
                bh[pr * 2][0] = r0; bh[pr * 2][1] = r1; bh[pr * 2 + 1][0] = r2; bh[pr * 2 + 1][1] = r3;
                uint32_t b1 = smem_u32(Bst + 32 * BSTR3 + (kk + lrow) * BSTR3 + wn * 32 + pr * 16 + lhalf);
                LDSM4T(r0, r1, r2, r3, b1);
                bl[pr * 2][0] = r0; bl[pr * 2][1] = r1; bl[pr * 2 + 1][0] = r2; bl[pr * 2 + 1][1] = r3;
            }
            #pragma unroll
            for (int mi = 0; mi < 4; mi++)
                #pragma unroll
                for (int ni = 0; ni < 4; ni++) {
                    MMA_BF16(acc[mi][ni], ah[mi], bh[ni]);
                    MMA_BF16(acc[mi][ni], ah[mi], bl[ni]);
                }
            uint32_t al[4][4];
            #pragma unroll
            for (int mi = 0; mi < 4; mi++) {
                uint32_t a1 = smem_u32(Ast + 128 * ASTR3 + (wm * 64 + mi * 16 + lrow) * ASTR3 + kk + lhalf);
                LDSM4(al[mi][0], al[mi][1], al[mi][2], al[mi][3], a1);
            }
            #pragma unroll
            for (int mi = 0; mi < 4; mi++)
                #pragma unroll
                for (int ni = 0; ni < 4; ni++)
                    MMA_BF16(acc[mi][ni], al[mi], bh[ni]);
        }
    }

    #pragma unroll
    for (int mi = 0; mi < 4; mi++) {
        int r0 = rowBase + wm * 64 + mi * 16 + (lane >> 2);
        #pragma unroll
        for (int ni = 0; ni < 4; ni++) {
            int c0 = colBase + wn * 32 + ni * 8 + (lane & 3) * 2;
            #pragma unroll
            for (int q = 0; q < 4; q++) {
                int r = r0 + (q >> 1) * 8;
                int c = c0 + (q & 1);
                if (c < N) {
                    float v = acc[mi][ni][q];
                    if (EP >= 1) v += bias[c];
                    Cf[(size_t)r * N + c] = v;
                }
            }
        }
    }
}

// ===== fp16 single-term GEMM (fc1, fc2) — BK=32, 3-stage, single barrier, 2 CTAs/SM =====
#define ASTR2 40
#define BSTR2 136
#define A2_ST (128*ASTR2)
#define B2_ST (32*BSTR2)
#define GEMM2_SMEM (3*(A2_ST + B2_ST) * 2)  // 56832

template<int EP>
__global__ __launch_bounds__(256, 2)
void mma_gemm2(const __half* __restrict__ A, const __half* __restrict__ B,
               const float* __restrict__ bias, const float* __restrict__ res,
               float* __restrict__ Cf, __half* __restrict__ Ch,
               int M, int N, int K) {
    extern __shared__ __half sm2[];
    __half* Asm = sm2;
    __half* Bsm = sm2 + 3 * A2_ST;

    int tid = threadIdx.x;
    int warp = tid >> 5, lane = tid & 31;
    int wm = warp & 1, wn = warp >> 1;
    int rowBase = blockIdx.y * 128, colBase = blockIdx.x * 128;

    const int KT = (K + 31) >> 5;
    float acc[4][4][4];
    #pragma unroll
    for (int i = 0; i < 4; i++)
        #pragma unroll
        for (int j = 0; j < 4; j++)
            #pragma unroll
            for (int q = 0; q < 4; q++) acc[i][j][q] = 0.f;

    auto load_stage = [&](int st, int kt) {
        int koff = kt * 32;
        __half* Ast = Asm + st * A2_ST;
        __half* Bst = Bsm + st * B2_ST;
        #pragma unroll
        for (int i = 0; i < 2; i++) {
            int chunk = i * 256 + tid;
            int r = chunk >> 2, cc = (chunk & 3) * 8;
            int k = koff + cc;
            uint32_t dst = smem_u32(Ast + r * ASTR2 + cc);
            const __half* src = A + (size_t)(rowBase + r) * K + (k < K ? k : 0);
            CP_ASYNC16(dst, src, (k < K) ? 16 : 0);
        }
        #pragma unroll
        for (int i = 0; i < 2; i++) {
            int chunk = i * 256 + tid;
            int r = chunk >> 4, cc = (chunk & 15) * 8;
            int k = koff + r, n = colBase + cc;
            bool ok = (k < K) && (n < N);
            uint32_t dst = smem_u32(Bst + r * BSTR2 + cc);
            const __half* src = B + (ok ? ((size_t)k * N + n) : 0);
            CP_ASYNC16(dst, src, ok ? 16 : 0);
        }
    };

    load_stage(0, 0); CP_COMMIT();
    if (KT > 1) { load_stage(1, 1); }
    CP_COMMIT();

    int lrow = lane & 15, lhalf = (lane >> 4) * 8;

    for (int kt = 0; kt < KT; kt++) {
        if (kt + 1 < KT) { asm volatile("cp.async.wait_group 1;"); }
        else             { asm volatile("cp.async.wait_group 0;"); }
        __syncthreads();
        if (kt + 2 < KT) { load_stage((kt + 2) % 3, kt + 2); CP_COMMIT(); }

        int st = kt % 3;
        __half* Ast = Asm + st * A2_ST;
        __half* Bst = Bsm + st * B2_ST;

        #pragma unroll
        for (int kk = 0; kk < 32; kk += 16) {
            uint32_t a[4][4], bb[4][2];
            #pragma unroll
            for (int mi = 0; mi < 4; mi++) {
                uint32_t a0 = smem_u32(Ast + (wm * 64 + mi * 16 + lrow) * ASTR2 + kk + lhalf);
                LDSM4(a[mi][0], a[mi][1], a[mi][2], a[mi][3], a0);
            }
            #pragma unroll
            for (int pr = 0; pr < 2; pr++) {
                uint32_t r0, r1, r2, r3;
                uint32_t b0 = smem_u32(Bst + (kk + lrow) * BSTR2 + wn * 32 + pr * 16 + lhalf);
                LDSM4T(r0, r1, r2, r3, b0);
                bb[pr * 2][0] = r0; bb[pr * 2][1] = r1; bb[pr * 2 + 1][0] = r2; bb[pr * 2 + 1][1] = r3;
            }
            #pragma unroll
            for (int mi = 0; mi < 4; mi++)
                #pragma unroll
                for (int ni = 0; ni < 4; ni++)
                    MMA_FP16(acc[mi][ni], a[mi], bb[ni]);
        }
    }

    #pragma unroll
    for (int mi = 0; mi < 4; mi++) {
        int r0 = rowBase + wm * 64 + mi * 16 + (lane >> 2);
        #pragma unroll
        for (int ni = 0; ni < 4; ni++) {
            int c0 = colBase + wn * 32 + ni * 8 + (lane & 3) * 2;
            #pragma unroll
            for (int q = 0; q < 4; q++) {
                int r = r0 + (q >> 1) * 8;
                int c = c0 + (q & 1);
                if (c < N) {
                    float v = acc[mi][ni][q] + bias[c];
                    size_t o = (size_t)r * N + c;
                    if (EP == 2) {
                        v = 0.5f * v * (1.0f + erff(v * 0.70710678118654752440f));
                        Ch[o] = __float2half(v);
                    } else {
                        v += res[o];
                        Cf[o] = v;
                    }
                }
            }
        }
    }
}

// ---------------- MHA (register-tiled) -> att bf16 split ----------------
#define MHA_SMEM ((3*64*HDP + 64*64)*4)
__global__ void mha_kernel(const float* __restrict__ qkv,
                           __nv_bfloat16* __restrict__ ahi, __nv_bfloat16* __restrict__ alo) {
    extern __shared__ float smf[];
    float* Q  = smf;
    float* Kx = Q + 64 * HDP;
    float* V  = Kx + 64 * HDP;
    float* SC = V + 64 * HDP;
    int h = blockIdx.x, b = blockIdx.y;
    int tid = threadIdx.x;
    const float* base = qkv + (size_t)(b * NTOK) * (3 * Cdim);
    for (int e = tid; e < 64 * HD; e += 256) {
        int t = e / HD, d = e % HD;
        Q[t * HDP + d]  = base[(size_t)t * (3 * Cdim) + h * HD + d];
        Kx[t * HDP + d] = base[(size_t)t * (3 * Cdim) + Cdim + h * HD + d];
        V[t * HDP + d]  = base[(size_t)t * (3 * Cdim) + 2 * Cdim + h * HD + d];
    }
    __syncthreads();
    const float scale = rsqrtf((float)HD);
    {
        int ti = tid >> 4, tj = tid & 15;
        float acc[4][4] = {};
        #pragma unroll 2
        for (int d = 0; d < HD; d++) {
            float qv[4], kv[4];
            #pragma unroll
            for (int r2 = 0; r2 < 4; r2++) qv[r2] = Q[(ti * 4 + r2) * HDP + d];
            #pragma unroll
            for (int c2 = 0; c2 < 4; c2++) kv[c2] = Kx[(tj * 4 + c2) * HDP + d];
            #pragma unroll
            for (int r2 = 0; r2 < 4; r2++)
                #pragma unroll
                for (int c2 = 0; c2 < 4; c2++) acc[r2][c2] += qv[r2] * kv[c2];
        }
        #pragma unroll
        for (int r2 = 0; r2 < 4; r2++)
            #pragma unroll
            for (int c2 = 0; c2 < 4; c2++)
                SC[(ti * 4 + r2) * 64 + tj * 4 + c2] = acc[r2][c2] * scale;
    }
    __syncthreads();
    if (tid < 64) {
        float* row = SC + tid * 64;
        float mx = -1e30f;
        for (int j = 0; j < 64; j++) mx = fmaxf(mx, row[j]);
        float s = 0.f;
        for (int j = 0; j < 64; j++) { float e = expf(row[j] - mx); row[j] = e; s += e; }
        float inv = 1.f / s;
        for (int j = 0; j < 64; j++) row[j] *= inv;
    }
    __syncthreads();
    {
        int ti = tid >> 4, td = tid & 15;
        if (td < 14) {
            float oacc[4][7] = {};
            for (int j = 0; j < 64; j++) {
                float pr[4], vv[7];
                #pragma unroll
                for (int r2 = 0; r2 < 4; r2++) pr[r2] = SC[(ti * 4 + r2) * 64 + j];
                #pragma unroll
                for (int c2 = 0; c2 < 7; c2++) vv[c2] = V[j * HDP + td * 7 + c2];
                #pragma unroll
                for (int r2 = 0; r2 < 4; r2++)
                    #pragma unroll
                    for (int c2 = 0; c2 < 7; c2++) oacc[r2][c2] += pr[r2] * vv[c2];
            }
            #pragma unroll
            for (int r2 = 0; r2 < 4; r2++)
                #pragma unroll
                for (int c2 = 0; c2 < 7; c2++)
                    split_write_bf(oacc[r2][c2], ahi, alo,
                        ((size_t)(b * NTOK + ti * 4 + r2)) * Cdim + h * HD + td * 7 + c2);
        }
    }
}

// ---------------- BiFormer ----------------
#define BFQ_SMEM ((64*28 + 192*64)*4)  // 56320
__global__ void bf_qkv_kernel(const float* __restrict__ o,
                              const float* __restrict__ w, const float* __restrict__ bias) {
    extern __shared__ float bq[];
    float* xin = bq;             // [64][28]
    float* ws  = bq + 64 * 28;   // [192][64]
    int y = blockIdx.x, b = blockIdx.y;
    int tid = threadIdx.x;
    for (int e = tid; e < 192 * 64; e += 256) ws[e] = w[e];
    for (int e = tid; e < 64 * 28; e += 256) {
        int c = e / 28, xx = e % 28;
        xin[e] = o[((size_t)b * 64 + c) * 784 + y * 28 + xx];
    }
    __syncthreads();
    for (int e = tid; e < 192 * 28; e += 256) {
        int oc = e / 28, xx = e % 28;
        float a = bias[oc];
        const float* wr = ws + oc * 64;
        #pragma unroll 16
        for (int c = 0; c < 64; c++) a += xin[c * 28 + xx] * wr[c];
        g_bfqkv[((size_t)b * 192 + oc) * 784 + y * 28 + xx] = a;
    }
}

__global__ void bf_routing_kernel() {
    int b = blockIdx.x;
    int tid = threadIdx.x;  // 256
    __shared__ float qr[64][NREG];
    __shared__ float kr[64][NREG];
    __shared__ float ar[NREG][NREG];
    for (int e = tid; e < 64 * NREG; e += 256) {
        int c = e / NREG, r = e % NREG;
        int rh = r / 7, rw = r % 7;
        float sq = 0.f, sk = 0.f;
        const float* qc = g_bfqkv + ((size_t)b * 192 + c) * 784;
        const float* kc = g_bfqkv + ((size_t)b * 192 + 64 + c) * 784;
        #pragma unroll
        for (int pr = 0; pr < 4; pr++)
            #pragma unroll
            for (int pc = 0; pc < 4; pc++) {
                int s = (rh * 4 + pr) * 28 + rw * 4 + pc;
                sq += qc[s]; sk += kc[s];
            }
        qr[c][r] = sq * 0.0625f;
        kr[c][r] = sk * 0.0625f;
    }
    __syncthreads();
    for (int e = tid; e < NREG * NREG; e += 256) {
        int i = e / NREG, j = e % NREG;
        float a = 0.f;
        #pragma unroll 16
        for (int c = 0; c < 64; c++) a += qr[c][i] * kr[c][j];
        ar[i][j] = a;
    }
    __syncthreads();
    if (tid < NREG) {
        float* row = ar[tid];
        #pragma unroll
        for (int j = 0; j < TOPK; j++) {
            float mx = -1e30f; int mi = 0;
            for (int s = 0; s < NREG; s++) if (row[s] > mx) { mx = row[s]; mi = s; }
            row[mi] = -1e30f;
            g_idx[(b * NREG + tid) * TOPK + j] = mi;
        }
    }
}

__global__ void bf_attn_kernel() {
    int r = blockIdx.x, h = blockIdx.y, b = blockIdx.z;
    __shared__ float q[16][8], kg[64][9], vg[64][9];
    __shared__ float sc[16][65];
    __shared__ int idx4[4];
    int tid = threadIdx.x;  // 128
    if (tid < 4) idx4[tid] = g_idx[(b * NREG + r) * TOPK + tid];
    int rh = r / 7, rw = r % 7;
    {
        int p = tid / 8, d = tid % 8;
        int s = (rh * 4 + p / 4) * 28 + rw * 4 + (p % 4);
        q[p][d] = g_bfqkv[((size_t)b * 192 + h * 8 + d) * 784 + s] * 0.125f;
    }
    __syncthreads();
    for (int e = tid; e < 512; e += 128) {
        int t = e / 8, d = e % 8;
        int reg = idx4[t / 16];
        int p2 = t % 16;
        int s = ((reg / 7) * 4 + p2 / 4) * 28 + (reg % 7) * 4 + (p2 % 4);
        kg[t][d] = g_bfqkv[((size_t)b * 192 + 64 + h * 8 + d) * 784 + s];
        vg[t][d] = g_bfqkv[((size_t)b * 192 + 128 + h * 8 + d) * 784 + s];
    }
    __syncthreads();
    {
        int p = tid >> 3, tg = tid & 7;
        float qreg[8];
        #pragma unroll
        for (int d = 0; d < 8; d++) qreg[d] = q[p][d];
        #pragma unroll
        for (int tt = 0; tt < 8; tt++) {
            int t = tt * 8 + tg;
            float a = 0.f;
            #pragma unroll
            for (int d = 0; d < 8; d++) a += qreg[d] * kg[t][d];
            sc[p][t] = a;
        }
    }
    __syncthreads();
    if (tid < 16) {
        float mx = -1e30f;
        for (int t = 0; t < 64; t++) mx = fmaxf(mx, sc[tid][t]);
        float s = 0.f;
        for (int t = 0; t < 64; t++) { float e = expf(sc[tid][t] - mx); sc[tid][t] = e; s += e; }
        float inv = 1.f / s;
        for (int t = 0; t < 64; t++) sc[tid][t] *= inv;
    }
    __syncthreads();
    {
        int p = tid / 8, d = tid % 8;
        float a = 0.f;
        #pragma unroll 8
        for (int t = 0; t < 64; t++) a += sc[p][t] * vg[t][d];
        int s = (rh * 4 + p / 4) * 28 + rw * 4 + (p % 4);
        g_attg[((size_t)b * 64 + h * 8 + d) * 784 + s] = a;
    }
}

__global__ void bf_out_kernel(const float* __restrict__ lepe_w, const float* __restrict__ lepe_b,
                              const float* __restrict__ out_w, const float* __restrict__ out_b,
                              float* __restrict__ outp) {
    int y = blockIdx.x, b = blockIdx.y;
    __shared__ float v3[3][64][28];
    __shared__ float tmp[64][28];
    __shared__ float ws[64][64];
    __shared__ float lw[64][9];
    int tid = threadIdx.x;
    for (int e = tid; e < 64 * 64; e += blockDim.x) ws[e >> 6][e & 63] = out_w[e];
    for (int e = tid; e < 64 * 9; e += blockDim.x) lw[e / 9][e % 9] = lepe_w[e];
    for (int ry = 0; ry < 3; ry++) {
        int yy = y + ry - 1;
        for (int e = tid; e < 64 * 28; e += blockDim.x) {
            int c = e / 28, xx = e % 28;
            v3[ry][c][xx] = (yy >= 0 && yy < 28)
                ? g_bfqkv[((size_t)b * 192 + 128 + c) * 784 + yy * 28 + xx] : 0.f;
        }
    }
    __syncthreads();
    for (int e = tid; e < 64 * 28; e += blockDim.x) {
        int c = e / 28, xx = e % 28;
        float a = g_attg[((size_t)b * 64 + c) * 784 + y * 28 + xx] + lepe_b[c];
        #pragma unroll
        for (int ky = 0; ky < 3; ky++)
            #pragma unroll
            for (int kx = 0; kx < 3; kx++) {
                int xx2 = xx + kx - 1;
                if (xx2 >= 0 && xx2 < 28) a += v3[ky][c][xx2] * lw[c][ky * 3 + kx];
            }
        tmp[c][xx] = a;
    }
    __syncthreads();
    for (int e = tid; e < 64 * 28; e += blockDim.x) {
        int oc = e / 28, xx = e % 28;
        float a = out_b[oc];
        const float* wr = ws[oc];
        #pragma unroll 16
        for (int c = 0; c < 64; c++) a += tmp[c][xx] * wr[c];
        outp[((size_t)b * 64 + oc) * 784 + y * 28 + xx] = a;
    }
}

// ---------------- launch ----------------
extern "C" void kernel_launch(void* const* d_in, const int* in_sizes, int n_in,
                              void* d_out, int out_size) {
    (void)in_sizes; (void)n_in; (void)out_size;
    const float* x        = (const float*)d_in[0];
    const float* norm1_g  = (const float*)d_in[1];
    const float* norm1_b  = (const float*)d_in[2];
    const float* qkv_w    = (const float*)d_in[3];
    const float* proj_w   = (const float*)d_in[4];
    const float* proj_b   = (const float*)d_in[5];
    const float* norm2_g  = (const float*)d_in[6];
    const float* norm2_b  = (const float*)d_in[7];
    const float* fc1_w    = (const float*)d_in[8];
    const float* fc1_b    = (const float*)d_in[9];
    const float* fc2_w    = (const float*)d_in[10];
    const float* fc2_b    = (const float*)d_in[11];
    const float* bf_qkv_w = (const float*)d_in[12];
    const float* bf_qkv_b = (const float*)d_in[13];
    const float* bf_lepe_w= (const float*)d_in[14];
    const float* bf_lepe_b= (const float*)d_in[15];
    const float* bf_out_w = (const float*)d_in[16];
    const float* bf_out_b = (const float*)d_in[17];
    float* out = (float*)d_out;

    __nv_bfloat16 *p_h_hi, *p_h_lo, *p_att_hi, *p_att_lo;
    __nv_bfloat16 *p_wqkv_hi, *p_wqkv_lo, *p_wproj_hi, *p_wproj_lo;
    __half *p_h2, *p_hid, *p_wfc1, *p_wfc2;
    float *p_qkv, *p_o, *p_xr;
    cudaGetSymbolAddress((void**)&p_h_hi, g_h_hi);     cudaGetSymbolAddress((void**)&p_h_lo, g_h_lo);
    cudaGetSymbolAddress((void**)&p_att_hi, g_att_hi); cudaGetSymbolAddress((void**)&p_att_lo, g_att_lo);
    cudaGetSymbolAddress((void**)&p_h2, g_h2);
    cudaGetSymbolAddress((void**)&p_hid, g_hid);
    cudaGetSymbolAddress((void**)&p_wqkv_hi, g_wqkv_hi);   cudaGetSymbolAddress((void**)&p_wqkv_lo, g_wqkv_lo);
    cudaGetSymbolAddress((void**)&p_wproj_hi, g_wproj_hi); cudaGetSymbolAddress((void**)&p_wproj_lo, g_wproj_lo);
    cudaGetSymbolAddress((void**)&p_wfc1, g_wfc1);
    cudaGetSymbolAddress((void**)&p_wfc2, g_wfc2);
    cudaGetSymbolAddress((void**)&p_qkv, g_qkv);
    cudaGetSymbolAddress((void**)&p_o, g_o);
    cudaGetSymbolAddress((void**)&p_xr, g_xr);

    cudaFuncSetAttribute(mha_kernel, cudaFuncAttributeMaxDynamicSharedMemorySize, MHA_SMEM);
    cudaFuncSetAttribute(bf_qkv_kernel, cudaFuncAttributeMaxDynamicSharedMemorySize, BFQ_SMEM);
    cudaFuncSetAttribute(mma_gemm3<0>, cudaFuncAttributeMaxDynamicSharedMemorySize, GEMM3_SMEM);
    cudaFuncSetAttribute(mma_gemm3<1>, cudaFuncAttributeMaxDynamicSharedMemorySize, GEMM3_SMEM);
    cudaFuncSetAttribute(mma_gemm2<2>, cudaFuncAttributeMaxDynamicSharedMemorySize, GEMM2_SMEM);
    cudaFuncSetAttribute(mma_gemm2<3>, cudaFuncAttributeMaxDynamicSharedMemorySize, GEMM2_SMEM);

    static cudaStream_t s1 = nullptr;
    static cudaEvent_t eFork = nullptr, eW = nullptr, eO = nullptr, eBF = nullptr;
    if (!s1) {
        cudaStreamCreateWithFlags(&s1, cudaStreamNonBlocking);
        cudaEventCreateWithFlags(&eFork, cudaEventDisableTiming);
        cudaEventCreateWithFlags(&eW,    cudaEventDisableTiming);
        cudaEventCreateWithFlags(&eO,    cudaEventDisableTiming);
        cudaEventCreateWithFlags(&eBF,   cudaEventDisableTiming);
    }

    // s0: LN1 (#1) and qkv split (#2) — gemm3 depends on both via stream order
    ln_kernel<<<ROWS, 256>>>(x, norm1_g, norm1_b, p_h_hi, p_h_lo);
    split_bf_kernel<<<(Cdim * 3 * Cdim / 4 + 255) / 256, 256>>>(qkv_w, p_wqkv_hi, p_wqkv_lo, Cdim * 3 * Cdim / 4);

    // fork
    cudaEventRecord(eFork, 0);
    cudaStreamWaitEvent(s1, eFork, 0);

    // s1: proj split (#3)
    split_bf_kernel<<<(Cdim * Cdim / 4 + 255) / 256, 256, 0, s1>>>(proj_w, p_wproj_hi, p_wproj_lo, Cdim * Cdim / 4);

    // s0: qkv GEMM (#4 — ncu capture target)
    mma_gemm3<0><<<dim3((3 * Cdim + 127) / 128, ROWS / 128), 256, GEMM3_SMEM>>>(
        p_h_hi, p_h_lo, p_wqkv_hi, p_wqkv_lo, nullptr,
        p_qkv, ROWS, 3 * Cdim, Cdim);

    // s1: fc weight converts (#5, #6) — overlap with qkv GEMM
    conv_fp_kernel<<<(Cdim * HID / 4 + 255) / 256, 256, 0, s1>>>(fc1_w, p_wfc1, Cdim * HID / 4);
    conv_fp_kernel<<<(HID * Cdim / 4 + 255) / 256, 256, 0, s1>>>(fc2_w, p_wfc2, HID * Cdim / 4);
    cudaEventRecord(eW, s1);

    // s0: MHA, proj
    mha_kernel<<<dim3(NHd, Bsz), 256, MHA_SMEM>>>(p_qkv, p_att_hi, p_att_lo);
    cudaStreamWaitEvent(0, eW, 0);
    mma_gemm3<1><<<dim3((Cdim + 127) / 128, ROWS / 128), 256, GEMM3_SMEM>>>(
        p_att_hi, p_att_lo, p_wproj_hi, p_wproj_lo, proj_b,
        p_o, ROWS, Cdim, Cdim);
    cudaEventRecord(eO, 0);

    // s1: BiFormer branch
    cudaStreamWaitEvent(s1, eO, 0);
    bf_qkv_kernel<<<dim3(28, Bsz), 256, BFQ_SMEM, s1>>>(p_o, bf_qkv_w, bf_qkv_b);
    bf_routing_kernel<<<Bsz, 256, 0, s1>>>();
    bf_attn_kernel<<<dim3(NREG, 8, Bsz), 128, 0, s1>>>();
    bf_out_kernel<<<dim3(28, Bsz), 256, 0, s1>>>(bf_lepe_w, bf_lepe_b, bf_out_w, bf_out_b, out + OUT_OFF);
    cudaEventRecord(eBF, s1);

    // s0: MLP branch
    ln2_kernel<<<ROWS, 256>>>(p_o, x, norm2_g, norm2_b, p_xr, p_h2);
    mma_gemm2<2><<<dim3((HID + 127) / 128, ROWS / 128), 256, GEMM2_SMEM>>>(
        p_h2, p_wfc1, fc1_b, nullptr,
        nullptr, p_hid, ROWS, HID, Cdim);
    mma_gemm2<3><<<dim3((Cdim + 127) / 128, ROWS / 128), 256, GEMM2_SMEM>>>(
        p_hid, p_wfc2, fc2_b, p_xr,
        out, nullptr, ROWS, Cdim, HID);

    // join
    cudaStreamWaitEvent(0, eBF, 0);
}

// round 15
// speedup vs baseline: 2.1925x; 1.0006x over previous
#include <cuda_runtime.h>
#include <cuda_bf16.h>
#include <cuda_fp16.h>
#include <math.h>
#include <stdint.h>

// ---------------- problem constants ----------------
#define Bsz   128
#define NTOK  64
#define Cdim  784
#define NHd   8
#define HD    98
#define HDP   99
#define HID   3136
#define ROWS  (Bsz*NTOK)  // 8192
#define NREG  49
#define TOPK  4
#define OUT_OFF (Bsz*NTOK*Cdim)

// ---------------- scratch ----------------
__device__ __nv_bfloat16 g_h_hi [ROWS*Cdim];
__device__ __nv_bfloat16 g_h_lo [ROWS*Cdim];
__device__ float         g_qkv  [ROWS*3*Cdim];
__device__ __nv_bfloat16 g_att_hi[ROWS*Cdim];
__device__ __nv_bfloat16 g_att_lo[ROWS*Cdim];
__device__ float         g_o    [ROWS*Cdim];
__device__ float         g_xr   [ROWS*Cdim];
__device__ __half        g_h2   [ROWS*Cdim];
__device__ __half        g_hid  [ROWS*HID];
// weight splits [K, N]
__device__ __nv_bfloat16 g_wqkv_hi[Cdim*3*Cdim];
__device__ __nv_bfloat16 g_wqkv_lo[Cdim*3*Cdim];
__device__ __nv_bfloat16 g_wproj_hi[Cdim*Cdim];
__device__ __nv_bfloat16 g_wproj_lo[Cdim*Cdim];
__device__ __half        g_wfc1 [Cdim*HID];
__device__ __half        g_wfc2 [HID*Cdim];
// biformer
__device__ float g_bfqkv[Bsz*192*784];
__device__ float g_attg [Bsz*64*784];
__device__ int   g_idx [Bsz*NREG*TOPK];

// ---------------- helpers ----------------
__device__ __forceinline__ uint32_t smem_u32(const void* p) {
    return (uint32_t)__cvta_generic_to_shared(p);
}
#define CP_ASYNC16(dst_u32, src, sz) \
    asm volatile("cp.async.cg.shared.global [%0], [%1], 16, %2;\n" :: "r"(dst_u32), "l"(src), "r"(sz))
#define CP_COMMIT() asm volatile("cp.async.commit_group;\n")
#define LDSM4(r0,r1,r2,r3,a) \
    asm volatile("ldmatrix.sync.aligned.m8n8.x4.shared.b16 {%0,%1,%2,%3},[%4];" \
        : "=r"(r0),"=r"(r1),"=r"(r2),"=r"(r3) : "r"(a))
#define LDSM4T(r0,r1,r2,r3,a) \
    asm volatile("ldmatrix.sync.aligned.m8n8.x4.trans.shared.b16 {%0,%1,%2,%3},[%4];" \
        : "=r"(r0),"=r"(r1),"=r"(r2),"=r"(r3) : "r"(a))
#define MMA_BF16(d, a, b) \
    asm volatile("mma.sync.aligned.m16n8k16.row.col.f32.bf16.bf16.f32 " \
        "{%0,%1,%2,%3},{%4,%5,%6,%7},{%8,%9},{%0,%1,%2,%3};" \
        : "+f"(d[0]),"+f"(d[1]),"+f"(d[2]),"+f"(d[3]) \
        : "r"(a[0]),"r"(a[1]),"r"(a[2]),"r"(a[3]),"r"(b[0]),"r"(b[1]))
#define MMA_FP16(d, a, b) \
    asm volatile("mma.sync.aligned.m16n8k16.row.col.f32.f16.f16.f32 " \
        "{%0,%1,%2,%3},{%4,%5,%6,%7},{%8,%9},{%0,%1,%2,%3};" \
        : "+f"(d[0]),"+f"(d[1]),"+f"(d[2]),"+f"(d[3]) \
        : "r"(a[0]),"r"(a[1]),"r"(a[2]),"r"(a[3]),"r"(b[0]),"r"(b[1]))

__device__ __forceinline__ void split_write_bf(float v, __nv_bfloat16* hi, __nv_bfloat16* lo, size_t o) {
    __nv_bfloat16 h = __float2bfloat16(v);
    hi[o] = h;
    lo[o] = __float2bfloat16(v - __bfloat162float(h));
}

// ---------------- weight prep (float4 vectorized) ----------------
__global__ void split_bf_kernel(const float* __restrict__ in, __nv_bfloat16* __restrict__ hi,
                                __nv_bfloat16* __restrict__ lo, int n4) {
    int i = blockIdx.x * blockDim.x + threadIdx.x;
    if (i < n4) {
        float4 v = ((const float4*)in)[i];
        __nv_bfloat16 h0 = __float2bfloat16(v.x), h1 = __float2bfloat16(v.y);
        __nv_bfloat16 h2 = __float2bfloat16(v.z), h3 = __float2bfloat16(v.w);
        ((__nv_bfloat162*)hi)[i * 2]     = __nv_bfloat162(h0, h1);
        ((__nv_bfloat162*)hi)[i * 2 + 1] = __nv_bfloat162(h2, h3);
        ((__nv_bfloat162*)lo)[i * 2]     = __nv_bfloat162(
            __float2bfloat16(v.x - __bfloat162float(h0)), __float2bfloat16(v.y - __bfloat162float(h1)));
        ((__nv_bfloat162*)lo)[i * 2 + 1] = __nv_bfloat162(
            __float2bfloat16(v.z - __bfloat162float(h2)), __float2bfloat16(v.w - __bfloat162float(h3)));
    }
}
__global__ void conv_fp_kernel(const float* __restrict__ in, __half* __restrict__ o, int n4) {
    int i = blockIdx.x * blockDim.x + threadIdx.x;
    if (i < n4) {
        float4 v = ((const float4*)in)[i];
        ((__half2*)o)[i * 2]     = __floats2half2_rn(v.x, v.y);
        ((__half2*)o)[i * 2 + 1] = __floats2half2_rn(v.z, v.w);
    }
}

// ---------------- LN1: x -> (h_hi, h_lo) bf16 (float4) ----------------
__global__ void ln_kernel(const float* __restrict__ x,
                          const float* __restrict__ g, const float* __restrict__ b,
                          __nv_bfloat16* __restrict__ ohi, __nv_bfloat16* __restrict__ olo) {
    int row = blockIdx.x;
    const float4* xr4 = (const float4*)(x + (size_t)row * Cdim);
    __shared__ float4 buf[Cdim / 4];
    __shared__ float rs[2];
    __shared__ float red[64];
    int tid = threadIdx.x;
    float s = 0.f, ss = 0.f;
    float4 v;
    if (tid < Cdim / 4) {
        v = xr4[tid];
        buf[tid] = v;
        s = v.x + v.y + v.z + v.w;
        ss = v.x * v.x + v.y * v.y + v.z * v.z + v.w * v.w;
    }
    for (int o = 16; o > 0; o >>= 1) { s += __shfl_down_sync(~0u, s, o); ss += __shfl_down_sync(~0u, ss, o); }
    int wid = tid >> 5, lid = tid & 31;
    if (lid == 0) { red[wid] = s; red[wid + 32] = ss; }
    __syncthreads();
    if (tid == 0) {
        float t = 0.f, tt = 0.f;
        int nw = blockDim.x >> 5;
        for (int i = 0; i < nw; i++) { t += red[i]; tt += red[i + 32]; }
        float mean = t / Cdim, var = tt / Cdim - mean * mean;
        rs[0] = mean; rs[1] = rsqrtf(var + 1e-5f);
    }
    __syncthreads();
    float mean = rs[0], inv = rs[1];
    if (tid < Cdim / 4) {
        v = buf[tid];
        float4 gv = ((const float4*)g)[tid];
        float4 bv = ((const float4*)b)[tid];
        float o0 = (v.x - mean) * inv * gv.x + bv.x;
        float o1 = (v.y - mean) * inv * gv.y + bv.y;
        float o2 = (v.z - mean) * inv * gv.z + bv.z;
        float o3 = (v.w - mean) * inv * gv.w + bv.w;
        size_t base2 = ((size_t)row * Cdim) / 2 + tid * 2;
        __nv_bfloat16 h0 = __float2bfloat16(o0), h1 = __float2bfloat16(o1);
        __nv_bfloat16 h2 = __float2bfloat16(o2), h3 = __float2bfloat16(o3);
        ((__nv_bfloat162*)ohi)[base2]     = __nv_bfloat162(h0, h1);
        ((__nv_bfloat162*)ohi)[base2 + 1] = __nv_bfloat162(h2, h3);
        ((__nv_bfloat162*)olo)[base2]     = __nv_bfloat162(
            __float2bfloat16(o0 - __bfloat162float(h0)), __float2bfloat16(o1 - __bfloat162float(h1)));
        ((__nv_bfloat162*)olo)[base2 + 1] = __nv_bfloat162(
            __float2bfloat16(o2 - __bfloat162float(h2)), __float2bfloat16(o3 - __bfloat162float(h3)));
    }
}

// ---------------- LN2: xr = o + x (fp32), h2 fp16 (float4) ----------------
__global__ void ln2_kernel(const float* __restrict__ ov, const float* __restrict__ x,
                           const float* __restrict__ g, const float* __restrict__ b,
                           float* __restrict__ xr_out, __half* __restrict__ oh) {
    int row = blockIdx.x;
    const float4* a4 = (const float4*)(ov + (size_t)row * Cdim);
    const float4* c4 = (const float4*)(x + (size_t)row * Cdim);
    __shared__ float4 buf[Cdim / 4];
    __shared__ float rs[2];
    __shared__ float red[64];
    int tid = threadIdx.x;
    float s = 0.f, ss = 0.f;
    if (tid < Cdim / 4) {
        float4 av = a4[tid], cv = c4[tid];
        float4 v = make_float4(av.x + cv.x, av.y + cv.y, av.z + cv.z, av.w + cv.w);
        buf[tid] = v;
        ((float4*)(xr_out + (size_t)row * Cdim))[tid] = v;
        s = v.x + v.y + v.z + v.w;
        ss = v.x * v.x + v.y * v.y + v.z * v.z + v.w * v.w;
    }
    for (int o = 16; o > 0; o >>= 1) { s += __shfl_down_sync(~0u, s, o); ss += __shfl_down_sync(~0u, ss, o); }
    int wid = tid >> 5, lid = tid & 31;
    if (lid == 0) { red[wid] = s; red[wid + 32] = ss; }
    __syncthreads();
    if (tid == 0) {
        float t = 0.f, tt = 0.f;
        int nw = blockDim.x >> 5;
        for (int i = 0; i < nw; i++) { t += red[i]; tt += red[i + 32]; }
        float mean = t / Cdim, var = tt / Cdim - mean * mean;
        rs[0] = mean; rs[1] = rsqrtf(var + 1e-5f);
    }
    __syncthreads();
    float mean = rs[0], inv = rs[1];
    if (tid < Cdim / 4) {
        float4 v = buf[tid];
        float4 gv = ((const float4*)g)[tid];
        float4 bv = ((const float4*)b)[tid];
        size_t base2 = ((size_t)row * Cdim) / 2 + tid * 2;
        ((__half2*)oh)[base2] = __floats2half2_rn(
            (v.x - mean) * inv * gv.x + bv.x, (v.y - mean) * inv * gv.y + bv.y);
        ((__half2*)oh)[base2 + 1] = __floats2half2_rn(
            (v.z - mean) * inv * gv.z + bv.z, (v.w - mean) * inv * gv.w + bv.w);
    }
}

// ===== bf16x3 GEMM (qkv, proj) — BK=32, 3-stage, single barrier, 2 CTAs/SM =====
#define ASTR3 40
#define BSTR3 136
#define A3_ST (2*128*ASTR3)
#define B3_ST (2*32*BSTR3)
#define GEMM3_SMEM (3*(A3_ST + B3_ST) * 2)  // 113664

template<int EP>
__global__ __launch_bounds__(256, 2)
void mma_gemm3(const __nv_bfloat16* __restrict__ Ah, const __nv_bfloat16* __restrict__ Al,
               const __nv_bfloat16* __restrict__ Bh, const __nv_bfloat16* __restrict__ Bl,
               const float* __restrict__ bias,
               float* __restrict__ Cf, int M, int N, int K) {
    extern __shared__ __nv_bfloat16 sm3[];
    __nv_bfloat16* Asm = sm3;
    __nv_bfloat16* Bsm = sm3 + 3 * A3_ST;

    int tid = threadIdx.x;
    int warp = tid >> 5, lane = tid & 31;
    int wm = warp & 1, wn = warp >> 1;
    int rowBase = blockIdx.y * 128, colBase = blockIdx.x * 128;

    const int KT = (K + 31) >> 5;
    float acc[4][4][4];
    #pragma unroll
    for (int i = 0; i < 4; i++)
        #pragma unroll
        for (int j = 0; j < 4; j++)
            #pragma unroll
            for (int q = 0; q < 4; q++) acc[i][j][q] = 0.f;

    auto load_stage = [&](int st, int kt) {
        int koff = kt * 32;
        __nv_bfloat16* Ast = Asm + st * A3_ST;
        __nv_bfloat16* Bst = Bsm + st * B3_ST;
        #pragma unroll
        for (int part = 0; part < 2; part++) {
            const __nv_bfloat16* Aasrc = part ? Al : Ah;
            #pragma unroll
            for (int i = 0; i < 2; i++) {
                int chunk = i * 256 + tid;
                int r = chunk >> 2, cc = (chunk & 3) * 8;
                int k = koff + cc;
                uint32_t dst = smem_u32(Ast + part * (128 * ASTR3) + r * ASTR3 + cc);
                const __nv_bfloat16* src = Aasrc + (size_t)(rowBase + r) * K + (k < K ? k : 0);
                CP_ASYNC16(dst, src, (k < K) ? 16 : 0);
            }
        }
        #pragma unroll
        for (int part = 0; part < 2; part++) {
            const __nv_bfloat16* Bbsrc = part ? Bl : Bh;
            #pragma unroll
            for (int i = 0; i < 2; i++) {
                int chunk = i * 256 + tid;
                int r = chunk >> 4, cc = (chunk & 15) * 8;
                int k = koff + r, n = colBase + cc;
                bool ok = (k < K) && (n < N);
                uint32_t dst = smem_u32(Bst + part * (32 * BSTR3) + r * BSTR3 + cc);
                const __nv_bfloat16* src = Bbsrc + (ok ? ((size_t)k * N + n) : 0);
                CP_ASYNC16(dst, src, ok ? 16 : 0);
            }
        }
    };

    load_stage(0, 0); CP_COMMIT();
    if (KT > 1) { load_stage(1, 1); }
    CP_COMMIT();

    int lrow = lane & 15, lhalf = (lane >> 4) * 8;

    for (int kt = 0; kt < KT; kt++) {
        if (kt + 1 < KT) { asm volatile("cp.async.wait_group 1;"); }
        else             { asm volatile("cp.async.wait_group 0;"); }
        __syncthreads();
        if (kt + 2 < KT) { load_stage((kt + 2) % 3, kt + 2); CP_COMMIT(); }

        int st = kt % 3;
        __nv_bfloat16* Ast = Asm + st * A3_ST;
        __nv_bfloat16* Bst = Bsm + st * B3_ST;

        #pragma unroll
        for (int kk = 0; kk < 32; kk += 16) {
            uint32_t ah[4][4], bh[4][2], bl[4][2];
            #pragma unroll
            for (int mi = 0; mi < 4; mi++) {
                uint32_t a0 = smem_u32(Ast + (wm * 64 + mi * 16 + lrow) * ASTR3 + kk + lhalf);
                LDSM4(ah[mi][0], ah[mi][1], ah[mi][2], ah[mi][3], a0);
            }
            #pragma unroll
            for (int pr = 0; pr < 2; pr++) {
                uint32_t r0, r1, r2, r3;
                uint32_t b0 = smem_u32(Bst + (kk + lrow) * BSTR3 + wn * 32 + pr * 16 + lhalf);
                LDSM4T(r0, r1, r2, r3, b0);
                bh[pr * 2][0] = r0; bh[pr * 2][1] = r1; bh[pr * 2 + 1][0] = r2; bh[pr * 2 + 1][1] = r3;
                uint32_t b1 = smem_u32(Bst + 32 * BSTR3 + (kk + lrow) * BSTR3 + wn * 32 + pr * 16 + lhalf);
                LDSM4T(r0, r1, r2, r3, b1);
                bl[pr * 2][0] = r0; bl[pr * 2][1] = r1; bl[pr * 2 + 1][0] = r2; bl[pr * 2 + 1][1] = r3;
            }
            #pragma unroll
            for (int mi = 0; mi < 4; mi++)
                #pragma unroll
                for (int ni = 0; ni < 4; ni++) {
                    MMA_BF16(acc[mi][ni], ah[mi], bh[ni]);
                    MMA_BF16(acc[mi][ni], ah[mi], bl[ni]);
                }
            uint32_t al[4][4];
            #pragma unroll
            for (int mi = 0; mi < 4; mi++) {
                uint32_t a1 = smem_u32(Ast + 128 * ASTR3 + (wm * 64 + mi * 16 + lrow) * ASTR3 + kk + lhalf);
                LDSM4(al[mi][0], al[mi][1], al[mi][2], al[mi][3], a1);
            }
            #pragma unroll
            for (int mi = 0; mi < 4; mi++)
                #pragma unroll
                for (int ni = 0; ni < 4; ni++)
                    MMA_BF16(acc[mi][ni], al[mi], bh[ni]);
        }
    }

    #pragma unroll
    for (int mi = 0; mi < 4; mi++) {
        int r0 = rowBase + wm * 64 + mi * 16 + (lane >> 2);
        #pragma unroll
        for (int ni = 0; ni < 4; ni++) {
            int c0 = colBase + wn * 32 + ni * 8 + (lane & 3) * 2;
            #pragma unroll
            for (int q = 0; q < 4; q++) {
                int r = r0 + (q >> 1) * 8;
                int c = c0 + (q & 1);
                if (c < N) {
                    float v = acc[mi][ni][q];
                    if (EP >= 1) v += bias[c];
                    Cf[(size_t)r * N + c] = v;
                }
            }
        }
    }
}

// ===== fp16 single-term GEMM (fc1, fc2) — BK=32, 3-stage, single barrier, 2 CTAs/SM =====
#define ASTR2 40
#define BSTR2 136
#define A2_ST (128*ASTR2)
#define B2_ST (32*BSTR2)
#define GEMM2_SMEM (3*(A2_ST + B2_ST) * 2)  // 56832

template<int EP>
__global__ __launch_bounds__(256, 2)
void mma_gemm2(const __half* __restrict__ A, const __half* __restrict__ B,
               const float* __restrict__ bias, const float* __restrict__ res,
               float* __restrict__ Cf, __half* __restrict__ Ch,
               int M, int N, int K) {
    extern __shared__ __half sm2[];
    __half* Asm = sm2;
    __half* Bsm = sm2 + 3 * A2_ST;

    int tid = threadIdx.x;
    int warp = tid >> 5, lane = tid & 31;
    int wm = warp & 1, wn = warp >> 1;
    int rowBase = blockIdx.y * 128, colBase = blockIdx.x * 128;

    const int KT = (K + 31) >> 5;
    float acc[4][4][4];
    #pragma unroll
    for (int i = 0; i < 4; i++)
        #pragma unroll
        for (int j = 0; j < 4; j++)
            #pragma unroll
            for (int q = 0; q < 4; q++) acc[i][j][q] = 0.f;

    auto load_stage = [&](int st, int kt) {
        int koff = kt * 32;
        __half* Ast = Asm + st * A2_ST;
        __half* Bst = Bsm + st * B2_ST;
        #pragma unroll
        for (int i = 0; i < 2; i++) {
            int chunk = i * 256 + tid;
            int r = chunk >> 2, cc = (chunk & 3) * 8;
            int k = koff + cc;
            uint32_t dst = smem_u32(Ast + r * ASTR2 + cc);
            const __half* src = A + (size_t)(rowBase + r) * K + (k < K ? k : 0);
            CP_ASYNC16(dst, src, (k < K) ? 16 : 0);
        }
        #pragma unroll
        for (int i = 0; i < 2; i++) {
            int chunk = i * 256 + tid;
            int r = chunk >> 4, cc = (chunk & 15) * 8;
            int k = koff + r, n = colBase + cc;
            bool ok = (k < K) && (n < N);
            uint32_t dst = smem_u32(Bst + r * BSTR2 + cc);
            const __half* src = B + (ok ? ((size_t)k * N + n) : 0);
            CP_ASYNC16(dst, src, ok ? 16 : 0);
        }
    };

    load_stage(0, 0); CP_COMMIT();
    if (KT > 1) { load_stage(1, 1); }
    CP_COMMIT();

    int lrow = lane & 15, lhalf = (lane >> 4) * 8;

    for (int kt = 0; kt < KT; kt++) {
        if (kt + 1 < KT) { asm volatile("cp.async.wait_group 1;"); }
        else             { asm volatile("cp.async.wait_group 0;"); }
        __syncthreads();
        if (kt + 2 < KT) { load_stage((kt + 2) % 3, kt + 2); CP_COMMIT(); }

        int st = kt % 3;
        __half* Ast = Asm + st * A2_ST;
        __half* Bst = Bsm + st * B2_ST;

        #pragma unroll
        for (int kk = 0; kk < 32; kk += 16) {
            uint32_t a[4][4], bb[4][2];
            #pragma unroll
            for (int mi = 0; mi < 4; mi++) {
                uint32_t a0 = smem_u32(Ast + (wm * 64 + mi * 16 + lrow) * ASTR2 + kk + lhalf);
                LDSM4(a[mi][0], a[mi][1], a[mi][2], a[mi][3], a0);
            }
            #pragma unroll
            for (int pr = 0; pr < 2; pr++) {
                uint32_t r0, r1, r2, r3;
                uint32_t b0 = smem_u32(Bst + (kk + lrow) * BSTR2 + wn * 32 + pr * 16 + lhalf);
                LDSM4T(r0, r1, r2, r3, b0);
                bb[pr * 2][0] = r0; bb[pr * 2][1] = r1; bb[pr * 2 + 1][0] = r2; bb[pr * 2 + 1][1] = r3;
            }
            #pragma unroll
            for (int mi = 0; mi < 4; mi++)
                #pragma unroll
                for (int ni = 0; ni < 4; ni++)
                    MMA_FP16(acc[mi][ni], a[mi], bb[ni]);
        }
    }

    #pragma unroll
    for (int mi = 0; mi < 4; mi++) {
        int r0 = rowBase + wm * 64 + mi * 16 + (lane >> 2);
        #pragma unroll
        for (int ni = 0; ni < 4; ni++) {
            int c0 = colBase + wn * 32 + ni * 8 + (lane & 3) * 2;
            #pragma unroll
            for (int q = 0; q < 4; q++) {
                int r = r0 + (q >> 1) * 8;
                int c = c0 + (q & 1);
                if (c < N) {
                    float v = acc[mi][ni][q] + bias[c];
                    size_t o = (size_t)r * N + c;
                    if (EP == 2) {
                        v = 0.5f * v * (1.0f + erff(v * 0.70710678118654752440f));
                        Ch[o] = __float2half(v);
                    } else {
                        v += res[o];
                        Cf[o] = v;
                    }
                }
            }
        }
    }
}

// ---------------- MHA (register-tiled) -> att bf16 split ----------------
#define MHA_SMEM ((3*64*HDP + 64*64)*4)
__global__ void mha_kernel(const float* __restrict__ qkv,
                           __nv_bfloat16* __restrict__ ahi, __nv_bfloat16* __restrict__ alo) {
    extern __shared__ float smf[];
    float* Q  = smf;
    float* Kx = Q + 64 * HDP;
    float* V  = Kx + 64 * HDP;
    float* SC = V + 64 * HDP;
    int h = blockIdx.x, b = blockIdx.y;
    int tid = threadIdx.x;
    const float* base = qkv + (size_t)(b * NTOK) * (3 * Cdim);
    for (int e = tid; e < 64 * HD; e += 256) {
        int t = e / HD, d = e % HD;
        Q[t * HDP + d]  = base[(size_t)t * (3 * Cdim) + h * HD + d];
        Kx[t * HDP + d] = base[(size_t)t * (3 * Cdim) + Cdim + h * HD + d];
        V[t * HDP + d]  = base[(size_t)t * (3 * Cdim) + 2 * Cdim + h * HD + d];
    }
    __syncthreads();
    const float scale = rsqrtf((float)HD);
    {
        int ti = tid >> 4, tj = tid & 15;
        float acc[4][4] = {};
        #pragma unroll 2
        for (int d = 0; d < HD; d++) {
            float qv[4], kv[4];
            #pragma unroll
            for (int r2 = 0; r2 < 4; r2++) qv[r2] = Q[(ti * 4 + r2) * HDP + d];
            #pragma unroll
            for (int c2 = 0; c2 < 4; c2++) kv[c2] = Kx[(tj * 4 + c2) * HDP + d];
            #pragma unroll
            for (int r2 = 0; r2 < 4; r2++)
                #pragma unroll
                for (int c2 = 0; c2 < 4; c2++) acc[r2][c2] += qv[r2] * kv[c2];
        }
        #pragma unroll
        for (int r2 = 0; r2 < 4; r2++)
            #pragma unroll
            for (int c2 = 0; c2 < 4; c2++)
                SC[(ti * 4 + r2) * 64 + tj * 4 + c2] = acc[r2][c2] * scale;
    }
    __syncthreads();
    if (tid < 64) {
        float* row = SC + tid * 64;
        float mx = -1e30f;
        for (int j = 0; j < 64; j++) mx = fmaxf(mx, row[j]);
        float s = 0.f;
        for (int j = 0; j < 64; j++) { float e = expf(row[j] - mx); row[j] = e; s += e; }
        float inv = 1.f / s;
        for (int j = 0; j < 64; j++) row[j] *= inv;
    }
    __syncthreads();
    {
        int ti = tid >> 4, td = tid & 15;
        if (td < 14) {
            float oacc[4][7] = {};
            for (int j = 0; j < 64; j++) {
                float pr[4], vv[7];
                #pragma unroll
                for (int r2 = 0; r2 < 4; r2++) pr[r2] = SC[(ti * 4 + r2) * 64 + j];
                #pragma unroll
                for (int c2 = 0; c2 < 7; c2++) vv[c2] = V[j * HDP + td * 7 + c2];
                #pragma unroll
                for (int r2 = 0; r2 < 4; r2++)
                    #pragma unroll
                    for (int c2 = 0; c2 < 7; c2++) oacc[r2][c2] += pr[r2] * vv[c2];
            }
            #pragma unroll
            for (int r2 = 0; r2 < 4; r2++)
                #pragma unroll
                for (int c2 = 0; c2 < 7; c2++)
                    split_write_bf(oacc[r2][c2], ahi, alo,
                        ((size_t)(b * NTOK + ti * 4 + r2)) * Cdim + h * HD + td * 7 + c2);
        }
    }
}

// ---------------- BiFormer ----------------
#define BFQ_SMEM ((64*28 + 192*64)*4)  // 56320
__global__ void bf_qkv_kernel(const float* __restrict__ o,
                              const float* __restrict__ w, const float* __restrict__ bias) {
    extern __shared__ float bq[];
    float* xin = bq;             // [64][28]
    float* ws  = bq + 64 * 28;   // [192][64]
    int y = blockIdx.x, b = blockIdx.y;
    int tid = threadIdx.x;
    for (int e = tid; e < 192 * 64; e += 256) ws[e] = w[e];
    for (int e = tid; e < 64 * 28; e += 256) {
        int c = e / 28, xx = e % 28;
        xin[e] = o[((size_t)b * 64 + c) * 784 + y * 28 + xx];
    }
    __syncthreads();
    for (int e = tid; e < 192 * 28; e += 256) {
        int oc = e / 28, xx = e % 28;
        float a = bias[oc];
        const float* wr = ws + oc * 64;
        #pragma unroll 16
        for (int c = 0; c < 64; c++) a += xin[c * 28 + xx] * wr[c];
        g_bfqkv[((size_t)b * 192 + oc) * 784 + y * 28 + xx] = a;
    }
}

__global__ void bf_routing_kernel() {
    int b = blockIdx.x;
    int tid = threadIdx.x;  // 256
    __shared__ float qr[64][NREG];
    __shared__ float kr[64][NREG];
    __shared__ float ar[NREG][NREG];
    for (int e = tid; e < 64 * NREG; e += 256) {
        int c = e / NREG, r = e % NREG;
        int rh = r / 7, rw = r % 7;
        float sq = 0.f, sk = 0.f;
        const float* qc = g_bfqkv + ((size_t)b * 192 + c) * 784;
        const float* kc = g_bfqkv + ((size_t)b * 192 + 64 + c) * 784;
        #pragma unroll
        for (int pr = 0; pr < 4; pr++)
            #pragma unroll
            for (int pc = 0; pc < 4; pc++) {
                int s = (rh * 4 + pr) * 28 + rw * 4 + pc;
                sq += qc[s]; sk += kc[s];
            }
        qr[c][r] = sq * 0.0625f;
        kr[c][r] = sk * 0.0625f;
    }
    __syncthreads();
    for (int e = tid; e < NREG * NREG; e += 256) {
        int i = e / NREG, j = e % NREG;
        float a = 0.f;
        #pragma unroll 16
        for (int c = 0; c < 64; c++) a += qr[c][i] * kr[c][j];
        ar[i][j] = a;
    }
    __syncthreads();
    if (tid < NREG) {
        float* row = ar[tid];
        #pragma unroll
        for (int j = 0; j < TOPK; j++) {
            float mx = -1e30f; int mi = 0;
            for (int s = 0; s < NREG; s++) if (row[s] > mx) { mx = row[s]; mi = s; }
            row[mi] = -1e30f;
            g_idx[(b * NREG + tid) * TOPK + j] = mi;
        }
    }
}

__global__ void bf_attn_kernel() {
    int r = blockIdx.x, h = blockIdx.y, b = blockIdx.z;
    __shared__ float q[16][8], kg[64][9], vg[64][9];
    __shared__ float sc[16][65];
    __shared__ int idx4[4];
    int tid = threadIdx.x;  // 128
    if (tid < 4) idx4[tid] = g_idx[(b * NREG + r) * TOPK + tid];
    int rh = r / 7, rw = r % 7;
    {
        int p = tid / 8, d = tid % 8;
        int s = (rh * 4 + p / 4) * 28 + rw * 4 + (p % 4);
        q[p][d] = g_bfqkv[((size_t)b * 192 + h * 8 + d) * 784 + s] * 0.125f;
    }
    __syncthreads();
    for (int e = tid; e < 512; e += 128) {
        int t = e / 8, d = e % 8;
        int reg = idx4[t / 16];
        int p2 = t % 16;
        int s = ((reg / 7) * 4 + p2 / 4) * 28 + (reg % 7) * 4 + (p2 % 4);
        kg[t][d] = g_bfqkv[((size_t)b * 192 + 64 + h * 8 + d) * 784 + s];
        vg[t][d] = g_bfqkv[((size_t)b * 192 + 128 + h * 8 + d) * 784 + s];
    }
    __syncthreads();
    {
        int p = tid >> 3, tg = tid & 7;
        float qreg[8];
        #pragma unroll
        for (int d = 0; d < 8; d++) qreg[d] = q[p][d];
        #pragma unroll
        for (int tt = 0; tt < 8; tt++) {
            int t = tt * 8 + tg;
            float a = 0.f;
            #pragma unroll
            for (int d = 0; d < 8; d++) a += qreg[d] * kg[t][d];
            sc[p][t] = a;
        }
    }
    __syncthreads();
    if (tid < 16) {
        float mx = -1e30f;
        for (int t = 0; t < 64; t++) mx = fmaxf(mx, sc[tid][t]);
        float s = 0.f;
        for (int t = 0; t < 64; t++) { float e = expf(sc[tid][t] - mx); sc[tid][t] = e; s += e; }
        float inv = 1.f / s;
        for (int t = 0; t < 64; t++) sc[tid][t] *= inv;
    }
    __syncthreads();
    {
        int p = tid / 8, d = tid % 8;
        float a = 0.f;
        #pragma unroll 8
        for (int t = 0; t < 64; t++) a += sc[p][t] * vg[t][d];
        int s = (rh * 4 + p / 4) * 28 + rw * 4 + (p % 4);
        g_attg[((size_t)b * 64 + h * 8 + d) * 784 + s] = a;
    }
}

__global__ void bf_out_kernel(const float* __restrict__ lepe_w, const float* __restrict__ lepe_b,
                              const float* __restrict__ out_w, const float* __restrict__ out_b,
                              float* __restrict__ outp) {
    int y = blockIdx.x, b = blockIdx.y;
    __shared__ float v3[3][64][28];
    __shared__ float tmp[64][28];
    __shared__ float ws[64][64];
    __shared__ float lw[64][9];
    int tid = threadIdx.x;
    for (int e = tid; e < 64 * 64; e += blockDim.x) ws[e >> 6][e & 63] = out_w[e];
    for (int e = tid; e < 64 * 9; e += blockDim.x) lw[e / 9][e % 9] = lepe_w[e];
    for (int ry = 0; ry < 3; ry++) {
        int yy = y + ry - 1;
        for (int e = tid; e < 64 * 28; e += blockDim.x) {
            int c = e / 28, xx = e % 28;
            v3[ry][c][xx] = (yy >= 0 && yy < 28)
                ? g_bfqkv[((size_t)b * 192 + 128 + c) * 784 + yy * 28 + xx] : 0.f;
        }
    }
    __syncthreads();
    for (int e = tid; e < 64 * 28; e += blockDim.x) {
        int c = e / 28, xx = e % 28;
        float a = g_attg[((size_t)b * 64 + c) * 784 + y * 28 + xx] + lepe_b[c];
        #pragma unroll
        for (int ky = 0; ky < 3; ky++)
            #pragma unroll
            for (int kx = 0; kx < 3; kx++) {
                int xx2 = xx + kx - 1;
                if (xx2 >= 0 && xx2 < 28) a += v3[ky][c][xx2] * lw[c][ky * 3 + kx];
            }
        tmp[c][xx] = a;
    }
    __syncthreads();
    for (int e = tid; e < 64 * 28; e += blockDim.x) {
        int oc = e / 28, xx = e % 28;
        float a = out_b[oc];
        const float* wr = ws[oc];
        #pragma unroll 16
        for (int c = 0; c < 64; c++) a += tmp[c][xx] * wr[c];
        outp[((size_t)b * 64 + oc) * 784 + y * 28 + xx] = a;
    }
}

// ---------------- launch ----------------
extern "C" void kernel_launch(void* const* d_in, const int* in_sizes, int n_in,
                              void* d_out, int out_size) {
    (void)in_sizes; (void)n_in; (void)out_size;
    const float* x        = (const float*)d_in[0];
    const float* norm1_g  = (const float*)d_in[1];
    const float* norm1_b  = (const float*)d_in[2];
    const float* qkv_w    = (const float*)d_in[3];
    const float* proj_w   = (const float*)d_in[4];
    const float* proj_b   = (const float*)d_in[5];
    const float* norm2_g  = (const float*)d_in[6];
    const float* norm2_b  = (const float*)d_in[7];
    const float* fc1_w    = (const float*)d_in[8];
    const float* fc1_b    = (const float*)d_in[9];
    const float* fc2_w    = (const float*)d_in[10];
    const float* fc2_b    = (const float*)d_in[11];
    const float* bf_qkv_w = (const float*)d_in[12];
    const float* bf_qkv_b = (const float*)d_in[13];
    const float* bf_lepe_w= (const float*)d_in[14];
    const float* bf_lepe_b= (const float*)d_in[15];
    const float* bf_out_w = (const float*)d_in[16];
    const float* bf_out_b = (const float*)d_in[17];
    float* out = (float*)d_out;

    __nv_bfloat16 *p_h_hi, *p_h_lo, *p_att_hi, *p_att_lo;
    __nv_bfloat16 *p_wqkv_hi, *p_wqkv_lo, *p_wproj_hi, *p_wproj_lo;
    __half *p_h2, *p_hid, *p_wfc1, *p_wfc2;
    float *p_qkv, *p_o, *p_xr;
    cudaGetSymbolAddress((void**)&p_h_hi, g_h_hi);     cudaGetSymbolAddress((void**)&p_h_lo, g_h_lo);
    cudaGetSymbolAddress((void**)&p_att_hi, g_att_hi); cudaGetSymbolAddress((void**)&p_att_lo, g_att_lo);
    cudaGetSymbolAddress((void**)&p_h2, g_h2);
    cudaGetSymbolAddress((void**)&p_hid, g_hid);
    cudaGetSymbolAddress((void**)&p_wqkv_hi, g_wqkv_hi);   cudaGetSymbolAddress((void**)&p_wqkv_lo, g_wqkv_lo);
    cudaGetSymbolAddress((void**)&p_wproj_hi, g_wproj_hi); cudaGetSymbolAddress((void**)&p_wproj_lo, g_wproj_lo);
    cudaGetSymbolAddress((void**)&p_wfc1, g_wfc1);
    cudaGetSymbolAddress((void**)&p_wfc2, g_wfc2);
    cudaGetSymbolAddress((void**)&p_qkv, g_qkv);
    cudaGetSymbolAddress((void**)&p_o, g_o);
    cudaGetSymbolAddress((void**)&p_xr, g_xr);

    cudaFuncSetAttribute(mha_kernel, cudaFuncAttributeMaxDynamicSharedMemorySize, MHA_SMEM);
    cudaFuncSetAttribute(bf_qkv_kernel, cudaFuncAttributeMaxDynamicSharedMemorySize, BFQ_SMEM);
    cudaFuncSetAttribute(mma_gemm3<0>, cudaFuncAttributeMaxDynamicSharedMemorySize, GEMM3_SMEM);
    cudaFuncSetAttribute(mma_gemm3<1>, cudaFuncAttributeMaxDynamicSharedMemorySize, GEMM3_SMEM);
    cudaFuncSetAttribute(mma_gemm2<2>, cudaFuncAttributeMaxDynamicSharedMemorySize, GEMM2_SMEM);
    cudaFuncSetAttribute(mma_gemm2<3>, cudaFuncAttributeMaxDynamicSharedMemorySize, GEMM2_SMEM);

    static cudaStream_t s1 = nullptr;
    static cudaEvent_t eFork = nullptr, eW = nullptr, eO = nullptr, eBF = nullptr;
    if (!s1) {
        cudaStreamCreateWithFlags(&s1, cudaStreamNonBlocking);
        cudaEventCreateWithFlags(&eFork, cudaEventDisableTiming);
        cudaEventCreateWithFlags(&eW,    cudaEventDisableTiming);
        cudaEventCreateWithFlags(&eO,    cudaEventDisableTiming);
        cudaEventCreateWithFlags(&eBF,   cudaEventDisableTiming);
    }

    // s0: LN1 (#1) and qkv split (#2) — gemm3 depends on both via stream order
    ln_kernel<<<ROWS, 256>>>(x, norm1_g, norm1_b, p_h_hi, p_h_lo);
    split_bf_kernel<<<(Cdim * 3 * Cdim / 4 + 255) / 256, 256>>>(qkv_w, p_wqkv_hi, p_wqkv_lo, Cdim * 3 * Cdim / 4);

    // fork
    cudaEventRecord(eFork, 0);
    cudaStreamWaitEvent(s1, eFork, 0);

    // s1: proj split (#3)
    split_bf_kernel<<<(Cdim * Cdim / 4 + 255) / 256, 256, 0, s1>>>(proj_w, p_wproj_hi, p_wproj_lo, Cdim * Cdim / 4);

    // s0: qkv GEMM (#4 — ncu capture target)
    mma_gemm3<0><<<dim3((3 * Cdim + 127) / 128, ROWS / 128), 256, GEMM3_SMEM>>>(
        p_h_hi, p_h_lo, p_wqkv_hi, p_wqkv_lo, nullptr,
        p_qkv, ROWS, 3 * Cdim, Cdim);

    // s1: fc weight converts (#5, #6) — overlap with qkv GEMM
    conv_fp_kernel<<<(Cdim * HID / 4 + 255) / 256, 256, 0, s1>>>(fc1_w, p_wfc1, Cdim * HID / 4);
    conv_fp_kernel<<<(HID * Cdim / 4 + 255) / 256, 256, 0, s1>>>(fc2_w, p_wfc2, HID * Cdim / 4);
    cudaEventRecord(eW, s1);

    // s0: MHA, proj
    mha_kernel<<<dim3(NHd, Bsz), 256, MHA_SMEM>>>(p_qkv, p_att_hi, p_att_lo);
    cudaStreamWaitEvent(0, eW, 0);
    mma_gemm3<1><<<dim3((Cdim + 127) / 128, ROWS / 128), 256, GEMM3_SMEM>>>(
        p_att_hi, p_att_lo, p_wproj_hi, p_wproj_lo, proj_b,
        p_o, ROWS, Cdim, Cdim);
    cudaEventRecord(eO, 0);

    // s1: BiFormer branch
    cudaStreamWaitEvent(s1, eO, 0);
    bf_qkv_kernel<<<dim3(28, Bsz), 256, BFQ_SMEM, s1>>>(p_o, bf_qkv_w, bf_qkv_b);
    bf_routing_kernel<<<Bsz, 256, 0, s1>>>();
    bf_attn_kernel<<<dim3(NREG, 8, Bsz), 128, 0, s1>>>();
    bf_out_kernel<<<dim3(28, Bsz), 256, 0, s1>>>(bf_lepe_w, bf_lepe_b, bf_out_w, bf_out_b, out + OUT_OFF);
    cudaEventRecord(eBF, s1);

    // s0: MLP branch
    ln2_kernel<<<ROWS, 256>>>(p_o, x, norm2_g, norm2_b, p_xr, p_h2);
    mma_gemm2<2><<<dim3((HID + 127) / 128, ROWS / 128), 256, GEMM2_SMEM>>>(
        p_h2, p_wfc1, fc1_b, nullptr,
        nullptr, p_hid, ROWS, HID, Cdim);
    mma_gemm2<3><<<dim3((Cdim + 127) / 128, ROWS / 128), 256, GEMM2_SMEM>>>(
        p_hid, p_wfc2, fc2_b, p_xr,
        out, nullptr, ROWS, Cdim, HID);

    // join
    cudaStreamWaitEvent(0, eBF, 0);
}

// round 16
// speedup vs baseline: 2.1940x; 1.0007x over previous
#include <cuda_runtime.h>
#include <cuda_bf16.h>
#include <cuda_fp16.h>
#include <math.h>
#include <stdint.h>

// ---------------- problem constants ----------------
#define Bsz   128
#define NTOK  64
#define Cdim  784
#define NHd   8
#define HD    98
#define HDP   99
#define HID   3136
#define ROWS  (Bsz*NTOK)  // 8192
#define NREG  49
#define TOPK  4
#define OUT_OFF (Bsz*NTOK*Cdim)

// ---------------- scratch ----------------
__device__ __nv_bfloat16 g_h_hi [ROWS*Cdim];
__device__ __nv_bfloat16 g_h_lo [ROWS*Cdim];
__device__ float         g_qkv  [ROWS*3*Cdim];
__device__ __nv_bfloat16 g_att_hi[ROWS*Cdim];
__device__ __nv_bfloat16 g_att_lo[ROWS*Cdim];
__device__ float         g_o    [ROWS*Cdim];
__device__ float         g_xr   [ROWS*Cdim];
__device__ __half        g_h2   [ROWS*Cdim];
__device__ __half        g_hid  [ROWS*HID];
// weight splits [K, N]
__device__ __nv_bfloat16 g_wqkv_hi[Cdim*3*Cdim];
__device__ __nv_bfloat16 g_wqkv_lo[Cdim*3*Cdim];
__device__ __nv_bfloat16 g_wproj_hi[Cdim*Cdim];
__device__ __nv_bfloat16 g_wproj_lo[Cdim*Cdim];
__device__ __half        g_wfc1 [Cdim*HID];
__device__ __half        g_wfc2 [HID*Cdim];
// biformer
__device__ float g_bfqkv[Bsz*192*784];
__device__ float g_attg [Bsz*64*784];
__device__ int   g_idx [Bsz*NREG*TOPK];

// ---------------- helpers ----------------
__device__ __forceinline__ uint32_t smem_u32(const void* p) {
    return (uint32_t)__cvta_generic_to_shared(p);
}
#define CP_ASYNC16(dst_u32, src, sz) \
    asm volatile("cp.async.cg.shared.global [%0], [%1], 16, %2;\n" :: "r"(dst_u32), "l"(src), "r"(sz))
#define CP_COMMIT() asm volatile("cp.async.commit_group;\n")
#define LDSM4(r0,r1,r2,r3,a) \
    asm volatile("ldmatrix.sync.aligned.m8n8.x4.shared.b16 {%0,%1,%2,%3},[%4];" \
        : "=r"(r0),"=r"(r1),"=r"(r2),"=r"(r3) : "r"(a))
#define LDSM4T(r0,r1,r2,r3,a) \
    asm volatile("ldmatrix.sync.aligned.m8n8.x4.trans.shared.b16 {%0,%1,%2,%3},[%4];" \
        : "=r"(r0),"=r"(r1),"=r"(r2),"=r"(r3) : "r"(a))
#define MMA_BF16(d, a, b) \
    asm volatile("mma.sync.aligned.m16n8k16.row.col.f32.bf16.bf16.f32 " \
        "{%0,%1,%2,%3},{%4,%5,%6,%7},{%8,%9},{%0,%1,%2,%3};" \
        : "+f"(d[0]),"+f"(d[1]),"+f"(d[2]),"+f"(d[3]) \
        : "r"(a[0]),"r"(a[1]),"r"(a[2]),"r"(a[3]),"r"(b[0]),"r"(b[1]))
#define MMA_FP16(d, a, b) \
    asm volatile("mma.sync.aligned.m16n8k16.row.col.f32.f16.f16.f32 " \
        "{%0,%1,%2,%3},{%4,%5,%6,%7},{%8,%9},{%0,%1,%2,%3};" \
        : "+f"(d[0]),"+f"(d[1]),"+f"(d[2]),"+f"(d[3]) \
        : "r"(a[0]),"r"(a[1]),"r"(a[2]),"r"(a[3]),"r"(b[0]),"r"(b[1]))

__device__ __forceinline__ void split_write_bf(float v, __nv_bfloat16* hi, __nv_bfloat16* lo, size_t o) {
    __nv_bfloat16 h = __float2bfloat16(v);
    hi[o] = h;
    lo[o] = __float2bfloat16(v - __bfloat162float(h));
}

// ---------------- weight prep (float4 vectorized) ----------------
__global__ void split_bf_kernel(const float* __restrict__ in, __nv_bfloat16* __restrict__ hi,
                                __nv_bfloat16* __restrict__ lo, int n4) {
    int i = blockIdx.x * blockDim.x + threadIdx.x;
    if (i < n4) {
        float4 v = ((const float4*)in)[i];
        __nv_bfloat16 h0 = __float2bfloat16(v.x), h1 = __float2bfloat16(v.y);
        __nv_bfloat16 h2 = __float2bfloat16(v.z), h3 = __float2bfloat16(v.w);
        ((__nv_bfloat162*)hi)[i * 2]     = __nv_bfloat162(h0, h1);
        ((__nv_bfloat162*)hi)[i * 2 + 1] = __nv_bfloat162(h2, h3);
        ((__nv_bfloat162*)lo)[i * 2]     = __nv_bfloat162(
            __float2bfloat16(v.x - __bfloat162float(h0)), __float2bfloat16(v.y - __bfloat162float(h1)));
        ((__nv_bfloat162*)lo)[i * 2 + 1] = __nv_bfloat162(
            __float2bfloat16(v.z - __bfloat162float(h2)), __float2bfloat16(v.w - __bfloat162float(h3)));
    }
}
__global__ void conv_fp_kernel(const float* __restrict__ in, __half* __restrict__ o, int n4) {
    int i = blockIdx.x * blockDim.x + threadIdx.x;
    if (i < n4) {
        float4 v = ((const float4*)in)[i];
        ((__half2*)o)[i * 2]     = __floats2half2_rn(v.x, v.y);
        ((__half2*)o)[i * 2 + 1] = __floats2half2_rn(v.z, v.w);
    }
}

// ---------------- LN1: x -> (h_hi, h_lo) bf16 (float4) ----------------
__global__ void ln_kernel(const float* __restrict__ x,
                          const float* __restrict__ g, const float* __restrict__ b,
                          __nv_bfloat16* __restrict__ ohi, __nv_bfloat16* __restrict__ olo) {
    int row = blockIdx.x;
    const float4* xr4 = (const float4*)(x + (size_t)row * Cdim);
    __shared__ float4 buf[Cdim / 4];
    __shared__ float rs[2];
    __shared__ float red[64];
    int tid = threadIdx.x;
    float s = 0.f, ss = 0.f;
    float4 v;
    if (tid < Cdim / 4) {
        v = xr4[tid];
        buf[tid] = v;
        s = v.x + v.y + v.z + v.w;
        ss = v.x * v.x + v.y * v.y + v.z * v.z + v.w * v.w;
    }
    for (int o = 16; o > 0; o >>= 1) { s += __shfl_down_sync(~0u, s, o); ss += __shfl_down_sync(~0u, ss, o); }
    int wid = tid >> 5, lid = tid & 31;
    if (lid == 0) { red[wid] = s; red[wid + 32] = ss; }
    __syncthreads();
    if (tid == 0) {
        float t = 0.f, tt = 0.f;
        int nw = blockDim.x >> 5;
        for (int i = 0; i < nw; i++) { t += red[i]; tt += red[i + 32]; }
        float mean = t / Cdim, var = tt / Cdim - mean * mean;
        rs[0] = mean; rs[1] = rsqrtf(var + 1e-5f);
    }
    __syncthreads();
    float mean = rs[0], inv = rs[1];
    if (tid < Cdim / 4) {
        v = buf[tid];
        float4 gv = ((const float4*)g)[tid];
        float4 bv = ((const float4*)b)[tid];
        float o0 = (v.x - mean) * inv * gv.x + bv.x;
        float o1 = (v.y - mean) * inv * gv.y + bv.y;
        float o2 = (v.z - mean) * inv * gv.z + bv.z;
        float o3 = (v.w - mean) * inv * gv.w + bv.w;
        size_t base2 = ((size_t)row * Cdim) / 2 + tid * 2;
        __nv_bfloat16 h0 = __float2bfloat16(o0), h1 = __float2bfloat16(o1);
        __nv_bfloat16 h2 = __float2bfloat16(o2), h3 = __float2bfloat16(o3);
        ((__nv_bfloat162*)ohi)[base2]     = __nv_bfloat162(h0, h1);
        ((__nv_bfloat162*)ohi)[base2 + 1] = __nv_bfloat162(h2, h3);
        ((__nv_bfloat162*)olo)[base2]     = __nv_bfloat162(
            __float2bfloat16(o0 - __bfloat162float(h0)), __float2bfloat16(o1 - __bfloat162float(h1)));
        ((__nv_bfloat162*)olo)[base2 + 1] = __nv_bfloat162(
            __float2bfloat16(o2 - __bfloat162float(h2)), __float2bfloat16(o3 - __bfloat162float(h3)));
    }
}

// ---------------- LN2: xr = o + x (fp32), h2 fp16 (float4) ----------------
__global__ void ln2_kernel(const float* __restrict__ ov, const float* __restrict__ x,
                           const float* __restrict__ g, const float* __restrict__ b,
                           float* __restrict__ xr_out, __half* __restrict__ oh) {
    int row = blockIdx.x;
    const float4* a4 = (const float4*)(ov + (size_t)row * Cdim);
    const float4* c4 = (const float4*)(x + (size_t)row * Cdim);
    __shared__ float4 buf[Cdim / 4];
    __shared__ float rs[2];
    __shared__ float red[64];
    int tid = threadIdx.x;
    float s = 0.f, ss = 0.f;
    if (tid < Cdim / 4) {
        float4 av = a4[tid], cv = c4[tid];
        float4 v = make_float4(av.x + cv.x, av.y + cv.y, av.z + cv.z, av.w + cv.w);
        buf[tid] = v;
        ((float4*)(xr_out + (size_t)row * Cdim))[tid] = v;
        s = v.x + v.y + v.z + v.w;
        ss = v.x * v.x + v.y * v.y + v.z * v.z + v.w * v.w;
    }
    for (int o = 16; o > 0; o >>= 1) { s += __shfl_down_sync(~0u, s, o); ss += __shfl_down_sync(~0u, ss, o); }
    int wid = tid >> 5, lid = tid & 31;
    if (lid == 0) { red[wid] = s; red[wid + 32] = ss; }
    __syncthreads();
    if (tid == 0) {
        float t = 0.f, tt = 0.f;
        int nw = blockDim.x >> 5;
        for (int i = 0; i < nw; i++) { t += red[i]; tt += red[i + 32]; }
        float mean = t / Cdim, var = tt / Cdim - mean * mean;
        rs[0] = mean; rs[1] = rsqrtf(var + 1e-5f);
    }
    __syncthreads();
    float mean = rs[0], inv = rs[1];
    if (tid < Cdim / 4) {
        float4 v = buf[tid];
        float4 gv = ((const float4*)g)[tid];
        float4 bv = ((const float4*)b)[tid];
        size_t base2 = ((size_t)row * Cdim) / 2 + tid * 2;
        ((__half2*)oh)[base2] = __floats2half2_rn(
            (v.x - mean) * inv * gv.x + bv.x, (v.y - mean) * inv * gv.y + bv.y);
        ((__half2*)oh)[base2 + 1] = __floats2half2_rn(
            (v.z - mean) * inv * gv.z + bv.z, (v.w - mean) * inv * gv.w + bv.w);
    }
}

// ===== bf16x3 GEMM (qkv, proj) — BK=32, 3-stage, single barrier, 2 CTAs/SM =====
#define ASTR3 40
#define BSTR3 136
#define A3_ST (2*128*ASTR3)
#define B3_ST (2*32*BSTR3)
#define GEMM3_SMEM (3*(A3_ST + B3_ST) * 2)  // 113664

template<int EP>
__global__ __launch_bounds__(256, 2)
void mma_gemm3(const __nv_bfloat16* __restrict__ Ah, const __nv_bfloat16* __restrict__ Al,
               const __nv_bfloat16* __restrict__ Bh, const __nv_bfloat16* __restrict__ Bl,
               const float* __restrict__ bias,
               float* __restrict__ Cf, int M, int N, int K) {
    extern __shared__ __nv_bfloat16 sm3[];
    __nv_bfloat16* Asm = sm3;
    __nv_bfloat16* Bsm = sm3 + 3 * A3_ST;

    int tid = threadIdx.x;
    int warp = tid >> 5, lane = tid & 31;
    int wm = warp & 1, wn = warp >> 1;
    int rowBase = blockIdx.y * 128, colBase = blockIdx.x * 128;

    const int KT = (K + 31) >> 5;
    float acc[4][4][4];
    #pragma unroll
    for (int i = 0; i < 4; i++)
        #pragma unroll
        for (int j = 0; j < 4; j++)
            #pragma unroll
            for (int q = 0; q < 4; q++) acc[i][j][q] = 0.f;

    auto load_stage = [&](int st, int kt) {
        int koff = kt * 32;
        __nv_bfloat16* Ast = Asm + st * A3_ST;
        __nv_bfloat16* Bst = Bsm + st * B3_ST;
        #pragma unroll
        for (int part = 0; part < 2; part++) {
            const __nv_bfloat16* Aasrc = part ? Al : Ah;
            #pragma unroll
            for (int i = 0; i < 2; i++) {
                int chunk = i * 256 + tid;
                int r = chunk >> 2, cc = (chunk & 3) * 8;
                int k = koff + cc;
                uint32_t dst = smem_u32(Ast + part * (128 * ASTR3) + r * ASTR3 + cc);
                const __nv_bfloat16* src = Aasrc + (size_t)(rowBase + r) * K + (k < K ? k : 0);
                CP_ASYNC16(dst, src, (k < K) ? 16 : 0);
            }
        }
        #pragma unroll
        for (int part = 0; part < 2; part++) {
            const __nv_bfloat16* Bbsrc = part ? Bl : Bh;
            #pragma unroll
            for (int i = 0; i < 2; i++) {
                int chunk = i * 256 + tid;
                int r = chunk >> 4, cc = (chunk & 15) * 8;
                int k = koff + r, n = colBase + cc;
                bool ok = (k < K) && (n < N);
                uint32_t dst = smem_u32(Bst + part * (32 * BSTR3) + r * BSTR3 + cc);
                const __nv_bfloat16* src = Bbsrc + (ok ? ((size_t)k * N + n) : 0);
                CP_ASYNC16(dst, src, ok ? 16 : 0);
            }
        }
    };

    load_stage(0, 0); CP_COMMIT();
    if (KT > 1) { load_stage(1, 1); }
    CP_COMMIT();

    int lrow = lane & 15, lhalf = (lane >> 4) * 8;

    for (int kt = 0; kt < KT; kt++) {
        if (kt + 1 < KT) { asm volatile("cp.async.wait_group 1;"); }
        else             { asm volatile("cp.async.wait_group 0;"); }
        __syncthreads();
        if (kt + 2 < KT) { load_stage((kt + 2) % 3, kt + 2); CP_COMMIT(); }

        int st = kt % 3;
        __nv_bfloat16* Ast = Asm + st * A3_ST;
        __nv_bfloat16* Bst = Bsm + st * B3_ST;

        #pragma unroll
        for (int kk = 0; kk < 32; kk += 16) {
            uint32_t ah[4][4], bh[4][2], bl[4][2];
            #pragma unroll
            for (int mi = 0; mi < 4; mi++) {
                uint32_t a0 = smem_u32(Ast + (wm * 64 + mi * 16 + lrow) * ASTR3 + kk + lhalf);
                LDSM4(ah[mi][0], ah[mi][1], ah[mi][2], ah[mi][3], a0);
            }
            #pragma unroll
            for (int pr = 0; pr < 2; pr++) {
                uint32_t r0, r1, r2, r3;
                uint32_t b0 = smem_u32(Bst + (kk + lrow) * BSTR3 + wn * 32 + pr * 16 + lhalf);
                LDSM4T(r0, r1, r2, r3, b0);
                bh[pr * 2][0] = r0; bh[pr * 2][1] = r1; bh[pr * 2 + 1][0] = r2; bh[pr * 2 + 1][1] = r3;
                uint32_t b1 = smem_u32(Bst + 32 * BSTR3 + (kk + lrow) * BSTR3 + wn * 32 + pr * 16 + lhalf);
                LDSM4T(r0, r1, r2, r3, b1);
                bl[pr * 2][0] = r0; bl[pr * 2][1] = r1; bl[pr * 2 + 1][0] = r2; bl[pr * 2 + 1][1] = r3;
            }
            #pragma unroll
            for (int mi = 0; mi < 4; mi++)
                #pragma unroll
                for (int ni = 0; ni < 4; ni++) {
                    MMA_BF16(acc[mi][ni], ah[mi], bh[ni]);
                    MMA_BF16(acc[mi][ni], ah[mi], bl[ni]);
                }
            uint32_t al[4][4];
            #pragma unroll
            for (int mi = 0; mi < 4; mi++) {
                uint32_t a1 = smem_u32(Ast + 128 * ASTR3 + (wm * 64 + mi * 16 + lrow) * ASTR3 + kk + lhalf);
                LDSM4(al[mi][0], al[mi][1], al[mi][2], al[mi][3], a1);
            }
            #pragma unroll
            for (int mi = 0; mi < 4; mi++)
                #pragma unroll
                for (int ni = 0; ni < 4; ni++)
                    MMA_BF16(acc[mi][ni], al[mi], bh[ni]);
        }
    }

    #pragma unroll
    for (int mi = 0; mi < 4; mi++) {
        int r0 = rowBase + wm * 64 + mi * 16 + (lane >> 2);
        #pragma unroll
        for (int ni = 0; ni < 4; ni++) {
            int c0 = colBase + wn * 32 + ni * 8 + (lane & 3) * 2;
            #pragma unroll
            for (int q = 0; q < 4; q++) {
                int r = r0 + (q >> 1) * 8;
                int c = c0 + (q & 1);
                if (c < N) {
                    float v = acc[mi][ni][q];
                    if (EP >= 1) v += bias[c];
                    Cf[(size_t)r * N + c] = v;
                }
            }
        }
    }
}

// ===== fp16 single-term GEMM (fc1, fc2) — BK=32, 3-stage, single barrier, 2 CTAs/SM =====
#define ASTR2 40
#define BSTR2 136
#define A2_ST (128*ASTR2)
#define B2_ST (32*BSTR2)
#define GEMM2_SMEM (3*(A2_ST + B2_ST) * 2)  // 56832

template<int EP>
__global__ __launch_bounds__(256, 2)
void mma_gemm2(const __half* __restrict__ A, const __half* __restrict__ B,
               const float* __restrict__ bias, const float* __restrict__ res,
               float* __restrict__ Cf, __half* __restrict__ Ch,
               int M, int N, int K) {
    extern __shared__ __half sm2[];
    __half* Asm = sm2;
    __half* Bsm = sm2 + 3 * A2_ST;

    int tid = threadIdx.x;
    int warp = tid >> 5, lane = tid & 31;
    int wm = warp & 1, wn = warp >> 1;
    int rowBase = blockIdx.y * 128, colBase = blockIdx.x * 128;

    const int KT = (K + 31) >> 5;
    float acc[4][4][4];
    #pragma unroll
    for (int i = 0; i < 4; i++)
        #pragma unroll
        for (int j = 0; j < 4; j++)
            #pragma unroll
            for (int q = 0; q < 4; q++) acc[i][j][q] = 0.f;

    auto load_stage = [&](int st, int kt) {
        int koff = kt * 32;
        __half* Ast = Asm + st * A2_ST;
        __half* Bst = Bsm + st * B2_ST;
        #pragma unroll
        for (int i = 0; i < 2; i++) {
            int chunk = i * 256 + tid;
            int r = chunk >> 2, cc = (chunk & 3) * 8;
            int k = koff + cc;
            uint32_t dst = smem_u32(Ast + r * ASTR2 + cc);
            const __half* src = A + (size_t)(rowBase + r) * K + (k < K ? k : 0);
            CP_ASYNC16(dst, src, (k < K) ? 16 : 0);
        }
        #pragma unroll
        for (int i = 0; i < 2; i++) {
            int chunk = i * 256 + tid;
            int r = chunk >> 4, cc = (chunk & 15) * 8;
            int k = koff + r, n = colBase + cc;
            bool ok = (k < K) && (n < N);
            uint32_t dst = smem_u32(Bst + r * BSTR2 + cc);
            const __half* src = B + (ok ? ((size_t)k * N + n) : 0);
            CP_ASYNC16(dst, src, ok ? 16 : 0);
        }
    };

    load_stage(0, 0); CP_COMMIT();
    if (KT > 1) { load_stage(1, 1); }
    CP_COMMIT();

    int lrow = lane & 15, lhalf = (lane >> 4) * 8;

    for (int kt = 0; kt < KT; kt++) {
        if (kt + 1 < KT) { asm volatile("cp.async.wait_group 1;"); }
        else             { asm volatile("cp.async.wait_group 0;"); }
        __syncthreads();
        if (kt + 2 < KT) { load_stage((kt + 2) % 3, kt + 2); CP_COMMIT(); }

        int st = kt % 3;
        __half* Ast = Asm + st * A2_ST;
        __half* Bst = Bsm + st * B2_ST;

        #pragma unroll
        for (int kk = 0; kk < 32; kk += 16) {
            uint32_t a[4][4], bb[4][2];
            #pragma unroll
            for (int mi = 0; mi < 4; mi++) {
                uint32_t a0 = smem_u32(Ast + (wm * 64 + mi * 16 + lrow) * ASTR2 + kk + lhalf);
                LDSM4(a[mi][0], a[mi][1], a[mi][2], a[mi][3], a0);
            }
            #pragma unroll
            for (int pr = 0; pr < 2; pr++) {
                uint32_t r0, r1, r2, r3;
                uint32_t b0 = smem_u32(Bst + (kk + lrow) * BSTR2 + wn * 32 + pr * 16 + lhalf);
                LDSM4T(r0, r1, r2, r3, b0);
                bb[pr * 2][0] = r0; bb[pr * 2][1] = r1; bb[pr * 2 + 1][0] = r2; bb[pr * 2 + 1][1] = r3;
            }
            #pragma unroll
            for (int mi = 0; mi < 4; mi++)
                #pragma unroll
                for (int ni = 0; ni < 4; ni++)
                    MMA_FP16(acc[mi][ni], a[mi], bb[ni]);
        }
    }

    #pragma unroll
    for (int mi = 0; mi < 4; mi++) {
        int r0 = rowBase + wm * 64 + mi * 16 + (lane >> 2);
        #pragma unroll
        for (int ni = 0; ni < 4; ni++) {
            int c0 = colBase + wn * 32 + ni * 8 + (lane & 3) * 2;
            #pragma unroll
            for (int q = 0; q < 4; q++) {
                int r = r0 + (q >> 1) * 8;
                int c = c0 + (q & 1);
                if (c < N) {
                    float v = acc[mi][ni][q] + bias[c];
                    size_t o = (size_t)r * N + c;
                    if (EP == 2) {
                        v = 0.5f * v * (1.0f + erff(v * 0.70710678118654752440f));
                        Ch[o] = __float2half(v);
                    } else {
                        v += res[o];
                        Cf[o] = v;
                    }
                }
            }
        }
    }
}

// ---------------- MHA (register-tiled) -> att bf16 split ----------------
#define MHA_SMEM ((3*64*HDP + 64*64)*4)
__global__ void mha_kernel(const float* __restrict__ qkv,
                           __nv_bfloat16* __restrict__ ahi, __nv_bfloat16* __restrict__ alo) {
    extern __shared__ float smf[];
    float* Q  = smf;
    float* Kx = Q + 64 * HDP;
    float* V  = Kx + 64 * HDP;
    float* SC = V + 64 * HDP;
    int h = blockIdx.x, b = blockIdx.y;
    int tid = threadIdx.x;
    const float* base = qkv + (size_t)(b * NTOK) * (3 * Cdim);
    for (int e = tid; e < 64 * HD; e += 256) {
        int t = e / HD, d = e % HD;
        Q[t * HDP + d]  = base[(size_t)t * (3 * Cdim) + h * HD + d];
        Kx[t * HDP + d] = base[(size_t)t * (3 * Cdim) + Cdim + h * HD + d];
        V[t * HDP + d]  = base[(size_t)t * (3 * Cdim) + 2 * Cdim + h * HD + d];
    }
    __syncthreads();
    const float scale = rsqrtf((float)HD);
    {
        int ti = tid >> 4, tj = tid & 15;
        float acc[4][4] = {};
        #pragma unroll 2
        for (int d = 0; d < HD; d++) {
            float qv[4], kv[4];
            #pragma unroll
            for (int r2 = 0; r2 < 4; r2++) qv[r2] = Q[(ti * 4 + r2) * HDP + d];
            #pragma unroll
            for (int c2 = 0; c2 < 4; c2++) kv[c2] = Kx[(tj * 4 + c2) * HDP + d];
            #pragma unroll
            for (int r2 = 0; r2 < 4; r2++)
                #pragma unroll
                for (int c2 = 0; c2 < 4; c2++) acc[r2][c2] += qv[r2] * kv[c2];
        }
        #pragma unroll
        for (int r2 = 0; r2 < 4; r2++)
            #pragma unroll
            for (int c2 = 0; c2 < 4; c2++)
                SC[(ti * 4 + r2) * 64 + tj * 4 + c2] = acc[r2][c2] * scale;
    }
    __syncthreads();
    if (tid < 64) {
        float* row = SC + tid * 64;
        float mx = -1e30f;
        for (int j = 0; j < 64; j++) mx = fmaxf(mx, row[j]);
        float s = 0.f;
        for (int j = 0; j < 64; j++) { float e = expf(row[j] - mx); row[j] = e; s += e; }
        float inv = 1.f / s;
        for (int j = 0; j < 64; j++) row[j] *= inv;
    }
    __syncthreads();
    {
        int ti = tid >> 4, td = tid & 15;
        if (td < 14) {
            float oacc[4][7] = {};
            for (int j = 0; j < 64; j++) {
                float pr[4], vv[7];
                #pragma unroll
                for (int r2 = 0; r2 < 4; r2++) pr[r2] = SC[(ti * 4 + r2) * 64 + j];
                #pragma unroll
                for (int c2 = 0; c2 < 7; c2++) vv[c2] = V[j * HDP + td * 7 + c2];
                #pragma unroll
                for (int r2 = 0; r2 < 4; r2++)
                    #pragma unroll
                    for (int c2 = 0; c2 < 7; c2++) oacc[r2][c2] += pr[r2] * vv[c2];
            }
            #pragma unroll
            for (int r2 = 0; r2 < 4; r2++)
                #pragma unroll
                for (int c2 = 0; c2 < 7; c2++)
                    split_write_bf(oacc[r2][c2], ahi, alo,
                        ((size_t)(b * NTOK + ti * 4 + r2)) * Cdim + h * HD + td * 7 + c2);
        }
    }
}

// ---------------- BiFormer ----------------
#define BFQ_SMEM ((64*28 + 192*64)*4)  // 56320
__global__ void bf_qkv_kernel(const float* __restrict__ o,
                              const float* __restrict__ w, const float* __restrict__ bias) {
    extern __shared__ float bq[];
    float* xin = bq;             // [64][28]
    float* ws  = bq + 64 * 28;   // [192][64]
    int y = blockIdx.x, b = blockIdx.y;
    int tid = threadIdx.x;
    for (int e = tid; e < 192 * 64; e += 256) ws[e] = w[e];
    for (int e = tid; e < 64 * 28; e += 256) {
        int c = e / 28, xx = e % 28;
        xin[e] = o[((size_t)b * 64 + c) * 784 + y * 28 + xx];
    }
    __syncthreads();
    for (int e = tid; e < 192 * 28; e += 256) {
        int oc = e / 28, xx = e % 28;
        float a = bias[oc];
        const float* wr = ws + oc * 64;
        #pragma unroll 16
        for (int c = 0; c < 64; c++) a += xin[c * 28 + xx] * wr[c];
        g_bfqkv[((size_t)b * 192 + oc) * 784 + y * 28 + xx] = a;
    }
}

__global__ void bf_routing_kernel() {
    int b = blockIdx.x;
    int tid = threadIdx.x;  // 256
    __shared__ float qr[64][NREG];
    __shared__ float kr[64][NREG];
    __shared__ float ar[NREG][NREG];
    for (int e = tid; e < 64 * NREG; e += 256) {
        int c = e / NREG, r = e % NREG;
        int rh = r / 7, rw = r % 7;
        float sq = 0.f, sk = 0.f;
        const float* qc = g_bfqkv + ((size_t)b * 192 + c) * 784;
        const float* kc = g_bfqkv + ((size_t)b * 192 + 64 + c) * 784;
        #pragma unroll
        for (int pr = 0; pr < 4; pr++)
            #pragma unroll
            for (int pc = 0; pc < 4; pc++) {
                int s = (rh * 4 + pr) * 28 + rw * 4 + pc;
                sq += qc[s]; sk += kc[s];
            }
        qr[c][r] = sq * 0.0625f;
        kr[c][r] = sk * 0.0625f;
    }
    __syncthreads();
    for (int e = tid; e < NREG * NREG; e += 256) {
        int i = e / NREG, j = e % NREG;
        float a = 0.f;
        #pragma unroll 16
        for (int c = 0; c < 64; c++) a += qr[c][i] * kr[c][j];
        ar[i][j] = a;
    }
    __syncthreads();
    if (tid < NREG) {
        float* row = ar[tid];
        #pragma unroll
        for (int j = 0; j < TOPK; j++) {
            float mx = -1e30f; int mi = 0;
            for (int s = 0; s < NREG; s++) if (row[s] > mx) { mx = row[s]; mi = s; }
            row[mi] = -1e30f;
            g_idx[(b * NREG + tid) * TOPK + j] = mi;
        }
    }
}

__global__ void bf_attn_kernel() {
    int r = blockIdx.x, h = blockIdx.y, b = blockIdx.z;
    __shared__ float q[16][8], kg[64][9], vg[64][9];
    __shared__ float sc[16][65];
    __shared__ int idx4[4];
    int tid = threadIdx.x;  // 128
    if (tid < 4) idx4[tid] = g_idx[(b * NREG + r) * TOPK + tid];
    int rh = r / 7, rw = r % 7;
    {
        int p = tid / 8, d = tid % 8;
        int s = (rh * 4 + p / 4) * 28 + rw * 4 + (p % 4);
        q[p][d] = g_bfqkv[((size_t)b * 192 + h * 8 + d) * 784 + s] * 0.125f;
    }
    __syncthreads();
    for (int e = tid; e < 512; e += 128) {
        int t = e / 8, d = e % 8;
        int reg = idx4[t / 16];
        int p2 = t % 16;
        int s = ((reg / 7) * 4 + p2 / 4) * 28 + (reg % 7) * 4 + (p2 % 4);
        kg[t][d] = g_bfqkv[((size_t)b * 192 + 64 + h * 8 + d) * 784 + s];
        vg[t][d] = g_bfqkv[((size_t)b * 192 + 128 + h * 8 + d) * 784 + s];
    }
    __syncthreads();
    {
        int p = tid >> 3, tg = tid & 7;
        float qreg[8];
        #pragma unroll
        for (int d = 0; d < 8; d++) qreg[d] = q[p][d];
        #pragma unroll
        for (int tt = 0; tt < 8; tt++) {
            int t = tt * 8 + tg;
            float a = 0.f;
            #pragma unroll
            for (int d = 0; d < 8; d++) a += qreg[d] * kg[t][d];
            sc[p][t] = a;
        }
    }
    __syncthreads();
    if (tid < 16) {
        float mx = -1e30f;
        for (int t = 0; t < 64; t++) mx = fmaxf(mx, sc[tid][t]);
        float s = 0.f;
        for (int t = 0; t < 64; t++) { float e = expf(sc[tid][t] - mx); sc[tid][t] = e; s += e; }
        float inv = 1.f / s;
        for (int t = 0; t < 64; t++) sc[tid][t] *= inv;
    }
    __syncthreads();
    {
        int p = tid / 8, d = tid % 8;
        float a = 0.f;
        #pragma unroll 8
        for (int t = 0; t < 64; t++) a += sc[p][t] * vg[t][d];
        int s = (rh * 4 + p / 4) * 28 + rw * 4 + (p % 4);
        g_attg[((size_t)b * 64 + h * 8 + d) * 784 + s] = a;
    }
}

__global__ void bf_out_kernel(const float* __restrict__ lepe_w, const float* __restrict__ lepe_b,
                              const float* __restrict__ out_w, const float* __restrict__ out_b,
                              float* __restrict__ outp) {
    int y = blockIdx.x, b = blockIdx.y;
    __shared__ float v3[3][64][28];
    __shared__ float tmp[64][28];
    __shared__ float ws[64][64];
    __shared__ float lw[64][9];
    int tid = threadIdx.x;
    for (int e = tid; e < 64 * 64; e += blockDim.x) ws[e >> 6][e & 63] = out_w[e];
    for (int e = tid; e < 64 * 9; e += blockDim.x) lw[e / 9][e % 9] = lepe_w[e];
    for (int ry = 0; ry < 3; ry++) {
        int yy = y + ry - 1;
        for (int e = tid; e < 64 * 28; e += blockDim.x) {
            int c = e / 28, xx = e % 28;
            v3[ry][c][xx] = (yy >= 0 && yy < 28)
                ? g_bfqkv[((size_t)b * 192 + 128 + c) * 784 + yy * 28 + xx] : 0.f;
        }
    }
    __syncthreads();
    for (int e = tid; e < 64 * 28; e += blockDim.x) {
        int c = e / 28, xx = e % 28;
        float a = g_attg[((size_t)b * 64 + c) * 784 + y * 28 + xx] + lepe_b[c];
        #pragma unroll
        for (int ky = 0; ky < 3; ky++)
            #pragma unroll
            for (int kx = 0; kx < 3; kx++) {
                int xx2 = xx + kx - 1;
                if (xx2 >= 0 && xx2 < 28) a += v3[ky][c][xx2] * lw[c][ky * 3 + kx];
            }
        tmp[c][xx] = a;
    }
    __syncthreads();
    for (int e = tid; e < 64 * 28; e += blockDim.x) {
        int oc = e / 28, xx = e % 28;
        float a = out_b[oc];
        const float* wr = ws[oc];
        #pragma unroll 16
        for (int c = 0; c < 64; c++) a += tmp[c][xx] * wr[c];
        outp[((size_t)b * 64 + oc) * 784 + y * 28 + xx] = a;
    }
}

// ---------------- launch ----------------
extern "C" void kernel_launch(void* const* d_in, const int* in_sizes, int n_in,
                              void* d_out, int out_size) {
    (void)in_sizes; (void)n_in; (void)out_size;
    const float* x        = (const float*)d_in[0];
    const float* norm1_g  = (const float*)d_in[1];
    const float* norm1_b  = (const float*)d_in[2];
    const float* qkv_w    = (const float*)d_in[3];
    const float* proj_w   = (const float*)d_in[4];
    const float* proj_b   = (const float*)d_in[5];
    const float* norm2_g  = (const float*)d_in[6];
    const float* norm2_b  = (const float*)d_in[7];
    const float* fc1_w    = (const float*)d_in[8];
    const float* fc1_b    = (const float*)d_in[9];
    const float* fc2_w    = (const float*)d_in[10];
    const float* fc2_b    = (const float*)d_in[11];
    const float* bf_qkv_w = (const float*)d_in[12];
    const float* bf_qkv_b = (const float*)d_in[13];
    const float* bf_lepe_w= (const float*)d_in[14];
    const float* bf_lepe_b= (const float*)d_in[15];
    const float* bf_out_w = (const float*)d_in[16];
    const float* bf_out_b = (const float*)d_in[17];
    float* out = (float*)d_out;

    __nv_bfloat16 *p_h_hi, *p_h_lo, *p_att_hi, *p_att_lo;
    __nv_bfloat16 *p_wqkv_hi, *p_wqkv_lo, *p_wproj_hi, *p_wproj_lo;
    __half *p_h2, *p_hid, *p_wfc1, *p_wfc2;
    float *p_qkv, *p_o, *p_xr;
    cudaGetSymbolAddress((void**)&p_h_hi, g_h_hi);     cudaGetSymbolAddress((void**)&p_h_lo, g_h_lo);
    cudaGetSymbolAddress((void**)&p_att_hi, g_att_hi); cudaGetSymbolAddress((void**)&p_att_lo, g_att_lo);
    cudaGetSymbolAddress((void**)&p_h2, g_h2);
    cudaGetSymbolAddress((void**)&p_hid, g_hid);
    cudaGetSymbolAddress((void**)&p_wqkv_hi, g_wqkv_hi);   cudaGetSymbolAddress((void**)&p_wqkv_lo, g_wqkv_lo);
    cudaGetSymbolAddress((void**)&p_wproj_hi, g_wproj_hi); cudaGetSymbolAddress((void**)&p_wproj_lo, g_wproj_lo);
    cudaGetSymbolAddress((void**)&p_wfc1, g_wfc1);
    cudaGetSymbolAddress((void**)&p_wfc2, g_wfc2);
    cudaGetSymbolAddress((void**)&p_qkv, g_qkv);
    cudaGetSymbolAddress((void**)&p_o, g_o);
    cudaGetSymbolAddress((void**)&p_xr, g_xr);

    cudaFuncSetAttribute(mha_kernel, cudaFuncAttributeMaxDynamicSharedMemorySize, MHA_SMEM);
    cudaFuncSetAttribute(bf_qkv_kernel, cudaFuncAttributeMaxDynamicSharedMemorySize, BFQ_SMEM);
    cudaFuncSetAttribute(mma_gemm3<0>, cudaFuncAttributeMaxDynamicSharedMemorySize, GEMM3_SMEM);
    cudaFuncSetAttribute(mma_gemm3<1>, cudaFuncAttributeMaxDynamicSharedMemorySize, GEMM3_SMEM);
    cudaFuncSetAttribute(mma_gemm2<2>, cudaFuncAttributeMaxDynamicSharedMemorySize, GEMM2_SMEM);
    cudaFuncSetAttribute(mma_gemm2<3>, cudaFuncAttributeMaxDynamicSharedMemorySize, GEMM2_SMEM);

    static cudaStream_t s1 = nullptr;
    static cudaEvent_t eFork = nullptr, eW = nullptr, eO = nullptr, eBF = nullptr;
    if (!s1) {
        cudaStreamCreateWithFlags(&s1, cudaStreamNonBlocking);
        cudaEventCreateWithFlags(&eFork, cudaEventDisableTiming);
        cudaEventCreateWithFlags(&eW,    cudaEventDisableTiming);
        cudaEventCreateWithFlags(&eO,    cudaEventDisableTiming);
        cudaEventCreateWithFlags(&eBF,   cudaEventDisableTiming);
    }

    // s0: LN1 (#1) and qkv split (#2) — gemm3 depends on both via stream order
    ln_kernel<<<ROWS, 256>>>(x, norm1_g, norm1_b, p_h_hi, p_h_lo);
    split_bf_kernel<<<(Cdim * 3 * Cdim / 4 + 255) / 256, 256>>>(qkv_w, p_wqkv_hi, p_wqkv_lo, Cdim * 3 * Cdim / 4);

    // fork
    cudaEventRecord(eFork, 0);
    cudaStreamWaitEvent(s1, eFork, 0);

    // s1: proj split (#3)
    split_bf_kernel<<<(Cdim * Cdim / 4 + 255) / 256, 256, 0, s1>>>(proj_w, p_wproj_hi, p_wproj_lo, Cdim * Cdim / 4);

    // s0: qkv GEMM (#4 — ncu capture target)
    mma_gemm3<0><<<dim3((3 * Cdim + 127) / 128, ROWS / 128), 256, GEMM3_SMEM>>>(
        p_h_hi, p_h_lo, p_wqkv_hi, p_wqkv_lo, nullptr,
        p_qkv, ROWS, 3 * Cdim, Cdim);

    // s1: fc weight converts (#5, #6) — overlap with qkv GEMM
    conv_fp_kernel<<<(Cdim * HID / 4 + 255) / 256, 256, 0, s1>>>(fc1_w, p_wfc1, Cdim * HID / 4);
    conv_fp_kernel<<<(HID * Cdim / 4 + 255) / 256, 256, 0, s1>>>(fc2_w, p_wfc2, HID * Cdim / 4);
    cudaEventRecord(eW, s1);

    // s0: MHA, proj
    mha_kernel<<<dim3(NHd, Bsz), 256, MHA_SMEM>>>(p_qkv, p_att_hi, p_att_lo);
    cudaStreamWaitEvent(0, eW, 0);
    mma_gemm3<1><<<dim3((Cdim + 127) / 128, ROWS / 128), 256, GEMM3_SMEM>>>(
        p_att_hi, p_att_lo, p_wproj_hi, p_wproj_lo, proj_b,
        p_o, ROWS, Cdim, Cdim);
    cudaEventRecord(eO, 0);

    // s1: BiFormer branch
    cudaStreamWaitEvent(s1, eO, 0);
    bf_qkv_kernel<<<dim3(28, Bsz), 256, BFQ_SMEM, s1>>>(p_o, bf_qkv_w, bf_qkv_b);
    bf_routing_kernel<<<Bsz, 256, 0, s1>>>();
    bf_attn_kernel<<<dim3(NREG, 8, Bsz), 128, 0, s1>>>();
    bf_out_kernel<<<dim3(28, Bsz), 256, 0, s1>>>(bf_lepe_w, bf_lepe_b, bf_out_w, bf_out_b, out + OUT_OFF);
    cudaEventRecord(eBF, s1);

    // s0: MLP branch
    ln2_kernel<<<ROWS, 256>>>(p_o, x, norm2_g, norm2_b, p_xr, p_h2);
    mma_gemm2<2><<<dim3((HID + 127) / 128, ROWS / 128), 256, GEMM2_SMEM>>>(
        p_h2, p_wfc1, fc1_b, nullptr,
        nullptr, p_hid, ROWS, HID, Cdim);
    mma_gemm2<3><<<dim3((Cdim + 127) / 128, ROWS / 128), 256, GEMM2_SMEM>>>(
        p_hid, p_wfc2, fc2_b, p_xr,
        out, nullptr, ROWS, Cdim, HID);

    // join
    cudaStreamWaitEvent(0, eBF, 0);
}